// round 1
// baseline (speedup 1.0000x reference)
#include <cuda_runtime.h>
#include <cuda_bf16.h>
#include <math.h>

// Problem constants
// B=64, T=1024, DIN=5, D=64, H=8, DH=8, NLOCAL=4, WS=128, DEPTH=2
#define NB 64
#define NT 1024
#define NDIN 5
#define ND 64
#define NTOK (NB*NT)           // 65536

// ---------------- scratch (static device allocations; no cudaMalloc) ----------
__device__ float g_h[NTOK*ND];        // 16 MB  running hidden state
__device__ float g_tmp[NTOK*ND];      // 16 MB  pre-conv h / layernormed x
__device__ float g_q[NTOK*ND];        // 16 MB  [b][h][t][dh]
__device__ float g_k[NTOK*ND];
__device__ float g_v[NTOK*ND];
__device__ float g_attn[NTOK*ND];     // 16 MB  [b][t][h*8+dh]
__device__ float g_y[NTOK*ND*4];      // 64 MB  FFN intermediate
__device__ float g_Wc[NDIN*ND];       // combined expand@emb weight
__device__ float g_bc[ND];            // combined bias

// ---------------- precompute combined expand+emb ------------------------------
__global__ void precompute_kernel(const float* __restrict__ ew, const float* __restrict__ eb,
                                  const float* __restrict__ mw, const float* __restrict__ mb,
                                  float* __restrict__ Wc, float* __restrict__ bc) {
    int j = threadIdx.x;             // 64 threads
    for (int i = 0; i < NDIN; i++) {
        float s = 0.f;
        for (int d = 0; d < ND; d++) s += ew[i*ND + d] * mw[d*ND + j];
        Wc[i*ND + j] = s;
    }
    float s = mb[j];
    for (int d = 0; d < ND; d++) s += eb[d] * mw[d*ND + j];
    bc[j] = s;
}

// ---------------- expand: x(.,5) @ Wc(5,64) + bc -> g_tmp ----------------------
__global__ void expand_kernel(const float* __restrict__ x, const float* __restrict__ Wc,
                              const float* __restrict__ bc, float* __restrict__ out) {
    __shared__ float Xs[64][NDIN];
    __shared__ float Ws[NDIN][ND];
    __shared__ float Bs[ND];
    int tid = threadIdx.x;                 // 256
    int row0 = blockIdx.x * 64;
    for (int idx = tid; idx < 64*NDIN; idx += 256) Xs[idx/NDIN][idx%NDIN] = x[row0*NDIN + idx];
    for (int idx = tid; idx < NDIN*ND; idx += 256) Ws[idx>>6][idx&63] = Wc[idx];
    if (tid < ND) Bs[tid] = bc[tid];
    __syncthreads();
    int r = tid >> 2, c = (tid & 3) * 16;
    float acc[16];
#pragma unroll
    for (int j = 0; j < 16; j++) acc[j] = Bs[c+j];
#pragma unroll
    for (int i = 0; i < NDIN; i++) {
        float xv = Xs[r][i];
#pragma unroll
        for (int j = 0; j < 16; j++) acc[j] += xv * Ws[i][c+j];
    }
#pragma unroll
    for (int j = 0; j < 16; j++) out[(row0+r)*ND + c + j] = acc[j];
}

// ---------------- conv as GEMM: C[to][(b,d)] = sum_{ti,k} W[to,ti,k]*hpad ------
// A = conv_w row-major (1024 x 3072); B gathered on the fly from g_tmp.
// epilogue: + conv_b[to] + pos_emb[to][d]; output g_h[b][to][d]
__global__ void conv_kernel(const float* __restrict__ A, const float* __restrict__ Hin,
                            const float* __restrict__ conv_b, const float* __restrict__ pos_emb,
                            float* __restrict__ Hout) {
    __shared__ float As[64][17];
    __shared__ float Bs[16][68];
    int tid = threadIdx.x;                 // 256
    int m0 = blockIdx.y * 64;              // to-tile
    int n0 = blockIdx.x * 64;              // (b,d)-tile
    int tm = (tid >> 4) * 4, tn = (tid & 15) * 4;
    float acc[4][4] = {};
    for (int k0 = 0; k0 < 3072; k0 += 16) {
        for (int idx = tid; idx < 64*16; idx += 256) {
            int i = idx >> 4, kk = idx & 15;
            As[i][kk] = A[(m0 + i)*3072 + k0 + kk];
        }
        for (int idx = tid; idx < 16*64; idx += 256) {
            int kk = idx >> 6, j = idx & 63;
            int K = k0 + kk;
            int ti = K / 3, kp = K - ti*3;
            int n = n0 + j;
            int b = n >> 6, d = (n & 63) + kp - 1;
            float val = 0.f;
            if (d >= 0 && d < ND) val = Hin[((b << 10) + ti)*ND + d];
            Bs[kk][j] = val;
        }
        __syncthreads();
#pragma unroll
        for (int kk = 0; kk < 16; kk++) {
            float a[4], bb[4];
#pragma unroll
            for (int i = 0; i < 4; i++) a[i] = As[tm+i][kk];
#pragma unroll
            for (int j = 0; j < 4; j++) bb[j] = Bs[kk][tn+j];
#pragma unroll
            for (int i = 0; i < 4; i++)
#pragma unroll
                for (int j = 0; j < 4; j++) acc[i][j] += a[i] * bb[j];
        }
        __syncthreads();
    }
#pragma unroll
    for (int i = 0; i < 4; i++) {
        int to = m0 + tm + i;
        float cb = conv_b[to];
#pragma unroll
        for (int j = 0; j < 4; j++) {
            int n = n0 + tn + j;
            int b = n >> 6, d = n & 63;
            Hout[((b << 10) + to)*ND + d] = acc[i][j] + cb + pos_emb[to*ND + d];
        }
    }
}

// ---------------- layernorm: 1 warp per token --------------------------------
__global__ void ln_kernel(const float* __restrict__ in, const float* __restrict__ s,
                          const float* __restrict__ b, float* __restrict__ out) {
    int warp = threadIdx.x >> 5, lane = threadIdx.x & 31;
    int tok = blockIdx.x * 8 + warp;
    const float* row = in + (long)tok * ND;
    float a0 = row[2*lane], a1 = row[2*lane+1];
    float sum = a0 + a1;
#pragma unroll
    for (int o = 16; o; o >>= 1) sum += __shfl_xor_sync(~0u, sum, o);
    float mu = sum * (1.f/64.f);
    float d0 = a0 - mu, d1 = a1 - mu;
    float vs = d0*d0 + d1*d1;
#pragma unroll
    for (int o = 16; o; o >>= 1) vs += __shfl_xor_sync(~0u, vs, o);
    float inv = rsqrtf(vs * (1.f/64.f) + 1e-5f);
    out[(long)tok*ND + 2*lane]   = d0*inv*s[2*lane]   + b[2*lane];
    out[(long)tok*ND + 2*lane+1] = d1*inv*s[2*lane+1] + b[2*lane+1];
}

// ---------------- generic 64x64 token GEMM -----------------------------------
// MODE 0: out[tok][j] = X@W + bias? + resid?       (plain layout)
// MODE 1: out in head layout [b][h][t][dh]
template<int MODE>
__global__ void gemm64_kernel(const float* __restrict__ X, const float* __restrict__ W,
                              const float* __restrict__ bias, const float* __restrict__ resid,
                              float* __restrict__ out) {
    __shared__ float Xs[64][65];
    __shared__ float Ws[64][64];
    int tid = threadIdx.x;                 // 256
    int row0 = blockIdx.x * 64;
    for (int idx = tid; idx < 4096; idx += 256) {
        int i = idx >> 6, j = idx & 63;
        Xs[i][j] = X[(row0 + i)*ND + j];
        Ws[i][j] = W[idx];
    }
    __syncthreads();
    int r = tid >> 2, c = (tid & 3) * 16;
    float acc[16] = {};
    for (int kk = 0; kk < 64; kk++) {
        float xv = Xs[r][kk];
#pragma unroll
        for (int j = 0; j < 16; j++) acc[j] += xv * Ws[kk][c+j];
    }
    int gt = row0 + r;
    if (MODE == 0) {
#pragma unroll
        for (int j = 0; j < 16; j++) {
            float vv = acc[j];
            if (bias)  vv += bias[c+j];
            if (resid) vv += resid[gt*ND + c + j];
            out[gt*ND + c + j] = vv;
        }
    } else {
        int b = gt >> 10, t = gt & 1023;
#pragma unroll
        for (int j = 0; j < 16; j++) {
            int col = c + j;
            int hh = col >> 3, dh = col & 7;
            out[(((b*8 + hh)*1024) + t)*8 + dh] = acc[j];
        }
    }
}

// ---------------- local windowed attention (heads 0..3) ----------------------
__global__ void local_attn_kernel(const float* __restrict__ q, const float* __restrict__ k,
                                  const float* __restrict__ v, float* __restrict__ attn) {
    int bid = blockIdx.x;                  // b*32 + h*8 + w
    int w = bid & 7, h = (bid >> 3) & 3, b = bid >> 5;
    __shared__ float Ks[384][8];
    __shared__ float Vs[384][8];
    int tid = threadIdx.x;                 // 128
    int base = ((b*8 + h)*1024) * 8;
    int jlo = (w == 0) ? 128 : 0;
    int jhi = (w == 7) ? 256 : 384;
    for (int idx = tid; idx < 384*8; idx += 128) {
        int j = idx >> 3, e = idx & 7;
        int tt = (w - 1)*128 + j;
        float kv = 0.f, vv = 0.f;
        if (tt >= 0 && tt < 1024) { kv = k[base + tt*8 + e]; vv = v[base + tt*8 + e]; }
        Ks[j][e] = kv; Vs[j][e] = vv;
    }
    __syncthreads();
    int t = w*128 + tid;
    float qr[8];
#pragma unroll
    for (int e = 0; e < 8; e++) qr[e] = q[base + t*8 + e];
    const float scale = 0.35355339059327373f;   // 1/sqrt(8)
    float m = -1e30f, l = 0.f, acc[8] = {};
    for (int j = jlo; j < jhi; j++) {
        float s = 0.f;
#pragma unroll
        for (int e = 0; e < 8; e++) s += qr[e] * Ks[j][e];
        s *= scale;
        float mn = fmaxf(m, s);
        float corr = __expf(m - mn);
        float p = __expf(s - mn);
        l = l*corr + p;
#pragma unroll
        for (int e = 0; e < 8; e++) acc[e] = acc[e]*corr + p*Vs[j][e];
        m = mn;
    }
    float inv = 1.f / l;
    int ob = ((b*1024 + t)*64) + h*8;
#pragma unroll
    for (int e = 0; e < 8; e++) attn[ob + e] = acc[e]*inv;
}

// ---------------- global linear attention (heads 4..7) -----------------------
__global__ void global_attn_kernel(const float* __restrict__ q, const float* __restrict__ k,
                                   const float* __restrict__ v, float* __restrict__ attn) {
    int b = blockIdx.x >> 2, h = blockIdx.x & 3;
    int tid = threadIdx.x;                 // 256
    int base = ((b*8 + 4 + h)*1024) * 8;
    __shared__ float red[8][72];
    __shared__ float M[8];
    __shared__ float C[64];
    int warp = tid >> 5, lane = tid & 31;

    // pass 1: per-d max over tokens
    float mx[8];
#pragma unroll
    for (int d = 0; d < 8; d++) mx[d] = -1e30f;
    for (int t = tid; t < 1024; t += 256) {
#pragma unroll
        for (int d = 0; d < 8; d++) mx[d] = fmaxf(mx[d], k[base + t*8 + d]);
    }
#pragma unroll
    for (int d = 0; d < 8; d++)
        for (int o = 16; o; o >>= 1) mx[d] = fmaxf(mx[d], __shfl_xor_sync(~0u, mx[d], o));
    if (lane == 0)
        for (int d = 0; d < 8; d++) red[warp][d] = mx[d];
    __syncthreads();
    if (tid < 8) {
        float m_ = red[0][tid];
        for (int wv = 1; wv < 8; wv++) m_ = fmaxf(m_, red[wv][tid]);
        M[tid] = m_;
    }
    __syncthreads();

    // pass 2: Z_d and ctx[d][e]
    float Z[8] = {}, ctx[64] = {};
    for (int t = tid; t < 1024; t += 256) {
        float kr[8], vr[8];
#pragma unroll
        for (int e = 0; e < 8; e++) { kr[e] = k[base + t*8 + e]; vr[e] = v[base + t*8 + e]; }
#pragma unroll
        for (int d = 0; d < 8; d++) {
            float e_ = __expf(kr[d] - M[d]);
            Z[d] += e_;
#pragma unroll
            for (int e = 0; e < 8; e++) ctx[d*8 + e] += e_ * vr[e];
        }
    }
#pragma unroll
    for (int i = 0; i < 8; i++)
        for (int o = 16; o; o >>= 1) Z[i] += __shfl_xor_sync(~0u, Z[i], o);
#pragma unroll
    for (int i = 0; i < 64; i++)
        for (int o = 16; o; o >>= 1) ctx[i] += __shfl_xor_sync(~0u, ctx[i], o);
    if (lane == 0) {
        for (int i = 0; i < 8; i++)  red[warp][i] = Z[i];
        for (int i = 0; i < 64; i++) red[warp][8 + i] = ctx[i];
    }
    __syncthreads();
    if (tid < 64) {
        float s = 0.f, z = 0.f;
        int d = tid >> 3;
        for (int wv = 0; wv < 8; wv++) { s += red[wv][8 + tid]; z += red[wv][d]; }
        C[tid] = s / z;
    }
    __syncthreads();

    // pass 3: softmax(q over dh)*scale @ C
    const float scale = 0.35355339059327373f;
    for (int t = tid; t < 1024; t += 256) {
        float qr[8]; float qm = -1e30f;
#pragma unroll
        for (int d = 0; d < 8; d++) { qr[d] = q[base + t*8 + d]; qm = fmaxf(qm, qr[d]); }
        float qs = 0.f;
#pragma unroll
        for (int d = 0; d < 8; d++) { qr[d] = __expf(qr[d] - qm); qs += qr[d]; }
        float inv = scale / qs;
        float o_[8] = {};
#pragma unroll
        for (int d = 0; d < 8; d++) {
            float p = qr[d] * inv;
#pragma unroll
            for (int e = 0; e < 8; e++) o_[e] += p * C[d*8 + e];
        }
        int ob = (b*1024 + t)*64 + (4 + h)*8;
#pragma unroll
        for (int e = 0; e < 8; e++) attn[ob + e] = o_[e];
    }
}

// ---------------- FFN1: X(.,64) @ W1(64,256) + b1 -> gelu -> Y ----------------
__global__ void ffn1_kernel(const float* __restrict__ X, const float* __restrict__ W1,
                            const float* __restrict__ b1, float* __restrict__ Y) {
    __shared__ float Xs[64][65];
    __shared__ float Ws[64][64];
    int tid = threadIdx.x, row0 = blockIdx.x * 64, c0 = blockIdx.y * 64;
    for (int idx = tid; idx < 4096; idx += 256) {
        int i = idx >> 6, j = idx & 63;
        Xs[i][j] = X[(row0 + i)*ND + j];
        Ws[i][j] = W1[i*256 + c0 + j];
    }
    __syncthreads();
    int r = tid >> 2, c = (tid & 3) * 16;
    float acc[16] = {};
    for (int kk = 0; kk < 64; kk++) {
        float xv = Xs[r][kk];
#pragma unroll
        for (int j = 0; j < 16; j++) acc[j] += xv * Ws[kk][c+j];
    }
    int gt = row0 + r;
#pragma unroll
    for (int j = 0; j < 16; j++) {
        float z = acc[j] + b1[c0 + c + j];
        float g = 0.5f * z * (1.f + erff(z * 0.70710678118654752f));
        Y[(long)gt*256 + c0 + c + j] = g;
    }
}

// ---------------- FFN2: Y(.,256) @ W2(256,64) + b2 + resid -> h ---------------
__global__ void ffn2_kernel(const float* __restrict__ Y, const float* __restrict__ W2,
                            const float* __restrict__ b2, const float* __restrict__ resid,
                            float* __restrict__ out) {
    __shared__ float Ys[64][65];
    __shared__ float Ws[64][64];
    int tid = threadIdx.x, row0 = blockIdx.x * 64;
    int r = tid >> 2, c = (tid & 3) * 16;
    float acc[16] = {};
    for (int kc = 0; kc < 4; kc++) {
        __syncthreads();
        for (int idx = tid; idx < 4096; idx += 256) {
            int i = idx >> 6, j = idx & 63;
            Ys[i][j] = Y[(long)(row0 + i)*256 + kc*64 + j];
            Ws[i][j] = W2[(kc*64 + i)*64 + j];
        }
        __syncthreads();
        for (int kk = 0; kk < 64; kk++) {
            float yv = Ys[r][kk];
#pragma unroll
            for (int j = 0; j < 16; j++) acc[j] += yv * Ws[kk][c+j];
        }
    }
    int gt = row0 + r;
#pragma unroll
    for (int j = 0; j < 16; j++)
        out[gt*ND + c + j] = acc[j] + b2[c+j] + resid[gt*ND + c + j];
}

// ---------------- collapse: h(.,64) @ cw(64,5) + cb -> out --------------------
__global__ void collapse_kernel(const float* __restrict__ h, const float* __restrict__ cw,
                                const float* __restrict__ cb, float* __restrict__ out) {
    __shared__ float Xs[64][65];
    __shared__ float Ws[64][NDIN];
    __shared__ float Bs[NDIN];
    int tid = threadIdx.x;                 // 64
    int row0 = blockIdx.x * 64;
    for (int idx = tid; idx < 4096; idx += 64) {
        int i = idx >> 6, j = idx & 63;
        Xs[i][j] = h[(row0 + i)*ND + j];
    }
    for (int idx = tid; idx < 64*NDIN; idx += 64) Ws[idx/NDIN][idx%NDIN] = cw[idx];
    if (tid < NDIN) Bs[tid] = cb[tid];
    __syncthreads();
    int r = tid;
    float acc[NDIN];
#pragma unroll
    for (int j = 0; j < NDIN; j++) acc[j] = Bs[j];
    for (int kk = 0; kk < 64; kk++) {
        float xv = Xs[r][kk];
#pragma unroll
        for (int j = 0; j < NDIN; j++) acc[j] += xv * Ws[kk][j];
    }
#pragma unroll
    for (int j = 0; j < NDIN; j++) out[(row0 + r)*NDIN + j] = acc[j];
}

// ---------------- launch ------------------------------------------------------
extern "C" void kernel_launch(void* const* d_in, const int* in_sizes, int n_in,
                              void* d_out, int out_size) {
    const float* x          = (const float*)d_in[0];
    const float* pos_emb    = (const float*)d_in[1];
    const float* expand_w   = (const float*)d_in[2];
    const float* expand_b   = (const float*)d_in[3];
    const float* emb_w      = (const float*)d_in[4];
    const float* emb_b      = (const float*)d_in[5];
    const float* conv_w     = (const float*)d_in[6];
    const float* conv_b     = (const float*)d_in[7];
    const float* ln1_s      = (const float*)d_in[8];
    const float* ln1_b      = (const float*)d_in[9];
    const float* wq         = (const float*)d_in[10];
    const float* wk         = (const float*)d_in[11];
    const float* wv         = (const float*)d_in[12];
    const float* wo         = (const float*)d_in[13];
    const float* wo_b       = (const float*)d_in[14];
    const float* ln2_s      = (const float*)d_in[15];
    const float* ln2_b      = (const float*)d_in[16];
    const float* ff_w1      = (const float*)d_in[17];
    const float* ff_b1      = (const float*)d_in[18];
    const float* ff_w2      = (const float*)d_in[19];
    const float* ff_b2      = (const float*)d_in[20];
    const float* collapse_w = (const float*)d_in[21];
    const float* collapse_b = (const float*)d_in[22];
    float* out = (float*)d_out;

    float *ph, *ptmp, *pq, *pk, *pv, *pattn, *py, *pWc, *pbc;
    cudaGetSymbolAddress((void**)&ph,   g_h);
    cudaGetSymbolAddress((void**)&ptmp, g_tmp);
    cudaGetSymbolAddress((void**)&pq,   g_q);
    cudaGetSymbolAddress((void**)&pk,   g_k);
    cudaGetSymbolAddress((void**)&pv,   g_v);
    cudaGetSymbolAddress((void**)&pattn,g_attn);
    cudaGetSymbolAddress((void**)&py,   g_y);
    cudaGetSymbolAddress((void**)&pWc,  g_Wc);
    cudaGetSymbolAddress((void**)&pbc,  g_bc);

    precompute_kernel<<<1, 64>>>(expand_w, expand_b, emb_w, emb_b, pWc, pbc);
    expand_kernel<<<NTOK/64, 256>>>(x, pWc, pbc, ptmp);
    conv_kernel<<<dim3(64, 16), 256>>>(conv_w, ptmp, conv_b, pos_emb, ph);

    for (int l = 0; l < 2; l++) {
        ln_kernel<<<NTOK/8, 256>>>(ph, ln1_s + l*64, ln1_b + l*64, ptmp);
        gemm64_kernel<1><<<NTOK/64, 256>>>(ptmp, wq + l*4096, nullptr, nullptr, pq);
        gemm64_kernel<1><<<NTOK/64, 256>>>(ptmp, wk + l*4096, nullptr, nullptr, pk);
        gemm64_kernel<1><<<NTOK/64, 256>>>(ptmp, wv + l*4096, nullptr, nullptr, pv);
        local_attn_kernel<<<NB*4*8, 128>>>(pq, pk, pv, pattn);
        global_attn_kernel<<<NB*4, 256>>>(pq, pk, pv, pattn);
        gemm64_kernel<0><<<NTOK/64, 256>>>(pattn, wo + l*4096, wo_b + l*64, ph, ph);
        ln_kernel<<<NTOK/8, 256>>>(ph, ln2_s + l*64, ln2_b + l*64, ptmp);
        ffn1_kernel<<<dim3(NTOK/64, 4), 256>>>(ptmp, ff_w1 + l*64*256, ff_b1 + l*256, py);
        ffn2_kernel<<<NTOK/64, 256>>>(py, ff_w2 + l*256*64, ff_b2 + l*64, ph, ph);
    }
    collapse_kernel<<<NTOK/64, 64>>>(ph, collapse_w, collapse_b, out);
}

// round 2
// speedup vs baseline: 1.1577x; 1.1577x over previous
#include <cuda_runtime.h>
#include <cuda_bf16.h>
#include <math.h>

// Problem constants: B=64, T=1024, DIN=5, D=64, H=8, DH=8, NLOCAL=4, WS=128, DEPTH=2
#define NB 64
#define NT 1024
#define NDIN 5
#define ND 64
#define NTOK (NB*NT)           // 65536

// ---------------- scratch (static device buffers) -----------------------------
__device__ float g_h[NTOK*ND];          // running hidden state
__device__ float g_hpad[NTOK*66];       // padded pre-conv activations (cols 0 and 65 stay zero forever)
__device__ float g_tmp[NTOK*ND];        // layernormed x
__device__ float g_q[NTOK*ND];          // [b][h][t][dh]
__device__ float g_k[NTOK*ND];
__device__ float g_v[NTOK*ND];
__device__ float g_attn[NTOK*ND];       // [b][t][h*8+dh]
__device__ float g_y[NTOK*ND*4];        // FFN intermediate
__device__ float g_Wc[NDIN*ND];
__device__ float g_bc[ND];

// ---------------- precompute combined expand@emb ------------------------------
__global__ void precompute_kernel(const float* __restrict__ ew, const float* __restrict__ eb,
                                  const float* __restrict__ mw, const float* __restrict__ mb,
                                  float* __restrict__ Wc, float* __restrict__ bc) {
    int j = threadIdx.x;             // 64 threads
    for (int i = 0; i < NDIN; i++) {
        float s = 0.f;
        for (int d = 0; d < ND; d++) s += ew[i*ND + d] * mw[d*ND + j];
        Wc[i*ND + j] = s;
    }
    float s = mb[j];
    for (int d = 0; d < ND; d++) s += eb[d] * mw[d*ND + j];
    bc[j] = s;
}

// ---------------- expand: x(.,5) @ Wc(5,64) + bc -> g_hpad (stride 66, off 1) --
__global__ void expand_kernel(const float* __restrict__ x, const float* __restrict__ Wc,
                              const float* __restrict__ bc, float* __restrict__ out) {
    __shared__ float Xs[64][NDIN];
    __shared__ float Ws[NDIN][ND];
    __shared__ float Bs[ND];
    int tid = threadIdx.x;                 // 256
    int row0 = blockIdx.x * 64;
    for (int idx = tid; idx < 64*NDIN; idx += 256) Xs[idx/NDIN][idx%NDIN] = x[row0*NDIN + idx];
    for (int idx = tid; idx < NDIN*ND; idx += 256) Ws[idx>>6][idx&63] = Wc[idx];
    if (tid < ND) Bs[tid] = bc[tid];
    __syncthreads();
    int r = tid >> 2, c = (tid & 3) * 16;
    float acc[16];
#pragma unroll
    for (int j = 0; j < 16; j++) acc[j] = Bs[c+j];
#pragma unroll
    for (int i = 0; i < NDIN; i++) {
        float xv = Xs[r][i];
#pragma unroll
        for (int j = 0; j < 16; j++) acc[j] += xv * Ws[i][c+j];
    }
    float* orow = out + (long)(row0+r)*66 + 1 + c;
#pragma unroll
    for (int j = 0; j < 16; j++) orow[j] = acc[j];
}

// ---------------- conv as GEMM: C = conv_w(1024x3072) @ Bgather(3072x4096) ----
// B[K=(ti,kp)][n=(b,d)] = Hpad[(b*1024+ti)*66 + d + kp]   (zero pads built in)
// epilogue: + conv_b[to] + pos_emb[to][d]; output g_h[b][to][d]
#define CBM 128
#define CBN 128
#define CBK 24
__global__ __launch_bounds__(256) void conv_kernel(
        const float* __restrict__ A, const float* __restrict__ Hpad,
        const float* __restrict__ conv_b, const float* __restrict__ pos_emb,
        float* __restrict__ Hout) {
    __shared__ float As[CBK][CBM];
    __shared__ float Bs[CBK][CBN];
    int tid = threadIdx.x;                 // 256
    int m0 = blockIdx.y * CBM;             // to-tile
    int n0 = blockIdx.x * CBN;             // (b,d)-tile
    int tx = tid & 15, ty = tid >> 4;
    int tm = ty * 8, tn = tx * 8;
    float acc[8][8] = {};
    int arow = tid >> 1;
    int aq = (tid & 1) * 3;
    int bhi = tid >> 7;                    // 0/1: upper bit of kk in B loads

    for (int k0 = 0; k0 < 3072; k0 += CBK) {
        // --- A tile: 128 rows x 24 cols, float4 global loads, transposed to smem
        const float4* Arow4 = (const float4*)(A + (m0 + arow)*3072 + k0);
#pragma unroll
        for (int u = 0; u < 3; u++) {
            float4 va = Arow4[aq + u];
            int kk = (aq + u) * 4;
            As[kk+0][arow] = va.x; As[kk+1][arow] = va.y;
            As[kk+2][arow] = va.z; As[kk+3][arow] = va.w;
        }
        // --- B tile: 24 x 128 gathered from padded activations
        int ti0 = k0 / 3;
        int j = tid & 127;
        int b = (n0 >> 6) + (j >> 6);
        long rowb = ((long)(b << 10)) * 66;
        int dcol = j & 63;
#pragma unroll
        for (int u = 0; u < 12; u++) {
            int kk = 2*u + bhi;
            int kt = kk / 3, kp = kk - kt*3;
            Bs[kk][j] = Hpad[rowb + (long)(ti0 + kt)*66 + dcol + kp];
        }
        __syncthreads();
#pragma unroll
        for (int kk = 0; kk < CBK; kk++) {
            float4 a0 = *(const float4*)&As[kk][tm];
            float4 a1 = *(const float4*)&As[kk][tm+4];
            float4 b0 = *(const float4*)&Bs[kk][tn];
            float4 b1 = *(const float4*)&Bs[kk][tn+4];
            float av[8] = {a0.x,a0.y,a0.z,a0.w,a1.x,a1.y,a1.z,a1.w};
            float bv[8] = {b0.x,b0.y,b0.z,b0.w,b1.x,b1.y,b1.z,b1.w};
#pragma unroll
            for (int i = 0; i < 8; i++)
#pragma unroll
                for (int jj = 0; jj < 8; jj++) acc[i][jj] += av[i] * bv[jj];
        }
        __syncthreads();
    }
    // epilogue
    int bo = (n0 + tn) >> 6;
    int d0 = tn & 63;
#pragma unroll
    for (int i = 0; i < 8; i++) {
        int to = m0 + tm + i;
        float cb = conv_b[to];
        const float4* prow = (const float4*)(pos_emb + to*64 + d0);
        float4 p0 = prow[0], p1 = prow[1];
        float4 o0, o1;
        o0.x = acc[i][0]+cb+p0.x; o0.y = acc[i][1]+cb+p0.y;
        o0.z = acc[i][2]+cb+p0.z; o0.w = acc[i][3]+cb+p0.w;
        o1.x = acc[i][4]+cb+p1.x; o1.y = acc[i][5]+cb+p1.y;
        o1.z = acc[i][6]+cb+p1.z; o1.w = acc[i][7]+cb+p1.w;
        float4* orow = (float4*)(Hout + ((long)(bo << 10) + to)*64 + d0);
        orow[0] = o0; orow[1] = o1;
    }
}

// ---------------- layernorm: 1 warp per token --------------------------------
__global__ void ln_kernel(const float* __restrict__ in, const float* __restrict__ s,
                          const float* __restrict__ b, float* __restrict__ out) {
    int warp = threadIdx.x >> 5, lane = threadIdx.x & 31;
    int tok = blockIdx.x * 8 + warp;
    const float2 aa = *(const float2*)(in + (long)tok * ND + 2*lane);
    float sum = aa.x + aa.y;
#pragma unroll
    for (int o = 16; o; o >>= 1) sum += __shfl_xor_sync(~0u, sum, o);
    float mu = sum * (1.f/64.f);
    float d0 = aa.x - mu, d1 = aa.y - mu;
    float vs = d0*d0 + d1*d1;
#pragma unroll
    for (int o = 16; o; o >>= 1) vs += __shfl_xor_sync(~0u, vs, o);
    float inv = rsqrtf(vs * (1.f/64.f) + 1e-5f);
    float2 ss = *(const float2*)(s + 2*lane);
    float2 bb = *(const float2*)(b + 2*lane);
    float2 o2; o2.x = d0*inv*ss.x + bb.x; o2.y = d1*inv*ss.y + bb.y;
    *(float2*)(out + (long)tok*ND + 2*lane) = o2;
}

// ---------------- fused QKV GEMM: X(64tok,64) @ {Wq,Wk,Wv} -> head layout -----
__global__ void qkv_kernel(const float* __restrict__ X,
                           const float* __restrict__ Wq, const float* __restrict__ Wk,
                           const float* __restrict__ Wv,
                           float* __restrict__ q, float* __restrict__ k, float* __restrict__ v) {
    __shared__ float Xs[64][65];
    __shared__ float Ws[64][64];
    int tid = threadIdx.x;                 // 256
    int row0 = blockIdx.x * 64;
    for (int idx = tid; idx < 1024; idx += 256) {
        int i = idx >> 4, j = (idx & 15) * 4;
        float4 xv = *(const float4*)(X + (row0 + i)*ND + j);
        Xs[i][j] = xv.x; Xs[i][j+1] = xv.y; Xs[i][j+2] = xv.z; Xs[i][j+3] = xv.w;
    }
    int r = tid >> 2, c = (tid & 3) * 16;
    int gt = row0 + r;
    int bb = gt >> 10, t = gt & 1023;
    const float* Wm[3] = {Wq, Wk, Wv};
    float* Om[3] = {q, k, v};
#pragma unroll
    for (int m = 0; m < 3; m++) {
        __syncthreads();
        const float* W = Wm[m];
        for (int idx = tid; idx < 1024; idx += 256) {
            *(float4*)&Ws[idx >> 4][(idx & 15)*4] = *(const float4*)(W + idx*4);
        }
        __syncthreads();
        float acc[16] = {};
        for (int kk = 0; kk < 64; kk++) {
            float xv = Xs[r][kk];
#pragma unroll
            for (int j = 0; j < 16; j++) acc[j] += xv * Ws[kk][c+j];
        }
        float* out = Om[m];
#pragma unroll
        for (int j = 0; j < 16; j++) {
            int col = c + j;
            int hh = col >> 3, dh = col & 7;
            out[(((bb*8 + hh)*1024) + t)*8 + dh] = acc[j];
        }
    }
}

// ---------------- generic 64x64 token GEMM (plain layout out) ----------------
__global__ void gemm64_kernel(const float* __restrict__ X, const float* __restrict__ W,
                              const float* __restrict__ bias, const float* __restrict__ resid,
                              float* __restrict__ out) {
    __shared__ float Xs[64][65];
    __shared__ float Ws[64][64];
    int tid = threadIdx.x;                 // 256
    int row0 = blockIdx.x * 64;
    for (int idx = tid; idx < 1024; idx += 256) {
        int i = idx >> 4, j = (idx & 15) * 4;
        float4 xv = *(const float4*)(X + (row0 + i)*ND + j);
        Xs[i][j] = xv.x; Xs[i][j+1] = xv.y; Xs[i][j+2] = xv.z; Xs[i][j+3] = xv.w;
        *(float4*)&Ws[i][j] = *(const float4*)(W + idx*4);
    }
    __syncthreads();
    int r = tid >> 2, c = (tid & 3) * 16;
    float acc[16] = {};
    for (int kk = 0; kk < 64; kk++) {
        float xv = Xs[r][kk];
#pragma unroll
        for (int j = 0; j < 16; j++) acc[j] += xv * Ws[kk][c+j];
    }
    int gt = row0 + r;
#pragma unroll
    for (int j = 0; j < 16; j++) {
        float vv = acc[j];
        if (bias)  vv += bias[c+j];
        if (resid) vv += resid[(long)gt*ND + c + j];
        out[(long)gt*ND + c + j] = vv;
    }
}

// ---------------- local windowed attention (heads 0..3) ----------------------
__global__ void local_attn_kernel(const float* __restrict__ q, const float* __restrict__ k,
                                  const float* __restrict__ v, float* __restrict__ attn) {
    int bid = blockIdx.x;                  // b*32 + h*8 + w
    int w = bid & 7, h = (bid >> 3) & 3, b = bid >> 5;
    __shared__ float Ks[384][8];
    __shared__ float Vs[384][8];
    int tid = threadIdx.x;                 // 128
    int base = ((b*8 + h)*1024) * 8;
    int jlo = (w == 0) ? 128 : 0;
    int jhi = (w == 7) ? 256 : 384;
    for (int idx = tid; idx < 384*8; idx += 128) {
        int j = idx >> 3, e = idx & 7;
        int tt = (w - 1)*128 + j;
        float kv = 0.f, vv = 0.f;
        if (tt >= 0 && tt < 1024) { kv = k[base + tt*8 + e]; vv = v[base + tt*8 + e]; }
        Ks[j][e] = kv; Vs[j][e] = vv;
    }
    __syncthreads();
    int t = w*128 + tid;
    float qr[8];
#pragma unroll
    for (int e = 0; e < 8; e++) qr[e] = q[base + t*8 + e];
    const float scale = 0.35355339059327373f;   // 1/sqrt(8)
    float m = -1e30f, l = 0.f, acc[8] = {};
    for (int j = jlo; j < jhi; j++) {
        float s = 0.f;
#pragma unroll
        for (int e = 0; e < 8; e++) s += qr[e] * Ks[j][e];
        s *= scale;
        float mn = fmaxf(m, s);
        float corr = __expf(m - mn);
        float p = __expf(s - mn);
        l = l*corr + p;
#pragma unroll
        for (int e = 0; e < 8; e++) acc[e] = acc[e]*corr + p*Vs[j][e];
        m = mn;
    }
    float inv = 1.f / l;
    int ob = ((b*1024 + t)*64) + h*8;
#pragma unroll
    for (int e = 0; e < 8; e++) attn[ob + e] = acc[e]*inv;
}

// ---------------- global linear attention (heads 4..7) -----------------------
__global__ void global_attn_kernel(const float* __restrict__ q, const float* __restrict__ k,
                                   const float* __restrict__ v, float* __restrict__ attn) {
    int b = blockIdx.x >> 2, h = blockIdx.x & 3;
    int tid = threadIdx.x;                 // 256
    int base = ((b*8 + 4 + h)*1024) * 8;
    __shared__ float red[8][72];
    __shared__ float M[8];
    __shared__ float C[64];
    int warp = tid >> 5, lane = tid & 31;

    float mx[8];
#pragma unroll
    for (int d = 0; d < 8; d++) mx[d] = -1e30f;
    for (int t = tid; t < 1024; t += 256) {
#pragma unroll
        for (int d = 0; d < 8; d++) mx[d] = fmaxf(mx[d], k[base + t*8 + d]);
    }
#pragma unroll
    for (int d = 0; d < 8; d++)
        for (int o = 16; o; o >>= 1) mx[d] = fmaxf(mx[d], __shfl_xor_sync(~0u, mx[d], o));
    if (lane == 0)
        for (int d = 0; d < 8; d++) red[warp][d] = mx[d];
    __syncthreads();
    if (tid < 8) {
        float m_ = red[0][tid];
        for (int wv = 1; wv < 8; wv++) m_ = fmaxf(m_, red[wv][tid]);
        M[tid] = m_;
    }
    __syncthreads();

    float Z[8] = {}, ctx[64] = {};
    for (int t = tid; t < 1024; t += 256) {
        float kr[8], vr[8];
#pragma unroll
        for (int e = 0; e < 8; e++) { kr[e] = k[base + t*8 + e]; vr[e] = v[base + t*8 + e]; }
#pragma unroll
        for (int d = 0; d < 8; d++) {
            float e_ = __expf(kr[d] - M[d]);
            Z[d] += e_;
#pragma unroll
            for (int e = 0; e < 8; e++) ctx[d*8 + e] += e_ * vr[e];
        }
    }
#pragma unroll
    for (int i = 0; i < 8; i++)
        for (int o = 16; o; o >>= 1) Z[i] += __shfl_xor_sync(~0u, Z[i], o);
#pragma unroll
    for (int i = 0; i < 64; i++)
        for (int o = 16; o; o >>= 1) ctx[i] += __shfl_xor_sync(~0u, ctx[i], o);
    if (lane == 0) {
        for (int i = 0; i < 8; i++)  red[warp][i] = Z[i];
        for (int i = 0; i < 64; i++) red[warp][8 + i] = ctx[i];
    }
    __syncthreads();
    if (tid < 64) {
        float s = 0.f, z = 0.f;
        int d = tid >> 3;
        for (int wv = 0; wv < 8; wv++) { s += red[wv][8 + tid]; z += red[wv][d]; }
        C[tid] = s / z;
    }
    __syncthreads();

    const float scale = 0.35355339059327373f;
    for (int t = tid; t < 1024; t += 256) {
        float qr[8]; float qm = -1e30f;
#pragma unroll
        for (int d = 0; d < 8; d++) { qr[d] = q[base + t*8 + d]; qm = fmaxf(qm, qr[d]); }
        float qs = 0.f;
#pragma unroll
        for (int d = 0; d < 8; d++) { qr[d] = __expf(qr[d] - qm); qs += qr[d]; }
        float inv = scale / qs;
        float o_[8] = {};
#pragma unroll
        for (int d = 0; d < 8; d++) {
            float p = qr[d] * inv;
#pragma unroll
            for (int e = 0; e < 8; e++) o_[e] += p * C[d*8 + e];
        }
        int ob = (b*1024 + t)*64 + (4 + h)*8;
#pragma unroll
        for (int e = 0; e < 8; e++) attn[ob + e] = o_[e];
    }
}

// ---------------- FFN1: X(.,64) @ W1(64,256) + b1 -> gelu -> Y ----------------
__global__ void ffn1_kernel(const float* __restrict__ X, const float* __restrict__ W1,
                            const float* __restrict__ b1, float* __restrict__ Y) {
    __shared__ float Xs[64][65];
    __shared__ float Ws[64][64];
    int tid = threadIdx.x, row0 = blockIdx.x * 64, c0 = blockIdx.y * 64;
    for (int idx = tid; idx < 1024; idx += 256) {
        int i = idx >> 4, j = (idx & 15) * 4;
        float4 xv = *(const float4*)(X + (row0 + i)*ND + j);
        Xs[i][j] = xv.x; Xs[i][j+1] = xv.y; Xs[i][j+2] = xv.z; Xs[i][j+3] = xv.w;
        *(float4*)&Ws[i][j] = *(const float4*)(W1 + i*256 + c0 + j);
    }
    __syncthreads();
    int r = tid >> 2, c = (tid & 3) * 16;
    float acc[16] = {};
    for (int kk = 0; kk < 64; kk++) {
        float xv = Xs[r][kk];
#pragma unroll
        for (int j = 0; j < 16; j++) acc[j] += xv * Ws[kk][c+j];
    }
    int gt = row0 + r;
#pragma unroll
    for (int j = 0; j < 16; j++) {
        float z = acc[j] + b1[c0 + c + j];
        float g = 0.5f * z * (1.f + erff(z * 0.70710678118654752f));
        Y[(long)gt*256 + c0 + c + j] = g;
    }
}

// ---------------- FFN2: Y(.,256) @ W2(256,64) + b2 + resid -> h ---------------
__global__ void ffn2_kernel(const float* __restrict__ Y, const float* __restrict__ W2,
                            const float* __restrict__ b2, const float* __restrict__ resid,
                            float* __restrict__ out) {
    __shared__ float Ys[64][65];
    __shared__ float Ws[64][64];
    int tid = threadIdx.x, row0 = blockIdx.x * 64;
    int r = tid >> 2, c = (tid & 3) * 16;
    float acc[16] = {};
    for (int kc = 0; kc < 4; kc++) {
        __syncthreads();
        for (int idx = tid; idx < 1024; idx += 256) {
            int i = idx >> 4, j = (idx & 15) * 4;
            float4 yv = *(const float4*)(Y + (long)(row0 + i)*256 + kc*64 + j);
            Ys[i][j] = yv.x; Ys[i][j+1] = yv.y; Ys[i][j+2] = yv.z; Ys[i][j+3] = yv.w;
            *(float4*)&Ws[i][j] = *(const float4*)(W2 + (kc*64 + i)*64 + j);
        }
        __syncthreads();
        for (int kk = 0; kk < 64; kk++) {
            float yv = Ys[r][kk];
#pragma unroll
            for (int j = 0; j < 16; j++) acc[j] += yv * Ws[kk][c+j];
        }
    }
    int gt = row0 + r;
#pragma unroll
    for (int j = 0; j < 16; j++)
        out[(long)gt*ND + c + j] = acc[j] + b2[c+j] + resid[(long)gt*ND + c + j];
}

// ---------------- collapse: h(.,64) @ cw(64,5) + cb -> out --------------------
__global__ void collapse_kernel(const float* __restrict__ h, const float* __restrict__ cw,
                                const float* __restrict__ cb, float* __restrict__ out) {
    __shared__ float Xs[64][65];
    __shared__ float Ws[64][NDIN];
    __shared__ float Bs[NDIN];
    int tid = threadIdx.x;                 // 64
    int row0 = blockIdx.x * 64;
    for (int idx = tid; idx < 4096; idx += 64) {
        int i = idx >> 6, j = idx & 63;
        Xs[i][j] = h[(long)(row0 + i)*ND + j];
    }
    for (int idx = tid; idx < 64*NDIN; idx += 64) Ws[idx/NDIN][idx%NDIN] = cw[idx];
    if (tid < NDIN) Bs[tid] = cb[tid];
    __syncthreads();
    int r = tid;
    float acc[NDIN];
#pragma unroll
    for (int j = 0; j < NDIN; j++) acc[j] = Bs[j];
    for (int kk = 0; kk < 64; kk++) {
        float xv = Xs[r][kk];
#pragma unroll
        for (int j = 0; j < NDIN; j++) acc[j] += xv * Ws[kk][j];
    }
#pragma unroll
    for (int j = 0; j < NDIN; j++) out[(row0 + r)*NDIN + j] = acc[j];
}

// ---------------- launch ------------------------------------------------------
extern "C" void kernel_launch(void* const* d_in, const int* in_sizes, int n_in,
                              void* d_out, int out_size) {
    const float* x          = (const float*)d_in[0];
    const float* pos_emb    = (const float*)d_in[1];
    const float* expand_w   = (const float*)d_in[2];
    const float* expand_b   = (const float*)d_in[3];
    const float* emb_w      = (const float*)d_in[4];
    const float* emb_b      = (const float*)d_in[5];
    const float* conv_w     = (const float*)d_in[6];
    const float* conv_b     = (const float*)d_in[7];
    const float* ln1_s      = (const float*)d_in[8];
    const float* ln1_b      = (const float*)d_in[9];
    const float* wq         = (const float*)d_in[10];
    const float* wk         = (const float*)d_in[11];
    const float* wv         = (const float*)d_in[12];
    const float* wo         = (const float*)d_in[13];
    const float* wo_b       = (const float*)d_in[14];
    const float* ln2_s      = (const float*)d_in[15];
    const float* ln2_b      = (const float*)d_in[16];
    const float* ff_w1      = (const float*)d_in[17];
    const float* ff_b1      = (const float*)d_in[18];
    const float* ff_w2      = (const float*)d_in[19];
    const float* ff_b2      = (const float*)d_in[20];
    const float* collapse_w = (const float*)d_in[21];
    const float* collapse_b = (const float*)d_in[22];
    float* out = (float*)d_out;

    float *ph, *php, *ptmp, *pq, *pk, *pv, *pattn, *py, *pWc, *pbc;
    cudaGetSymbolAddress((void**)&ph,   g_h);
    cudaGetSymbolAddress((void**)&php,  g_hpad);
    cudaGetSymbolAddress((void**)&ptmp, g_tmp);
    cudaGetSymbolAddress((void**)&pq,   g_q);
    cudaGetSymbolAddress((void**)&pk,   g_k);
    cudaGetSymbolAddress((void**)&pv,   g_v);
    cudaGetSymbolAddress((void**)&pattn,g_attn);
    cudaGetSymbolAddress((void**)&py,   g_y);
    cudaGetSymbolAddress((void**)&pWc,  g_Wc);
    cudaGetSymbolAddress((void**)&pbc,  g_bc);

    precompute_kernel<<<1, 64>>>(expand_w, expand_b, emb_w, emb_b, pWc, pbc);
    expand_kernel<<<NTOK/64, 256>>>(x, pWc, pbc, php);
    conv_kernel<<<dim3(4096/CBN, 1024/CBM), 256>>>(conv_w, php, conv_b, pos_emb, ph);

    for (int l = 0; l < 2; l++) {
        ln_kernel<<<NTOK/8, 256>>>(ph, ln1_s + l*64, ln1_b + l*64, ptmp);
        qkv_kernel<<<NTOK/64, 256>>>(ptmp, wq + l*4096, wk + l*4096, wv + l*4096, pq, pk, pv);
        local_attn_kernel<<<NB*4*8, 128>>>(pq, pk, pv, pattn);
        global_attn_kernel<<<NB*4, 256>>>(pq, pk, pv, pattn);
        gemm64_kernel<<<NTOK/64, 256>>>(pattn, wo + l*4096, wo_b + l*64, ph, ph);
        ln_kernel<<<NTOK/8, 256>>>(ph, ln2_s + l*64, ln2_b + l*64, ptmp);
        ffn1_kernel<<<dim3(NTOK/64, 4), 256>>>(ptmp, ff_w1 + l*64*256, ff_b1 + l*256, py);
        ffn2_kernel<<<NTOK/64, 256>>>(py, ff_w2 + l*256*64, ff_b2 + l*64, ph, ph);
    }
    collapse_kernel<<<NTOK/64, 64>>>(ph, collapse_w, collapse_b, out);
}

// round 5
// speedup vs baseline: 2.2006x; 1.9009x over previous
#include <cuda_runtime.h>
#include <cuda_bf16.h>
#include <math.h>

// Problem constants: B=64, T=1024, DIN=5, D=64, H=8, DH=8, NLOCAL=4, WS=128, DEPTH=2
#define NB 64
#define NT 1024
#define NDIN 5
#define ND 64
#define NTOK (NB*NT)           // 65536

// ---------------- scratch (static device buffers) -----------------------------
__device__ float g_h[NTOK*ND];          // running hidden state
__device__ float g_hpad[NTOK*66];       // padded pre-conv activations (cols 0,65 stay zero)
__device__ float g_q[NTOK*ND];          // [b][h][t][dh]
__device__ float g_k[NTOK*ND];
__device__ float g_v[NTOK*ND];
__device__ float g_attn[NTOK*ND];       // [b][t][h*8+dh]
__device__ float g_y[NTOK*ND*4];        // FFN intermediate
__device__ float g_Wc[NDIN*ND];
__device__ float g_bc[ND];

// ---------------- precompute combined expand@emb ------------------------------
__global__ void precompute_kernel(const float* __restrict__ ew, const float* __restrict__ eb,
                                  const float* __restrict__ mw, const float* __restrict__ mb,
                                  float* __restrict__ Wc, float* __restrict__ bc) {
    int j = threadIdx.x;             // 64 threads
    for (int i = 0; i < NDIN; i++) {
        float s = 0.f;
        for (int d = 0; d < ND; d++) s += ew[i*ND + d] * mw[d*ND + j];
        Wc[i*ND + j] = s;
    }
    float s = mb[j];
    for (int d = 0; d < ND; d++) s += eb[d] * mw[d*ND + j];
    bc[j] = s;
}

// ---------------- expand: x(.,5) @ Wc(5,64) + bc -> g_hpad (stride 66, off 1) --
__global__ void expand_kernel(const float* __restrict__ x, const float* __restrict__ Wc,
                              const float* __restrict__ bc, float* __restrict__ out) {
    __shared__ float Xs[64][NDIN];
    __shared__ float Ws[NDIN][ND];
    __shared__ float Bs[ND];
    int tid = threadIdx.x;                 // 256
    int row0 = blockIdx.x * 64;
    for (int idx = tid; idx < 64*NDIN; idx += 256) Xs[idx/NDIN][idx%NDIN] = x[row0*NDIN + idx];
    for (int idx = tid; idx < NDIN*ND; idx += 256) Ws[idx>>6][idx&63] = Wc[idx];
    if (tid < ND) Bs[tid] = bc[tid];
    __syncthreads();
    int r = tid >> 2, c = (tid & 3) * 16;
    float acc[16];
#pragma unroll
    for (int j = 0; j < 16; j++) acc[j] = Bs[c+j];
#pragma unroll
    for (int i = 0; i < NDIN; i++) {
        float xv = Xs[r][i];
#pragma unroll
        for (int j = 0; j < 16; j++) acc[j] += xv * Ws[i][c+j];
    }
    float* orow = out + (long)(row0+r)*66 + 1 + c;
#pragma unroll
    for (int j = 0; j < 16; j++) orow[j] = acc[j];
}

// ---------------- conv as GEMM, double-buffered --------------------------------
// C[to][(b,d)] = sum_K conv_w[to][K] * Hpad[(b*1024 + K/3)*66 + d + K%3]
#define CBM 128
#define CBN 128
#define CBK 16
__global__ __launch_bounds__(256) void conv_kernel(
        const float* __restrict__ A, const float* __restrict__ Hpad,
        const float* __restrict__ conv_b, const float* __restrict__ pos_emb,
        float* __restrict__ Hout) {
    __shared__ float As[2][CBK][CBM+4];
    __shared__ float Bs[2][CBK][CBN+4];
    int tid = threadIdx.x;                 // 256
    int m0 = blockIdx.y * CBM;             // to-tile
    int n0 = blockIdx.x * CBN;             // (b,d)-tile
    int tx = tid & 15, ty = tid >> 4;
    int tm = ty * 8, tn = tx * 8;
    float acc[8][8] = {};

    // per-thread load coordinates
    int arow = tid >> 1;                   // 0..127
    int acol0 = (tid & 1) * 8;             // 0 or 8
    int bj = tid & 127;                    // 0..127
    int bk0 = (tid >> 7) * 8;              // 0 or 8
    int bb = (n0 >> 6) + (bj >> 6);
    long browbase = ((long)(bb << 10)) * 66;
    int bd = bj & 63;

    // prologue: tile 0 directly to smem buf 0
    {
        const float4* Arow4 = (const float4*)(A + (m0 + arow)*3072 + acol0);
        float4 va0 = Arow4[0], va1 = Arow4[1];
        As[0][acol0+0][arow] = va0.x; As[0][acol0+1][arow] = va0.y;
        As[0][acol0+2][arow] = va0.z; As[0][acol0+3][arow] = va0.w;
        As[0][acol0+4][arow] = va1.x; As[0][acol0+5][arow] = va1.y;
        As[0][acol0+6][arow] = va1.z; As[0][acol0+7][arow] = va1.w;
#pragma unroll
        for (int u = 0; u < 8; u++) {
            int K = bk0 + u;
            int kt = K / 3, kp = K - kt*3;
            Bs[0][bk0+u][bj] = Hpad[browbase + (long)kt*66 + bd + kp];
        }
    }
    __syncthreads();

    int cur = 0;
    for (int k0 = CBK; k0 <= 3072; k0 += CBK) {
        float ar[8], br[8];
        bool more = (k0 < 3072);
        if (more) {
            const float4* Arow4 = (const float4*)(A + (m0 + arow)*3072 + k0 + acol0);
            float4 va0 = Arow4[0], va1 = Arow4[1];
            ar[0]=va0.x; ar[1]=va0.y; ar[2]=va0.z; ar[3]=va0.w;
            ar[4]=va1.x; ar[5]=va1.y; ar[6]=va1.z; ar[7]=va1.w;
#pragma unroll
            for (int u = 0; u < 8; u++) {
                int K = k0 + bk0 + u;
                int kt = K / 3, kp = K - kt*3;
                br[u] = Hpad[browbase + (long)kt*66 + bd + kp];
            }
        }
        // compute on buf cur
#pragma unroll
        for (int kk = 0; kk < CBK; kk++) {
            float4 a0 = *(const float4*)&As[cur][kk][tm];
            float4 a1 = *(const float4*)&As[cur][kk][tm+4];
            float4 b0 = *(const float4*)&Bs[cur][kk][tn];
            float4 b1 = *(const float4*)&Bs[cur][kk][tn+4];
            float av[8] = {a0.x,a0.y,a0.z,a0.w,a1.x,a1.y,a1.z,a1.w};
            float bv[8] = {b0.x,b0.y,b0.z,b0.w,b1.x,b1.y,b1.z,b1.w};
#pragma unroll
            for (int i = 0; i < 8; i++)
#pragma unroll
                for (int jj = 0; jj < 8; jj++) acc[i][jj] += av[i] * bv[jj];
        }
        if (more) {
            int nb = cur ^ 1;
#pragma unroll
            for (int u = 0; u < 8; u++) As[nb][acol0+u][arow] = ar[u];
#pragma unroll
            for (int u = 0; u < 8; u++) Bs[nb][bk0+u][bj] = br[u];
        }
        __syncthreads();
        cur ^= 1;
    }

    // epilogue
    int bo = (n0 + tn) >> 6;
    int d0 = tn & 63;
#pragma unroll
    for (int i = 0; i < 8; i++) {
        int to = m0 + tm + i;
        float cb = conv_b[to];
        const float4* prow = (const float4*)(pos_emb + to*64 + d0);
        float4 p0 = prow[0], p1 = prow[1];
        float4 o0, o1;
        o0.x = acc[i][0]+cb+p0.x; o0.y = acc[i][1]+cb+p0.y;
        o0.z = acc[i][2]+cb+p0.z; o0.w = acc[i][3]+cb+p0.w;
        o1.x = acc[i][4]+cb+p1.x; o1.y = acc[i][5]+cb+p1.y;
        o1.z = acc[i][6]+cb+p1.z; o1.w = acc[i][7]+cb+p1.w;
        float4* orow = (float4*)(Hout + ((long)(bo << 10) + to)*64 + d0);
        orow[0] = o0; orow[1] = o1;
    }
}

// ---------------- shared helper: load 64x64 X tile + layernorm in smem ---------
// NOTE: pad=68 floats (272B) keeps float4 stores 16B-aligned on every row.
__device__ __forceinline__ void load_ln_tile(const float* __restrict__ X, int row0,
                                             const float* __restrict__ s, const float* __restrict__ b,
                                             float Xs[64][68], int tid) {
    for (int idx = tid; idx < 1024; idx += 256) {
        int i = idx >> 4, j = (idx & 15) * 4;
        *(float4*)&Xs[i][j] = *(const float4*)(X + (long)(row0 + i)*ND + j);
    }
    __syncthreads();
    int r = tid >> 2, qd = (tid & 3) * 16;
    float sum = 0.f;
#pragma unroll
    for (int jj = 0; jj < 16; jj++) sum += Xs[r][qd + jj];
    sum += __shfl_xor_sync(~0u, sum, 1);
    sum += __shfl_xor_sync(~0u, sum, 2);
    float mu = sum * (1.f/64.f);
    float vs = 0.f;
#pragma unroll
    for (int jj = 0; jj < 16; jj++) { float d = Xs[r][qd + jj] - mu; vs += d*d; }
    vs += __shfl_xor_sync(~0u, vs, 1);
    vs += __shfl_xor_sync(~0u, vs, 2);
    float inv = rsqrtf(vs * (1.f/64.f) + 1e-5f);
#pragma unroll
    for (int jj = 0; jj < 16; jj++) {
        int c = qd + jj;
        Xs[r][c] = (Xs[r][c] - mu) * inv * s[c] + b[c];
    }
    __syncthreads();
}

// ---------------- fused LN + QKV GEMM -> head layout --------------------------
__global__ __launch_bounds__(256) void lnqkv_kernel(
        const float* __restrict__ X, const float* __restrict__ lns, const float* __restrict__ lnb,
        const float* __restrict__ Wq, const float* __restrict__ Wk, const float* __restrict__ Wv,
        float* __restrict__ q, float* __restrict__ k, float* __restrict__ v) {
    __shared__ float Xs[64][68];
    __shared__ float Ws[64][64];
    int tid = threadIdx.x;                 // 256
    int row0 = blockIdx.x * 64;
    load_ln_tile(X, row0, lns, lnb, Xs, tid);

    int tm = (tid >> 4) * 4, tn = (tid & 15) * 4;
    const float* Wm[3] = {Wq, Wk, Wv};
    float* Om[3] = {q, k, v};
#pragma unroll
    for (int m = 0; m < 3; m++) {
        if (m) __syncthreads();
        const float* W = Wm[m];
#pragma unroll
        for (int u = 0; u < 4; u++) {
            int idx = tid + u*256;
            *(float4*)&Ws[idx >> 4][(idx & 15)*4] = *(const float4*)(W + idx*4);
        }
        __syncthreads();
        float acc[4][4] = {};
        for (int kk = 0; kk < 64; kk++) {
            float a0 = Xs[tm+0][kk], a1 = Xs[tm+1][kk], a2 = Xs[tm+2][kk], a3 = Xs[tm+3][kk];
            float4 bw = *(const float4*)&Ws[kk][tn];
            acc[0][0]+=a0*bw.x; acc[0][1]+=a0*bw.y; acc[0][2]+=a0*bw.z; acc[0][3]+=a0*bw.w;
            acc[1][0]+=a1*bw.x; acc[1][1]+=a1*bw.y; acc[1][2]+=a1*bw.z; acc[1][3]+=a1*bw.w;
            acc[2][0]+=a2*bw.x; acc[2][1]+=a2*bw.y; acc[2][2]+=a2*bw.z; acc[2][3]+=a2*bw.w;
            acc[3][0]+=a3*bw.x; acc[3][1]+=a3*bw.y; acc[3][2]+=a3*bw.z; acc[3][3]+=a3*bw.w;
        }
        float* out = Om[m];
        int hh = tn >> 3, dh = tn & 7;
#pragma unroll
        for (int i = 0; i < 4; i++) {
            int gt = row0 + tm + i;
            int bb = gt >> 10, t = gt & 1023;
            float4 o4; o4.x = acc[i][0]; o4.y = acc[i][1]; o4.z = acc[i][2]; o4.w = acc[i][3];
            *(float4*)(out + (((long)(bb*8 + hh)*1024) + t)*8 + dh) = o4;
        }
    }
}

// ---------------- WO GEMM: attn @ Wo + bias + resid -> h ----------------------
__global__ __launch_bounds__(256) void wo_kernel(
        const float* __restrict__ X, const float* __restrict__ W,
        const float* __restrict__ bias, const float* __restrict__ resid,
        float* __restrict__ out) {
    __shared__ float Xs[64][68];
    __shared__ float Ws[64][64];
    int tid = threadIdx.x;                 // 256
    int row0 = blockIdx.x * 64;
    for (int idx = tid; idx < 1024; idx += 256) {
        int i = idx >> 4, j = (idx & 15) * 4;
        *(float4*)&Xs[i][j] = *(const float4*)(X + (long)(row0 + i)*ND + j);
        *(float4*)&Ws[i][j] = *(const float4*)(W + idx*4);
    }
    __syncthreads();
    int tm = (tid >> 4) * 4, tn = (tid & 15) * 4;
    float acc[4][4] = {};
    for (int kk = 0; kk < 64; kk++) {
        float a0 = Xs[tm+0][kk], a1 = Xs[tm+1][kk], a2 = Xs[tm+2][kk], a3 = Xs[tm+3][kk];
        float4 bw = *(const float4*)&Ws[kk][tn];
        acc[0][0]+=a0*bw.x; acc[0][1]+=a0*bw.y; acc[0][2]+=a0*bw.z; acc[0][3]+=a0*bw.w;
        acc[1][0]+=a1*bw.x; acc[1][1]+=a1*bw.y; acc[1][2]+=a1*bw.z; acc[1][3]+=a1*bw.w;
        acc[2][0]+=a2*bw.x; acc[2][1]+=a2*bw.y; acc[2][2]+=a2*bw.z; acc[2][3]+=a2*bw.w;
        acc[3][0]+=a3*bw.x; acc[3][1]+=a3*bw.y; acc[3][2]+=a3*bw.z; acc[3][3]+=a3*bw.w;
    }
    float4 bb4 = *(const float4*)(bias + tn);
#pragma unroll
    for (int i = 0; i < 4; i++) {
        long gt = row0 + tm + i;
        float4 rr = *(const float4*)(resid + gt*ND + tn);
        float4 o4;
        o4.x = acc[i][0] + bb4.x + rr.x; o4.y = acc[i][1] + bb4.y + rr.y;
        o4.z = acc[i][2] + bb4.z + rr.z; o4.w = acc[i][3] + bb4.w + rr.w;
        *(float4*)(out + gt*ND + tn) = o4;
    }
}

// ---------------- fused LN + FFN1 (+ gelu): one 64-col chunk per blockIdx.y ----
__global__ __launch_bounds__(256) void lnffn1_kernel(
        const float* __restrict__ X, const float* __restrict__ lns, const float* __restrict__ lnb,
        const float* __restrict__ W1, const float* __restrict__ b1,
        float* __restrict__ Y) {
    __shared__ float Xs[64][68];
    __shared__ float Ws[64][64];
    int tid = threadIdx.x;
    int row0 = blockIdx.x * 64, c0 = blockIdx.y * 64;
    load_ln_tile(X, row0, lns, lnb, Xs, tid);
    for (int idx = tid; idx < 1024; idx += 256) {
        int i = idx >> 4, j = (idx & 15) * 4;
        *(float4*)&Ws[i][j] = *(const float4*)(W1 + i*256 + c0 + j);
    }
    __syncthreads();
    int tm = (tid >> 4) * 4, tn = (tid & 15) * 4;
    float acc[4][4] = {};
    for (int kk = 0; kk < 64; kk++) {
        float a0 = Xs[tm+0][kk], a1 = Xs[tm+1][kk], a2 = Xs[tm+2][kk], a3 = Xs[tm+3][kk];
        float4 bw = *(const float4*)&Ws[kk][tn];
        acc[0][0]+=a0*bw.x; acc[0][1]+=a0*bw.y; acc[0][2]+=a0*bw.z; acc[0][3]+=a0*bw.w;
        acc[1][0]+=a1*bw.x; acc[1][1]+=a1*bw.y; acc[1][2]+=a1*bw.z; acc[1][3]+=a1*bw.w;
        acc[2][0]+=a2*bw.x; acc[2][1]+=a2*bw.y; acc[2][2]+=a2*bw.z; acc[2][3]+=a2*bw.w;
        acc[3][0]+=a3*bw.x; acc[3][1]+=a3*bw.y; acc[3][2]+=a3*bw.z; acc[3][3]+=a3*bw.w;
    }
    float4 bb4 = *(const float4*)(b1 + c0 + tn);
    float bv[4] = {bb4.x, bb4.y, bb4.z, bb4.w};
#pragma unroll
    for (int i = 0; i < 4; i++) {
        long gt = row0 + tm + i;
        float4 o4;
        float* o = (float*)&o4;
#pragma unroll
        for (int j = 0; j < 4; j++) {
            float z = acc[i][j] + bv[j];
            o[j] = 0.5f * z * (1.f + erff(z * 0.70710678118654752f));
        }
        *(float4*)(Y + gt*256 + c0 + tn) = o4;
    }
}

// ---------------- FFN2: Y(.,256) @ W2(256,64) + b2 + resid -> h ---------------
__global__ __launch_bounds__(256) void ffn2_kernel(
        const float* __restrict__ Y, const float* __restrict__ W2,
        const float* __restrict__ b2, const float* __restrict__ resid,
        float* __restrict__ out) {
    __shared__ float Ys[64][68];
    __shared__ float Ws[64][64];
    int tid = threadIdx.x, row0 = blockIdx.x * 64;
    int tm = (tid >> 4) * 4, tn = (tid & 15) * 4;
    float acc[4][4] = {};
    for (int kc = 0; kc < 4; kc++) {
        __syncthreads();
        for (int idx = tid; idx < 1024; idx += 256) {
            int i = idx >> 4, j = (idx & 15) * 4;
            *(float4*)&Ys[i][j] = *(const float4*)(Y + (long)(row0 + i)*256 + kc*64 + j);
            *(float4*)&Ws[i][j] = *(const float4*)(W2 + (kc*64 + i)*64 + j);
        }
        __syncthreads();
        for (int kk = 0; kk < 64; kk++) {
            float a0 = Ys[tm+0][kk], a1 = Ys[tm+1][kk], a2 = Ys[tm+2][kk], a3 = Ys[tm+3][kk];
            float4 bw = *(const float4*)&Ws[kk][tn];
            acc[0][0]+=a0*bw.x; acc[0][1]+=a0*bw.y; acc[0][2]+=a0*bw.z; acc[0][3]+=a0*bw.w;
            acc[1][0]+=a1*bw.x; acc[1][1]+=a1*bw.y; acc[1][2]+=a1*bw.z; acc[1][3]+=a1*bw.w;
            acc[2][0]+=a2*bw.x; acc[2][1]+=a2*bw.y; acc[2][2]+=a2*bw.z; acc[2][3]+=a2*bw.w;
            acc[3][0]+=a3*bw.x; acc[3][1]+=a3*bw.y; acc[3][2]+=a3*bw.z; acc[3][3]+=a3*bw.w;
        }
    }
    float4 bb4 = *(const float4*)(b2 + tn);
#pragma unroll
    for (int i = 0; i < 4; i++) {
        long gt = row0 + tm + i;
        float4 rr = *(const float4*)(resid + gt*ND + tn);
        float4 o4;
        o4.x = acc[i][0] + bb4.x + rr.x; o4.y = acc[i][1] + bb4.y + rr.y;
        o4.z = acc[i][2] + bb4.z + rr.z; o4.w = acc[i][3] + bb4.w + rr.w;
        *(float4*)(out + gt*ND + tn) = o4;
    }
}

// ---------------- local windowed attention (heads 0..3) ----------------------
__global__ __launch_bounds__(128) void local_attn_kernel(
        const float* __restrict__ q, const float* __restrict__ k,
        const float* __restrict__ v, float* __restrict__ attn) {
    int bid = blockIdx.x;                  // b*32 + h*8 + w
    int w = bid & 7, h = (bid >> 3) & 3, b = bid >> 5;
    __shared__ float Ks[384][8];
    __shared__ float Vs[384][8];
    int tid = threadIdx.x;                 // 128
    int base = ((b*8 + h)*1024) * 8;
    int jlo = (w == 0) ? 128 : 0;
    int jhi = (w == 7) ? 256 : 384;
    for (int idx = tid; idx < 768; idx += 128) {
        int j = idx >> 1, half = (idx & 1) * 4;
        int tt = (w - 1)*128 + j;
        float4 kv = {0,0,0,0}, vv = {0,0,0,0};
        if (tt >= 0 && tt < 1024) {
            kv = *(const float4*)(k + base + tt*8 + half);
            vv = *(const float4*)(v + base + tt*8 + half);
        }
        *(float4*)&Ks[j][half] = kv;
        *(float4*)&Vs[j][half] = vv;
    }
    __syncthreads();
    int t = w*128 + tid;
    float4 q0 = *(const float4*)(q + base + t*8);
    float4 q1 = *(const float4*)(q + base + t*8 + 4);
    float qr[8] = {q0.x,q0.y,q0.z,q0.w,q1.x,q1.y,q1.z,q1.w};
    const float scale = 0.35355339059327373f;   // 1/sqrt(8)
    float m = -1e30f, l = 0.f, acc[8] = {};
    for (int j = jlo; j < jhi; j++) {
        float4 k0 = *(const float4*)&Ks[j][0];
        float4 k1 = *(const float4*)&Ks[j][4];
        float s = qr[0]*k0.x + qr[1]*k0.y + qr[2]*k0.z + qr[3]*k0.w
                + qr[4]*k1.x + qr[5]*k1.y + qr[6]*k1.z + qr[7]*k1.w;
        s *= scale;
        float mn = fmaxf(m, s);
        float corr = __expf(m - mn);
        float p = __expf(s - mn);
        l = l*corr + p;
        float4 v0 = *(const float4*)&Vs[j][0];
        float4 v1 = *(const float4*)&Vs[j][4];
        acc[0] = acc[0]*corr + p*v0.x; acc[1] = acc[1]*corr + p*v0.y;
        acc[2] = acc[2]*corr + p*v0.z; acc[3] = acc[3]*corr + p*v0.w;
        acc[4] = acc[4]*corr + p*v1.x; acc[5] = acc[5]*corr + p*v1.y;
        acc[6] = acc[6]*corr + p*v1.z; acc[7] = acc[7]*corr + p*v1.w;
        m = mn;
    }
    float inv = 1.f / l;
    float4 o0, o1;
    o0.x = acc[0]*inv; o0.y = acc[1]*inv; o0.z = acc[2]*inv; o0.w = acc[3]*inv;
    o1.x = acc[4]*inv; o1.y = acc[5]*inv; o1.z = acc[6]*inv; o1.w = acc[7]*inv;
    long ob = ((long)(b*1024 + t)*64) + h*8;
    *(float4*)(attn + ob) = o0;
    *(float4*)(attn + ob + 4) = o1;
}

// ---------------- global linear attention (heads 4..7) -----------------------
__global__ void global_attn_kernel(const float* __restrict__ q, const float* __restrict__ k,
                                   const float* __restrict__ v, float* __restrict__ attn) {
    int b = blockIdx.x >> 2, h = blockIdx.x & 3;
    int tid = threadIdx.x;                 // 256
    int base = ((b*8 + 4 + h)*1024) * 8;
    __shared__ float red[8][72];
    __shared__ float M[8];
    __shared__ float C[64];
    int warp = tid >> 5, lane = tid & 31;

    float mx[8];
#pragma unroll
    for (int d = 0; d < 8; d++) mx[d] = -1e30f;
    for (int t = tid; t < 1024; t += 256) {
        float4 k0 = *(const float4*)(k + base + t*8);
        float4 k1 = *(const float4*)(k + base + t*8 + 4);
        mx[0]=fmaxf(mx[0],k0.x); mx[1]=fmaxf(mx[1],k0.y); mx[2]=fmaxf(mx[2],k0.z); mx[3]=fmaxf(mx[3],k0.w);
        mx[4]=fmaxf(mx[4],k1.x); mx[5]=fmaxf(mx[5],k1.y); mx[6]=fmaxf(mx[6],k1.z); mx[7]=fmaxf(mx[7],k1.w);
    }
#pragma unroll
    for (int d = 0; d < 8; d++)
        for (int o = 16; o; o >>= 1) mx[d] = fmaxf(mx[d], __shfl_xor_sync(~0u, mx[d], o));
    if (lane == 0)
        for (int d = 0; d < 8; d++) red[warp][d] = mx[d];
    __syncthreads();
    if (tid < 8) {
        float m_ = red[0][tid];
        for (int wv = 1; wv < 8; wv++) m_ = fmaxf(m_, red[wv][tid]);
        M[tid] = m_;
    }
    __syncthreads();

    float Z[8] = {}, ctx[64] = {};
    for (int t = tid; t < 1024; t += 256) {
        float4 k0 = *(const float4*)(k + base + t*8);
        float4 k1 = *(const float4*)(k + base + t*8 + 4);
        float4 v0 = *(const float4*)(v + base + t*8);
        float4 v1 = *(const float4*)(v + base + t*8 + 4);
        float kr[8] = {k0.x,k0.y,k0.z,k0.w,k1.x,k1.y,k1.z,k1.w};
        float vr[8] = {v0.x,v0.y,v0.z,v0.w,v1.x,v1.y,v1.z,v1.w};
#pragma unroll
        for (int d = 0; d < 8; d++) {
            float e_ = __expf(kr[d] - M[d]);
            Z[d] += e_;
#pragma unroll
            for (int e = 0; e < 8; e++) ctx[d*8 + e] += e_ * vr[e];
        }
    }
#pragma unroll
    for (int i = 0; i < 8; i++)
        for (int o = 16; o; o >>= 1) Z[i] += __shfl_xor_sync(~0u, Z[i], o);
#pragma unroll
    for (int i = 0; i < 64; i++)
        for (int o = 16; o; o >>= 1) ctx[i] += __shfl_xor_sync(~0u, ctx[i], o);
    if (lane == 0) {
        for (int i = 0; i < 8; i++)  red[warp][i] = Z[i];
        for (int i = 0; i < 64; i++) red[warp][8 + i] = ctx[i];
    }
    __syncthreads();
    if (tid < 64) {
        float s = 0.f, z = 0.f;
        int d = tid >> 3;
        for (int wv = 0; wv < 8; wv++) { s += red[wv][8 + tid]; z += red[wv][d]; }
        C[tid] = s / z;
    }
    __syncthreads();

    const float scale = 0.35355339059327373f;
    for (int t = tid; t < 1024; t += 256) {
        float4 q0 = *(const float4*)(q + base + t*8);
        float4 q1 = *(const float4*)(q + base + t*8 + 4);
        float qr[8] = {q0.x,q0.y,q0.z,q0.w,q1.x,q1.y,q1.z,q1.w};
        float qm = -1e30f;
#pragma unroll
        for (int d = 0; d < 8; d++) qm = fmaxf(qm, qr[d]);
        float qs = 0.f;
#pragma unroll
        for (int d = 0; d < 8; d++) { qr[d] = __expf(qr[d] - qm); qs += qr[d]; }
        float inv = scale / qs;
        float o_[8] = {};
#pragma unroll
        for (int d = 0; d < 8; d++) {
            float p = qr[d] * inv;
#pragma unroll
            for (int e = 0; e < 8; e++) o_[e] += p * C[d*8 + e];
        }
        long ob = (long)(b*1024 + t)*64 + (4 + h)*8;
        float4 oo0, oo1;
        oo0.x=o_[0]; oo0.y=o_[1]; oo0.z=o_[2]; oo0.w=o_[3];
        oo1.x=o_[4]; oo1.y=o_[5]; oo1.z=o_[6]; oo1.w=o_[7];
        *(float4*)(attn + ob) = oo0;
        *(float4*)(attn + ob + 4) = oo1;
    }
}

// ---------------- collapse: h(.,64) @ cw(64,5) + cb -> out --------------------
__global__ void collapse_kernel(const float* __restrict__ h, const float* __restrict__ cw,
                                const float* __restrict__ cb, float* __restrict__ out) {
    __shared__ float Xs[64][68];
    __shared__ float Ws[64][NDIN];
    __shared__ float Bs[NDIN];
    int tid = threadIdx.x;                 // 64
    int row0 = blockIdx.x * 64;
    for (int idx = tid; idx < 1024; idx += 64) {
        int i = idx >> 4, j = (idx & 15) * 4;
        *(float4*)&Xs[i][j] = *(const float4*)(h + (long)(row0 + i)*ND + j);
    }
    for (int idx = tid; idx < 64*NDIN; idx += 64) Ws[idx/NDIN][idx%NDIN] = cw[idx];
    if (tid < NDIN) Bs[tid] = cb[tid];
    __syncthreads();
    int r = tid;
    float acc[NDIN];
#pragma unroll
    for (int j = 0; j < NDIN; j++) acc[j] = Bs[j];
    for (int kk = 0; kk < 64; kk++) {
        float xv = Xs[r][kk];
#pragma unroll
        for (int j = 0; j < NDIN; j++) acc[j] += xv * Ws[kk][j];
    }
#pragma unroll
    for (int j = 0; j < NDIN; j++) out[(row0 + r)*NDIN + j] = acc[j];
}

// ---------------- launch ------------------------------------------------------
extern "C" void kernel_launch(void* const* d_in, const int* in_sizes, int n_in,
                              void* d_out, int out_size) {
    const float* x          = (const float*)d_in[0];
    const float* pos_emb    = (const float*)d_in[1];
    const float* expand_w   = (const float*)d_in[2];
    const float* expand_b   = (const float*)d_in[3];
    const float* emb_w      = (const float*)d_in[4];
    const float* emb_b      = (const float*)d_in[5];
    const float* conv_w     = (const float*)d_in[6];
    const float* conv_b     = (const float*)d_in[7];
    const float* ln1_s      = (const float*)d_in[8];
    const float* ln1_b      = (const float*)d_in[9];
    const float* wq         = (const float*)d_in[10];
    const float* wk         = (const float*)d_in[11];
    const float* wv         = (const float*)d_in[12];
    const float* wo         = (const float*)d_in[13];
    const float* wo_b       = (const float*)d_in[14];
    const float* ln2_s      = (const float*)d_in[15];
    const float* ln2_b      = (const float*)d_in[16];
    const float* ff_w1      = (const float*)d_in[17];
    const float* ff_b1      = (const float*)d_in[18];
    const float* ff_w2      = (const float*)d_in[19];
    const float* ff_b2      = (const float*)d_in[20];
    const float* collapse_w = (const float*)d_in[21];
    const float* collapse_b = (const float*)d_in[22];
    float* out = (float*)d_out;

    float *ph, *php, *pq, *pk, *pv, *pattn, *py, *pWc, *pbc;
    cudaGetSymbolAddress((void**)&ph,   g_h);
    cudaGetSymbolAddress((void**)&php,  g_hpad);
    cudaGetSymbolAddress((void**)&pq,   g_q);
    cudaGetSymbolAddress((void**)&pk,   g_k);
    cudaGetSymbolAddress((void**)&pv,   g_v);
    cudaGetSymbolAddress((void**)&pattn,g_attn);
    cudaGetSymbolAddress((void**)&py,   g_y);
    cudaGetSymbolAddress((void**)&pWc,  g_Wc);
    cudaGetSymbolAddress((void**)&pbc,  g_bc);

    precompute_kernel<<<1, 64>>>(expand_w, expand_b, emb_w, emb_b, pWc, pbc);
    expand_kernel<<<NTOK/64, 256>>>(x, pWc, pbc, php);
    conv_kernel<<<dim3(4096/CBN, 1024/CBM), 256>>>(conv_w, php, conv_b, pos_emb, ph);

    for (int l = 0; l < 2; l++) {
        lnqkv_kernel<<<NTOK/64, 256>>>(ph, ln1_s + l*64, ln1_b + l*64,
                                       wq + l*4096, wk + l*4096, wv + l*4096, pq, pk, pv);
        local_attn_kernel<<<NB*4*8, 128>>>(pq, pk, pv, pattn);
        global_attn_kernel<<<NB*4, 256>>>(pq, pk, pv, pattn);
        wo_kernel<<<NTOK/64, 256>>>(pattn, wo + l*4096, wo_b + l*64, ph, ph);
        lnffn1_kernel<<<dim3(NTOK/64, 4), 256>>>(ph, ln2_s + l*64, ln2_b + l*64,
                                                 ff_w1 + l*64*256, ff_b1 + l*256, py);
        ffn2_kernel<<<NTOK/64, 256>>>(py, ff_w2 + l*256*64, ff_b2 + l*64, ph, ph);
    }
    collapse_kernel<<<NTOK/64, 64>>>(ph, collapse_w, collapse_b, out);
}

// round 7
// speedup vs baseline: 2.2898x; 1.0405x over previous
#include <cuda_runtime.h>
#include <cuda_bf16.h>
#include <cstdint>
#include <math.h>

// Problem constants: B=64, T=1024, DIN=5, D=64, H=8, DH=8, NLOCAL=4, WS=128, DEPTH=2
#define NB 64
#define NT 1024
#define NDIN 5
#define ND 64
#define NTOK (NB*NT)           // 65536

// ---------------- scratch (static device buffers) -----------------------------
__device__ float g_h[NTOK*ND];          // running hidden state
__device__ float g_hpad[NTOK*66];       // padded pre-conv activations (cols 0,65 stay zero)
__device__ float g_q[NTOK*ND];          // [b][h][t][dh]
__device__ float g_k[NTOK*ND];
__device__ float g_v[NTOK*ND];
__device__ float g_attn[NTOK*ND];       // [b][t][h*8+dh]
__device__ float g_y[NTOK*ND*4];        // FFN intermediate
__device__ float g_Wc[NDIN*ND];
__device__ float g_bc[ND];

// ---------------- tf32 helpers -------------------------------------------------
__device__ __forceinline__ uint32_t f2tf32(float x) {
    uint32_t r;
    asm("cvt.rna.tf32.f32 %0, %1;" : "=r"(r) : "f"(x));
    return r;
}
__device__ __forceinline__ void mma_tf32(float* c, const uint32_t* a, const uint32_t* b) {
    asm volatile("mma.sync.aligned.m16n8k8.row.col.f32.tf32.tf32.f32 "
        "{%0,%1,%2,%3}, {%4,%5,%6,%7}, {%8,%9}, {%0,%1,%2,%3};"
        : "+f"(c[0]), "+f"(c[1]), "+f"(c[2]), "+f"(c[3])
        : "r"(a[0]), "r"(a[1]), "r"(a[2]), "r"(a[3]), "r"(b[0]), "r"(b[1]));
}

// ---------------- precompute combined expand@emb ------------------------------
__global__ void precompute_kernel(const float* __restrict__ ew, const float* __restrict__ eb,
                                  const float* __restrict__ mw, const float* __restrict__ mb,
                                  float* __restrict__ Wc, float* __restrict__ bc) {
    int j = threadIdx.x;             // 64 threads
    for (int i = 0; i < NDIN; i++) {
        float s = 0.f;
        for (int d = 0; d < ND; d++) s += ew[i*ND + d] * mw[d*ND + j];
        Wc[i*ND + j] = s;
    }
    float s = mb[j];
    for (int d = 0; d < ND; d++) s += eb[d] * mw[d*ND + j];
    bc[j] = s;
}

// ---------------- expand: x(.,5) @ Wc(5,64) + bc -> g_hpad (stride 66, off 1) --
__global__ void expand_kernel(const float* __restrict__ x, const float* __restrict__ Wc,
                              const float* __restrict__ bc, float* __restrict__ out) {
    __shared__ float Xs[64][NDIN];
    __shared__ float Ws[NDIN][ND];
    __shared__ float Bs[ND];
    int tid = threadIdx.x;                 // 256
    int row0 = blockIdx.x * 64;
    for (int idx = tid; idx < 64*NDIN; idx += 256) Xs[idx/NDIN][idx%NDIN] = x[row0*NDIN + idx];
    for (int idx = tid; idx < NDIN*ND; idx += 256) Ws[idx>>6][idx&63] = Wc[idx];
    if (tid < ND) Bs[tid] = bc[tid];
    __syncthreads();
    int r = tid >> 2, c = (tid & 3) * 16;
    float acc[16];
#pragma unroll
    for (int j = 0; j < 16; j++) acc[j] = Bs[c+j];
#pragma unroll
    for (int i = 0; i < NDIN; i++) {
        float xv = Xs[r][i];
#pragma unroll
        for (int j = 0; j < 16; j++) acc[j] += xv * Ws[i][c+j];
    }
    float* orow = out + (long)(row0+r)*66 + 1 + c;
#pragma unroll
    for (int j = 0; j < 16; j++) orow[j] = acc[j];
}

// ---------------- conv as GEMM, 3xTF32 tensor-core path ------------------------
// C[to][(b,d)] = sum_K conv_w[to][K] * Hpad[(b*1024 + K/3)*66 + d + K%3]
#define CBM 128
#define CBN 128
#define CBK 16
__global__ __launch_bounds__(256) void conv_kernel(
        const float* __restrict__ A, const float* __restrict__ Hpad,
        const float* __restrict__ conv_b, const float* __restrict__ pos_emb,
        float* __restrict__ Hout) {
    __shared__ float As[2][CBK][CBM+4];
    __shared__ float Bs[2][CBK][CBN+4];
    int tid = threadIdx.x;                 // 256
    int m0 = blockIdx.y * CBM;             // to-tile
    int n0 = blockIdx.x * CBN;             // (b,d)-tile

    // loader coords (identical to the verified fp32 version)
    int arow = tid >> 1;                   // 0..127
    int acol0 = (tid & 1) * 8;             // 0 or 8
    int bj = tid & 127;                    // 0..127
    int bk0 = (tid >> 7) * 8;              // 0 or 8
    int bb = (n0 >> 6) + (bj >> 6);
    long browbase = ((long)(bb << 10)) * 66;
    int bd = bj & 63;

    // warp/mma coords
    int w = tid >> 5, lane = tid & 31;
    int gid = lane >> 2, t4 = lane & 3;
    int warpM = w >> 1, warpN = w & 1;     // 4 x 2 warp grid
    int mbase = warpM * 32, nbase = warpN * 64;

    float acc[2][8][4];
#pragma unroll
    for (int mt = 0; mt < 2; mt++)
#pragma unroll
        for (int nt = 0; nt < 8; nt++)
#pragma unroll
            for (int r = 0; r < 4; r++) acc[mt][nt][r] = 0.f;

    // prologue: tile 0 -> smem buf 0
    {
        const float4* Arow4 = (const float4*)(A + (m0 + arow)*3072 + acol0);
        float4 va0 = Arow4[0], va1 = Arow4[1];
        As[0][acol0+0][arow] = va0.x; As[0][acol0+1][arow] = va0.y;
        As[0][acol0+2][arow] = va0.z; As[0][acol0+3][arow] = va0.w;
        As[0][acol0+4][arow] = va1.x; As[0][acol0+5][arow] = va1.y;
        As[0][acol0+6][arow] = va1.z; As[0][acol0+7][arow] = va1.w;
#pragma unroll
        for (int u = 0; u < 8; u++) {
            int K = bk0 + u;
            int kt = K / 3, kp = K - kt*3;
            Bs[0][bk0+u][bj] = Hpad[browbase + (long)kt*66 + bd + kp];
        }
    }
    __syncthreads();

    int cur = 0;
    for (int k0 = CBK; k0 <= 3072; k0 += CBK) {
        float ar[8], br[8];
        bool more = (k0 < 3072);
        if (more) {
            const float4* Arow4 = (const float4*)(A + (m0 + arow)*3072 + k0 + acol0);
            float4 va0 = Arow4[0], va1 = Arow4[1];
            ar[0]=va0.x; ar[1]=va0.y; ar[2]=va0.z; ar[3]=va0.w;
            ar[4]=va1.x; ar[5]=va1.y; ar[6]=va1.z; ar[7]=va1.w;
#pragma unroll
            for (int u = 0; u < 8; u++) {
                int K = k0 + bk0 + u;
                int kt = K / 3, kp = K - kt*3;
                br[u] = Hpad[browbase + (long)kt*66 + bd + kp];
            }
        }
        // ---- compute on buffer cur: 2 ksteps of k=8, 3xTF32 ----
#pragma unroll
        for (int ks = 0; ks < 2; ks++) {
            int kb = ks * 8;
            // A fragments (2 m-tiles)
            float af[2][4];
#pragma unroll
            for (int mt = 0; mt < 2; mt++) {
                int mrow = mbase + mt*16 + gid;
                af[mt][0] = As[cur][kb + t4    ][mrow];
                af[mt][1] = As[cur][kb + t4    ][mrow + 8];
                af[mt][2] = As[cur][kb + t4 + 4][mrow];
                af[mt][3] = As[cur][kb + t4 + 4][mrow + 8];
            }
            // B fragments (8 n-tiles)
            float bf[8][2];
#pragma unroll
            for (int nt = 0; nt < 8; nt++) {
                int ncol = nbase + nt*8 + gid;
                bf[nt][0] = Bs[cur][kb + t4    ][ncol];
                bf[nt][1] = Bs[cur][kb + t4 + 4][ncol];
            }
            // split to hi/lo tf32
            uint32_t ah[2][4], al[2][4];
#pragma unroll
            for (int mt = 0; mt < 2; mt++)
#pragma unroll
                for (int r = 0; r < 4; r++) {
                    uint32_t h = f2tf32(af[mt][r]);
                    ah[mt][r] = h;
                    al[mt][r] = f2tf32(af[mt][r] - __uint_as_float(h));
                }
            uint32_t bh[8][2], bl[8][2];
#pragma unroll
            for (int nt = 0; nt < 8; nt++)
#pragma unroll
                for (int r = 0; r < 2; r++) {
                    uint32_t h = f2tf32(bf[nt][r]);
                    bh[nt][r] = h;
                    bl[nt][r] = f2tf32(bf[nt][r] - __uint_as_float(h));
                }
            // 3-term mma
#pragma unroll
            for (int mt = 0; mt < 2; mt++)
#pragma unroll
                for (int nt = 0; nt < 8; nt++) {
                    mma_tf32(acc[mt][nt], al[mt], bh[nt]);
                    mma_tf32(acc[mt][nt], ah[mt], bl[nt]);
                    mma_tf32(acc[mt][nt], ah[mt], bh[nt]);
                }
        }
        if (more) {
            int nb = cur ^ 1;
#pragma unroll
            for (int u = 0; u < 8; u++) As[nb][acol0+u][arow] = ar[u];
#pragma unroll
            for (int u = 0; u < 8; u++) Bs[nb][bk0+u][bj] = br[u];
        }
        __syncthreads();
        cur ^= 1;
    }

    // ---- epilogue: +conv_b +pos_emb, scatter to [b][to][d] ----
#pragma unroll
    for (int mt = 0; mt < 2; mt++) {
        int row0r = m0 + mbase + mt*16 + gid;   // and +8
        float cb0 = conv_b[row0r];
        float cb1 = conv_b[row0r + 8];
#pragma unroll
        for (int nt = 0; nt < 8; nt++) {
            int coln = n0 + nbase + nt*8 + t4*2;
            int b_ = coln >> 6, d_ = coln & 63;
            float2 pe0 = *(const float2*)(pos_emb + row0r*64 + d_);
            float2 pe1 = *(const float2*)(pos_emb + (row0r+8)*64 + d_);
            float2 o0, o1;
            o0.x = acc[mt][nt][0] + cb0 + pe0.x;
            o0.y = acc[mt][nt][1] + cb0 + pe0.y;
            o1.x = acc[mt][nt][2] + cb1 + pe1.x;
            o1.y = acc[mt][nt][3] + cb1 + pe1.y;
            *(float2*)(Hout + ((long)(b_ << 10) + row0r)*64 + d_) = o0;
            *(float2*)(Hout + ((long)(b_ << 10) + row0r + 8)*64 + d_) = o1;
        }
    }
}

// ---------------- shared helper: load 64x64 X tile + layernorm in smem ---------
__device__ __forceinline__ void load_ln_tile(const float* __restrict__ X, int row0,
                                             const float* __restrict__ s, const float* __restrict__ b,
                                             float Xs[64][68], int tid) {
    for (int idx = tid; idx < 1024; idx += 256) {
        int i = idx >> 4, j = (idx & 15) * 4;
        *(float4*)&Xs[i][j] = *(const float4*)(X + (long)(row0 + i)*ND + j);
    }
    __syncthreads();
    int r = tid >> 2, qd = (tid & 3) * 16;
    float sum = 0.f;
#pragma unroll
    for (int jj = 0; jj < 16; jj++) sum += Xs[r][qd + jj];
    sum += __shfl_xor_sync(~0u, sum, 1);
    sum += __shfl_xor_sync(~0u, sum, 2);
    float mu = sum * (1.f/64.f);
    float vs = 0.f;
#pragma unroll
    for (int jj = 0; jj < 16; jj++) { float d = Xs[r][qd + jj] - mu; vs += d*d; }
    vs += __shfl_xor_sync(~0u, vs, 1);
    vs += __shfl_xor_sync(~0u, vs, 2);
    float inv = rsqrtf(vs * (1.f/64.f) + 1e-5f);
#pragma unroll
    for (int jj = 0; jj < 16; jj++) {
        int c = qd + jj;
        Xs[r][c] = (Xs[r][c] - mu) * inv * s[c] + b[c];
    }
    __syncthreads();
}

// ---------------- fused LN + QKV GEMM -> head layout --------------------------
__global__ __launch_bounds__(256) void lnqkv_kernel(
        const float* __restrict__ X, const float* __restrict__ lns, const float* __restrict__ lnb,
        const float* __restrict__ Wq, const float* __restrict__ Wk, const float* __restrict__ Wv,
        float* __restrict__ q, float* __restrict__ k, float* __restrict__ v) {
    __shared__ float Xs[64][68];
    __shared__ float Ws[64][64];
    int tid = threadIdx.x;                 // 256
    int row0 = blockIdx.x * 64;
    load_ln_tile(X, row0, lns, lnb, Xs, tid);

    int tm = (tid >> 4) * 4, tn = (tid & 15) * 4;
    const float* Wm[3] = {Wq, Wk, Wv};
    float* Om[3] = {q, k, v};
#pragma unroll
    for (int m = 0; m < 3; m++) {
        if (m) __syncthreads();
        const float* W = Wm[m];
#pragma unroll
        for (int u = 0; u < 4; u++) {
            int idx = tid + u*256;
            *(float4*)&Ws[idx >> 4][(idx & 15)*4] = *(const float4*)(W + idx*4);
        }
        __syncthreads();
        float acc[4][4] = {};
        for (int kk = 0; kk < 64; kk++) {
            float a0 = Xs[tm+0][kk], a1 = Xs[tm+1][kk], a2 = Xs[tm+2][kk], a3 = Xs[tm+3][kk];
            float4 bw = *(const float4*)&Ws[kk][tn];
            acc[0][0]+=a0*bw.x; acc[0][1]+=a0*bw.y; acc[0][2]+=a0*bw.z; acc[0][3]+=a0*bw.w;
            acc[1][0]+=a1*bw.x; acc[1][1]+=a1*bw.y; acc[1][2]+=a1*bw.z; acc[1][3]+=a1*bw.w;
            acc[2][0]+=a2*bw.x; acc[2][1]+=a2*bw.y; acc[2][2]+=a2*bw.z; acc[2][3]+=a2*bw.w;
            acc[3][0]+=a3*bw.x; acc[3][1]+=a3*bw.y; acc[3][2]+=a3*bw.z; acc[3][3]+=a3*bw.w;
        }
        float* out = Om[m];
        int hh = tn >> 3, dh = tn & 7;
#pragma unroll
        for (int i = 0; i < 4; i++) {
            int gt = row0 + tm + i;
            int bb = gt >> 10, t = gt & 1023;
            float4 o4; o4.x = acc[i][0]; o4.y = acc[i][1]; o4.z = acc[i][2]; o4.w = acc[i][3];
            *(float4*)(out + (((long)(bb*8 + hh)*1024) + t)*8 + dh) = o4;
        }
    }
}

// ---------------- WO GEMM: attn @ Wo + bias + resid -> h ----------------------
__global__ __launch_bounds__(256) void wo_kernel(
        const float* __restrict__ X, const float* __restrict__ W,
        const float* __restrict__ bias, const float* __restrict__ resid,
        float* __restrict__ out) {
    __shared__ float Xs[64][68];
    __shared__ float Ws[64][64];
    int tid = threadIdx.x;                 // 256
    int row0 = blockIdx.x * 64;
    for (int idx = tid; idx < 1024; idx += 256) {
        int i = idx >> 4, j = (idx & 15) * 4;
        *(float4*)&Xs[i][j] = *(const float4*)(X + (long)(row0 + i)*ND + j);
        *(float4*)&Ws[i][j] = *(const float4*)(W + idx*4);
    }
    __syncthreads();
    int tm = (tid >> 4) * 4, tn = (tid & 15) * 4;
    float acc[4][4] = {};
    for (int kk = 0; kk < 64; kk++) {
        float a0 = Xs[tm+0][kk], a1 = Xs[tm+1][kk], a2 = Xs[tm+2][kk], a3 = Xs[tm+3][kk];
        float4 bw = *(const float4*)&Ws[kk][tn];
        acc[0][0]+=a0*bw.x; acc[0][1]+=a0*bw.y; acc[0][2]+=a0*bw.z; acc[0][3]+=a0*bw.w;
        acc[1][0]+=a1*bw.x; acc[1][1]+=a1*bw.y; acc[1][2]+=a1*bw.z; acc[1][3]+=a1*bw.w;
        acc[2][0]+=a2*bw.x; acc[2][1]+=a2*bw.y; acc[2][2]+=a2*bw.z; acc[2][3]+=a2*bw.w;
        acc[3][0]+=a3*bw.x; acc[3][1]+=a3*bw.y; acc[3][2]+=a3*bw.z; acc[3][3]+=a3*bw.w;
    }
    float4 bb4 = *(const float4*)(bias + tn);
#pragma unroll
    for (int i = 0; i < 4; i++) {
        long gt = row0 + tm + i;
        float4 rr = *(const float4*)(resid + gt*ND + tn);
        float4 o4;
        o4.x = acc[i][0] + bb4.x + rr.x; o4.y = acc[i][1] + bb4.y + rr.y;
        o4.z = acc[i][2] + bb4.z + rr.z; o4.w = acc[i][3] + bb4.w + rr.w;
        *(float4*)(out + gt*ND + tn) = o4;
    }
}

// ---------------- fused LN + FFN1 (+ gelu): all 4 chunks in one block ---------
__global__ __launch_bounds__(256) void lnffn1_kernel(
        const float* __restrict__ X, const float* __restrict__ lns, const float* __restrict__ lnb,
        const float* __restrict__ W1, const float* __restrict__ b1,
        float* __restrict__ Y) {
    __shared__ float Xs[64][68];
    __shared__ float Ws[64][64];
    int tid = threadIdx.x;
    int row0 = blockIdx.x * 64;
    load_ln_tile(X, row0, lns, lnb, Xs, tid);
    int tm = (tid >> 4) * 4, tn = (tid & 15) * 4;
    for (int c0 = 0; c0 < 256; c0 += 64) {
        for (int idx = tid; idx < 1024; idx += 256) {
            int i = idx >> 4, j = (idx & 15) * 4;
            *(float4*)&Ws[i][j] = *(const float4*)(W1 + i*256 + c0 + j);
        }
        __syncthreads();
        float acc[4][4] = {};
        for (int kk = 0; kk < 64; kk++) {
            float a0 = Xs[tm+0][kk], a1 = Xs[tm+1][kk], a2 = Xs[tm+2][kk], a3 = Xs[tm+3][kk];
            float4 bw = *(const float4*)&Ws[kk][tn];
            acc[0][0]+=a0*bw.x; acc[0][1]+=a0*bw.y; acc[0][2]+=a0*bw.z; acc[0][3]+=a0*bw.w;
            acc[1][0]+=a1*bw.x; acc[1][1]+=a1*bw.y; acc[1][2]+=a1*bw.z; acc[1][3]+=a1*bw.w;
            acc[2][0]+=a2*bw.x; acc[2][1]+=a2*bw.y; acc[2][2]+=a2*bw.z; acc[2][3]+=a2*bw.w;
            acc[3][0]+=a3*bw.x; acc[3][1]+=a3*bw.y; acc[3][2]+=a3*bw.z; acc[3][3]+=a3*bw.w;
        }
        float4 bb4 = *(const float4*)(b1 + c0 + tn);
        float bv[4] = {bb4.x, bb4.y, bb4.z, bb4.w};
#pragma unroll
        for (int i = 0; i < 4; i++) {
            long gt = row0 + tm + i;
            float4 o4;
            float* o = (float*)&o4;
#pragma unroll
            for (int j = 0; j < 4; j++) {
                float z = acc[i][j] + bv[j];
                o[j] = 0.5f * z * (1.f + erff(z * 0.70710678118654752f));
            }
            *(float4*)(Y + gt*256 + c0 + tn) = o4;
        }
        __syncthreads();
    }
}

// ---------------- FFN2: Y(.,256) @ W2(256,64) + b2 + resid -> h ---------------
__global__ __launch_bounds__(256) void ffn2_kernel(
        const float* __restrict__ Y, const float* __restrict__ W2,
        const float* __restrict__ b2, const float* __restrict__ resid,
        float* __restrict__ out) {
    __shared__ float Ys[64][68];
    __shared__ float Ws[64][64];
    int tid = threadIdx.x, row0 = blockIdx.x * 64;
    int tm = (tid >> 4) * 4, tn = (tid & 15) * 4;
    float acc[4][4] = {};
    for (int kc = 0; kc < 4; kc++) {
        __syncthreads();
        for (int idx = tid; idx < 1024; idx += 256) {
            int i = idx >> 4, j = (idx & 15) * 4;
            *(float4*)&Ys[i][j] = *(const float4*)(Y + (long)(row0 + i)*256 + kc*64 + j);
            *(float4*)&Ws[i][j] = *(const float4*)(W2 + (kc*64 + i)*64 + j);
        }
        __syncthreads();
        for (int kk = 0; kk < 64; kk++) {
            float a0 = Ys[tm+0][kk], a1 = Ys[tm+1][kk], a2 = Ys[tm+2][kk], a3 = Ys[tm+3][kk];
            float4 bw = *(const float4*)&Ws[kk][tn];
            acc[0][0]+=a0*bw.x; acc[0][1]+=a0*bw.y; acc[0][2]+=a0*bw.z; acc[0][3]+=a0*bw.w;
            acc[1][0]+=a1*bw.x; acc[1][1]+=a1*bw.y; acc[1][2]+=a1*bw.z; acc[1][3]+=a1*bw.w;
            acc[2][0]+=a2*bw.x; acc[2][1]+=a2*bw.y; acc[2][2]+=a2*bw.z; acc[2][3]+=a2*bw.w;
            acc[3][0]+=a3*bw.x; acc[3][1]+=a3*bw.y; acc[3][2]+=a3*bw.z; acc[3][3]+=a3*bw.w;
        }
    }
    float4 bb4 = *(const float4*)(b2 + tn);
#pragma unroll
    for (int i = 0; i < 4; i++) {
        long gt = row0 + tm + i;
        float4 rr = *(const float4*)(resid + gt*ND + tn);
        float4 o4;
        o4.x = acc[i][0] + bb4.x + rr.x; o4.y = acc[i][1] + bb4.y + rr.y;
        o4.z = acc[i][2] + bb4.z + rr.z; o4.w = acc[i][3] + bb4.w + rr.w;
        *(float4*)(out + gt*ND + tn) = o4;
    }
}

// ---------------- local windowed attention (heads 0..3) ----------------------
__global__ __launch_bounds__(128) void local_attn_kernel(
        const float* __restrict__ q, const float* __restrict__ k,
        const float* __restrict__ v, float* __restrict__ attn) {
    int bid = blockIdx.x;                  // b*32 + h*8 + w
    int w = bid & 7, h = (bid >> 3) & 3, b = bid >> 5;
    __shared__ float Ks[384][8];
    __shared__ float Vs[384][8];
    int tid = threadIdx.x;                 // 128
    int base = ((b*8 + h)*1024) * 8;
    int jlo = (w == 0) ? 128 : 0;
    int jhi = (w == 7) ? 256 : 384;
    for (int idx = tid; idx < 768; idx += 128) {
        int j = idx >> 1, half = (idx & 1) * 4;
        int tt = (w - 1)*128 + j;
        float4 kv = {0,0,0,0}, vv = {0,0,0,0};
        if (tt >= 0 && tt < 1024) {
            kv = *(const float4*)(k + base + tt*8 + half);
            vv = *(const float4*)(v + base + tt*8 + half);
        }
        *(float4*)&Ks[j][half] = kv;
        *(float4*)&Vs[j][half] = vv;
    }
    __syncthreads();
    int t = w*128 + tid;
    float4 q0 = *(const float4*)(q + base + t*8);
    float4 q1 = *(const float4*)(q + base + t*8 + 4);
    float qr[8] = {q0.x,q0.y,q0.z,q0.w,q1.x,q1.y,q1.z,q1.w};
    const float scale = 0.35355339059327373f;   // 1/sqrt(8)
    float m = -1e30f, l = 0.f, acc[8] = {};
    for (int j = jlo; j < jhi; j++) {
        float4 k0 = *(const float4*)&Ks[j][0];
        float4 k1 = *(const float4*)&Ks[j][4];
        float s = qr[0]*k0.x + qr[1]*k0.y + qr[2]*k0.z + qr[3]*k0.w
                + qr[4]*k1.x + qr[5]*k1.y + qr[6]*k1.z + qr[7]*k1.w;
        s *= scale;
        float mn = fmaxf(m, s);
        float corr = __expf(m - mn);
        float p = __expf(s - mn);
        l = l*corr + p;
        float4 v0 = *(const float4*)&Vs[j][0];
        float4 v1 = *(const float4*)&Vs[j][4];
        acc[0] = acc[0]*corr + p*v0.x; acc[1] = acc[1]*corr + p*v0.y;
        acc[2] = acc[2]*corr + p*v0.z; acc[3] = acc[3]*corr + p*v0.w;
        acc[4] = acc[4]*corr + p*v1.x; acc[5] = acc[5]*corr + p*v1.y;
        acc[6] = acc[6]*corr + p*v1.z; acc[7] = acc[7]*corr + p*v1.w;
        m = mn;
    }
    float inv = 1.f / l;
    float4 o0, o1;
    o0.x = acc[0]*inv; o0.y = acc[1]*inv; o0.z = acc[2]*inv; o0.w = acc[3]*inv;
    o1.x = acc[4]*inv; o1.y = acc[5]*inv; o1.z = acc[6]*inv; o1.w = acc[7]*inv;
    long ob = ((long)(b*1024 + t)*64) + h*8;
    *(float4*)(attn + ob) = o0;
    *(float4*)(attn + ob + 4) = o1;
}

// ---------------- global linear attention (heads 4..7) -----------------------
__global__ void global_attn_kernel(const float* __restrict__ q, const float* __restrict__ k,
                                   const float* __restrict__ v, float* __restrict__ attn) {
    int b = blockIdx.x >> 2, h = blockIdx.x & 3;
    int tid = threadIdx.x;                 // 256
    int base = ((b*8 + 4 + h)*1024) * 8;
    __shared__ float red[8][72];
    __shared__ float M[8];
    __shared__ float C[64];
    int warp = tid >> 5, lane = tid & 31;

    float mx[8];
#pragma unroll
    for (int d = 0; d < 8; d++) mx[d] = -1e30f;
    for (int t = tid; t < 1024; t += 256) {
        float4 k0 = *(const float4*)(k + base + t*8);
        float4 k1 = *(const float4*)(k + base + t*8 + 4);
        mx[0]=fmaxf(mx[0],k0.x); mx[1]=fmaxf(mx[1],k0.y); mx[2]=fmaxf(mx[2],k0.z); mx[3]=fmaxf(mx[3],k0.w);
        mx[4]=fmaxf(mx[4],k1.x); mx[5]=fmaxf(mx[5],k1.y); mx[6]=fmaxf(mx[6],k1.z); mx[7]=fmaxf(mx[7],k1.w);
    }
#pragma unroll
    for (int d = 0; d < 8; d++)
        for (int o = 16; o; o >>= 1) mx[d] = fmaxf(mx[d], __shfl_xor_sync(~0u, mx[d], o));
    if (lane == 0)
        for (int d = 0; d < 8; d++) red[warp][d] = mx[d];
    __syncthreads();
    if (tid < 8) {
        float m_ = red[0][tid];
        for (int wv = 1; wv < 8; wv++) m_ = fmaxf(m_, red[wv][tid]);
        M[tid] = m_;
    }
    __syncthreads();

    float Z[8] = {}, ctx[64] = {};
    for (int t = tid; t < 1024; t += 256) {
        float4 k0 = *(const float4*)(k + base + t*8);
        float4 k1 = *(const float4*)(k + base + t*8 + 4);
        float4 v0 = *(const float4*)(v + base + t*8);
        float4 v1 = *(const float4*)(v + base + t*8 + 4);
        float kr[8] = {k0.x,k0.y,k0.z,k0.w,k1.x,k1.y,k1.z,k1.w};
        float vr[8] = {v0.x,v0.y,v0.z,v0.w,v1.x,v1.y,v1.z,v1.w};
#pragma unroll
        for (int d = 0; d < 8; d++) {
            float e_ = __expf(kr[d] - M[d]);
            Z[d] += e_;
#pragma unroll
            for (int e = 0; e < 8; e++) ctx[d*8 + e] += e_ * vr[e];
        }
    }
#pragma unroll
    for (int i = 0; i < 8; i++)
        for (int o = 16; o; o >>= 1) Z[i] += __shfl_xor_sync(~0u, Z[i], o);
#pragma unroll
    for (int i = 0; i < 64; i++)
        for (int o = 16; o; o >>= 1) ctx[i] += __shfl_xor_sync(~0u, ctx[i], o);
    if (lane == 0) {
        for (int i = 0; i < 8; i++)  red[warp][i] = Z[i];
        for (int i = 0; i < 64; i++) red[warp][8 + i] = ctx[i];
    }
    __syncthreads();
    if (tid < 64) {
        float s = 0.f, z = 0.f;
        int d = tid >> 3;
        for (int wv = 0; wv < 8; wv++) { s += red[wv][8 + tid]; z += red[wv][d]; }
        C[tid] = s / z;
    }
    __syncthreads();

    const float scale = 0.35355339059327373f;
    for (int t = tid; t < 1024; t += 256) {
        float4 q0 = *(const float4*)(q + base + t*8);
        float4 q1 = *(const float4*)(q + base + t*8 + 4);
        float qr[8] = {q0.x,q0.y,q0.z,q0.w,q1.x,q1.y,q1.z,q1.w};
        float qm = -1e30f;
#pragma unroll
        for (int d = 0; d < 8; d++) qm = fmaxf(qm, qr[d]);
        float qs = 0.f;
#pragma unroll
        for (int d = 0; d < 8; d++) { qr[d] = __expf(qr[d] - qm); qs += qr[d]; }
        float inv = scale / qs;
        float o_[8] = {};
#pragma unroll
        for (int d = 0; d < 8; d++) {
            float p = qr[d] * inv;
#pragma unroll
            for (int e = 0; e < 8; e++) o_[e] += p * C[d*8 + e];
        }
        long ob = (long)(b*1024 + t)*64 + (4 + h)*8;
        float4 oo0, oo1;
        oo0.x=o_[0]; oo0.y=o_[1]; oo0.z=o_[2]; oo0.w=o_[3];
        oo1.x=o_[4]; oo1.y=o_[5]; oo1.z=o_[6]; oo1.w=o_[7];
        *(float4*)(attn + ob) = oo0;
        *(float4*)(attn + ob + 4) = oo1;
    }
}

// ---------------- collapse: h(.,64) @ cw(64,5) + cb -> out --------------------
__global__ void collapse_kernel(const float* __restrict__ h, const float* __restrict__ cw,
                                const float* __restrict__ cb, float* __restrict__ out) {
    __shared__ float Xs[64][68];
    __shared__ float Ws[64][NDIN];
    __shared__ float Bs[NDIN];
    int tid = threadIdx.x;                 // 64
    int row0 = blockIdx.x * 64;
    for (int idx = tid; idx < 1024; idx += 64) {
        int i = idx >> 4, j = (idx & 15) * 4;
        *(float4*)&Xs[i][j] = *(const float4*)(h + (long)(row0 + i)*ND + j);
    }
    for (int idx = tid; idx < 64*NDIN; idx += 64) Ws[idx/NDIN][idx%NDIN] = cw[idx];
    if (tid < NDIN) Bs[tid] = cb[tid];
    __syncthreads();
    int r = tid;
    float acc[NDIN];
#pragma unroll
    for (int j = 0; j < NDIN; j++) acc[j] = Bs[j];
    for (int kk = 0; kk < 64; kk++) {
        float xv = Xs[r][kk];
#pragma unroll
        for (int j = 0; j < NDIN; j++) acc[j] += xv * Ws[kk][j];
    }
#pragma unroll
    for (int j = 0; j < NDIN; j++) out[(row0 + r)*NDIN + j] = acc[j];
}

// ---------------- launch ------------------------------------------------------
extern "C" void kernel_launch(void* const* d_in, const int* in_sizes, int n_in,
                              void* d_out, int out_size) {
    const float* x          = (const float*)d_in[0];
    const float* pos_emb    = (const float*)d_in[1];
    const float* expand_w   = (const float*)d_in[2];
    const float* expand_b   = (const float*)d_in[3];
    const float* emb_w      = (const float*)d_in[4];
    const float* emb_b      = (const float*)d_in[5];
    const float* conv_w     = (const float*)d_in[6];
    const float* conv_b     = (const float*)d_in[7];
    const float* ln1_s      = (const float*)d_in[8];
    const float* ln1_b      = (const float*)d_in[9];
    const float* wq         = (const float*)d_in[10];
    const float* wk         = (const float*)d_in[11];
    const float* wv         = (const float*)d_in[12];
    const float* wo         = (const float*)d_in[13];
    const float* wo_b       = (const float*)d_in[14];
    const float* ln2_s      = (const float*)d_in[15];
    const float* ln2_b      = (const float*)d_in[16];
    const float* ff_w1      = (const float*)d_in[17];
    const float* ff_b1      = (const float*)d_in[18];
    const float* ff_w2      = (const float*)d_in[19];
    const float* ff_b2      = (const float*)d_in[20];
    const float* collapse_w = (const float*)d_in[21];
    const float* collapse_b = (const float*)d_in[22];
    float* out = (float*)d_out;

    float *ph, *php, *pq, *pk, *pv, *pattn, *py, *pWc, *pbc;
    cudaGetSymbolAddress((void**)&ph,   g_h);
    cudaGetSymbolAddress((void**)&php,  g_hpad);
    cudaGetSymbolAddress((void**)&pq,   g_q);
    cudaGetSymbolAddress((void**)&pk,   g_k);
    cudaGetSymbolAddress((void**)&pv,   g_v);
    cudaGetSymbolAddress((void**)&pattn,g_attn);
    cudaGetSymbolAddress((void**)&py,   g_y);
    cudaGetSymbolAddress((void**)&pWc,  g_Wc);
    cudaGetSymbolAddress((void**)&pbc,  g_bc);

    precompute_kernel<<<1, 64>>>(expand_w, expand_b, emb_w, emb_b, pWc, pbc);
    expand_kernel<<<NTOK/64, 256>>>(x, pWc, pbc, php);
    conv_kernel<<<dim3(4096/CBN, 1024/CBM), 256>>>(conv_w, php, conv_b, pos_emb, ph);

    for (int l = 0; l < 2; l++) {
        lnqkv_kernel<<<NTOK/64, 256>>>(ph, ln1_s + l*64, ln1_b + l*64,
                                       wq + l*4096, wk + l*4096, wv + l*4096, pq, pk, pv);
        local_attn_kernel<<<NB*4*8, 128>>>(pq, pk, pv, pattn);
        global_attn_kernel<<<NB*4, 256>>>(pq, pk, pv, pattn);
        wo_kernel<<<NTOK/64, 256>>>(pattn, wo + l*4096, wo_b + l*64, ph, ph);
        lnffn1_kernel<<<NTOK/64, 256>>>(ph, ln2_s + l*64, ln2_b + l*64,
                                        ff_w1 + l*64*256, ff_b1 + l*256, py);
        ffn2_kernel<<<NTOK/64, 256>>>(py, ff_w2 + l*256*64, ff_b2 + l*64, ph, ph);
    }
    collapse_kernel<<<NTOK/64, 64>>>(ph, collapse_w, collapse_b, out);
}

// round 8
// speedup vs baseline: 3.0254x; 1.3213x over previous
#include <cuda_runtime.h>
#include <cuda_bf16.h>
#include <cstdint>
#include <math.h>

// Problem constants: B=64, T=1024, DIN=5, D=64, H=8, DH=8, NLOCAL=4, WS=128, DEPTH=2
#define NB 64
#define NT 1024
#define NDIN 5
#define ND 64
#define NTOK (NB*NT)           // 65536

// ---------------- scratch (static device buffers) -----------------------------
__device__ float g_h[NTOK*ND];          // running hidden state
__device__ float g_hpad[NTOK*66];       // padded pre-conv activations (cols 0,65 stay zero)
__device__ float g_q[NTOK*ND];          // [b][h][t][dh]
__device__ float g_k[NTOK*ND];
__device__ float g_v[NTOK*ND];
__device__ float g_attn[NTOK*ND];       // [b][t][h*8+dh]
__device__ float g_y[NTOK*ND*4];        // FFN intermediate
__device__ float g_Wc[NDIN*ND];
__device__ float g_bc[ND];

// ---------------- bf16 split helpers ------------------------------------------
// pack2: two fp32 -> packed bf16x2 hi (lo16 = x0) plus packed residual mid.
__device__ __forceinline__ void pack2(float x0, float x1, uint32_t& hi, uint32_t& mid) {
    uint32_t h;
    asm("cvt.rn.bf16x2.f32 %0, %1, %2;" : "=r"(h) : "f"(x1), "f"(x0));
    float f0 = __uint_as_float(h << 16);
    float f1 = __uint_as_float(h & 0xFFFF0000u);
    float r0 = x0 - f0, r1 = x1 - f1;
    asm("cvt.rn.bf16x2.f32 %0, %1, %2;" : "=r"(mid) : "f"(r1), "f"(r0));
    hi = h;
}
__device__ __forceinline__ void mma_bf16(float* c, const uint32_t* a, const uint32_t* b) {
    asm volatile("mma.sync.aligned.m16n8k16.row.col.f32.bf16.bf16.f32 "
        "{%0,%1,%2,%3}, {%4,%5,%6,%7}, {%8,%9}, {%0,%1,%2,%3};"
        : "+f"(c[0]), "+f"(c[1]), "+f"(c[2]), "+f"(c[3])
        : "r"(a[0]), "r"(a[1]), "r"(a[2]), "r"(a[3]), "r"(b[0]), "r"(b[1]));
}

// ---------------- precompute combined expand@emb ------------------------------
__global__ void precompute_kernel(const float* __restrict__ ew, const float* __restrict__ eb,
                                  const float* __restrict__ mw, const float* __restrict__ mb,
                                  float* __restrict__ Wc, float* __restrict__ bc) {
    int j = threadIdx.x;             // 64 threads
    for (int i = 0; i < NDIN; i++) {
        float s = 0.f;
        for (int d = 0; d < ND; d++) s += ew[i*ND + d] * mw[d*ND + j];
        Wc[i*ND + j] = s;
    }
    float s = mb[j];
    for (int d = 0; d < ND; d++) s += eb[d] * mw[d*ND + j];
    bc[j] = s;
}

// ---------------- expand: x(.,5) @ Wc(5,64) + bc -> g_hpad (stride 66, off 1) --
__global__ void expand_kernel(const float* __restrict__ x, const float* __restrict__ Wc,
                              const float* __restrict__ bc, float* __restrict__ out) {
    __shared__ float Xs[64][NDIN];
    __shared__ float Ws[NDIN][ND];
    __shared__ float Bs[ND];
    int tid = threadIdx.x;                 // 256
    int row0 = blockIdx.x * 64;
    for (int idx = tid; idx < 64*NDIN; idx += 256) Xs[idx/NDIN][idx%NDIN] = x[row0*NDIN + idx];
    for (int idx = tid; idx < NDIN*ND; idx += 256) Ws[idx>>6][idx&63] = Wc[idx];
    if (tid < ND) Bs[tid] = bc[tid];
    __syncthreads();
    int r = tid >> 2, c = (tid & 3) * 16;
    float acc[16];
#pragma unroll
    for (int j = 0; j < 16; j++) acc[j] = Bs[c+j];
#pragma unroll
    for (int i = 0; i < NDIN; i++) {
        float xv = Xs[r][i];
#pragma unroll
        for (int j = 0; j < 16; j++) acc[j] += xv * Ws[i][c+j];
    }
    float* orow = out + (long)(row0+r)*66 + 1 + c;
#pragma unroll
    for (int j = 0; j < 16; j++) orow[j] = acc[j];
}

// ---------------- conv as GEMM, bf16x3 split on m16n8k16 ----------------------
// C[to][(b,d)] = sum_K conv_w[to][K] * Hpad[(b*1024 + K/3)*66 + d + K%3]
#define CBM 128
#define CBN 128
#define CBK 16
__global__ __launch_bounds__(256) void conv_kernel(
        const float* __restrict__ A, const float* __restrict__ Hpad,
        const float* __restrict__ conv_b, const float* __restrict__ pos_emb,
        float* __restrict__ Hout) {
    // packed bf16x2 tiles: [row][k-pair], row stride 9 u32
    __shared__ uint32_t Ah[2][CBM][9], Am[2][CBM][9];
    __shared__ uint32_t Bh[2][CBN][9], Bm[2][CBN][9];
    int tid = threadIdx.x;                 // 256
    int m0 = blockIdx.y * CBM;             // to-tile
    int n0 = blockIdx.x * CBN;             // (b,d)-tile

    // loader coords
    int arow = tid >> 1;                   // 0..127
    int acol0 = (tid & 1) * 8;             // k offset 0/8
    int ap = acol0 >> 1;                   // packed idx 0/4
    int bj = tid & 127;                    // n col
    int bk0 = (tid >> 7) * 8;              // k offset 0/8
    int bp = bk0 >> 1;
    int bb = (n0 >> 6) + (bj >> 6);
    long browbase = ((long)(bb << 10)) * 66;
    int bd = bj & 63;

    // mma coords
    int w = tid >> 5, lane = tid & 31;
    int gid = lane >> 2, t4 = lane & 3;
    int warpM = w >> 1, warpN = w & 1;     // 4 x 2 warp grid
    int mbase = warpM * 32, nbase = warpN * 64;

    float acc[2][8][4];
#pragma unroll
    for (int mt = 0; mt < 2; mt++)
#pragma unroll
        for (int nt = 0; nt < 8; nt++)
#pragma unroll
            for (int r = 0; r < 4; r++) acc[mt][nt][r] = 0.f;

    auto loadA = [&](int k0, int buf) {
        const float4* p = (const float4*)(A + (m0 + arow)*3072 + k0 + acol0);
        float4 v0 = p[0], v1 = p[1];
        uint32_t h, m_;
        pack2(v0.x, v0.y, h, m_); Ah[buf][arow][ap+0] = h; Am[buf][arow][ap+0] = m_;
        pack2(v0.z, v0.w, h, m_); Ah[buf][arow][ap+1] = h; Am[buf][arow][ap+1] = m_;
        pack2(v1.x, v1.y, h, m_); Ah[buf][arow][ap+2] = h; Am[buf][arow][ap+2] = m_;
        pack2(v1.z, v1.w, h, m_); Ah[buf][arow][ap+3] = h; Am[buf][arow][ap+3] = m_;
    };
    auto loadB = [&](int k0, int buf) {
        float br[8];
#pragma unroll
        for (int u = 0; u < 8; u++) {
            int K = k0 + bk0 + u;
            int kt = K / 3, kp = K - kt*3;
            br[u] = Hpad[browbase + (long)kt*66 + bd + kp];
        }
        uint32_t h, m_;
        pack2(br[0], br[1], h, m_); Bh[buf][bj][bp+0] = h; Bm[buf][bj][bp+0] = m_;
        pack2(br[2], br[3], h, m_); Bh[buf][bj][bp+1] = h; Bm[buf][bj][bp+1] = m_;
        pack2(br[4], br[5], h, m_); Bh[buf][bj][bp+2] = h; Bm[buf][bj][bp+2] = m_;
        pack2(br[6], br[7], h, m_); Bh[buf][bj][bp+3] = h; Bm[buf][bj][bp+3] = m_;
    };

    loadA(0, 0); loadB(0, 0);
    __syncthreads();

    int cur = 0;
    for (int k0 = CBK; k0 <= 3072; k0 += CBK) {
        if (k0 < 3072) { loadA(k0, cur ^ 1); loadB(k0, cur ^ 1); }
        // fragments from buffer cur
        uint32_t ah[2][4], am[2][4];
#pragma unroll
        for (int mt = 0; mt < 2; mt++) {
            int r0 = mbase + mt*16 + gid;
            ah[mt][0] = Ah[cur][r0  ][t4];   ah[mt][1] = Ah[cur][r0+8][t4];
            ah[mt][2] = Ah[cur][r0  ][t4+4]; ah[mt][3] = Ah[cur][r0+8][t4+4];
            am[mt][0] = Am[cur][r0  ][t4];   am[mt][1] = Am[cur][r0+8][t4];
            am[mt][2] = Am[cur][r0  ][t4+4]; am[mt][3] = Am[cur][r0+8][t4+4];
        }
#pragma unroll
        for (int nt = 0; nt < 8; nt++) {
            int n = nbase + nt*8 + gid;
            uint32_t bhf[2] = { Bh[cur][n][t4], Bh[cur][n][t4+4] };
            uint32_t bmf[2] = { Bm[cur][n][t4], Bm[cur][n][t4+4] };
#pragma unroll
            for (int mt = 0; mt < 2; mt++) {
                mma_bf16(acc[mt][nt], ah[mt], bhf);
                mma_bf16(acc[mt][nt], ah[mt], bmf);
                mma_bf16(acc[mt][nt], am[mt], bhf);
            }
        }
        __syncthreads();
        cur ^= 1;
    }

    // ---- epilogue: +conv_b +pos_emb, scatter to [b][to][d] ----
#pragma unroll
    for (int mt = 0; mt < 2; mt++) {
        int row0r = m0 + mbase + mt*16 + gid;   // and +8
        float cb0 = conv_b[row0r];
        float cb1 = conv_b[row0r + 8];
#pragma unroll
        for (int nt = 0; nt < 8; nt++) {
            int coln = n0 + nbase + nt*8 + t4*2;
            int b_ = coln >> 6, d_ = coln & 63;
            float2 pe0 = *(const float2*)(pos_emb + row0r*64 + d_);
            float2 pe1 = *(const float2*)(pos_emb + (row0r+8)*64 + d_);
            float2 o0, o1;
            o0.x = acc[mt][nt][0] + cb0 + pe0.x;
            o0.y = acc[mt][nt][1] + cb0 + pe0.y;
            o1.x = acc[mt][nt][2] + cb1 + pe1.x;
            o1.y = acc[mt][nt][3] + cb1 + pe1.y;
            *(float2*)(Hout + ((long)(b_ << 10) + row0r)*64 + d_) = o0;
            *(float2*)(Hout + ((long)(b_ << 10) + row0r + 8)*64 + d_) = o1;
        }
    }
}

// ---------------- shared helper: load 64x64 X tile + layernorm in smem ---------
__device__ __forceinline__ void load_ln_tile(const float* __restrict__ X, int row0,
                                             const float* __restrict__ s, const float* __restrict__ b,
                                             float Xs[64][68], int tid) {
    for (int idx = tid; idx < 1024; idx += 256) {
        int i = idx >> 4, j = (idx & 15) * 4;
        *(float4*)&Xs[i][j] = *(const float4*)(X + (long)(row0 + i)*ND + j);
    }
    __syncthreads();
    int r = tid >> 2, qd = (tid & 3) * 16;
    float sum = 0.f;
#pragma unroll
    for (int jj = 0; jj < 16; jj++) sum += Xs[r][qd + jj];
    sum += __shfl_xor_sync(~0u, sum, 1);
    sum += __shfl_xor_sync(~0u, sum, 2);
    float mu = sum * (1.f/64.f);
    float vs = 0.f;
#pragma unroll
    for (int jj = 0; jj < 16; jj++) { float d = Xs[r][qd + jj] - mu; vs += d*d; }
    vs += __shfl_xor_sync(~0u, vs, 1);
    vs += __shfl_xor_sync(~0u, vs, 2);
    float inv = rsqrtf(vs * (1.f/64.f) + 1e-5f);
#pragma unroll
    for (int jj = 0; jj < 16; jj++) {
        int c = qd + jj;
        Xs[r][c] = (Xs[r][c] - mu) * inv * s[c] + b[c];
    }
    __syncthreads();
}

// ---------------- fused LN + QKV GEMM -> head layout --------------------------
__global__ __launch_bounds__(256) void lnqkv_kernel(
        const float* __restrict__ X, const float* __restrict__ lns, const float* __restrict__ lnb,
        const float* __restrict__ Wq, const float* __restrict__ Wk, const float* __restrict__ Wv,
        float* __restrict__ q, float* __restrict__ k, float* __restrict__ v) {
    __shared__ float Xs[64][68];
    __shared__ float Ws[64][64];
    int tid = threadIdx.x;                 // 256
    int row0 = blockIdx.x * 64;
    load_ln_tile(X, row0, lns, lnb, Xs, tid);

    int tm = (tid >> 4) * 4, tn = (tid & 15) * 4;
    const float* Wm[3] = {Wq, Wk, Wv};
    float* Om[3] = {q, k, v};
#pragma unroll
    for (int m = 0; m < 3; m++) {
        if (m) __syncthreads();
        const float* W = Wm[m];
#pragma unroll
        for (int u = 0; u < 4; u++) {
            int idx = tid + u*256;
            *(float4*)&Ws[idx >> 4][(idx & 15)*4] = *(const float4*)(W + idx*4);
        }
        __syncthreads();
        float acc[4][4] = {};
        for (int kk = 0; kk < 64; kk++) {
            float a0 = Xs[tm+0][kk], a1 = Xs[tm+1][kk], a2 = Xs[tm+2][kk], a3 = Xs[tm+3][kk];
            float4 bw = *(const float4*)&Ws[kk][tn];
            acc[0][0]+=a0*bw.x; acc[0][1]+=a0*bw.y; acc[0][2]+=a0*bw.z; acc[0][3]+=a0*bw.w;
            acc[1][0]+=a1*bw.x; acc[1][1]+=a1*bw.y; acc[1][2]+=a1*bw.z; acc[1][3]+=a1*bw.w;
            acc[2][0]+=a2*bw.x; acc[2][1]+=a2*bw.y; acc[2][2]+=a2*bw.z; acc[2][3]+=a2*bw.w;
            acc[3][0]+=a3*bw.x; acc[3][1]+=a3*bw.y; acc[3][2]+=a3*bw.z; acc[3][3]+=a3*bw.w;
        }
        float* out = Om[m];
        int hh = tn >> 3, dh = tn & 7;
#pragma unroll
        for (int i = 0; i < 4; i++) {
            int gt = row0 + tm + i;
            int bb = gt >> 10, t = gt & 1023;
            float4 o4; o4.x = acc[i][0]; o4.y = acc[i][1]; o4.z = acc[i][2]; o4.w = acc[i][3];
            *(float4*)(out + (((long)(bb*8 + hh)*1024) + t)*8 + dh) = o4;
        }
    }
}

// ---------------- WO GEMM: attn @ Wo + bias + resid -> h ----------------------
__global__ __launch_bounds__(256) void wo_kernel(
        const float* __restrict__ X, const float* __restrict__ W,
        const float* __restrict__ bias, const float* __restrict__ resid,
        float* __restrict__ out) {
    __shared__ float Xs[64][68];
    __shared__ float Ws[64][64];
    int tid = threadIdx.x;                 // 256
    int row0 = blockIdx.x * 64;
    for (int idx = tid; idx < 1024; idx += 256) {
        int i = idx >> 4, j = (idx & 15) * 4;
        *(float4*)&Xs[i][j] = *(const float4*)(X + (long)(row0 + i)*ND + j);
        *(float4*)&Ws[i][j] = *(const float4*)(W + idx*4);
    }
    __syncthreads();
    int tm = (tid >> 4) * 4, tn = (tid & 15) * 4;
    float acc[4][4] = {};
    for (int kk = 0; kk < 64; kk++) {
        float a0 = Xs[tm+0][kk], a1 = Xs[tm+1][kk], a2 = Xs[tm+2][kk], a3 = Xs[tm+3][kk];
        float4 bw = *(const float4*)&Ws[kk][tn];
        acc[0][0]+=a0*bw.x; acc[0][1]+=a0*bw.y; acc[0][2]+=a0*bw.z; acc[0][3]+=a0*bw.w;
        acc[1][0]+=a1*bw.x; acc[1][1]+=a1*bw.y; acc[1][2]+=a1*bw.z; acc[1][3]+=a1*bw.w;
        acc[2][0]+=a2*bw.x; acc[2][1]+=a2*bw.y; acc[2][2]+=a2*bw.z; acc[2][3]+=a2*bw.w;
        acc[3][0]+=a3*bw.x; acc[3][1]+=a3*bw.y; acc[3][2]+=a3*bw.z; acc[3][3]+=a3*bw.w;
    }
    float4 bb4 = *(const float4*)(bias + tn);
#pragma unroll
    for (int i = 0; i < 4; i++) {
        long gt = row0 + tm + i;
        float4 rr = *(const float4*)(resid + gt*ND + tn);
        float4 o4;
        o4.x = acc[i][0] + bb4.x + rr.x; o4.y = acc[i][1] + bb4.y + rr.y;
        o4.z = acc[i][2] + bb4.z + rr.z; o4.w = acc[i][3] + bb4.w + rr.w;
        *(float4*)(out + gt*ND + tn) = o4;
    }
}

// ---------------- fused LN + FFN1 (+ gelu): all 4 chunks in one block ---------
__global__ __launch_bounds__(256) void lnffn1_kernel(
        const float* __restrict__ X, const float* __restrict__ lns, const float* __restrict__ lnb,
        const float* __restrict__ W1, const float* __restrict__ b1,
        float* __restrict__ Y) {
    __shared__ float Xs[64][68];
    __shared__ float Ws[64][64];
    int tid = threadIdx.x;
    int row0 = blockIdx.x * 64;
    load_ln_tile(X, row0, lns, lnb, Xs, tid);
    int tm = (tid >> 4) * 4, tn = (tid & 15) * 4;
    for (int c0 = 0; c0 < 256; c0 += 64) {
        for (int idx = tid; idx < 1024; idx += 256) {
            int i = idx >> 4, j = (idx & 15) * 4;
            *(float4*)&Ws[i][j] = *(const float4*)(W1 + i*256 + c0 + j);
        }
        __syncthreads();
        float acc[4][4] = {};
        for (int kk = 0; kk < 64; kk++) {
            float a0 = Xs[tm+0][kk], a1 = Xs[tm+1][kk], a2 = Xs[tm+2][kk], a3 = Xs[tm+3][kk];
            float4 bw = *(const float4*)&Ws[kk][tn];
            acc[0][0]+=a0*bw.x; acc[0][1]+=a0*bw.y; acc[0][2]+=a0*bw.z; acc[0][3]+=a0*bw.w;
            acc[1][0]+=a1*bw.x; acc[1][1]+=a1*bw.y; acc[1][2]+=a1*bw.z; acc[1][3]+=a1*bw.w;
            acc[2][0]+=a2*bw.x; acc[2][1]+=a2*bw.y; acc[2][2]+=a2*bw.z; acc[2][3]+=a2*bw.w;
            acc[3][0]+=a3*bw.x; acc[3][1]+=a3*bw.y; acc[3][2]+=a3*bw.z; acc[3][3]+=a3*bw.w;
        }
        float4 bb4 = *(const float4*)(b1 + c0 + tn);
        float bv[4] = {bb4.x, bb4.y, bb4.z, bb4.w};
#pragma unroll
        for (int i = 0; i < 4; i++) {
            long gt = row0 + tm + i;
            float4 o4;
            float* o = (float*)&o4;
#pragma unroll
            for (int j = 0; j < 4; j++) {
                float z = acc[i][j] + bv[j];
                o[j] = 0.5f * z * (1.f + erff(z * 0.70710678118654752f));
            }
            *(float4*)(Y + gt*256 + c0 + tn) = o4;
        }
        __syncthreads();
    }
}

// ---------------- FFN2: Y(.,256) @ W2(256,64) + b2 + resid -> h ---------------
__global__ __launch_bounds__(256) void ffn2_kernel(
        const float* __restrict__ Y, const float* __restrict__ W2,
        const float* __restrict__ b2, const float* __restrict__ resid,
        float* __restrict__ out) {
    __shared__ float Ys[64][68];
    __shared__ float Ws[64][64];
    int tid = threadIdx.x, row0 = blockIdx.x * 64;
    int tm = (tid >> 4) * 4, tn = (tid & 15) * 4;
    float acc[4][4] = {};
    for (int kc = 0; kc < 4; kc++) {
        __syncthreads();
        for (int idx = tid; idx < 1024; idx += 256) {
            int i = idx >> 4, j = (idx & 15) * 4;
            *(float4*)&Ys[i][j] = *(const float4*)(Y + (long)(row0 + i)*256 + kc*64 + j);
            *(float4*)&Ws[i][j] = *(const float4*)(W2 + (kc*64 + i)*64 + j);
        }
        __syncthreads();
        for (int kk = 0; kk < 64; kk++) {
            float a0 = Ys[tm+0][kk], a1 = Ys[tm+1][kk], a2 = Ys[tm+2][kk], a3 = Ys[tm+3][kk];
            float4 bw = *(const float4*)&Ws[kk][tn];
            acc[0][0]+=a0*bw.x; acc[0][1]+=a0*bw.y; acc[0][2]+=a0*bw.z; acc[0][3]+=a0*bw.w;
            acc[1][0]+=a1*bw.x; acc[1][1]+=a1*bw.y; acc[1][2]+=a1*bw.z; acc[1][3]+=a1*bw.w;
            acc[2][0]+=a2*bw.x; acc[2][1]+=a2*bw.y; acc[2][2]+=a2*bw.z; acc[2][3]+=a2*bw.w;
            acc[3][0]+=a3*bw.x; acc[3][1]+=a3*bw.y; acc[3][2]+=a3*bw.z; acc[3][3]+=a3*bw.w;
        }
    }
    float4 bb4 = *(const float4*)(b2 + tn);
#pragma unroll
    for (int i = 0; i < 4; i++) {
        long gt = row0 + tm + i;
        float4 rr = *(const float4*)(resid + gt*ND + tn);
        float4 o4;
        o4.x = acc[i][0] + bb4.x + rr.x; o4.y = acc[i][1] + bb4.y + rr.y;
        o4.z = acc[i][2] + bb4.z + rr.z; o4.w = acc[i][3] + bb4.w + rr.w;
        *(float4*)(out + gt*ND + tn) = o4;
    }
}

// ---------------- local windowed attention (heads 0..3), bound-max softmax ----
__global__ __launch_bounds__(128) void local_attn_kernel(
        const float* __restrict__ q, const float* __restrict__ k,
        const float* __restrict__ v, float* __restrict__ attn) {
    int bid = blockIdx.x;                  // b*32 + h*8 + w
    int w = bid & 7, h = (bid >> 3) & 3, b = bid >> 5;
    __shared__ float Ks[384][8];
    __shared__ float Vs[384][8];
    __shared__ float wmax[4];
    int tid = threadIdx.x;                 // 128
    int base = ((b*8 + h)*1024) * 8;
    int jlo = (w == 0) ? 128 : 0;
    int jhi = (w == 7) ? 256 : 384;
    for (int idx = tid; idx < 768; idx += 128) {
        int j = idx >> 1, half = (idx & 1) * 4;
        int tt = (w - 1)*128 + j;
        float4 kv = {0,0,0,0}, vv = {0,0,0,0};
        if (tt >= 0 && tt < 1024) {
            kv = *(const float4*)(k + base + tt*8 + half);
            vv = *(const float4*)(v + base + tt*8 + half);
        }
        *(float4*)&Ks[j][half] = kv;
        *(float4*)&Vs[j][half] = vv;
    }
    __syncthreads();
    // max squared key norm over the window
    float nm = 0.f;
    for (int r = tid; r < 384; r += 128) {
        float4 k0 = *(const float4*)&Ks[r][0];
        float4 k1 = *(const float4*)&Ks[r][4];
        float s2 = k0.x*k0.x + k0.y*k0.y + k0.z*k0.z + k0.w*k0.w
                 + k1.x*k1.x + k1.y*k1.y + k1.z*k1.z + k1.w*k1.w;
        nm = fmaxf(nm, s2);
    }
#pragma unroll
    for (int o = 16; o; o >>= 1) nm = fmaxf(nm, __shfl_xor_sync(~0u, nm, o));
    if ((tid & 31) == 0) wmax[tid >> 5] = nm;
    __syncthreads();
    float kmax2 = fmaxf(fmaxf(wmax[0], wmax[1]), fmaxf(wmax[2], wmax[3]));

    int t = w*128 + tid;
    float4 q0 = *(const float4*)(q + base + t*8);
    float4 q1 = *(const float4*)(q + base + t*8 + 4);
    float qr[8] = {q0.x,q0.y,q0.z,q0.w,q1.x,q1.y,q1.z,q1.w};
    const float scale = 0.35355339059327373f;   // 1/sqrt(8)
    float qn2 = 0.f;
#pragma unroll
    for (int e = 0; e < 8; e++) qn2 += qr[e]*qr[e];
    float m = scale * sqrtf(qn2 * kmax2);       // >= all scores; softmax invariant
    float l = 0.f, acc[8] = {};
    for (int j = jlo; j < jhi; j++) {
        float4 k0 = *(const float4*)&Ks[j][0];
        float4 k1 = *(const float4*)&Ks[j][4];
        float s = qr[0]*k0.x + qr[1]*k0.y + qr[2]*k0.z + qr[3]*k0.w
                + qr[4]*k1.x + qr[5]*k1.y + qr[6]*k1.z + qr[7]*k1.w;
        float p = __expf(s*scale - m);
        l += p;
        float4 v0 = *(const float4*)&Vs[j][0];
        float4 v1 = *(const float4*)&Vs[j][4];
        acc[0] += p*v0.x; acc[1] += p*v0.y; acc[2] += p*v0.z; acc[3] += p*v0.w;
        acc[4] += p*v1.x; acc[5] += p*v1.y; acc[6] += p*v1.z; acc[7] += p*v1.w;
    }
    float inv = 1.f / l;
    float4 o0, o1;
    o0.x = acc[0]*inv; o0.y = acc[1]*inv; o0.z = acc[2]*inv; o0.w = acc[3]*inv;
    o1.x = acc[4]*inv; o1.y = acc[5]*inv; o1.z = acc[6]*inv; o1.w = acc[7]*inv;
    long ob = ((long)(b*1024 + t)*64) + h*8;
    *(float4*)(attn + ob) = o0;
    *(float4*)(attn + ob + 4) = o1;
}

// ---------------- global linear attention (heads 4..7) -----------------------
__global__ void global_attn_kernel(const float* __restrict__ q, const float* __restrict__ k,
                                   const float* __restrict__ v, float* __restrict__ attn) {
    int b = blockIdx.x >> 2, h = blockIdx.x & 3;
    int tid = threadIdx.x;                 // 256
    int base = ((b*8 + 4 + h)*1024) * 8;
    __shared__ float red[8][72];
    __shared__ float M[8];
    __shared__ float C[64];
    int warp = tid >> 5, lane = tid & 31;

    float mx[8];
#pragma unroll
    for (int d = 0; d < 8; d++) mx[d] = -1e30f;
    for (int t = tid; t < 1024; t += 256) {
        float4 k0 = *(const float4*)(k + base + t*8);
        float4 k1 = *(const float4*)(k + base + t*8 + 4);
        mx[0]=fmaxf(mx[0],k0.x); mx[1]=fmaxf(mx[1],k0.y); mx[2]=fmaxf(mx[2],k0.z); mx[3]=fmaxf(mx[3],k0.w);
        mx[4]=fmaxf(mx[4],k1.x); mx[5]=fmaxf(mx[5],k1.y); mx[6]=fmaxf(mx[6],k1.z); mx[7]=fmaxf(mx[7],k1.w);
    }
#pragma unroll
    for (int d = 0; d < 8; d++)
        for (int o = 16; o; o >>= 1) mx[d] = fmaxf(mx[d], __shfl_xor_sync(~0u, mx[d], o));
    if (lane == 0)
        for (int d = 0; d < 8; d++) red[warp][d] = mx[d];
    __syncthreads();
    if (tid < 8) {
        float m_ = red[0][tid];
        for (int wv = 1; wv < 8; wv++) m_ = fmaxf(m_, red[wv][tid]);
        M[tid] = m_;
    }
    __syncthreads();

    float Z[8] = {}, ctx[64] = {};
    for (int t = tid; t < 1024; t += 256) {
        float4 k0 = *(const float4*)(k + base + t*8);
        float4 k1 = *(const float4*)(k + base + t*8 + 4);
        float4 v0 = *(const float4*)(v + base + t*8);
        float4 v1 = *(const float4*)(v + base + t*8 + 4);
        float kr[8] = {k0.x,k0.y,k0.z,k0.w,k1.x,k1.y,k1.z,k1.w};
        float vr[8] = {v0.x,v0.y,v0.z,v0.w,v1.x,v1.y,v1.z,v1.w};
#pragma unroll
        for (int d = 0; d < 8; d++) {
            float e_ = __expf(kr[d] - M[d]);
            Z[d] += e_;
#pragma unroll
            for (int e = 0; e < 8; e++) ctx[d*8 + e] += e_ * vr[e];
        }
    }
#pragma unroll
    for (int i = 0; i < 8; i++)
        for (int o = 16; o; o >>= 1) Z[i] += __shfl_xor_sync(~0u, Z[i], o);
#pragma unroll
    for (int i = 0; i < 64; i++)
        for (int o = 16; o; o >>= 1) ctx[i] += __shfl_xor_sync(~0u, ctx[i], o);
    if (lane == 0) {
        for (int i = 0; i < 8; i++)  red[warp][i] = Z[i];
        for (int i = 0; i < 64; i++) red[warp][8 + i] = ctx[i];
    }
    __syncthreads();
    if (tid < 64) {
        float s = 0.f, z = 0.f;
        int d = tid >> 3;
        for (int wv = 0; wv < 8; wv++) { s += red[wv][8 + tid]; z += red[wv][d]; }
        C[tid] = s / z;
    }
    __syncthreads();

    const float scale = 0.35355339059327373f;
    for (int t = tid; t < 1024; t += 256) {
        float4 q0 = *(const float4*)(q + base + t*8);
        float4 q1 = *(const float4*)(q + base + t*8 + 4);
        float qr[8] = {q0.x,q0.y,q0.z,q0.w,q1.x,q1.y,q1.z,q1.w};
        float qm = -1e30f;
#pragma unroll
        for (int d = 0; d < 8; d++) qm = fmaxf(qm, qr[d]);
        float qs = 0.f;
#pragma unroll
        for (int d = 0; d < 8; d++) { qr[d] = __expf(qr[d] - qm); qs += qr[d]; }
        float inv = scale / qs;
        float o_[8] = {};
#pragma unroll
        for (int d = 0; d < 8; d++) {
            float p = qr[d] * inv;
#pragma unroll
            for (int e = 0; e < 8; e++) o_[e] += p * C[d*8 + e];
        }
        long ob = (long)(b*1024 + t)*64 + (4 + h)*8;
        float4 oo0, oo1;
        oo0.x=o_[0]; oo0.y=o_[1]; oo0.z=o_[2]; oo0.w=o_[3];
        oo1.x=o_[4]; oo1.y=o_[5]; oo1.z=o_[6]; oo1.w=o_[7];
        *(float4*)(attn + ob) = oo0;
        *(float4*)(attn + ob + 4) = oo1;
    }
}

// ---------------- collapse: h(.,64) @ cw(64,5) + cb -> out --------------------
__global__ void collapse_kernel(const float* __restrict__ h, const float* __restrict__ cw,
                                const float* __restrict__ cb, float* __restrict__ out) {
    __shared__ float Xs[64][68];
    __shared__ float Ws[64][NDIN];
    __shared__ float Bs[NDIN];
    int tid = threadIdx.x;                 // 64
    int row0 = blockIdx.x * 64;
    for (int idx = tid; idx < 1024; idx += 64) {
        int i = idx >> 4, j = (idx & 15) * 4;
        *(float4*)&Xs[i][j] = *(const float4*)(h + (long)(row0 + i)*ND + j);
    }
    for (int idx = tid; idx < 64*NDIN; idx += 64) Ws[idx/NDIN][idx%NDIN] = cw[idx];
    if (tid < NDIN) Bs[tid] = cb[tid];
    __syncthreads();
    int r = tid;
    float acc[NDIN];
#pragma unroll
    for (int j = 0; j < NDIN; j++) acc[j] = Bs[j];
    for (int kk = 0; kk < 64; kk++) {
        float xv = Xs[r][kk];
#pragma unroll
        for (int j = 0; j < NDIN; j++) acc[j] += xv * Ws[kk][j];
    }
#pragma unroll
    for (int j = 0; j < NDIN; j++) out[(row0 + r)*NDIN + j] = acc[j];
}

// ---------------- launch ------------------------------------------------------
extern "C" void kernel_launch(void* const* d_in, const int* in_sizes, int n_in,
                              void* d_out, int out_size) {
    const float* x          = (const float*)d_in[0];
    const float* pos_emb    = (const float*)d_in[1];
    const float* expand_w   = (const float*)d_in[2];
    const float* expand_b   = (const float*)d_in[3];
    const float* emb_w      = (const float*)d_in[4];
    const float* emb_b      = (const float*)d_in[5];
    const float* conv_w     = (const float*)d_in[6];
    const float* conv_b     = (const float*)d_in[7];
    const float* ln1_s      = (const float*)d_in[8];
    const float* ln1_b      = (const float*)d_in[9];
    const float* wq         = (const float*)d_in[10];
    const float* wk         = (const float*)d_in[11];
    const float* wv         = (const float*)d_in[12];
    const float* wo         = (const float*)d_in[13];
    const float* wo_b       = (const float*)d_in[14];
    const float* ln2_s      = (const float*)d_in[15];
    const float* ln2_b      = (const float*)d_in[16];
    const float* ff_w1      = (const float*)d_in[17];
    const float* ff_b1      = (const float*)d_in[18];
    const float* ff_w2      = (const float*)d_in[19];
    const float* ff_b2      = (const float*)d_in[20];
    const float* collapse_w = (const float*)d_in[21];
    const float* collapse_b = (const float*)d_in[22];
    float* out = (float*)d_out;

    float *ph, *php, *pq, *pk, *pv, *pattn, *py, *pWc, *pbc;
    cudaGetSymbolAddress((void**)&ph,   g_h);
    cudaGetSymbolAddress((void**)&php,  g_hpad);
    cudaGetSymbolAddress((void**)&pq,   g_q);
    cudaGetSymbolAddress((void**)&pk,   g_k);
    cudaGetSymbolAddress((void**)&pv,   g_v);
    cudaGetSymbolAddress((void**)&pattn,g_attn);
    cudaGetSymbolAddress((void**)&py,   g_y);
    cudaGetSymbolAddress((void**)&pWc,  g_Wc);
    cudaGetSymbolAddress((void**)&pbc,  g_bc);

    precompute_kernel<<<1, 64>>>(expand_w, expand_b, emb_w, emb_b, pWc, pbc);
    expand_kernel<<<NTOK/64, 256>>>(x, pWc, pbc, php);
    conv_kernel<<<dim3(4096/CBN, 1024/CBM), 256>>>(conv_w, php, conv_b, pos_emb, ph);

    for (int l = 0; l < 2; l++) {
        lnqkv_kernel<<<NTOK/64, 256>>>(ph, ln1_s + l*64, ln1_b + l*64,
                                       wq + l*4096, wk + l*4096, wv + l*4096, pq, pk, pv);
        local_attn_kernel<<<NB*4*8, 128>>>(pq, pk, pv, pattn);
        global_attn_kernel<<<NB*4, 256>>>(pq, pk, pv, pattn);
        wo_kernel<<<NTOK/64, 256>>>(pattn, wo + l*4096, wo_b + l*64, ph, ph);
        lnffn1_kernel<<<NTOK/64, 256>>>(ph, ln2_s + l*64, ln2_b + l*64,
                                        ff_w1 + l*64*256, ff_b1 + l*256, py);
        ffn2_kernel<<<NTOK/64, 256>>>(py, ff_w2 + l*256*64, ff_b2 + l*64, ph, ph);
    }
    collapse_kernel<<<NTOK/64, 64>>>(ph, collapse_w, collapse_b, out);
}

// round 9
// speedup vs baseline: 3.0415x; 1.0053x over previous
#include <cuda_runtime.h>
#include <cuda_bf16.h>
#include <cstdint>
#include <math.h>

// Problem constants: B=64, T=1024, DIN=5, D=64, H=8, DH=8, NLOCAL=4, WS=128, DEPTH=2
#define NB 64
#define NT 1024
#define NDIN 5
#define ND 64
#define NTOK (NB*NT)           // 65536

// ---------------- scratch (static device buffers) -----------------------------
__device__ float g_h[NTOK*ND];          // running hidden state
__device__ float g_hpad[NTOK*66];       // padded pre-conv activations (cols 0,65 stay zero)
__device__ float g_q[NTOK*ND];          // [b][h][t][dh]
__device__ float g_k[NTOK*ND];
__device__ float g_v[NTOK*ND];
__device__ float g_attn[NTOK*ND];       // [b][t][h*8+dh]
__device__ float g_y[NTOK*ND*4];        // FFN intermediate
__device__ float g_Wc[NDIN*ND];
__device__ float g_bc[ND];

// ---------------- bf16 split helpers ------------------------------------------
__device__ __forceinline__ void pack2(float x0, float x1, uint32_t& hi, uint32_t& mid) {
    uint32_t h;
    asm("cvt.rn.bf16x2.f32 %0, %1, %2;" : "=r"(h) : "f"(x1), "f"(x0));
    float f0 = __uint_as_float(h << 16);
    float f1 = __uint_as_float(h & 0xFFFF0000u);
    float r0 = x0 - f0, r1 = x1 - f1;
    asm("cvt.rn.bf16x2.f32 %0, %1, %2;" : "=r"(mid) : "f"(r1), "f"(r0));
    hi = h;
}
__device__ __forceinline__ void mma_bf16(float* c, const uint32_t* a, const uint32_t* b) {
    asm volatile("mma.sync.aligned.m16n8k16.row.col.f32.bf16.bf16.f32 "
        "{%0,%1,%2,%3}, {%4,%5,%6,%7}, {%8,%9}, {%0,%1,%2,%3};"
        : "+f"(c[0]), "+f"(c[1]), "+f"(c[2]), "+f"(c[3])
        : "r"(a[0]), "r"(a[1]), "r"(a[2]), "r"(a[3]), "r"(b[0]), "r"(b[1]));
}

// ---------------- precompute combined expand@emb ------------------------------
__global__ void precompute_kernel(const float* __restrict__ ew, const float* __restrict__ eb,
                                  const float* __restrict__ mw, const float* __restrict__ mb,
                                  float* __restrict__ Wc, float* __restrict__ bc) {
    int j = threadIdx.x;             // 64 threads
    for (int i = 0; i < NDIN; i++) {
        float s = 0.f;
        for (int d = 0; d < ND; d++) s += ew[i*ND + d] * mw[d*ND + j];
        Wc[i*ND + j] = s;
    }
    float s = mb[j];
    for (int d = 0; d < ND; d++) s += eb[d] * mw[d*ND + j];
    bc[j] = s;
}

// ---------------- expand: x(.,5) @ Wc(5,64) + bc -> g_hpad (stride 66, off 1) --
__global__ void expand_kernel(const float* __restrict__ x, const float* __restrict__ Wc,
                              const float* __restrict__ bc, float* __restrict__ out) {
    __shared__ float Xs[64][NDIN];
    __shared__ float Ws[NDIN][ND];
    __shared__ float Bs[ND];
    int tid = threadIdx.x;                 // 256
    int row0 = blockIdx.x * 64;
    for (int idx = tid; idx < 64*NDIN; idx += 256) Xs[idx/NDIN][idx%NDIN] = x[row0*NDIN + idx];
    for (int idx = tid; idx < NDIN*ND; idx += 256) Ws[idx>>6][idx&63] = Wc[idx];
    if (tid < ND) Bs[tid] = bc[tid];
    __syncthreads();
    int r = tid >> 2, c = (tid & 3) * 16;
    float acc[16];
#pragma unroll
    for (int j = 0; j < 16; j++) acc[j] = Bs[c+j];
#pragma unroll
    for (int i = 0; i < NDIN; i++) {
        float xv = Xs[r][i];
#pragma unroll
        for (int j = 0; j < 16; j++) acc[j] += xv * Ws[i][c+j];
    }
    float* orow = out + (long)(row0+r)*66 + 1 + c;
#pragma unroll
    for (int j = 0; j < 16; j++) orow[j] = acc[j];
}

// ---------------- conv as GEMM, bf16x3 split on m16n8k16 (unchanged, verified) -
#define CBM 128
#define CBN 128
#define CBK 16
__global__ __launch_bounds__(256) void conv_kernel(
        const float* __restrict__ A, const float* __restrict__ Hpad,
        const float* __restrict__ conv_b, const float* __restrict__ pos_emb,
        float* __restrict__ Hout) {
    __shared__ uint32_t Ah[2][CBM][9], Am[2][CBM][9];
    __shared__ uint32_t Bh[2][CBN][9], Bm[2][CBN][9];
    int tid = threadIdx.x;
    int m0 = blockIdx.y * CBM;
    int n0 = blockIdx.x * CBN;

    int arow = tid >> 1;
    int acol0 = (tid & 1) * 8;
    int ap = acol0 >> 1;
    int bj = tid & 127;
    int bk0 = (tid >> 7) * 8;
    int bp = bk0 >> 1;
    int bb = (n0 >> 6) + (bj >> 6);
    long browbase = ((long)(bb << 10)) * 66;
    int bd = bj & 63;

    int w = tid >> 5, lane = tid & 31;
    int gid = lane >> 2, t4 = lane & 3;
    int warpM = w >> 1, warpN = w & 1;
    int mbase = warpM * 32, nbase = warpN * 64;

    float acc[2][8][4];
#pragma unroll
    for (int mt = 0; mt < 2; mt++)
#pragma unroll
        for (int nt = 0; nt < 8; nt++)
#pragma unroll
            for (int r = 0; r < 4; r++) acc[mt][nt][r] = 0.f;

    auto loadA = [&](int k0, int buf) {
        const float4* p = (const float4*)(A + (m0 + arow)*3072 + k0 + acol0);
        float4 v0 = p[0], v1 = p[1];
        uint32_t h, m_;
        pack2(v0.x, v0.y, h, m_); Ah[buf][arow][ap+0] = h; Am[buf][arow][ap+0] = m_;
        pack2(v0.z, v0.w, h, m_); Ah[buf][arow][ap+1] = h; Am[buf][arow][ap+1] = m_;
        pack2(v1.x, v1.y, h, m_); Ah[buf][arow][ap+2] = h; Am[buf][arow][ap+2] = m_;
        pack2(v1.z, v1.w, h, m_); Ah[buf][arow][ap+3] = h; Am[buf][arow][ap+3] = m_;
    };
    auto loadB = [&](int k0, int buf) {
        float br[8];
#pragma unroll
        for (int u = 0; u < 8; u++) {
            int K = k0 + bk0 + u;
            int kt = K / 3, kp = K - kt*3;
            br[u] = Hpad[browbase + (long)kt*66 + bd + kp];
        }
        uint32_t h, m_;
        pack2(br[0], br[1], h, m_); Bh[buf][bj][bp+0] = h; Bm[buf][bj][bp+0] = m_;
        pack2(br[2], br[3], h, m_); Bh[buf][bj][bp+1] = h; Bm[buf][bj][bp+1] = m_;
        pack2(br[4], br[5], h, m_); Bh[buf][bj][bp+2] = h; Bm[buf][bj][bp+2] = m_;
        pack2(br[6], br[7], h, m_); Bh[buf][bj][bp+3] = h; Bm[buf][bj][bp+3] = m_;
    };

    loadA(0, 0); loadB(0, 0);
    __syncthreads();

    int cur = 0;
    for (int k0 = CBK; k0 <= 3072; k0 += CBK) {
        if (k0 < 3072) { loadA(k0, cur ^ 1); loadB(k0, cur ^ 1); }
        uint32_t ah[2][4], am[2][4];
#pragma unroll
        for (int mt = 0; mt < 2; mt++) {
            int r0 = mbase + mt*16 + gid;
            ah[mt][0] = Ah[cur][r0  ][t4];   ah[mt][1] = Ah[cur][r0+8][t4];
            ah[mt][2] = Ah[cur][r0  ][t4+4]; ah[mt][3] = Ah[cur][r0+8][t4+4];
            am[mt][0] = Am[cur][r0  ][t4];   am[mt][1] = Am[cur][r0+8][t4];
            am[mt][2] = Am[cur][r0  ][t4+4]; am[mt][3] = Am[cur][r0+8][t4+4];
        }
#pragma unroll
        for (int nt = 0; nt < 8; nt++) {
            int n = nbase + nt*8 + gid;
            uint32_t bhf[2] = { Bh[cur][n][t4], Bh[cur][n][t4+4] };
            uint32_t bmf[2] = { Bm[cur][n][t4], Bm[cur][n][t4+4] };
#pragma unroll
            for (int mt = 0; mt < 2; mt++) {
                mma_bf16(acc[mt][nt], ah[mt], bhf);
                mma_bf16(acc[mt][nt], ah[mt], bmf);
                mma_bf16(acc[mt][nt], am[mt], bhf);
            }
        }
        __syncthreads();
        cur ^= 1;
    }

#pragma unroll
    for (int mt = 0; mt < 2; mt++) {
        int row0r = m0 + mbase + mt*16 + gid;
        float cb0 = conv_b[row0r];
        float cb1 = conv_b[row0r + 8];
#pragma unroll
        for (int nt = 0; nt < 8; nt++) {
            int coln = n0 + nbase + nt*8 + t4*2;
            int b_ = coln >> 6, d_ = coln & 63;
            float2 pe0 = *(const float2*)(pos_emb + row0r*64 + d_);
            float2 pe1 = *(const float2*)(pos_emb + (row0r+8)*64 + d_);
            float2 o0, o1;
            o0.x = acc[mt][nt][0] + cb0 + pe0.x;
            o0.y = acc[mt][nt][1] + cb0 + pe0.y;
            o1.x = acc[mt][nt][2] + cb1 + pe1.x;
            o1.y = acc[mt][nt][3] + cb1 + pe1.y;
            *(float2*)(Hout + ((long)(b_ << 10) + row0r)*64 + d_) = o0;
            *(float2*)(Hout + ((long)(b_ << 10) + row0r + 8)*64 + d_) = o1;
        }
    }
}

// ================= mma-based 64-token GEMM family ==============================
// Shared packers: 64 rows x 64 cols -> bf16 hi/mid tiles in fragment-friendly order.

// pack X tile (optionally layernormed). X row stride ldx, column offset coloff.
__device__ __forceinline__ void pack_x64(const float* __restrict__ X, long row0, int ldx, int coloff,
                                         const float* __restrict__ lns, const float* __restrict__ lnb,
                                         bool doLN,
                                         uint32_t Xh[64][33], uint32_t Xm[64][33], int tid) {
    int r = tid >> 2, q = (tid & 3) * 16;
    const float* row = X + (row0 + r) * (long)ldx + coloff + q;
    float xv[16];
    *(float4*)&xv[0]  = *(const float4*)(row);
    *(float4*)&xv[4]  = *(const float4*)(row + 4);
    *(float4*)&xv[8]  = *(const float4*)(row + 8);
    *(float4*)&xv[12] = *(const float4*)(row + 12);
    if (doLN) {
        float sum = 0.f;
#pragma unroll
        for (int j = 0; j < 16; j++) sum += xv[j];
        sum += __shfl_xor_sync(~0u, sum, 1);
        sum += __shfl_xor_sync(~0u, sum, 2);
        float mu = sum * (1.f/64.f);
        float vs = 0.f;
#pragma unroll
        for (int j = 0; j < 16; j++) { float d = xv[j] - mu; vs += d*d; }
        vs += __shfl_xor_sync(~0u, vs, 1);
        vs += __shfl_xor_sync(~0u, vs, 2);
        float inv = rsqrtf(vs * (1.f/64.f) + 1e-5f);
#pragma unroll
        for (int j = 0; j < 16; j++) xv[j] = (xv[j] - mu) * inv * lns[q+j] + lnb[q+j];
    }
    int p0 = q >> 1;
#pragma unroll
    for (int u = 0; u < 8; u++) {
        uint32_t h, m_;
        pack2(xv[2*u], xv[2*u+1], h, m_);
        Xh[r][p0+u] = h; Xm[r][p0+u] = m_;
    }
}

// pack W tile: 64 k-rows x 64 n-cols from W (row stride ldw, column offset coloff).
__device__ __forceinline__ void pack_w64(const float* __restrict__ W, int ldw, int coloff,
                                         uint32_t Wh[64][33], uint32_t Wm[64][33], int tid) {
    int n = tid & 63, p0 = (tid >> 6) * 8;
#pragma unroll
    for (int u = 0; u < 8; u++) {
        int k = 2*(p0+u);
        float w0 = W[(long)k*ldw + coloff + n];
        float w1 = W[(long)(k+1)*ldw + coloff + n];
        uint32_t h, m_;
        pack2(w0, w1, h, m_);
        Wh[n][p0+u] = h; Wm[n][p0+u] = m_;
    }
}

// compute: per-warp tile 16 rows x 32 cols; acc[nf][4]
__device__ __forceinline__ void mma64_compute(const uint32_t Xh[64][33], const uint32_t Xm[64][33],
                                              const uint32_t Wh[64][33], const uint32_t Wm[64][33],
                                              float acc[4][4], int mb, int nb, int gid, int t4) {
#pragma unroll
    for (int kc = 0; kc < 4; kc++) {
        int kp = kc*8;
        uint32_t ah[4], am[4];
        ah[0] = Xh[mb+gid  ][kp+t4];   ah[1] = Xh[mb+gid+8][kp+t4];
        ah[2] = Xh[mb+gid  ][kp+t4+4]; ah[3] = Xh[mb+gid+8][kp+t4+4];
        am[0] = Xm[mb+gid  ][kp+t4];   am[1] = Xm[mb+gid+8][kp+t4];
        am[2] = Xm[mb+gid  ][kp+t4+4]; am[3] = Xm[mb+gid+8][kp+t4+4];
#pragma unroll
        for (int nf = 0; nf < 4; nf++) {
            int n = nb + nf*8 + gid;
            uint32_t bh[2] = { Wh[n][kp+t4], Wh[n][kp+t4+4] };
            uint32_t bm[2] = { Wm[n][kp+t4], Wm[n][kp+t4+4] };
            mma_bf16(acc[nf], ah, bh);
            mma_bf16(acc[nf], ah, bm);
            mma_bf16(acc[nf], am, bh);
        }
    }
}

// ---------------- fused LN + QKV (mma) -> head layout -------------------------
__global__ __launch_bounds__(256) void lnqkv_kernel(
        const float* __restrict__ X, const float* __restrict__ lns, const float* __restrict__ lnb,
        const float* __restrict__ Wq, const float* __restrict__ Wk, const float* __restrict__ Wv,
        float* __restrict__ q, float* __restrict__ k, float* __restrict__ v) {
    __shared__ uint32_t Xh[64][33], Xm[64][33];
    __shared__ uint32_t Wh[64][33], Wm[64][33];
    int tid = threadIdx.x;
    long row0 = (long)blockIdx.x * 64;
    int w = tid >> 5, lane = tid & 31;
    int gid = lane >> 2, t4 = lane & 3;
    int mb = (w & 3) * 16, nb = (w >> 2) * 32;

    pack_x64(X, row0, ND, 0, lns, lnb, true, Xh, Xm, tid);
    const float* Wms[3] = {Wq, Wk, Wv};
    float* Om[3] = {q, k, v};
#pragma unroll
    for (int m = 0; m < 3; m++) {
        if (m) __syncthreads();
        pack_w64(Wms[m], ND, 0, Wh, Wm, tid);
        __syncthreads();
        float acc[4][4] = {};
        mma64_compute(Xh, Xm, Wh, Wm, acc, mb, nb, gid, t4);
        float* out = Om[m];
        int dh = t4*2;
#pragma unroll
        for (int nf = 0; nf < 4; nf++) {
            int h = (nb >> 3) + nf;
            long gt0 = row0 + mb + gid;
            long gt1 = gt0 + 8;
            long b0 = gt0 >> 10, t0 = gt0 & 1023;
            long b1 = gt1 >> 10, t1 = gt1 & 1023;
            float2 o0; o0.x = acc[nf][0]; o0.y = acc[nf][1];
            float2 o1; o1.x = acc[nf][2]; o1.y = acc[nf][3];
            *(float2*)(out + (((b0*8 + h)*1024) + t0)*8 + dh) = o0;
            *(float2*)(out + (((b1*8 + h)*1024) + t1)*8 + dh) = o1;
        }
    }
}

// ---------------- WO (mma): attn @ Wo + bias + resid -> h ---------------------
__global__ __launch_bounds__(256) void wo_kernel(
        const float* __restrict__ X, const float* __restrict__ W,
        const float* __restrict__ bias, const float* __restrict__ resid,
        float* __restrict__ out) {
    __shared__ uint32_t Xh[64][33], Xm[64][33];
    __shared__ uint32_t Wh[64][33], Wm[64][33];
    int tid = threadIdx.x;
    long row0 = (long)blockIdx.x * 64;
    int w = tid >> 5, lane = tid & 31;
    int gid = lane >> 2, t4 = lane & 3;
    int mb = (w & 3) * 16, nb = (w >> 2) * 32;

    pack_x64(X, row0, ND, 0, nullptr, nullptr, false, Xh, Xm, tid);
    pack_w64(W, ND, 0, Wh, Wm, tid);
    __syncthreads();
    float acc[4][4] = {};
    mma64_compute(Xh, Xm, Wh, Wm, acc, mb, nb, gid, t4);
#pragma unroll
    for (int nf = 0; nf < 4; nf++) {
        int col = nb + nf*8 + t4*2;
        float2 bb = *(const float2*)(bias + col);
        long r0 = row0 + mb + gid, r1 = r0 + 8;
        float2 rr0 = *(const float2*)(resid + r0*ND + col);
        float2 rr1 = *(const float2*)(resid + r1*ND + col);
        float2 o0, o1;
        o0.x = acc[nf][0] + bb.x + rr0.x; o0.y = acc[nf][1] + bb.y + rr0.y;
        o1.x = acc[nf][2] + bb.x + rr1.x; o1.y = acc[nf][3] + bb.y + rr1.y;
        *(float2*)(out + r0*ND + col) = o0;
        *(float2*)(out + r1*ND + col) = o1;
    }
}

// ---------------- fused LN + FFN1 + gelu (mma) --------------------------------
__global__ __launch_bounds__(256) void lnffn1_kernel(
        const float* __restrict__ X, const float* __restrict__ lns, const float* __restrict__ lnb,
        const float* __restrict__ W1, const float* __restrict__ b1,
        float* __restrict__ Y) {
    __shared__ uint32_t Xh[64][33], Xm[64][33];
    __shared__ uint32_t Wh[64][33], Wm[64][33];
    int tid = threadIdx.x;
    long row0 = (long)blockIdx.x * 64;
    int w = tid >> 5, lane = tid & 31;
    int gid = lane >> 2, t4 = lane & 3;
    int mb = (w & 3) * 16, nb = (w >> 2) * 32;

    pack_x64(X, row0, ND, 0, lns, lnb, true, Xh, Xm, tid);
    for (int c = 0; c < 4; c++) {
        if (c) __syncthreads();
        pack_w64(W1, 256, c*64, Wh, Wm, tid);
        __syncthreads();
        float acc[4][4] = {};
        mma64_compute(Xh, Xm, Wh, Wm, acc, mb, nb, gid, t4);
#pragma unroll
        for (int nf = 0; nf < 4; nf++) {
            int col = c*64 + nb + nf*8 + t4*2;
            float2 bb = *(const float2*)(b1 + col);
            long r0 = row0 + mb + gid, r1 = r0 + 8;
            float z;
            float2 o0, o1;
            z = acc[nf][0] + bb.x; o0.x = 0.5f*z*(1.f + erff(z*0.70710678118654752f));
            z = acc[nf][1] + bb.y; o0.y = 0.5f*z*(1.f + erff(z*0.70710678118654752f));
            z = acc[nf][2] + bb.x; o1.x = 0.5f*z*(1.f + erff(z*0.70710678118654752f));
            z = acc[nf][3] + bb.y; o1.y = 0.5f*z*(1.f + erff(z*0.70710678118654752f));
            *(float2*)(Y + r0*256 + col) = o0;
            *(float2*)(Y + r1*256 + col) = o1;
        }
    }
}

// ---------------- FFN2 (mma): Y @ W2 + b2 + resid -> h ------------------------
__global__ __launch_bounds__(256) void ffn2_kernel(
        const float* __restrict__ Y, const float* __restrict__ W2,
        const float* __restrict__ b2, const float* __restrict__ resid,
        float* __restrict__ out) {
    __shared__ uint32_t Xh[64][33], Xm[64][33];
    __shared__ uint32_t Wh[64][33], Wm[64][33];
    int tid = threadIdx.x;
    long row0 = (long)blockIdx.x * 64;
    int w = tid >> 5, lane = tid & 31;
    int gid = lane >> 2, t4 = lane & 3;
    int mb = (w & 3) * 16, nb = (w >> 2) * 32;

    float acc[4][4] = {};
    for (int kc = 0; kc < 4; kc++) {
        if (kc) __syncthreads();
        pack_x64(Y, row0, 256, kc*64, nullptr, nullptr, false, Xh, Xm, tid);
        pack_w64(W2 + kc*64*64, 64, 0, Wh, Wm, tid);
        __syncthreads();
        mma64_compute(Xh, Xm, Wh, Wm, acc, mb, nb, gid, t4);
    }
#pragma unroll
    for (int nf = 0; nf < 4; nf++) {
        int col = nb + nf*8 + t4*2;
        float2 bb = *(const float2*)(b2 + col);
        long r0 = row0 + mb + gid, r1 = r0 + 8;
        float2 rr0 = *(const float2*)(resid + r0*ND + col);
        float2 rr1 = *(const float2*)(resid + r1*ND + col);
        float2 o0, o1;
        o0.x = acc[nf][0] + bb.x + rr0.x; o0.y = acc[nf][1] + bb.y + rr0.y;
        o1.x = acc[nf][2] + bb.x + rr1.x; o1.y = acc[nf][3] + bb.y + rr1.y;
        *(float2*)(out + r0*ND + col) = o0;
        *(float2*)(out + r1*ND + col) = o1;
    }
}

// ---------------- local windowed attention (heads 0..3), bound-max softmax ----
__global__ __launch_bounds__(128) void local_attn_kernel(
        const float* __restrict__ q, const float* __restrict__ k,
        const float* __restrict__ v, float* __restrict__ attn) {
    int bid = blockIdx.x;                  // b*32 + h*8 + w
    int w = bid & 7, h = (bid >> 3) & 3, b = bid >> 5;
    __shared__ float Ks[384][8];
    __shared__ float Vs[384][8];
    __shared__ float wmax[4];
    int tid = threadIdx.x;                 // 128
    int base = ((b*8 + h)*1024) * 8;
    int jlo = (w == 0) ? 128 : 0;
    int jhi = (w == 7) ? 256 : 384;
    for (int idx = tid; idx < 768; idx += 128) {
        int j = idx >> 1, half = (idx & 1) * 4;
        int tt = (w - 1)*128 + j;
        float4 kv = {0,0,0,0}, vv = {0,0,0,0};
        if (tt >= 0 && tt < 1024) {
            kv = *(const float4*)(k + base + tt*8 + half);
            vv = *(const float4*)(v + base + tt*8 + half);
        }
        *(float4*)&Ks[j][half] = kv;
        *(float4*)&Vs[j][half] = vv;
    }
    __syncthreads();
    float nm = 0.f;
    for (int r = tid; r < 384; r += 128) {
        float4 k0 = *(const float4*)&Ks[r][0];
        float4 k1 = *(const float4*)&Ks[r][4];
        float s2 = k0.x*k0.x + k0.y*k0.y + k0.z*k0.z + k0.w*k0.w
                 + k1.x*k1.x + k1.y*k1.y + k1.z*k1.z + k1.w*k1.w;
        nm = fmaxf(nm, s2);
    }
#pragma unroll
    for (int o = 16; o; o >>= 1) nm = fmaxf(nm, __shfl_xor_sync(~0u, nm, o));
    if ((tid & 31) == 0) wmax[tid >> 5] = nm;
    __syncthreads();
    float kmax2 = fmaxf(fmaxf(wmax[0], wmax[1]), fmaxf(wmax[2], wmax[3]));

    int t = w*128 + tid;
    float4 q0 = *(const float4*)(q + base + t*8);
    float4 q1 = *(const float4*)(q + base + t*8 + 4);
    float qr[8] = {q0.x,q0.y,q0.z,q0.w,q1.x,q1.y,q1.z,q1.w};
    const float scale = 0.35355339059327373f;   // 1/sqrt(8)
    float qn2 = 0.f;
#pragma unroll
    for (int e = 0; e < 8; e++) qn2 += qr[e]*qr[e];
    float m = scale * sqrtf(qn2 * kmax2);
    float l = 0.f, acc[8] = {};
    for (int j = jlo; j < jhi; j++) {
        float4 k0 = *(const float4*)&Ks[j][0];
        float4 k1 = *(const float4*)&Ks[j][4];
        float s = qr[0]*k0.x + qr[1]*k0.y + qr[2]*k0.z + qr[3]*k0.w
                + qr[4]*k1.x + qr[5]*k1.y + qr[6]*k1.z + qr[7]*k1.w;
        float p = __expf(s*scale - m);
        l += p;
        float4 v0 = *(const float4*)&Vs[j][0];
        float4 v1 = *(const float4*)&Vs[j][4];
        acc[0] += p*v0.x; acc[1] += p*v0.y; acc[2] += p*v0.z; acc[3] += p*v0.w;
        acc[4] += p*v1.x; acc[5] += p*v1.y; acc[6] += p*v1.z; acc[7] += p*v1.w;
    }
    float inv = 1.f / l;
    float4 o0, o1;
    o0.x = acc[0]*inv; o0.y = acc[1]*inv; o0.z = acc[2]*inv; o0.w = acc[3]*inv;
    o1.x = acc[4]*inv; o1.y = acc[5]*inv; o1.z = acc[6]*inv; o1.w = acc[7]*inv;
    long ob = ((long)(b*1024 + t)*64) + h*8;
    *(float4*)(attn + ob) = o0;
    *(float4*)(attn + ob + 4) = o1;
}

// ---------------- global linear attention (heads 4..7) -----------------------
__global__ void global_attn_kernel(const float* __restrict__ q, const float* __restrict__ k,
                                   const float* __restrict__ v, float* __restrict__ attn) {
    int b = blockIdx.x >> 2, h = blockIdx.x & 3;
    int tid = threadIdx.x;                 // 256
    int base = ((b*8 + 4 + h)*1024) * 8;
    __shared__ float red[8][72];
    __shared__ float M[8];
    __shared__ float C[64];
    int warp = tid >> 5, lane = tid & 31;

    float mx[8];
#pragma unroll
    for (int d = 0; d < 8; d++) mx[d] = -1e30f;
    for (int t = tid; t < 1024; t += 256) {
        float4 k0 = *(const float4*)(k + base + t*8);
        float4 k1 = *(const float4*)(k + base + t*8 + 4);
        mx[0]=fmaxf(mx[0],k0.x); mx[1]=fmaxf(mx[1],k0.y); mx[2]=fmaxf(mx[2],k0.z); mx[3]=fmaxf(mx[3],k0.w);
        mx[4]=fmaxf(mx[4],k1.x); mx[5]=fmaxf(mx[5],k1.y); mx[6]=fmaxf(mx[6],k1.z); mx[7]=fmaxf(mx[7],k1.w);
    }
#pragma unroll
    for (int d = 0; d < 8; d++)
        for (int o = 16; o; o >>= 1) mx[d] = fmaxf(mx[d], __shfl_xor_sync(~0u, mx[d], o));
    if (lane == 0)
        for (int d = 0; d < 8; d++) red[warp][d] = mx[d];
    __syncthreads();
    if (tid < 8) {
        float m_ = red[0][tid];
        for (int wv = 1; wv < 8; wv++) m_ = fmaxf(m_, red[wv][tid]);
        M[tid] = m_;
    }
    __syncthreads();

    float Z[8] = {}, ctx[64] = {};
    for (int t = tid; t < 1024; t += 256) {
        float4 k0 = *(const float4*)(k + base + t*8);
        float4 k1 = *(const float4*)(k + base + t*8 + 4);
        float4 v0 = *(const float4*)(v + base + t*8);
        float4 v1 = *(const float4*)(v + base + t*8 + 4);
        float kr[8] = {k0.x,k0.y,k0.z,k0.w,k1.x,k1.y,k1.z,k1.w};
        float vr[8] = {v0.x,v0.y,v0.z,v0.w,v1.x,v1.y,v1.z,v1.w};
#pragma unroll
        for (int d = 0; d < 8; d++) {
            float e_ = __expf(kr[d] - M[d]);
            Z[d] += e_;
#pragma unroll
            for (int e = 0; e < 8; e++) ctx[d*8 + e] += e_ * vr[e];
        }
    }
#pragma unroll
    for (int i = 0; i < 8; i++)
        for (int o = 16; o; o >>= 1) Z[i] += __shfl_xor_sync(~0u, Z[i], o);
#pragma unroll
    for (int i = 0; i < 64; i++)
        for (int o = 16; o; o >>= 1) ctx[i] += __shfl_xor_sync(~0u, ctx[i], o);
    if (lane == 0) {
        for (int i = 0; i < 8; i++)  red[warp][i] = Z[i];
        for (int i = 0; i < 64; i++) red[warp][8 + i] = ctx[i];
    }
    __syncthreads();
    if (tid < 64) {
        float s = 0.f, z = 0.f;
        int d = tid >> 3;
        for (int wv = 0; wv < 8; wv++) { s += red[wv][8 + tid]; z += red[wv][d]; }
        C[tid] = s / z;
    }
    __syncthreads();

    const float scale = 0.35355339059327373f;
    for (int t = tid; t < 1024; t += 256) {
        float4 q0 = *(const float4*)(q + base + t*8);
        float4 q1 = *(const float4*)(q + base + t*8 + 4);
        float qr[8] = {q0.x,q0.y,q0.z,q0.w,q1.x,q1.y,q1.z,q1.w};
        float qm = -1e30f;
#pragma unroll
        for (int d = 0; d < 8; d++) qm = fmaxf(qm, qr[d]);
        float qs = 0.f;
#pragma unroll
        for (int d = 0; d < 8; d++) { qr[d] = __expf(qr[d] - qm); qs += qr[d]; }
        float inv = scale / qs;
        float o_[8] = {};
#pragma unroll
        for (int d = 0; d < 8; d++) {
            float p = qr[d] * inv;
#pragma unroll
            for (int e = 0; e < 8; e++) o_[e] += p * C[d*8 + e];
        }
        long ob = (long)(b*1024 + t)*64 + (4 + h)*8;
        float4 oo0, oo1;
        oo0.x=o_[0]; oo0.y=o_[1]; oo0.z=o_[2]; oo0.w=o_[3];
        oo1.x=o_[4]; oo1.y=o_[5]; oo1.z=o_[6]; oo1.w=o_[7];
        *(float4*)(attn + ob) = oo0;
        *(float4*)(attn + ob + 4) = oo1;
    }
}

// ---------------- collapse: h(.,64) @ cw(64,5) + cb -> out --------------------
__global__ void collapse_kernel(const float* __restrict__ h, const float* __restrict__ cw,
                                const float* __restrict__ cb, float* __restrict__ out) {
    __shared__ float Xs[64][68];
    __shared__ float Ws[64][NDIN];
    __shared__ float Bs[NDIN];
    int tid = threadIdx.x;                 // 64
    int row0 = blockIdx.x * 64;
    for (int idx = tid; idx < 1024; idx += 64) {
        int i = idx >> 4, j = (idx & 15) * 4;
        *(float4*)&Xs[i][j] = *(const float4*)(h + (long)(row0 + i)*ND + j);
    }
    for (int idx = tid; idx < 64*NDIN; idx += 64) Ws[idx/NDIN][idx%NDIN] = cw[idx];
    if (tid < NDIN) Bs[tid] = cb[tid];
    __syncthreads();
    int r = tid;
    float acc[NDIN];
#pragma unroll
    for (int j = 0; j < NDIN; j++) acc[j] = Bs[j];
    for (int kk = 0; kk < 64; kk++) {
        float xv = Xs[r][kk];
#pragma unroll
        for (int j = 0; j < NDIN; j++) acc[j] += xv * Ws[kk][j];
    }
#pragma unroll
    for (int j = 0; j < NDIN; j++) out[(row0 + r)*NDIN + j] = acc[j];
}

// ---------------- launch ------------------------------------------------------
extern "C" void kernel_launch(void* const* d_in, const int* in_sizes, int n_in,
                              void* d_out, int out_size) {
    const float* x          = (const float*)d_in[0];
    const float* pos_emb    = (const float*)d_in[1];
    const float* expand_w   = (const float*)d_in[2];
    const float* expand_b   = (const float*)d_in[3];
    const float* emb_w      = (const float*)d_in[4];
    const float* emb_b      = (const float*)d_in[5];
    const float* conv_w     = (const float*)d_in[6];
    const float* conv_b     = (const float*)d_in[7];
    const float* ln1_s      = (const float*)d_in[8];
    const float* ln1_b      = (const float*)d_in[9];
    const float* wq         = (const float*)d_in[10];
    const float* wk         = (const float*)d_in[11];
    const float* wv         = (const float*)d_in[12];
    const float* wo         = (const float*)d_in[13];
    const float* wo_b       = (const float*)d_in[14];
    const float* ln2_s      = (const float*)d_in[15];
    const float* ln2_b      = (const float*)d_in[16];
    const float* ff_w1      = (const float*)d_in[17];
    const float* ff_b1      = (const float*)d_in[18];
    const float* ff_w2      = (const float*)d_in[19];
    const float* ff_b2      = (const float*)d_in[20];
    const float* collapse_w = (const float*)d_in[21];
    const float* collapse_b = (const float*)d_in[22];
    float* out = (float*)d_out;

    float *ph, *php, *pq, *pk, *pv, *pattn, *py, *pWc, *pbc;
    cudaGetSymbolAddress((void**)&ph,   g_h);
    cudaGetSymbolAddress((void**)&php,  g_hpad);
    cudaGetSymbolAddress((void**)&pq,   g_q);
    cudaGetSymbolAddress((void**)&pk,   g_k);
    cudaGetSymbolAddress((void**)&pv,   g_v);
    cudaGetSymbolAddress((void**)&pattn,g_attn);
    cudaGetSymbolAddress((void**)&py,   g_y);
    cudaGetSymbolAddress((void**)&pWc,  g_Wc);
    cudaGetSymbolAddress((void**)&pbc,  g_bc);

    precompute_kernel<<<1, 64>>>(expand_w, expand_b, emb_w, emb_b, pWc, pbc);
    expand_kernel<<<NTOK/64, 256>>>(x, pWc, pbc, php);
    conv_kernel<<<dim3(4096/CBN, 1024/CBM), 256>>>(conv_w, php, conv_b, pos_emb, ph);

    for (int l = 0; l < 2; l++) {
        lnqkv_kernel<<<NTOK/64, 256>>>(ph, ln1_s + l*64, ln1_b + l*64,
                                       wq + l*4096, wk + l*4096, wv + l*4096, pq, pk, pv);
        local_attn_kernel<<<NB*4*8, 128>>>(pq, pk, pv, pattn);
        global_attn_kernel<<<NB*4, 256>>>(pq, pk, pv, pattn);
        wo_kernel<<<NTOK/64, 256>>>(pattn, wo + l*4096, wo_b + l*64, ph, ph);
        lnffn1_kernel<<<NTOK/64, 256>>>(ph, ln2_s + l*64, ln2_b + l*64,
                                        ff_w1 + l*64*256, ff_b1 + l*256, py);
        ffn2_kernel<<<NTOK/64, 256>>>(py, ff_w2 + l*256*64, ff_b2 + l*64, ph, ph);
    }
    collapse_kernel<<<NTOK/64, 64>>>(ph, collapse_w, collapse_b, out);
}

// round 10
// speedup vs baseline: 3.3399x; 1.0981x over previous
#include <cuda_runtime.h>
#include <cuda_bf16.h>
#include <cstdint>
#include <math.h>

// Problem constants: B=64, T=1024, DIN=5, D=64, H=8, DH=8, NLOCAL=4, WS=128, DEPTH=2
#define NB 64
#define NT 1024
#define NDIN 5
#define ND 64
#define NTOK (NB*NT)           // 65536

// ---------------- scratch (static device buffers) -----------------------------
__device__ float g_h[NTOK*ND];          // running hidden state
__device__ float g_hpad[NTOK*66];       // padded pre-conv activations (cols 0,65 stay zero)
__device__ float g_q[NTOK*ND];          // [b][h][t][dh]
__device__ float g_k[NTOK*ND];
__device__ float g_v[NTOK*ND];
__device__ float g_attn[NTOK*ND];       // [b][t][h*8+dh]
__device__ float g_y[NTOK*ND*4];        // FFN intermediate
__device__ float g_Wc[NDIN*ND];
__device__ float g_bc[ND];
// packed-weight tiles: 24 tiles x 64 n x 32 kpairs
__device__ uint32_t g_WpH[24*2048], g_WpM[24*2048];
// packed conv A: [1024 m][1536 kpair]
__device__ uint32_t g_AH[1024*1536], g_AM[1024*1536];
// packed conv B: [1536 kpair][4096 n]
__device__ uint32_t g_BH[1536*4096], g_BM[1536*4096];

// ---------------- bf16 split helpers ------------------------------------------
__device__ __forceinline__ void pack2(float x0, float x1, uint32_t& hi, uint32_t& mid) {
    uint32_t h;
    asm("cvt.rn.bf16x2.f32 %0, %1, %2;" : "=r"(h) : "f"(x1), "f"(x0));
    float f0 = __uint_as_float(h << 16);
    float f1 = __uint_as_float(h & 0xFFFF0000u);
    float r0 = x0 - f0, r1 = x1 - f1;
    asm("cvt.rn.bf16x2.f32 %0, %1, %2;" : "=r"(mid) : "f"(r1), "f"(r0));
    hi = h;
}
__device__ __forceinline__ void mma_bf16(float* c, const uint32_t* a, const uint32_t* b) {
    asm volatile("mma.sync.aligned.m16n8k16.row.col.f32.bf16.bf16.f32 "
        "{%0,%1,%2,%3}, {%4,%5,%6,%7}, {%8,%9}, {%0,%1,%2,%3};"
        : "+f"(c[0]), "+f"(c[1]), "+f"(c[2]), "+f"(c[3])
        : "r"(a[0]), "r"(a[1]), "r"(a[2]), "r"(a[3]), "r"(b[0]), "r"(b[1]));
}

// ---------------- precompute combined expand@emb ------------------------------
__global__ void precompute_kernel(const float* __restrict__ ew, const float* __restrict__ eb,
                                  const float* __restrict__ mw, const float* __restrict__ mb,
                                  float* __restrict__ Wc, float* __restrict__ bc) {
    int j = threadIdx.x;             // 64 threads
    for (int i = 0; i < NDIN; i++) {
        float s = 0.f;
        for (int d = 0; d < ND; d++) s += ew[i*ND + d] * mw[d*ND + j];
        Wc[i*ND + j] = s;
    }
    float s = mb[j];
    for (int d = 0; d < ND; d++) s += eb[d] * mw[d*ND + j];
    bc[j] = s;
}

// ---------------- expand: x(.,5) @ Wc(5,64) + bc -> g_hpad (stride 66, off 1) --
__global__ void expand_kernel(const float* __restrict__ x, const float* __restrict__ Wc,
                              const float* __restrict__ bc, float* __restrict__ out) {
    __shared__ float Xs[64][NDIN];
    __shared__ float Ws[NDIN][ND];
    __shared__ float Bs[ND];
    int tid = threadIdx.x;                 // 256
    int row0 = blockIdx.x * 64;
    for (int idx = tid; idx < 64*NDIN; idx += 256) Xs[idx/NDIN][idx%NDIN] = x[row0*NDIN + idx];
    for (int idx = tid; idx < NDIN*ND; idx += 256) Ws[idx>>6][idx&63] = Wc[idx];
    if (tid < ND) Bs[tid] = bc[tid];
    __syncthreads();
    int r = tid >> 2, c = (tid & 3) * 16;
    float acc[16];
#pragma unroll
    for (int j = 0; j < 16; j++) acc[j] = Bs[c+j];
#pragma unroll
    for (int i = 0; i < NDIN; i++) {
        float xv = Xs[r][i];
#pragma unroll
        for (int j = 0; j < 16; j++) acc[j] += xv * Ws[i][c+j];
    }
    float* orow = out + (long)(row0+r)*66 + 1 + c;
#pragma unroll
    for (int j = 0; j < 16; j++) orow[j] = acc[j];
}

// ---------------- weight pre-pack: 24 tiles of 64x64 --------------------------
__global__ void packw_kernel(const float* __restrict__ wq, const float* __restrict__ wk,
                             const float* __restrict__ wv, const float* __restrict__ wo,
                             const float* __restrict__ w1, const float* __restrict__ w2,
                             uint32_t* __restrict__ WpH, uint32_t* __restrict__ WpM) {
    int tile = blockIdx.x;        // 0..23
    int l = tile / 12, t = tile - l*12;
    const float* src; int ldw, coloff;
    if (t == 0)      { src = wq + l*4096; ldw = 64; coloff = 0; }
    else if (t == 1) { src = wk + l*4096; ldw = 64; coloff = 0; }
    else if (t == 2) { src = wv + l*4096; ldw = 64; coloff = 0; }
    else if (t == 3) { src = wo + l*4096; ldw = 64; coloff = 0; }
    else if (t < 8)  { src = w1 + l*64*256; ldw = 256; coloff = (t-4)*64; }
    else             { src = w2 + l*256*64 + (t-8)*64*64; ldw = 64; coloff = 0; }
    int tid = threadIdx.x;        // 256
    int n = tid & 63, p0 = (tid >> 6) * 8;
    uint32_t* dh = WpH + tile*2048 + n*32;
    uint32_t* dm = WpM + tile*2048 + n*32;
#pragma unroll
    for (int u = 0; u < 8; u++) {
        int k = 2*(p0+u);
        float w0 = src[(long)k*ldw + coloff + n];
        float w1v = src[(long)(k+1)*ldw + coloff + n];
        uint32_t h, m_;
        pack2(w0, w1v, h, m_);
        dh[p0+u] = h; dm[p0+u] = m_;
    }
}

// ---------------- conv A pre-pack: conv_w -> [m][kpair] ------------------------
__global__ void packa_kernel(const float* __restrict__ A,
                             uint32_t* __restrict__ AH, uint32_t* __restrict__ AM) {
    int idx = blockIdx.x*256 + threadIdx.x;       // pair index [1024*1536)
    float2 v = *(const float2*)(A + (long)idx*2);
    uint32_t h, m_;
    pack2(v.x, v.y, h, m_);
    AH[idx] = h; AM[idx] = m_;
}

// ---------------- conv B pre-pack: gather Hpad -> [kpair][n] -------------------
__global__ void packb_kernel(const float* __restrict__ Hpad,
                             uint32_t* __restrict__ BH, uint32_t* __restrict__ BM) {
    int idx = blockIdx.x*256 + threadIdx.x;       // [1536*4096)
    int kp2 = idx >> 12;
    int n = idx & 4095;
    int b = n >> 6, d = n & 63;
    long rowb = ((long)b << 10) * 66;
    int K0 = kp2*2, K1 = K0 + 1;
    int kt0 = K0/3, kq0 = K0 - kt0*3;
    int kt1 = K1/3, kq1 = K1 - kt1*3;
    float x0 = Hpad[rowb + (long)kt0*66 + d + kq0];
    float x1 = Hpad[rowb + (long)kt1*66 + d + kq1];
    uint32_t h, m_;
    pack2(x0, x1, h, m_);
    BH[idx] = h; BM[idx] = m_;
}

// ---------------- conv as GEMM, bf16x3 m16n8k16, pre-packed operands ----------
#define CBM 128
#define CBN 128
#define CBK 16
__global__ __launch_bounds__(256) void conv_kernel(
        const uint32_t* __restrict__ AH, const uint32_t* __restrict__ AM,
        const uint32_t* __restrict__ BH, const uint32_t* __restrict__ BM,
        const float* __restrict__ conv_b, const float* __restrict__ pos_emb,
        float* __restrict__ Hout) {
    __shared__ uint32_t Ah[2][CBM][9], Am[2][CBM][9];
    __shared__ uint32_t Bh[2][CBN][9], Bm[2][CBN][9];
    int tid = threadIdx.x;
    int m0 = blockIdx.y * CBM;
    int n0 = blockIdx.x * CBN;

    int arow = tid >> 1;
    int ap = (tid & 1) * 4;               // kpair offset 0/4
    int bj = tid & 127;
    int bp = (tid >> 7) * 4;              // kpair offset 0/4

    int w = tid >> 5, lane = tid & 31;
    int gid = lane >> 2, t4 = lane & 3;
    int warpM = w >> 1, warpN = w & 1;
    int mbase = warpM * 32, nbase = warpN * 64;

    float acc[2][8][4];
#pragma unroll
    for (int mt = 0; mt < 2; mt++)
#pragma unroll
        for (int nt = 0; nt < 8; nt++)
#pragma unroll
            for (int r = 0; r < 4; r++) acc[mt][nt][r] = 0.f;

    auto loadA = [&](int k0, int buf) {
        const uint32_t* ph = AH + (long)(m0 + arow)*1536 + (k0 >> 1) + ap;
        const uint32_t* pm = AM + (long)(m0 + arow)*1536 + (k0 >> 1) + ap;
        uint4 vh = *(const uint4*)ph;
        uint4 vm = *(const uint4*)pm;
        Ah[buf][arow][ap+0] = vh.x; Ah[buf][arow][ap+1] = vh.y;
        Ah[buf][arow][ap+2] = vh.z; Ah[buf][arow][ap+3] = vh.w;
        Am[buf][arow][ap+0] = vm.x; Am[buf][arow][ap+1] = vm.y;
        Am[buf][arow][ap+2] = vm.z; Am[buf][arow][ap+3] = vm.w;
    };
    auto loadB = [&](int k0, int buf) {
        long base = (long)((k0 >> 1) + bp) * 4096 + n0 + bj;
#pragma unroll
        for (int u = 0; u < 4; u++) {
            Bh[buf][bj][bp+u] = BH[base + (long)u*4096];
            Bm[buf][bj][bp+u] = BM[base + (long)u*4096];
        }
    };

    loadA(0, 0); loadB(0, 0);
    __syncthreads();

    int cur = 0;
    for (int k0 = CBK; k0 <= 3072; k0 += CBK) {
        if (k0 < 3072) { loadA(k0, cur ^ 1); loadB(k0, cur ^ 1); }
        uint32_t ah[2][4], am[2][4];
#pragma unroll
        for (int mt = 0; mt < 2; mt++) {
            int r0 = mbase + mt*16 + gid;
            ah[mt][0] = Ah[cur][r0  ][t4];   ah[mt][1] = Ah[cur][r0+8][t4];
            ah[mt][2] = Ah[cur][r0  ][t4+4]; ah[mt][3] = Ah[cur][r0+8][t4+4];
            am[mt][0] = Am[cur][r0  ][t4];   am[mt][1] = Am[cur][r0+8][t4];
            am[mt][2] = Am[cur][r0  ][t4+4]; am[mt][3] = Am[cur][r0+8][t4+4];
        }
#pragma unroll
        for (int nt = 0; nt < 8; nt++) {
            int n = nbase + nt*8 + gid;
            uint32_t bhf[2] = { Bh[cur][n][t4], Bh[cur][n][t4+4] };
            uint32_t bmf[2] = { Bm[cur][n][t4], Bm[cur][n][t4+4] };
#pragma unroll
            for (int mt = 0; mt < 2; mt++) {
                mma_bf16(acc[mt][nt], ah[mt], bhf);
                mma_bf16(acc[mt][nt], ah[mt], bmf);
                mma_bf16(acc[mt][nt], am[mt], bhf);
            }
        }
        __syncthreads();
        cur ^= 1;
    }

#pragma unroll
    for (int mt = 0; mt < 2; mt++) {
        int row0r = m0 + mbase + mt*16 + gid;
        float cb0 = conv_b[row0r];
        float cb1 = conv_b[row0r + 8];
#pragma unroll
        for (int nt = 0; nt < 8; nt++) {
            int coln = n0 + nbase + nt*8 + t4*2;
            int b_ = coln >> 6, d_ = coln & 63;
            float2 pe0 = *(const float2*)(pos_emb + row0r*64 + d_);
            float2 pe1 = *(const float2*)(pos_emb + (row0r+8)*64 + d_);
            float2 o0, o1;
            o0.x = acc[mt][nt][0] + cb0 + pe0.x;
            o0.y = acc[mt][nt][1] + cb0 + pe0.y;
            o1.x = acc[mt][nt][2] + cb1 + pe1.x;
            o1.y = acc[mt][nt][3] + cb1 + pe1.y;
            *(float2*)(Hout + ((long)(b_ << 10) + row0r)*64 + d_) = o0;
            *(float2*)(Hout + ((long)(b_ << 10) + row0r + 8)*64 + d_) = o1;
        }
    }
}

// ================= mma-based 64-token GEMM family ==============================

// pack X tile (optionally layernormed). X row stride ldx, column offset coloff.
__device__ __forceinline__ void pack_x64(const float* __restrict__ X, long row0, int ldx, int coloff,
                                         const float* __restrict__ lns, const float* __restrict__ lnb,
                                         bool doLN,
                                         uint32_t Xh[64][33], uint32_t Xm[64][33], int tid) {
    int r = tid >> 2, q = (tid & 3) * 16;
    const float* row = X + (row0 + r) * (long)ldx + coloff + q;
    float xv[16];
    *(float4*)&xv[0]  = *(const float4*)(row);
    *(float4*)&xv[4]  = *(const float4*)(row + 4);
    *(float4*)&xv[8]  = *(const float4*)(row + 8);
    *(float4*)&xv[12] = *(const float4*)(row + 12);
    if (doLN) {
        float sum = 0.f;
#pragma unroll
        for (int j = 0; j < 16; j++) sum += xv[j];
        sum += __shfl_xor_sync(~0u, sum, 1);
        sum += __shfl_xor_sync(~0u, sum, 2);
        float mu = sum * (1.f/64.f);
        float vs = 0.f;
#pragma unroll
        for (int j = 0; j < 16; j++) { float d = xv[j] - mu; vs += d*d; }
        vs += __shfl_xor_sync(~0u, vs, 1);
        vs += __shfl_xor_sync(~0u, vs, 2);
        float inv = rsqrtf(vs * (1.f/64.f) + 1e-5f);
#pragma unroll
        for (int j = 0; j < 16; j++) xv[j] = (xv[j] - mu) * inv * lns[q+j] + lnb[q+j];
    }
    int p0 = q >> 1;
#pragma unroll
    for (int u = 0; u < 8; u++) {
        uint32_t h, m_;
        pack2(xv[2*u], xv[2*u+1], h, m_);
        Xh[r][p0+u] = h; Xm[r][p0+u] = m_;
    }
}

// copy pre-packed W tile (2048 u32 each) into smem
__device__ __forceinline__ void copy_w64(const uint32_t* __restrict__ WpH,
                                         const uint32_t* __restrict__ WpM, int tile,
                                         uint32_t Wh[64][36], uint32_t Wm[64][36], int tid) {
    int n = tid >> 2, qp = (tid & 3) * 8;
    const uint32_t* sh = WpH + tile*2048 + n*32 + qp;
    const uint32_t* sm = WpM + tile*2048 + n*32 + qp;
    *(uint4*)&Wh[n][qp]   = *(const uint4*)sh;
    *(uint4*)&Wh[n][qp+4] = *(const uint4*)(sh+4);
    *(uint4*)&Wm[n][qp]   = *(const uint4*)sm;
    *(uint4*)&Wm[n][qp+4] = *(const uint4*)(sm+4);
}

// compute: per-warp tile 16 rows x 32 cols; acc[nf][4]
__device__ __forceinline__ void mma64_compute(const uint32_t Xh[64][33], const uint32_t Xm[64][33],
                                              const uint32_t Wh[64][36], const uint32_t Wm[64][36],
                                              float acc[4][4], int mb, int nb, int gid, int t4) {
#pragma unroll
    for (int kc = 0; kc < 4; kc++) {
        int kp = kc*8;
        uint32_t ah[4], am[4];
        ah[0] = Xh[mb+gid  ][kp+t4];   ah[1] = Xh[mb+gid+8][kp+t4];
        ah[2] = Xh[mb+gid  ][kp+t4+4]; ah[3] = Xh[mb+gid+8][kp+t4+4];
        am[0] = Xm[mb+gid  ][kp+t4];   am[1] = Xm[mb+gid+8][kp+t4];
        am[2] = Xm[mb+gid  ][kp+t4+4]; am[3] = Xm[mb+gid+8][kp+t4+4];
#pragma unroll
        for (int nf = 0; nf < 4; nf++) {
            int n = nb + nf*8 + gid;
            uint32_t bh[2] = { Wh[n][kp+t4], Wh[n][kp+t4+4] };
            uint32_t bm[2] = { Wm[n][kp+t4], Wm[n][kp+t4+4] };
            mma_bf16(acc[nf], ah, bh);
            mma_bf16(acc[nf], ah, bm);
            mma_bf16(acc[nf], am, bh);
        }
    }
}

// ---------------- fused LN + QKV (mma) -> head layout -------------------------
__global__ __launch_bounds__(256) void lnqkv_kernel(
        const float* __restrict__ X, const float* __restrict__ lns, const float* __restrict__ lnb,
        const uint32_t* __restrict__ WpH, const uint32_t* __restrict__ WpM, int tile0,
        float* __restrict__ q, float* __restrict__ k, float* __restrict__ v) {
    __shared__ uint32_t Xh[64][33], Xm[64][33];
    __shared__ uint32_t Wh[64][36], Wm[64][36];
    int tid = threadIdx.x;
    long row0 = (long)blockIdx.x * 64;
    int w = tid >> 5, lane = tid & 31;
    int gid = lane >> 2, t4 = lane & 3;
    int mb = (w & 3) * 16, nb = (w >> 2) * 32;

    pack_x64(X, row0, ND, 0, lns, lnb, true, Xh, Xm, tid);
    float* Om[3] = {q, k, v};
#pragma unroll
    for (int m = 0; m < 3; m++) {
        if (m) __syncthreads();
        copy_w64(WpH, WpM, tile0 + m, Wh, Wm, tid);
        __syncthreads();
        float acc[4][4] = {};
        mma64_compute(Xh, Xm, Wh, Wm, acc, mb, nb, gid, t4);
        float* out = Om[m];
        int dh = t4*2;
#pragma unroll
        for (int nf = 0; nf < 4; nf++) {
            int h = (nb >> 3) + nf;
            long gt0 = row0 + mb + gid;
            long gt1 = gt0 + 8;
            long b0 = gt0 >> 10, t0 = gt0 & 1023;
            long b1 = gt1 >> 10, t1 = gt1 & 1023;
            float2 o0; o0.x = acc[nf][0]; o0.y = acc[nf][1];
            float2 o1; o1.x = acc[nf][2]; o1.y = acc[nf][3];
            *(float2*)(out + (((b0*8 + h)*1024) + t0)*8 + dh) = o0;
            *(float2*)(out + (((b1*8 + h)*1024) + t1)*8 + dh) = o1;
        }
    }
}

// ---------------- WO (mma): attn @ Wo + bias + resid -> h ---------------------
__global__ __launch_bounds__(256) void wo_kernel(
        const float* __restrict__ X,
        const uint32_t* __restrict__ WpH, const uint32_t* __restrict__ WpM, int tile,
        const float* __restrict__ bias, const float* __restrict__ resid,
        float* __restrict__ out) {
    __shared__ uint32_t Xh[64][33], Xm[64][33];
    __shared__ uint32_t Wh[64][36], Wm[64][36];
    int tid = threadIdx.x;
    long row0 = (long)blockIdx.x * 64;
    int w = tid >> 5, lane = tid & 31;
    int gid = lane >> 2, t4 = lane & 3;
    int mb = (w & 3) * 16, nb = (w >> 2) * 32;

    pack_x64(X, row0, ND, 0, nullptr, nullptr, false, Xh, Xm, tid);
    copy_w64(WpH, WpM, tile, Wh, Wm, tid);
    __syncthreads();
    float acc[4][4] = {};
    mma64_compute(Xh, Xm, Wh, Wm, acc, mb, nb, gid, t4);
#pragma unroll
    for (int nf = 0; nf < 4; nf++) {
        int col = nb + nf*8 + t4*2;
        float2 bb = *(const float2*)(bias + col);
        long r0 = row0 + mb + gid, r1 = r0 + 8;
        float2 rr0 = *(const float2*)(resid + r0*ND + col);
        float2 rr1 = *(const float2*)(resid + r1*ND + col);
        float2 o0, o1;
        o0.x = acc[nf][0] + bb.x + rr0.x; o0.y = acc[nf][1] + bb.y + rr0.y;
        o1.x = acc[nf][2] + bb.x + rr1.x; o1.y = acc[nf][3] + bb.y + rr1.y;
        *(float2*)(out + r0*ND + col) = o0;
        *(float2*)(out + r1*ND + col) = o1;
    }
}

// ---------------- fused LN + FFN1 + gelu (mma) --------------------------------
__global__ __launch_bounds__(256) void lnffn1_kernel(
        const float* __restrict__ X, const float* __restrict__ lns, const float* __restrict__ lnb,
        const uint32_t* __restrict__ WpH, const uint32_t* __restrict__ WpM, int tile0,
        const float* __restrict__ b1, float* __restrict__ Y) {
    __shared__ uint32_t Xh[64][33], Xm[64][33];
    __shared__ uint32_t Wh[64][36], Wm[64][36];
    int tid = threadIdx.x;
    long row0 = (long)blockIdx.x * 64;
    int w = tid >> 5, lane = tid & 31;
    int gid = lane >> 2, t4 = lane & 3;
    int mb = (w & 3) * 16, nb = (w >> 2) * 32;

    pack_x64(X, row0, ND, 0, lns, lnb, true, Xh, Xm, tid);
    for (int c = 0; c < 4; c++) {
        if (c) __syncthreads();
        copy_w64(WpH, WpM, tile0 + c, Wh, Wm, tid);
        __syncthreads();
        float acc[4][4] = {};
        mma64_compute(Xh, Xm, Wh, Wm, acc, mb, nb, gid, t4);
#pragma unroll
        for (int nf = 0; nf < 4; nf++) {
            int col = c*64 + nb + nf*8 + t4*2;
            float2 bb = *(const float2*)(b1 + col);
            long r0 = row0 + mb + gid, r1 = r0 + 8;
            float z;
            float2 o0, o1;
            z = acc[nf][0] + bb.x; o0.x = 0.5f*z*(1.f + erff(z*0.70710678118654752f));
            z = acc[nf][1] + bb.y; o0.y = 0.5f*z*(1.f + erff(z*0.70710678118654752f));
            z = acc[nf][2] + bb.x; o1.x = 0.5f*z*(1.f + erff(z*0.70710678118654752f));
            z = acc[nf][3] + bb.y; o1.y = 0.5f*z*(1.f + erff(z*0.70710678118654752f));
            *(float2*)(Y + r0*256 + col) = o0;
            *(float2*)(Y + r1*256 + col) = o1;
        }
    }
}

// ---------------- FFN2 (mma): Y @ W2 + b2 + resid -> h ------------------------
__global__ __launch_bounds__(256) void ffn2_kernel(
        const float* __restrict__ Y,
        const uint32_t* __restrict__ WpH, const uint32_t* __restrict__ WpM, int tile0,
        const float* __restrict__ b2, const float* __restrict__ resid,
        float* __restrict__ out) {
    __shared__ uint32_t Xh[64][33], Xm[64][33];
    __shared__ uint32_t Wh[64][36], Wm[64][36];
    int tid = threadIdx.x;
    long row0 = (long)blockIdx.x * 64;
    int w = tid >> 5, lane = tid & 31;
    int gid = lane >> 2, t4 = lane & 3;
    int mb = (w & 3) * 16, nb = (w >> 2) * 32;

    float acc[4][4] = {};
    for (int kc = 0; kc < 4; kc++) {
        if (kc) __syncthreads();
        pack_x64(Y, row0, 256, kc*64, nullptr, nullptr, false, Xh, Xm, tid);
        copy_w64(WpH, WpM, tile0 + kc, Wh, Wm, tid);
        __syncthreads();
        mma64_compute(Xh, Xm, Wh, Wm, acc, mb, nb, gid, t4);
    }
#pragma unroll
    for (int nf = 0; nf < 4; nf++) {
        int col = nb + nf*8 + t4*2;
        float2 bb = *(const float2*)(b2 + col);
        long r0 = row0 + mb + gid, r1 = r0 + 8;
        float2 rr0 = *(const float2*)(resid + r0*ND + col);
        float2 rr1 = *(const float2*)(resid + r1*ND + col);
        float2 o0, o1;
        o0.x = acc[nf][0] + bb.x + rr0.x; o0.y = acc[nf][1] + bb.y + rr0.y;
        o1.x = acc[nf][2] + bb.x + rr1.x; o1.y = acc[nf][3] + bb.y + rr1.y;
        *(float2*)(out + r0*ND + col) = o0;
        *(float2*)(out + r1*ND + col) = o1;
    }
}

// ---------------- local windowed attention (heads 0..3), bound-max softmax ----
__global__ __launch_bounds__(128) void local_attn_kernel(
        const float* __restrict__ q, const float* __restrict__ k,
        const float* __restrict__ v, float* __restrict__ attn) {
    int bid = blockIdx.x;                  // b*32 + h*8 + w
    int w = bid & 7, h = (bid >> 3) & 3, b = bid >> 5;
    __shared__ float Ks[384][8];
    __shared__ float Vs[384][8];
    __shared__ float wmax[4];
    int tid = threadIdx.x;                 // 128
    int base = ((b*8 + h)*1024) * 8;
    int jlo = (w == 0) ? 128 : 0;
    int jhi = (w == 7) ? 256 : 384;
    for (int idx = tid; idx < 768; idx += 128) {
        int j = idx >> 1, half = (idx & 1) * 4;
        int tt = (w - 1)*128 + j;
        float4 kv = {0,0,0,0}, vv = {0,0,0,0};
        if (tt >= 0 && tt < 1024) {
            kv = *(const float4*)(k + base + tt*8 + half);
            vv = *(const float4*)(v + base + tt*8 + half);
        }
        *(float4*)&Ks[j][half] = kv;
        *(float4*)&Vs[j][half] = vv;
    }
    __syncthreads();
    float nm = 0.f;
    for (int r = tid; r < 384; r += 128) {
        float4 k0 = *(const float4*)&Ks[r][0];
        float4 k1 = *(const float4*)&Ks[r][4];
        float s2 = k0.x*k0.x + k0.y*k0.y + k0.z*k0.z + k0.w*k0.w
                 + k1.x*k1.x + k1.y*k1.y + k1.z*k1.z + k1.w*k1.w;
        nm = fmaxf(nm, s2);
    }
#pragma unroll
    for (int o = 16; o; o >>= 1) nm = fmaxf(nm, __shfl_xor_sync(~0u, nm, o));
    if ((tid & 31) == 0) wmax[tid >> 5] = nm;
    __syncthreads();
    float kmax2 = fmaxf(fmaxf(wmax[0], wmax[1]), fmaxf(wmax[2], wmax[3]));

    int t = w*128 + tid;
    float4 q0 = *(const float4*)(q + base + t*8);
    float4 q1 = *(const float4*)(q + base + t*8 + 4);
    float qr[8] = {q0.x,q0.y,q0.z,q0.w,q1.x,q1.y,q1.z,q1.w};
    const float scale = 0.35355339059327373f;   // 1/sqrt(8)
    float qn2 = 0.f;
#pragma unroll
    for (int e = 0; e < 8; e++) qn2 += qr[e]*qr[e];
    float m = scale * sqrtf(qn2 * kmax2);
    float l = 0.f, acc[8] = {};
    for (int j = jlo; j < jhi; j++) {
        float4 k0 = *(const float4*)&Ks[j][0];
        float4 k1 = *(const float4*)&Ks[j][4];
        float s = qr[0]*k0.x + qr[1]*k0.y + qr[2]*k0.z + qr[3]*k0.w
                + qr[4]*k1.x + qr[5]*k1.y + qr[6]*k1.z + qr[7]*k1.w;
        float p = __expf(s*scale - m);
        l += p;
        float4 v0 = *(const float4*)&Vs[j][0];
        float4 v1 = *(const float4*)&Vs[j][4];
        acc[0] += p*v0.x; acc[1] += p*v0.y; acc[2] += p*v0.z; acc[3] += p*v0.w;
        acc[4] += p*v1.x; acc[5] += p*v1.y; acc[6] += p*v1.z; acc[7] += p*v1.w;
    }
    float inv = 1.f / l;
    float4 o0, o1;
    o0.x = acc[0]*inv; o0.y = acc[1]*inv; o0.z = acc[2]*inv; o0.w = acc[3]*inv;
    o1.x = acc[4]*inv; o1.y = acc[5]*inv; o1.z = acc[6]*inv; o1.w = acc[7]*inv;
    long ob = ((long)(b*1024 + t)*64) + h*8;
    *(float4*)(attn + ob) = o0;
    *(float4*)(attn + ob + 4) = o1;
}

// ---------------- global linear attention (heads 4..7) -----------------------
__global__ void global_attn_kernel(const float* __restrict__ q, const float* __restrict__ k,
                                   const float* __restrict__ v, float* __restrict__ attn) {
    int b = blockIdx.x >> 2, h = blockIdx.x & 3;
    int tid = threadIdx.x;                 // 256
    int base = ((b*8 + 4 + h)*1024) * 8;
    __shared__ float red[8][72];
    __shared__ float M[8];
    __shared__ float C[64];
    int warp = tid >> 5, lane = tid & 31;

    float mx[8];
#pragma unroll
    for (int d = 0; d < 8; d++) mx[d] = -1e30f;
    for (int t = tid; t < 1024; t += 256) {
        float4 k0 = *(const float4*)(k + base + t*8);
        float4 k1 = *(const float4*)(k + base + t*8 + 4);
        mx[0]=fmaxf(mx[0],k0.x); mx[1]=fmaxf(mx[1],k0.y); mx[2]=fmaxf(mx[2],k0.z); mx[3]=fmaxf(mx[3],k0.w);
        mx[4]=fmaxf(mx[4],k1.x); mx[5]=fmaxf(mx[5],k1.y); mx[6]=fmaxf(mx[6],k1.z); mx[7]=fmaxf(mx[7],k1.w);
    }
#pragma unroll
    for (int d = 0; d < 8; d++)
        for (int o = 16; o; o >>= 1) mx[d] = fmaxf(mx[d], __shfl_xor_sync(~0u, mx[d], o));
    if (lane == 0)
        for (int d = 0; d < 8; d++) red[warp][d] = mx[d];
    __syncthreads();
    if (tid < 8) {
        float m_ = red[0][tid];
        for (int wv = 1; wv < 8; wv++) m_ = fmaxf(m_, red[wv][tid]);
        M[tid] = m_;
    }
    __syncthreads();

    float Z[8] = {}, ctx[64] = {};
    for (int t = tid; t < 1024; t += 256) {
        float4 k0 = *(const float4*)(k + base + t*8);
        float4 k1 = *(const float4*)(k + base + t*8 + 4);
        float4 v0 = *(const float4*)(v + base + t*8);
        float4 v1 = *(const float4*)(v + base + t*8 + 4);
        float kr[8] = {k0.x,k0.y,k0.z,k0.w,k1.x,k1.y,k1.z,k1.w};
        float vr[8] = {v0.x,v0.y,v0.z,v0.w,v1.x,v1.y,v1.z,v1.w};
#pragma unroll
        for (int d = 0; d < 8; d++) {
            float e_ = __expf(kr[d] - M[d]);
            Z[d] += e_;
#pragma unroll
            for (int e = 0; e < 8; e++) ctx[d*8 + e] += e_ * vr[e];
        }
    }
#pragma unroll
    for (int i = 0; i < 8; i++)
        for (int o = 16; o; o >>= 1) Z[i] += __shfl_xor_sync(~0u, Z[i], o);
#pragma unroll
    for (int i = 0; i < 64; i++)
        for (int o = 16; o; o >>= 1) ctx[i] += __shfl_xor_sync(~0u, ctx[i], o);
    if (lane == 0) {
        for (int i = 0; i < 8; i++)  red[warp][i] = Z[i];
        for (int i = 0; i < 64; i++) red[warp][8 + i] = ctx[i];
    }
    __syncthreads();
    if (tid < 64) {
        float s = 0.f, z = 0.f;
        int d = tid >> 3;
        for (int wv = 0; wv < 8; wv++) { s += red[wv][8 + tid]; z += red[wv][d]; }
        C[tid] = s / z;
    }
    __syncthreads();

    const float scale = 0.35355339059327373f;
    for (int t = tid; t < 1024; t += 256) {
        float4 q0 = *(const float4*)(q + base + t*8);
        float4 q1 = *(const float4*)(q + base + t*8 + 4);
        float qr[8] = {q0.x,q0.y,q0.z,q0.w,q1.x,q1.y,q1.z,q1.w};
        float qm = -1e30f;
#pragma unroll
        for (int d = 0; d < 8; d++) qm = fmaxf(qm, qr[d]);
        float qs = 0.f;
#pragma unroll
        for (int d = 0; d < 8; d++) { qr[d] = __expf(qr[d] - qm); qs += qr[d]; }
        float inv = scale / qs;
        float o_[8] = {};
#pragma unroll
        for (int d = 0; d < 8; d++) {
            float p = qr[d] * inv;
#pragma unroll
            for (int e = 0; e < 8; e++) o_[e] += p * C[d*8 + e];
        }
        long ob = (long)(b*1024 + t)*64 + (4 + h)*8;
        float4 oo0, oo1;
        oo0.x=o_[0]; oo0.y=o_[1]; oo0.z=o_[2]; oo0.w=o_[3];
        oo1.x=o_[4]; oo1.y=o_[5]; oo1.z=o_[6]; oo1.w=o_[7];
        *(float4*)(attn + ob) = oo0;
        *(float4*)(attn + ob + 4) = oo1;
    }
}

// ---------------- collapse: h(.,64) @ cw(64,5) + cb -> out --------------------
__global__ void collapse_kernel(const float* __restrict__ h, const float* __restrict__ cw,
                                const float* __restrict__ cb, float* __restrict__ out) {
    __shared__ float Xs[64][68];
    __shared__ float Ws[64][NDIN];
    __shared__ float Bs[NDIN];
    int tid = threadIdx.x;                 // 64
    int row0 = blockIdx.x * 64;
    for (int idx = tid; idx < 1024; idx += 64) {
        int i = idx >> 4, j = (idx & 15) * 4;
        *(float4*)&Xs[i][j] = *(const float4*)(h + (long)(row0 + i)*ND + j);
    }
    for (int idx = tid; idx < 64*NDIN; idx += 64) Ws[idx/NDIN][idx%NDIN] = cw[idx];
    if (tid < NDIN) Bs[tid] = cb[tid];
    __syncthreads();
    int r = tid;
    float acc[NDIN];
#pragma unroll
    for (int j = 0; j < NDIN; j++) acc[j] = Bs[j];
    for (int kk = 0; kk < 64; kk++) {
        float xv = Xs[r][kk];
#pragma unroll
        for (int j = 0; j < NDIN; j++) acc[j] += xv * Ws[kk][j];
    }
#pragma unroll
    for (int j = 0; j < NDIN; j++) out[(row0 + r)*NDIN + j] = acc[j];
}

// ---------------- launch ------------------------------------------------------
extern "C" void kernel_launch(void* const* d_in, const int* in_sizes, int n_in,
                              void* d_out, int out_size) {
    const float* x          = (const float*)d_in[0];
    const float* pos_emb    = (const float*)d_in[1];
    const float* expand_w   = (const float*)d_in[2];
    const float* expand_b   = (const float*)d_in[3];
    const float* emb_w      = (const float*)d_in[4];
    const float* emb_b      = (const float*)d_in[5];
    const float* conv_w     = (const float*)d_in[6];
    const float* conv_b     = (const float*)d_in[7];
    const float* ln1_s      = (const float*)d_in[8];
    const float* ln1_b      = (const float*)d_in[9];
    const float* wq         = (const float*)d_in[10];
    const float* wk         = (const float*)d_in[11];
    const float* wv         = (const float*)d_in[12];
    const float* wo         = (const float*)d_in[13];
    const float* wo_b       = (const float*)d_in[14];
    const float* ln2_s      = (const float*)d_in[15];
    const float* ln2_b      = (const float*)d_in[16];
    const float* ff_w1      = (const float*)d_in[17];
    const float* ff_b1      = (const float*)d_in[18];
    const float* ff_w2      = (const float*)d_in[19];
    const float* ff_b2      = (const float*)d_in[20];
    const float* collapse_w = (const float*)d_in[21];
    const float* collapse_b = (const float*)d_in[22];
    float* out = (float*)d_out;

    float *ph, *php, *pq, *pk, *pv, *pattn, *py, *pWc, *pbc;
    uint32_t *pWpH, *pWpM, *pAH, *pAM, *pBH, *pBM;
    cudaGetSymbolAddress((void**)&ph,   g_h);
    cudaGetSymbolAddress((void**)&php,  g_hpad);
    cudaGetSymbolAddress((void**)&pq,   g_q);
    cudaGetSymbolAddress((void**)&pk,   g_k);
    cudaGetSymbolAddress((void**)&pv,   g_v);
    cudaGetSymbolAddress((void**)&pattn,g_attn);
    cudaGetSymbolAddress((void**)&py,   g_y);
    cudaGetSymbolAddress((void**)&pWc,  g_Wc);
    cudaGetSymbolAddress((void**)&pbc,  g_bc);
    cudaGetSymbolAddress((void**)&pWpH, g_WpH);
    cudaGetSymbolAddress((void**)&pWpM, g_WpM);
    cudaGetSymbolAddress((void**)&pAH,  g_AH);
    cudaGetSymbolAddress((void**)&pAM,  g_AM);
    cudaGetSymbolAddress((void**)&pBH,  g_BH);
    cudaGetSymbolAddress((void**)&pBM,  g_BM);

    precompute_kernel<<<1, 64>>>(expand_w, expand_b, emb_w, emb_b, pWc, pbc);
    packw_kernel<<<24, 256>>>(wq, wk, wv, wo, ff_w1, ff_w2, pWpH, pWpM);
    packa_kernel<<<(1024*1536)/256, 256>>>(conv_w, pAH, pAM);
    expand_kernel<<<NTOK/64, 256>>>(x, pWc, pbc, php);
    packb_kernel<<<(1536*4096)/256, 256>>>(php, pBH, pBM);
    conv_kernel<<<dim3(4096/CBN, 1024/CBM), 256>>>(pAH, pAM, pBH, pBM, conv_b, pos_emb, ph);

    for (int l = 0; l < 2; l++) {
        int tb = l*12;
        lnqkv_kernel<<<NTOK/64, 256>>>(ph, ln1_s + l*64, ln1_b + l*64,
                                       pWpH, pWpM, tb + 0, pq, pk, pv);
        local_attn_kernel<<<NB*4*8, 128>>>(pq, pk, pv, pattn);
        global_attn_kernel<<<NB*4, 256>>>(pq, pk, pv, pattn);
        wo_kernel<<<NTOK/64, 256>>>(pattn, pWpH, pWpM, tb + 3, wo_b + l*64, ph, ph);
        lnffn1_kernel<<<NTOK/64, 256>>>(ph, ln2_s + l*64, ln2_b + l*64,
                                        pWpH, pWpM, tb + 4, ff_b1 + l*256, py);
        ffn2_kernel<<<NTOK/64, 256>>>(py, pWpH, pWpM, tb + 8, ff_b2 + l*64, ph, ph);
    }
    collapse_kernel<<<NTOK/64, 64>>>(ph, collapse_w, collapse_b, out);
}

// round 11
// speedup vs baseline: 3.5621x; 1.0665x over previous
#include <cuda_runtime.h>
#include <cuda_bf16.h>
#include <cstdint>
#include <math.h>

// Problem constants: B=64, T=1024, DIN=5, D=64, H=8, DH=8, NLOCAL=4, WS=128, DEPTH=2
#define NB 64
#define NT 1024
#define NDIN 5
#define ND 64
#define NTOK (NB*NT)           // 65536

// ---------------- scratch (static device buffers) -----------------------------
__device__ float g_h[NTOK*ND];          // running hidden state
__device__ float g_q[NTOK*ND];          // [b][h][t][dh]
__device__ float g_k[NTOK*ND];
__device__ float g_v[NTOK*ND];
__device__ float g_attn[NTOK*ND];       // [b][t][h*8+dh]
__device__ float g_Wc[NDIN*ND];
__device__ float g_bc[ND];
// packed-weight tiles: 24 tiles x 64 n x 32 kpairs
__device__ uint32_t g_WpH[24*2048], g_WpM[24*2048];
// packed conv A: [1024 m][1536 kpair]
__device__ uint32_t g_AH[1024*1536], g_AM[1024*1536];
// packed conv B: [1536 kpair][4096 n]
__device__ uint32_t g_BH[1536*4096], g_BM[1536*4096];

// ---------------- bf16 split helpers ------------------------------------------
__device__ __forceinline__ void pack2(float x0, float x1, uint32_t& hi, uint32_t& mid) {
    uint32_t h;
    asm("cvt.rn.bf16x2.f32 %0, %1, %2;" : "=r"(h) : "f"(x1), "f"(x0));
    float f0 = __uint_as_float(h << 16);
    float f1 = __uint_as_float(h & 0xFFFF0000u);
    float r0 = x0 - f0, r1 = x1 - f1;
    asm("cvt.rn.bf16x2.f32 %0, %1, %2;" : "=r"(mid) : "f"(r1), "f"(r0));
    hi = h;
}
__device__ __forceinline__ void mma_bf16(float* c, const uint32_t* a, const uint32_t* b) {
    asm volatile("mma.sync.aligned.m16n8k16.row.col.f32.bf16.bf16.f32 "
        "{%0,%1,%2,%3}, {%4,%5,%6,%7}, {%8,%9}, {%0,%1,%2,%3};"
        : "+f"(c[0]), "+f"(c[1]), "+f"(c[2]), "+f"(c[3])
        : "r"(a[0]), "r"(a[1]), "r"(a[2]), "r"(a[3]), "r"(b[0]), "r"(b[1]));
}

// ---------------- precompute combined expand@emb ------------------------------
__global__ void precompute_kernel(const float* __restrict__ ew, const float* __restrict__ eb,
                                  const float* __restrict__ mw, const float* __restrict__ mb,
                                  float* __restrict__ Wc, float* __restrict__ bc) {
    int j = threadIdx.x;             // 64 threads
    for (int i = 0; i < NDIN; i++) {
        float s = 0.f;
        for (int d = 0; d < ND; d++) s += ew[i*ND + d] * mw[d*ND + j];
        Wc[i*ND + j] = s;
    }
    float s = mb[j];
    for (int d = 0; d < ND; d++) s += eb[d] * mw[d*ND + j];
    bc[j] = s;
}

// ---------------- weight pre-pack: 24 tiles of 64x64 --------------------------
__global__ void packw_kernel(const float* __restrict__ wq, const float* __restrict__ wk,
                             const float* __restrict__ wv, const float* __restrict__ wo,
                             const float* __restrict__ w1, const float* __restrict__ w2,
                             uint32_t* __restrict__ WpH, uint32_t* __restrict__ WpM) {
    int tile = blockIdx.x;        // 0..23
    int l = tile / 12, t = tile - l*12;
    const float* src; int ldw, coloff;
    if (t == 0)      { src = wq + l*4096; ldw = 64; coloff = 0; }
    else if (t == 1) { src = wk + l*4096; ldw = 64; coloff = 0; }
    else if (t == 2) { src = wv + l*4096; ldw = 64; coloff = 0; }
    else if (t == 3) { src = wo + l*4096; ldw = 64; coloff = 0; }
    else if (t < 8)  { src = w1 + l*64*256; ldw = 256; coloff = (t-4)*64; }
    else             { src = w2 + l*256*64 + (t-8)*64*64; ldw = 64; coloff = 0; }
    int tid = threadIdx.x;        // 256
    int n = tid & 63, p0 = (tid >> 6) * 8;
    uint32_t* dh = WpH + tile*2048 + n*32;
    uint32_t* dm = WpM + tile*2048 + n*32;
#pragma unroll
    for (int u = 0; u < 8; u++) {
        int k = 2*(p0+u);
        float w0 = src[(long)k*ldw + coloff + n];
        float w1v = src[(long)(k+1)*ldw + coloff + n];
        uint32_t h, m_;
        pack2(w0, w1v, h, m_);
        dh[p0+u] = h; dm[p0+u] = m_;
    }
}

// ---------------- conv A pre-pack: conv_w -> [m][kpair] ------------------------
__global__ void packa_kernel(const float* __restrict__ A,
                             uint32_t* __restrict__ AH, uint32_t* __restrict__ AM) {
    int idx = blockIdx.x*256 + threadIdx.x;       // pair index [1024*1536)
    float2 v = *(const float2*)(A + (long)idx*2);
    uint32_t h, m_;
    pack2(v.x, v.y, h, m_);
    AH[idx] = h; AM[idx] = m_;
}

// ---------------- conv B pre-pack WITH fused expand ----------------------------
// B[K][(b,d)] = h[b][K/3][d + K%3 - 1], h = x @ Wc + bc, zero out-of-range.
__global__ void packbx_kernel(const float* __restrict__ x,
                              const float* __restrict__ Wc, const float* __restrict__ bc,
                              uint32_t* __restrict__ BH, uint32_t* __restrict__ BM) {
    int idx = blockIdx.x*256 + threadIdx.x;       // [1536*4096)
    int kp2 = idx >> 12;
    int n = idx & 4095;
    int b = n >> 6, d = n & 63;
    int K0 = kp2*2, K1 = K0 + 1;
    int kt0 = K0/3, kq0 = K0 - kt0*3;
    int kt1 = K1/3, kq1 = K1 - kt1*3;
    int d0 = d + kq0 - 1, d1 = d + kq1 - 1;
    float v0 = 0.f, v1 = 0.f;
    if (d0 >= 0 && d0 < 64) {
        const float* xr = x + ((long)(b << 10) + kt0) * NDIN;
        v0 = bc[d0];
#pragma unroll
        for (int i = 0; i < NDIN; i++) v0 += xr[i] * Wc[i*ND + d0];
    }
    if (d1 >= 0 && d1 < 64) {
        const float* xr = x + ((long)(b << 10) + kt1) * NDIN;
        v1 = bc[d1];
#pragma unroll
        for (int i = 0; i < NDIN; i++) v1 += xr[i] * Wc[i*ND + d1];
    }
    uint32_t h, m_;
    pack2(v0, v1, h, m_);
    BH[idx] = h; BM[idx] = m_;
}

// ---------------- conv as GEMM, bf16x3 m16n8k16, pre-packed operands ----------
#define CBM 128
#define CBN 128
#define CBK 16
__global__ __launch_bounds__(256) void conv_kernel(
        const uint32_t* __restrict__ AH, const uint32_t* __restrict__ AM,
        const uint32_t* __restrict__ BH, const uint32_t* __restrict__ BM,
        const float* __restrict__ conv_b, const float* __restrict__ pos_emb,
        float* __restrict__ Hout) {
    __shared__ uint32_t Ah[2][CBM][9], Am[2][CBM][9];
    __shared__ uint32_t Bh[2][CBN][9], Bm[2][CBN][9];
    int tid = threadIdx.x;
    int m0 = blockIdx.y * CBM;
    int n0 = blockIdx.x * CBN;

    int arow = tid >> 1;
    int ap = (tid & 1) * 4;
    int bj = tid & 127;
    int bp = (tid >> 7) * 4;

    int w = tid >> 5, lane = tid & 31;
    int gid = lane >> 2, t4 = lane & 3;
    int warpM = w >> 1, warpN = w & 1;
    int mbase = warpM * 32, nbase = warpN * 64;

    float acc[2][8][4];
#pragma unroll
    for (int mt = 0; mt < 2; mt++)
#pragma unroll
        for (int nt = 0; nt < 8; nt++)
#pragma unroll
            for (int r = 0; r < 4; r++) acc[mt][nt][r] = 0.f;

    auto loadA = [&](int k0, int buf) {
        const uint32_t* ph = AH + (long)(m0 + arow)*1536 + (k0 >> 1) + ap;
        const uint32_t* pm = AM + (long)(m0 + arow)*1536 + (k0 >> 1) + ap;
        uint4 vh = *(const uint4*)ph;
        uint4 vm = *(const uint4*)pm;
        Ah[buf][arow][ap+0] = vh.x; Ah[buf][arow][ap+1] = vh.y;
        Ah[buf][arow][ap+2] = vh.z; Ah[buf][arow][ap+3] = vh.w;
        Am[buf][arow][ap+0] = vm.x; Am[buf][arow][ap+1] = vm.y;
        Am[buf][arow][ap+2] = vm.z; Am[buf][arow][ap+3] = vm.w;
    };
    auto loadB = [&](int k0, int buf) {
        long base = (long)((k0 >> 1) + bp) * 4096 + n0 + bj;
#pragma unroll
        for (int u = 0; u < 4; u++) {
            Bh[buf][bj][bp+u] = BH[base + (long)u*4096];
            Bm[buf][bj][bp+u] = BM[base + (long)u*4096];
        }
    };

    loadA(0, 0); loadB(0, 0);
    __syncthreads();

    int cur = 0;
    for (int k0 = CBK; k0 <= 3072; k0 += CBK) {
        if (k0 < 3072) { loadA(k0, cur ^ 1); loadB(k0, cur ^ 1); }
        uint32_t ah[2][4], am[2][4];
#pragma unroll
        for (int mt = 0; mt < 2; mt++) {
            int r0 = mbase + mt*16 + gid;
            ah[mt][0] = Ah[cur][r0  ][t4];   ah[mt][1] = Ah[cur][r0+8][t4];
            ah[mt][2] = Ah[cur][r0  ][t4+4]; ah[mt][3] = Ah[cur][r0+8][t4+4];
            am[mt][0] = Am[cur][r0  ][t4];   am[mt][1] = Am[cur][r0+8][t4];
            am[mt][2] = Am[cur][r0  ][t4+4]; am[mt][3] = Am[cur][r0+8][t4+4];
        }
#pragma unroll
        for (int nt = 0; nt < 8; nt++) {
            int n = nbase + nt*8 + gid;
            uint32_t bhf[2] = { Bh[cur][n][t4], Bh[cur][n][t4+4] };
            uint32_t bmf[2] = { Bm[cur][n][t4], Bm[cur][n][t4+4] };
#pragma unroll
            for (int mt = 0; mt < 2; mt++) {
                mma_bf16(acc[mt][nt], ah[mt], bhf);
                mma_bf16(acc[mt][nt], ah[mt], bmf);
                mma_bf16(acc[mt][nt], am[mt], bhf);
            }
        }
        __syncthreads();
        cur ^= 1;
    }

#pragma unroll
    for (int mt = 0; mt < 2; mt++) {
        int row0r = m0 + mbase + mt*16 + gid;
        float cb0 = conv_b[row0r];
        float cb1 = conv_b[row0r + 8];
#pragma unroll
        for (int nt = 0; nt < 8; nt++) {
            int coln = n0 + nbase + nt*8 + t4*2;
            int b_ = coln >> 6, d_ = coln & 63;
            float2 pe0 = *(const float2*)(pos_emb + row0r*64 + d_);
            float2 pe1 = *(const float2*)(pos_emb + (row0r+8)*64 + d_);
            float2 o0, o1;
            o0.x = acc[mt][nt][0] + cb0 + pe0.x;
            o0.y = acc[mt][nt][1] + cb0 + pe0.y;
            o1.x = acc[mt][nt][2] + cb1 + pe1.x;
            o1.y = acc[mt][nt][3] + cb1 + pe1.y;
            *(float2*)(Hout + ((long)(b_ << 10) + row0r)*64 + d_) = o0;
            *(float2*)(Hout + ((long)(b_ << 10) + row0r + 8)*64 + d_) = o1;
        }
    }
}

// ================= mma-based 64-token GEMM helpers =============================
typedef uint32_t XT[33];
typedef uint32_t WT[36];

__device__ __forceinline__ void pack_x64(const float* __restrict__ X, long row0, int ldx, int coloff,
                                         const float* __restrict__ lns, const float* __restrict__ lnb,
                                         bool doLN, XT* Xh, XT* Xm, int tid) {
    int r = tid >> 2, q = (tid & 3) * 16;
    const float* row = X + (row0 + r) * (long)ldx + coloff + q;
    float xv[16];
    *(float4*)&xv[0]  = *(const float4*)(row);
    *(float4*)&xv[4]  = *(const float4*)(row + 4);
    *(float4*)&xv[8]  = *(const float4*)(row + 8);
    *(float4*)&xv[12] = *(const float4*)(row + 12);
    if (doLN) {
        float sum = 0.f;
#pragma unroll
        for (int j = 0; j < 16; j++) sum += xv[j];
        sum += __shfl_xor_sync(~0u, sum, 1);
        sum += __shfl_xor_sync(~0u, sum, 2);
        float mu = sum * (1.f/64.f);
        float vs = 0.f;
#pragma unroll
        for (int j = 0; j < 16; j++) { float d = xv[j] - mu; vs += d*d; }
        vs += __shfl_xor_sync(~0u, vs, 1);
        vs += __shfl_xor_sync(~0u, vs, 2);
        float inv = rsqrtf(vs * (1.f/64.f) + 1e-5f);
#pragma unroll
        for (int j = 0; j < 16; j++) xv[j] = (xv[j] - mu) * inv * lns[q+j] + lnb[q+j];
    }
    int p0 = q >> 1;
#pragma unroll
    for (int u = 0; u < 8; u++) {
        uint32_t h, m_;
        pack2(xv[2*u], xv[2*u+1], h, m_);
        Xh[r][p0+u] = h; Xm[r][p0+u] = m_;
    }
}

__device__ __forceinline__ void copy_w64(const uint32_t* __restrict__ WpH,
                                         const uint32_t* __restrict__ WpM, int tile,
                                         WT* Wh, WT* Wm, int tid) {
    int n = tid >> 2, qp = (tid & 3) * 8;
    const uint32_t* sh = WpH + tile*2048 + n*32 + qp;
    const uint32_t* sm = WpM + tile*2048 + n*32 + qp;
    *(uint4*)&Wh[n][qp]   = *(const uint4*)sh;
    *(uint4*)&Wh[n][qp+4] = *(const uint4*)(sh+4);
    *(uint4*)&Wm[n][qp]   = *(const uint4*)sm;
    *(uint4*)&Wm[n][qp+4] = *(const uint4*)(sm+4);
}

__device__ __forceinline__ void mma64_compute(const XT* Xh, const XT* Xm,
                                              const WT* Wh, const WT* Wm,
                                              float acc[4][4], int mb, int nb, int gid, int t4) {
#pragma unroll
    for (int kc = 0; kc < 4; kc++) {
        int kp = kc*8;
        uint32_t ah[4], am[4];
        ah[0] = Xh[mb+gid  ][kp+t4];   ah[1] = Xh[mb+gid+8][kp+t4];
        ah[2] = Xh[mb+gid  ][kp+t4+4]; ah[3] = Xh[mb+gid+8][kp+t4+4];
        am[0] = Xm[mb+gid  ][kp+t4];   am[1] = Xm[mb+gid+8][kp+t4];
        am[2] = Xm[mb+gid  ][kp+t4+4]; am[3] = Xm[mb+gid+8][kp+t4+4];
#pragma unroll
        for (int nf = 0; nf < 4; nf++) {
            int n = nb + nf*8 + gid;
            uint32_t bh[2] = { Wh[n][kp+t4], Wh[n][kp+t4+4] };
            uint32_t bm[2] = { Wm[n][kp+t4], Wm[n][kp+t4+4] };
            mma_bf16(acc[nf], ah, bh);
            mma_bf16(acc[nf], ah, bm);
            mma_bf16(acc[nf], am, bh);
        }
    }
}

// ---------------- fused LN + QKV (mma) -> head layout -------------------------
__global__ __launch_bounds__(256) void lnqkv_kernel(
        const float* __restrict__ X, const float* __restrict__ lns, const float* __restrict__ lnb,
        const uint32_t* __restrict__ WpH, const uint32_t* __restrict__ WpM, int tile0,
        float* __restrict__ q, float* __restrict__ k, float* __restrict__ v) {
    __shared__ uint32_t Xh[64][33], Xm[64][33];
    __shared__ uint32_t Wh[64][36], Wm[64][36];
    int tid = threadIdx.x;
    long row0 = (long)blockIdx.x * 64;
    int w = tid >> 5, lane = tid & 31;
    int gid = lane >> 2, t4 = lane & 3;
    int mb = (w & 3) * 16, nb = (w >> 2) * 32;

    pack_x64(X, row0, ND, 0, lns, lnb, true, Xh, Xm, tid);
    float* Om[3] = {q, k, v};
#pragma unroll
    for (int m = 0; m < 3; m++) {
        if (m) __syncthreads();
        copy_w64(WpH, WpM, tile0 + m, Wh, Wm, tid);
        __syncthreads();
        float acc[4][4] = {};
        mma64_compute(Xh, Xm, Wh, Wm, acc, mb, nb, gid, t4);
        float* out = Om[m];
        int dh = t4*2;
#pragma unroll
        for (int nf = 0; nf < 4; nf++) {
            int h = (nb >> 3) + nf;
            long gt0 = row0 + mb + gid;
            long gt1 = gt0 + 8;
            long b0 = gt0 >> 10, t0 = gt0 & 1023;
            long b1 = gt1 >> 10, t1 = gt1 & 1023;
            float2 o0; o0.x = acc[nf][0]; o0.y = acc[nf][1];
            float2 o1; o1.x = acc[nf][2]; o1.y = acc[nf][3];
            *(float2*)(out + (((b0*8 + h)*1024) + t0)*8 + dh) = o0;
            *(float2*)(out + (((b1*8 + h)*1024) + t1)*8 + dh) = o1;
        }
    }
}

// ---------------- FUSED: wo + resid + ln2 + ffn1 + gelu + ffn2 + resid --------
// dynamic smem: Hs[64][68] f32 | Xh,Xm[64][33] | Wh,Wm[64][36] | Yh,Ym[64][33]
#define FUSED_SMEM (17408 + 2*8448 + 2*9216 + 2*8448)
__global__ __launch_bounds__(256) void attn_ffn_kernel(
        const float* __restrict__ attnIn,
        const uint32_t* __restrict__ WpH, const uint32_t* __restrict__ WpM,
        int woTile, int f1Tile0, int f2Tile0,
        const float* __restrict__ wo_b,
        const float* __restrict__ ln2s, const float* __restrict__ ln2b,
        const float* __restrict__ b1, const float* __restrict__ b2,
        float* __restrict__ h) {
    extern __shared__ char smem[];
    float (*Hs)[68] = (float(*)[68])smem;
    XT* Xh = (XT*)(smem + 17408);
    XT* Xm = (XT*)(smem + 17408 + 8448);
    WT* Wh = (WT*)(smem + 17408 + 2*8448);
    WT* Wm = (WT*)(smem + 17408 + 2*8448 + 9216);
    XT* Yh = (XT*)(smem + 17408 + 2*8448 + 2*9216);
    XT* Ym = (XT*)(smem + 17408 + 2*8448 + 2*9216 + 8448);

    int tid = threadIdx.x;
    long row0 = (long)blockIdx.x * 64;
    int w = tid >> 5, lane = tid & 31;
    int gid = lane >> 2, t4 = lane & 3;
    int mb = (w & 3) * 16, nb = (w >> 2) * 32;

    // ---- 1. wo GEMM ----
    pack_x64(attnIn, row0, ND, 0, nullptr, nullptr, false, Xh, Xm, tid);
    copy_w64(WpH, WpM, woTile, Wh, Wm, tid);
    __syncthreads();
    float acc[4][4] = {};
    mma64_compute(Xh, Xm, Wh, Wm, acc, mb, nb, gid, t4);
    // h_new = acc + wo_b + resid -> Hs (smem only)
#pragma unroll
    for (int nf = 0; nf < 4; nf++) {
        int col = nb + nf*8 + t4*2;
        float2 bb = *(const float2*)(wo_b + col);
        long r0 = row0 + mb + gid, r1 = r0 + 8;
        float2 rr0 = *(const float2*)(h + r0*ND + col);
        float2 rr1 = *(const float2*)(h + r1*ND + col);
        Hs[mb+gid  ][col]   = acc[nf][0] + bb.x + rr0.x;
        Hs[mb+gid  ][col+1] = acc[nf][1] + bb.y + rr0.y;
        Hs[mb+gid+8][col]   = acc[nf][2] + bb.x + rr1.x;
        Hs[mb+gid+8][col+1] = acc[nf][3] + bb.y + rr1.y;
    }
    __syncthreads();

    // ---- 2. LN2 on Hs -> pack into Xh/Xm ----
    {
        int r = tid >> 2, q = (tid & 3) * 16;
        float xv[16];
#pragma unroll
        for (int j = 0; j < 16; j++) xv[j] = Hs[r][q+j];
        float sum = 0.f;
#pragma unroll
        for (int j = 0; j < 16; j++) sum += xv[j];
        sum += __shfl_xor_sync(~0u, sum, 1);
        sum += __shfl_xor_sync(~0u, sum, 2);
        float mu = sum * (1.f/64.f);
        float vs = 0.f;
#pragma unroll
        for (int j = 0; j < 16; j++) { float d = xv[j] - mu; vs += d*d; }
        vs += __shfl_xor_sync(~0u, vs, 1);
        vs += __shfl_xor_sync(~0u, vs, 2);
        float inv = rsqrtf(vs * (1.f/64.f) + 1e-5f);
        int p0 = q >> 1;
#pragma unroll
        for (int u = 0; u < 8; u++) {
            float y0 = (xv[2*u]   - mu) * inv * ln2s[q+2*u]   + ln2b[q+2*u];
            float y1 = (xv[2*u+1] - mu) * inv * ln2s[q+2*u+1] + ln2b[q+2*u+1];
            uint32_t hh, m_;
            pack2(y0, y1, hh, m_);
            Xh[r][p0+u] = hh; Xm[r][p0+u] = m_;
        }
    }

    // ---- 3. chunk-interleaved ffn1 -> gelu -> Y smem -> ffn2 accumulate ----
    float acc2[4][4] = {};
    for (int c = 0; c < 4; c++) {
        __syncthreads();                           // Wh free, Yh consumed
        copy_w64(WpH, WpM, f1Tile0 + c, Wh, Wm, tid);
        __syncthreads();
        float ya[4][4] = {};
        mma64_compute(Xh, Xm, Wh, Wm, ya, mb, nb, gid, t4);
        // gelu + bias, pack into Y smem: pairIdx = nb/2 + nf*4 + t4
#pragma unroll
        for (int nf = 0; nf < 4; nf++) {
            int col = c*64 + nb + nf*8 + t4*2;
            float2 bb = *(const float2*)(b1 + col);
            float z0 = ya[nf][0] + bb.x, z1 = ya[nf][1] + bb.y;
            float z2 = ya[nf][2] + bb.x, z3 = ya[nf][3] + bb.y;
            float y0 = 0.5f*z0*(1.f + erff(z0*0.70710678118654752f));
            float y1 = 0.5f*z1*(1.f + erff(z1*0.70710678118654752f));
            float y2 = 0.5f*z2*(1.f + erff(z2*0.70710678118654752f));
            float y3 = 0.5f*z3*(1.f + erff(z3*0.70710678118654752f));
            int pi = (nb >> 1) + nf*4 + t4;
            uint32_t hh, m_;
            pack2(y0, y1, hh, m_); Yh[mb+gid  ][pi] = hh; Ym[mb+gid  ][pi] = m_;
            pack2(y2, y3, hh, m_); Yh[mb+gid+8][pi] = hh; Ym[mb+gid+8][pi] = m_;
        }
        __syncthreads();                           // Y visible, Wh free
        copy_w64(WpH, WpM, f2Tile0 + c, Wh, Wm, tid);
        __syncthreads();
        mma64_compute(Yh, Ym, Wh, Wm, acc2, mb, nb, gid, t4);
    }

    // ---- 4. epilogue: h = acc2 + b2 + Hs ----
#pragma unroll
    for (int nf = 0; nf < 4; nf++) {
        int col = nb + nf*8 + t4*2;
        float2 bb = *(const float2*)(b2 + col);
        long r0 = row0 + mb + gid, r1 = r0 + 8;
        float2 o0, o1;
        o0.x = acc2[nf][0] + bb.x + Hs[mb+gid  ][col];
        o0.y = acc2[nf][1] + bb.y + Hs[mb+gid  ][col+1];
        o1.x = acc2[nf][2] + bb.x + Hs[mb+gid+8][col];
        o1.y = acc2[nf][3] + bb.y + Hs[mb+gid+8][col+1];
        *(float2*)(h + r0*ND + col) = o0;
        *(float2*)(h + r1*ND + col) = o1;
    }
}

// ---------------- local windowed attention (heads 0..3), bound-max softmax ----
__global__ __launch_bounds__(128) void local_attn_kernel(
        const float* __restrict__ q, const float* __restrict__ k,
        const float* __restrict__ v, float* __restrict__ attn) {
    int bid = blockIdx.x;                  // b*32 + h*8 + w
    int w = bid & 7, h = (bid >> 3) & 3, b = bid >> 5;
    __shared__ float Ks[384][8];
    __shared__ float Vs[384][8];
    __shared__ float wmax[4];
    int tid = threadIdx.x;                 // 128
    int base = ((b*8 + h)*1024) * 8;
    int jlo = (w == 0) ? 128 : 0;
    int jhi = (w == 7) ? 256 : 384;
    for (int idx = tid; idx < 768; idx += 128) {
        int j = idx >> 1, half = (idx & 1) * 4;
        int tt = (w - 1)*128 + j;
        float4 kv = {0,0,0,0}, vv = {0,0,0,0};
        if (tt >= 0 && tt < 1024) {
            kv = *(const float4*)(k + base + tt*8 + half);
            vv = *(const float4*)(v + base + tt*8 + half);
        }
        *(float4*)&Ks[j][half] = kv;
        *(float4*)&Vs[j][half] = vv;
    }
    __syncthreads();
    float nm = 0.f;
    for (int r = tid; r < 384; r += 128) {
        float4 k0 = *(const float4*)&Ks[r][0];
        float4 k1 = *(const float4*)&Ks[r][4];
        float s2 = k0.x*k0.x + k0.y*k0.y + k0.z*k0.z + k0.w*k0.w
                 + k1.x*k1.x + k1.y*k1.y + k1.z*k1.z + k1.w*k1.w;
        nm = fmaxf(nm, s2);
    }
#pragma unroll
    for (int o = 16; o; o >>= 1) nm = fmaxf(nm, __shfl_xor_sync(~0u, nm, o));
    if ((tid & 31) == 0) wmax[tid >> 5] = nm;
    __syncthreads();
    float kmax2 = fmaxf(fmaxf(wmax[0], wmax[1]), fmaxf(wmax[2], wmax[3]));

    int t = w*128 + tid;
    float4 q0 = *(const float4*)(q + base + t*8);
    float4 q1 = *(const float4*)(q + base + t*8 + 4);
    float qr[8] = {q0.x,q0.y,q0.z,q0.w,q1.x,q1.y,q1.z,q1.w};
    const float scale = 0.35355339059327373f;   // 1/sqrt(8)
    float qn2 = 0.f;
#pragma unroll
    for (int e = 0; e < 8; e++) qn2 += qr[e]*qr[e];
    float m = scale * sqrtf(qn2 * kmax2);
    float l = 0.f, acc[8] = {};
    for (int j = jlo; j < jhi; j++) {
        float4 k0 = *(const float4*)&Ks[j][0];
        float4 k1 = *(const float4*)&Ks[j][4];
        float s = qr[0]*k0.x + qr[1]*k0.y + qr[2]*k0.z + qr[3]*k0.w
                + qr[4]*k1.x + qr[5]*k1.y + qr[6]*k1.z + qr[7]*k1.w;
        float p = __expf(s*scale - m);
        l += p;
        float4 v0 = *(const float4*)&Vs[j][0];
        float4 v1 = *(const float4*)&Vs[j][4];
        acc[0] += p*v0.x; acc[1] += p*v0.y; acc[2] += p*v0.z; acc[3] += p*v0.w;
        acc[4] += p*v1.x; acc[5] += p*v1.y; acc[6] += p*v1.z; acc[7] += p*v1.w;
    }
    float inv = 1.f / l;
    float4 o0, o1;
    o0.x = acc[0]*inv; o0.y = acc[1]*inv; o0.z = acc[2]*inv; o0.w = acc[3]*inv;
    o1.x = acc[4]*inv; o1.y = acc[5]*inv; o1.z = acc[6]*inv; o1.w = acc[7]*inv;
    long ob = ((long)(b*1024 + t)*64) + h*8;
    *(float4*)(attn + ob) = o0;
    *(float4*)(attn + ob + 4) = o1;
}

// ---------------- global linear attention (heads 4..7) -----------------------
__global__ void global_attn_kernel(const float* __restrict__ q, const float* __restrict__ k,
                                   const float* __restrict__ v, float* __restrict__ attn) {
    int b = blockIdx.x >> 2, h = blockIdx.x & 3;
    int tid = threadIdx.x;                 // 256
    int base = ((b*8 + 4 + h)*1024) * 8;
    __shared__ float red[8][72];
    __shared__ float M[8];
    __shared__ float C[64];
    int warp = tid >> 5, lane = tid & 31;

    float mx[8];
#pragma unroll
    for (int d = 0; d < 8; d++) mx[d] = -1e30f;
    for (int t = tid; t < 1024; t += 256) {
        float4 k0 = *(const float4*)(k + base + t*8);
        float4 k1 = *(const float4*)(k + base + t*8 + 4);
        mx[0]=fmaxf(mx[0],k0.x); mx[1]=fmaxf(mx[1],k0.y); mx[2]=fmaxf(mx[2],k0.z); mx[3]=fmaxf(mx[3],k0.w);
        mx[4]=fmaxf(mx[4],k1.x); mx[5]=fmaxf(mx[5],k1.y); mx[6]=fmaxf(mx[6],k1.z); mx[7]=fmaxf(mx[7],k1.w);
    }
#pragma unroll
    for (int d = 0; d < 8; d++)
        for (int o = 16; o; o >>= 1) mx[d] = fmaxf(mx[d], __shfl_xor_sync(~0u, mx[d], o));
    if (lane == 0)
        for (int d = 0; d < 8; d++) red[warp][d] = mx[d];
    __syncthreads();
    if (tid < 8) {
        float m_ = red[0][tid];
        for (int wv = 1; wv < 8; wv++) m_ = fmaxf(m_, red[wv][tid]);
        M[tid] = m_;
    }
    __syncthreads();

    float Z[8] = {}, ctx[64] = {};
    for (int t = tid; t < 1024; t += 256) {
        float4 k0 = *(const float4*)(k + base + t*8);
        float4 k1 = *(const float4*)(k + base + t*8 + 4);
        float4 v0 = *(const float4*)(v + base + t*8);
        float4 v1 = *(const float4*)(v + base + t*8 + 4);
        float kr[8] = {k0.x,k0.y,k0.z,k0.w,k1.x,k1.y,k1.z,k1.w};
        float vr[8] = {v0.x,v0.y,v0.z,v0.w,v1.x,v1.y,v1.z,v1.w};
#pragma unroll
        for (int d = 0; d < 8; d++) {
            float e_ = __expf(kr[d] - M[d]);
            Z[d] += e_;
#pragma unroll
            for (int e = 0; e < 8; e++) ctx[d*8 + e] += e_ * vr[e];
        }
    }
#pragma unroll
    for (int i = 0; i < 8; i++)
        for (int o = 16; o; o >>= 1) Z[i] += __shfl_xor_sync(~0u, Z[i], o);
#pragma unroll
    for (int i = 0; i < 64; i++)
        for (int o = 16; o; o >>= 1) ctx[i] += __shfl_xor_sync(~0u, ctx[i], o);
    if (lane == 0) {
        for (int i = 0; i < 8; i++)  red[warp][i] = Z[i];
        for (int i = 0; i < 64; i++) red[warp][8 + i] = ctx[i];
    }
    __syncthreads();
    if (tid < 64) {
        float s = 0.f, z = 0.f;
        int d = tid >> 3;
        for (int wv = 0; wv < 8; wv++) { s += red[wv][8 + tid]; z += red[wv][d]; }
        C[tid] = s / z;
    }
    __syncthreads();

    const float scale = 0.35355339059327373f;
    for (int t = tid; t < 1024; t += 256) {
        float4 q0 = *(const float4*)(q + base + t*8);
        float4 q1 = *(const float4*)(q + base + t*8 + 4);
        float qr[8] = {q0.x,q0.y,q0.z,q0.w,q1.x,q1.y,q1.z,q1.w};
        float qm = -1e30f;
#pragma unroll
        for (int d = 0; d < 8; d++) qm = fmaxf(qm, qr[d]);
        float qs = 0.f;
#pragma unroll
        for (int d = 0; d < 8; d++) { qr[d] = __expf(qr[d] - qm); qs += qr[d]; }
        float inv = scale / qs;
        float o_[8] = {};
#pragma unroll
        for (int d = 0; d < 8; d++) {
            float p = qr[d] * inv;
#pragma unroll
            for (int e = 0; e < 8; e++) o_[e] += p * C[d*8 + e];
        }
        long ob = (long)(b*1024 + t)*64 + (4 + h)*8;
        float4 oo0, oo1;
        oo0.x=o_[0]; oo0.y=o_[1]; oo0.z=o_[2]; oo0.w=o_[3];
        oo1.x=o_[4]; oo1.y=o_[5]; oo1.z=o_[6]; oo1.w=o_[7];
        *(float4*)(attn + ob) = oo0;
        *(float4*)(attn + ob + 4) = oo1;
    }
}

// ---------------- collapse: h(.,64) @ cw(64,5) + cb -> out --------------------
__global__ void collapse_kernel(const float* __restrict__ h, const float* __restrict__ cw,
                                const float* __restrict__ cb, float* __restrict__ out) {
    __shared__ float Xs[64][68];
    __shared__ float Ws[64][NDIN];
    __shared__ float Bs[NDIN];
    int tid = threadIdx.x;                 // 64
    int row0 = blockIdx.x * 64;
    for (int idx = tid; idx < 1024; idx += 64) {
        int i = idx >> 4, j = (idx & 15) * 4;
        *(float4*)&Xs[i][j] = *(const float4*)(h + (long)(row0 + i)*ND + j);
    }
    for (int idx = tid; idx < 64*NDIN; idx += 64) Ws[idx/NDIN][idx%NDIN] = cw[idx];
    if (tid < NDIN) Bs[tid] = cb[tid];
    __syncthreads();
    int r = tid;
    float acc[NDIN];
#pragma unroll
    for (int j = 0; j < NDIN; j++) acc[j] = Bs[j];
    for (int kk = 0; kk < 64; kk++) {
        float xv = Xs[r][kk];
#pragma unroll
        for (int j = 0; j < NDIN; j++) acc[j] += xv * Ws[kk][j];
    }
#pragma unroll
    for (int j = 0; j < NDIN; j++) out[(row0 + r)*NDIN + j] = acc[j];
}

// ---------------- launch ------------------------------------------------------
extern "C" void kernel_launch(void* const* d_in, const int* in_sizes, int n_in,
                              void* d_out, int out_size) {
    const float* x          = (const float*)d_in[0];
    const float* pos_emb    = (const float*)d_in[1];
    const float* expand_w   = (const float*)d_in[2];
    const float* expand_b   = (const float*)d_in[3];
    const float* emb_w      = (const float*)d_in[4];
    const float* emb_b      = (const float*)d_in[5];
    const float* conv_w     = (const float*)d_in[6];
    const float* conv_b     = (const float*)d_in[7];
    const float* ln1_s      = (const float*)d_in[8];
    const float* ln1_b      = (const float*)d_in[9];
    const float* wq         = (const float*)d_in[10];
    const float* wk         = (const float*)d_in[11];
    const float* wv         = (const float*)d_in[12];
    const float* wo         = (const float*)d_in[13];
    const float* wo_b       = (const float*)d_in[14];
    const float* ln2_s      = (const float*)d_in[15];
    const float* ln2_b      = (const float*)d_in[16];
    const float* ff_w1      = (const float*)d_in[17];
    const float* ff_b1      = (const float*)d_in[18];
    const float* ff_w2      = (const float*)d_in[19];
    const float* ff_b2      = (const float*)d_in[20];
    const float* collapse_w = (const float*)d_in[21];
    const float* collapse_b = (const float*)d_in[22];
    float* out = (float*)d_out;

    float *ph, *pq, *pk, *pv, *pattn, *pWc, *pbc;
    uint32_t *pWpH, *pWpM, *pAH, *pAM, *pBH, *pBM;
    cudaGetSymbolAddress((void**)&ph,   g_h);
    cudaGetSymbolAddress((void**)&pq,   g_q);
    cudaGetSymbolAddress((void**)&pk,   g_k);
    cudaGetSymbolAddress((void**)&pv,   g_v);
    cudaGetSymbolAddress((void**)&pattn,g_attn);
    cudaGetSymbolAddress((void**)&pWc,  g_Wc);
    cudaGetSymbolAddress((void**)&pbc,  g_bc);
    cudaGetSymbolAddress((void**)&pWpH, g_WpH);
    cudaGetSymbolAddress((void**)&pWpM, g_WpM);
    cudaGetSymbolAddress((void**)&pAH,  g_AH);
    cudaGetSymbolAddress((void**)&pAM,  g_AM);
    cudaGetSymbolAddress((void**)&pBH,  g_BH);
    cudaGetSymbolAddress((void**)&pBM,  g_BM);

    static bool attrSet = false;
    if (!attrSet) {
        cudaFuncSetAttribute(attn_ffn_kernel, cudaFuncAttributeMaxDynamicSharedMemorySize, FUSED_SMEM);
        attrSet = true;
    }

    precompute_kernel<<<1, 64>>>(expand_w, expand_b, emb_w, emb_b, pWc, pbc);
    packw_kernel<<<24, 256>>>(wq, wk, wv, wo, ff_w1, ff_w2, pWpH, pWpM);
    packa_kernel<<<(1024*1536)/256, 256>>>(conv_w, pAH, pAM);
    packbx_kernel<<<(1536*4096)/256, 256>>>(x, pWc, pbc, pBH, pBM);
    conv_kernel<<<dim3(4096/CBN, 1024/CBM), 256>>>(pAH, pAM, pBH, pBM, conv_b, pos_emb, ph);

    for (int l = 0; l < 2; l++) {
        int tb = l*12;
        lnqkv_kernel<<<NTOK/64, 256>>>(ph, ln1_s + l*64, ln1_b + l*64,
                                       pWpH, pWpM, tb + 0, pq, pk, pv);
        local_attn_kernel<<<NB*4*8, 128>>>(pq, pk, pv, pattn);
        global_attn_kernel<<<NB*4, 256>>>(pq, pk, pv, pattn);
        attn_ffn_kernel<<<NTOK/64, 256, FUSED_SMEM>>>(
            pattn, pWpH, pWpM, tb + 3, tb + 4, tb + 8,
            wo_b + l*64, ln2_s + l*64, ln2_b + l*64,
            ff_b1 + l*256, ff_b2 + l*64, ph);
    }
    collapse_kernel<<<NTOK/64, 64>>>(ph, collapse_w, collapse_b, out);
}

// round 12
// speedup vs baseline: 4.0453x; 1.1357x over previous
#include <cuda_runtime.h>
#include <cuda_bf16.h>
#include <cstdint>
#include <math.h>

// Problem constants: B=64, T=1024, DIN=5, D=64, H=8, DH=8, NLOCAL=4, WS=128, DEPTH=2
#define NB 64
#define NT 1024
#define NDIN 5
#define ND 64
#define NTOK (NB*NT)           // 65536

// ---------------- scratch (static device buffers) -----------------------------
__device__ float g_h[NTOK*ND];          // running hidden state
__device__ float g_q[NTOK*ND];          // [b][h][t][dh]
__device__ float g_k[NTOK*ND];
__device__ float g_v[NTOK*ND];
__device__ float g_attn[NTOK*ND];       // [b][t][h*8+dh]
__device__ float g_Wc[NDIN*ND];
__device__ float g_bc[ND];
// packed-weight tiles: 24 tiles x 64 n x 32 kpairs
__device__ uint32_t g_WpH[24*2048], g_WpM[24*2048];
// packed conv A: [1024 m][1536 kpair]
__device__ uint32_t g_AH[1024*1536], g_AM[1024*1536];
// packed conv B: [1536 kpair][4096 n]
__device__ uint32_t g_BH[1536*4096], g_BM[1536*4096];

// ---------------- bf16 split helpers ------------------------------------------
__device__ __forceinline__ void pack2(float x0, float x1, uint32_t& hi, uint32_t& mid) {
    uint32_t h;
    asm("cvt.rn.bf16x2.f32 %0, %1, %2;" : "=r"(h) : "f"(x1), "f"(x0));
    float f0 = __uint_as_float(h << 16);
    float f1 = __uint_as_float(h & 0xFFFF0000u);
    float r0 = x0 - f0, r1 = x1 - f1;
    asm("cvt.rn.bf16x2.f32 %0, %1, %2;" : "=r"(mid) : "f"(r1), "f"(r0));
    hi = h;
}
__device__ __forceinline__ void mma_bf16(float* c, const uint32_t* a, const uint32_t* b) {
    asm volatile("mma.sync.aligned.m16n8k16.row.col.f32.bf16.bf16.f32 "
        "{%0,%1,%2,%3}, {%4,%5,%6,%7}, {%8,%9}, {%0,%1,%2,%3};"
        : "+f"(c[0]), "+f"(c[1]), "+f"(c[2]), "+f"(c[3])
        : "r"(a[0]), "r"(a[1]), "r"(a[2]), "r"(a[3]), "r"(b[0]), "r"(b[1]));
}

// ---------------- precompute combined expand@emb ------------------------------
__global__ void precompute_kernel(const float* __restrict__ ew, const float* __restrict__ eb,
                                  const float* __restrict__ mw, const float* __restrict__ mb,
                                  float* __restrict__ Wc, float* __restrict__ bc) {
    int j = threadIdx.x;             // 64 threads
    for (int i = 0; i < NDIN; i++) {
        float s = 0.f;
        for (int d = 0; d < ND; d++) s += ew[i*ND + d] * mw[d*ND + j];
        Wc[i*ND + j] = s;
    }
    float s = mb[j];
    for (int d = 0; d < ND; d++) s += eb[d] * mw[d*ND + j];
    bc[j] = s;
}

// ---------------- weight pre-pack: 24 tiles of 64x64 --------------------------
__global__ void packw_kernel(const float* __restrict__ wq, const float* __restrict__ wk,
                             const float* __restrict__ wv, const float* __restrict__ wo,
                             const float* __restrict__ w1, const float* __restrict__ w2,
                             uint32_t* __restrict__ WpH, uint32_t* __restrict__ WpM) {
    int tile = blockIdx.x;        // 0..23
    int l = tile / 12, t = tile - l*12;
    const float* src; int ldw, coloff;
    if (t == 0)      { src = wq + l*4096; ldw = 64; coloff = 0; }
    else if (t == 1) { src = wk + l*4096; ldw = 64; coloff = 0; }
    else if (t == 2) { src = wv + l*4096; ldw = 64; coloff = 0; }
    else if (t == 3) { src = wo + l*4096; ldw = 64; coloff = 0; }
    else if (t < 8)  { src = w1 + l*64*256; ldw = 256; coloff = (t-4)*64; }
    else             { src = w2 + l*256*64 + (t-8)*64*64; ldw = 64; coloff = 0; }
    int tid = threadIdx.x;        // 256
    int n = tid & 63, p0 = (tid >> 6) * 8;
    uint32_t* dh = WpH + tile*2048 + n*32;
    uint32_t* dm = WpM + tile*2048 + n*32;
#pragma unroll
    for (int u = 0; u < 8; u++) {
        int k = 2*(p0+u);
        float w0 = src[(long)k*ldw + coloff + n];
        float w1v = src[(long)(k+1)*ldw + coloff + n];
        uint32_t h, m_;
        pack2(w0, w1v, h, m_);
        dh[p0+u] = h; dm[p0+u] = m_;
    }
}

// ---------------- conv A pre-pack: conv_w -> [m][kpair] ------------------------
__global__ void packa_kernel(const float* __restrict__ A,
                             uint32_t* __restrict__ AH, uint32_t* __restrict__ AM) {
    int idx = blockIdx.x*256 + threadIdx.x;       // pair index [1024*1536)
    float2 v = *(const float2*)(A + (long)idx*2);
    uint32_t h, m_;
    pack2(v.x, v.y, h, m_);
    AH[idx] = h; AM[idx] = m_;
}

// ---------------- conv B pre-pack WITH fused expand ----------------------------
__global__ void packbx_kernel(const float* __restrict__ x,
                              const float* __restrict__ Wc, const float* __restrict__ bc,
                              uint32_t* __restrict__ BH, uint32_t* __restrict__ BM) {
    int idx = blockIdx.x*256 + threadIdx.x;       // [1536*4096)
    int kp2 = idx >> 12;
    int n = idx & 4095;
    int b = n >> 6, d = n & 63;
    int K0 = kp2*2, K1 = K0 + 1;
    int kt0 = K0/3, kq0 = K0 - kt0*3;
    int kt1 = K1/3, kq1 = K1 - kt1*3;
    int d0 = d + kq0 - 1, d1 = d + kq1 - 1;
    float v0 = 0.f, v1 = 0.f;
    if (d0 >= 0 && d0 < 64) {
        const float* xr = x + ((long)(b << 10) + kt0) * NDIN;
        v0 = bc[d0];
#pragma unroll
        for (int i = 0; i < NDIN; i++) v0 += xr[i] * Wc[i*ND + d0];
    }
    if (d1 >= 0 && d1 < 64) {
        const float* xr = x + ((long)(b << 10) + kt1) * NDIN;
        v1 = bc[d1];
#pragma unroll
        for (int i = 0; i < NDIN; i++) v1 += xr[i] * Wc[i*ND + d1];
    }
    uint32_t h, m_;
    pack2(v0, v1, h, m_);
    BH[idx] = h; BM[idx] = m_;
}

// ---------------- conv as GEMM, bf16x3 m16n8k16, stride-12 tiles ---------------
#define CBM 128
#define CBN 128
#define CBK 16
#define CONV_SMEM (4*2*128*12*4)   // 49152 B
__global__ __launch_bounds__(256) void conv_kernel(
        const uint32_t* __restrict__ AH, const uint32_t* __restrict__ AM,
        const uint32_t* __restrict__ BH, const uint32_t* __restrict__ BM,
        const float* __restrict__ conv_b, const float* __restrict__ pos_emb,
        float* __restrict__ Hout) {
    extern __shared__ uint32_t cs[];
    uint32_t (*Ah)[128][12] = (uint32_t(*)[128][12])cs;
    uint32_t (*Am)[128][12] = (uint32_t(*)[128][12])(cs + 2*128*12);
    uint32_t (*Bh)[128][12] = (uint32_t(*)[128][12])(cs + 4*128*12);
    uint32_t (*Bm)[128][12] = (uint32_t(*)[128][12])(cs + 6*128*12);
    int tid = threadIdx.x;
    int m0 = blockIdx.y * CBM;
    int n0 = blockIdx.x * CBN;

    int arow = tid >> 1;
    int ap = (tid & 1) * 4;
    int bj = tid & 127;
    int bp = (tid >> 7) * 4;

    int w = tid >> 5, lane = tid & 31;
    int gid = lane >> 2, t4 = lane & 3;
    int warpM = w >> 1, warpN = w & 1;
    int mbase = warpM * 32, nbase = warpN * 64;

    float acc[2][8][4];
#pragma unroll
    for (int mt = 0; mt < 2; mt++)
#pragma unroll
        for (int nt = 0; nt < 8; nt++)
#pragma unroll
            for (int r = 0; r < 4; r++) acc[mt][nt][r] = 0.f;

    auto loadA = [&](int k0, int buf) {
        const uint32_t* ph = AH + (long)(m0 + arow)*1536 + (k0 >> 1) + ap;
        const uint32_t* pm = AM + (long)(m0 + arow)*1536 + (k0 >> 1) + ap;
        uint4 vh = *(const uint4*)ph;
        uint4 vm = *(const uint4*)pm;
        Ah[buf][arow][ap+0] = vh.x; Ah[buf][arow][ap+1] = vh.y;
        Ah[buf][arow][ap+2] = vh.z; Ah[buf][arow][ap+3] = vh.w;
        Am[buf][arow][ap+0] = vm.x; Am[buf][arow][ap+1] = vm.y;
        Am[buf][arow][ap+2] = vm.z; Am[buf][arow][ap+3] = vm.w;
    };
    auto loadB = [&](int k0, int buf) {
        long base = (long)((k0 >> 1) + bp) * 4096 + n0 + bj;
#pragma unroll
        for (int u = 0; u < 4; u++) {
            Bh[buf][bj][bp+u] = BH[base + (long)u*4096];
            Bm[buf][bj][bp+u] = BM[base + (long)u*4096];
        }
    };

    loadA(0, 0); loadB(0, 0);
    __syncthreads();

    int cur = 0;
    for (int k0 = CBK; k0 <= 3072; k0 += CBK) {
        if (k0 < 3072) { loadA(k0, cur ^ 1); loadB(k0, cur ^ 1); }
        uint32_t ah[2][4], am[2][4];
#pragma unroll
        for (int mt = 0; mt < 2; mt++) {
            int r0 = mbase + mt*16 + gid;
            ah[mt][0] = Ah[cur][r0  ][t4];   ah[mt][1] = Ah[cur][r0+8][t4];
            ah[mt][2] = Ah[cur][r0  ][t4+4]; ah[mt][3] = Ah[cur][r0+8][t4+4];
            am[mt][0] = Am[cur][r0  ][t4];   am[mt][1] = Am[cur][r0+8][t4];
            am[mt][2] = Am[cur][r0  ][t4+4]; am[mt][3] = Am[cur][r0+8][t4+4];
        }
#pragma unroll
        for (int nt = 0; nt < 8; nt++) {
            int n = nbase + nt*8 + gid;
            uint32_t bhf[2] = { Bh[cur][n][t4], Bh[cur][n][t4+4] };
            uint32_t bmf[2] = { Bm[cur][n][t4], Bm[cur][n][t4+4] };
#pragma unroll
            for (int mt = 0; mt < 2; mt++) {
                mma_bf16(acc[mt][nt], ah[mt], bhf);
                mma_bf16(acc[mt][nt], ah[mt], bmf);
                mma_bf16(acc[mt][nt], am[mt], bhf);
            }
        }
        __syncthreads();
        cur ^= 1;
    }

#pragma unroll
    for (int mt = 0; mt < 2; mt++) {
        int row0r = m0 + mbase + mt*16 + gid;
        float cb0 = conv_b[row0r];
        float cb1 = conv_b[row0r + 8];
#pragma unroll
        for (int nt = 0; nt < 8; nt++) {
            int coln = n0 + nbase + nt*8 + t4*2;
            int b_ = coln >> 6, d_ = coln & 63;
            float2 pe0 = *(const float2*)(pos_emb + row0r*64 + d_);
            float2 pe1 = *(const float2*)(pos_emb + (row0r+8)*64 + d_);
            float2 o0, o1;
            o0.x = acc[mt][nt][0] + cb0 + pe0.x;
            o0.y = acc[mt][nt][1] + cb0 + pe0.y;
            o1.x = acc[mt][nt][2] + cb1 + pe1.x;
            o1.y = acc[mt][nt][3] + cb1 + pe1.y;
            *(float2*)(Hout + ((long)(b_ << 10) + row0r)*64 + d_) = o0;
            *(float2*)(Hout + ((long)(b_ << 10) + row0r + 8)*64 + d_) = o1;
        }
    }
}

// ================= mma-based 64-token GEMM helpers =============================
// stride 36 (=4 mod 32) -> fragment loads hit 32 distinct banks
typedef uint32_t XT[36];
typedef uint32_t WT[36];

__device__ __forceinline__ void pack_x64(const float* __restrict__ X, long row0, int ldx, int coloff,
                                         const float* __restrict__ lns, const float* __restrict__ lnb,
                                         bool doLN, XT* Xh, XT* Xm, int tid) {
    int r = tid >> 2, q = (tid & 3) * 16;
    const float* row = X + (row0 + r) * (long)ldx + coloff + q;
    float xv[16];
    *(float4*)&xv[0]  = *(const float4*)(row);
    *(float4*)&xv[4]  = *(const float4*)(row + 4);
    *(float4*)&xv[8]  = *(const float4*)(row + 8);
    *(float4*)&xv[12] = *(const float4*)(row + 12);
    if (doLN) {
        float sum = 0.f;
#pragma unroll
        for (int j = 0; j < 16; j++) sum += xv[j];
        sum += __shfl_xor_sync(~0u, sum, 1);
        sum += __shfl_xor_sync(~0u, sum, 2);
        float mu = sum * (1.f/64.f);
        float vs = 0.f;
#pragma unroll
        for (int j = 0; j < 16; j++) { float d = xv[j] - mu; vs += d*d; }
        vs += __shfl_xor_sync(~0u, vs, 1);
        vs += __shfl_xor_sync(~0u, vs, 2);
        float inv = rsqrtf(vs * (1.f/64.f) + 1e-5f);
#pragma unroll
        for (int j = 0; j < 16; j++) xv[j] = (xv[j] - mu) * inv * lns[q+j] + lnb[q+j];
    }
    int p0 = q >> 1;
#pragma unroll
    for (int u = 0; u < 8; u++) {
        uint32_t h, m_;
        pack2(xv[2*u], xv[2*u+1], h, m_);
        Xh[r][p0+u] = h; Xm[r][p0+u] = m_;
    }
}

__device__ __forceinline__ void copy_w64(const uint32_t* __restrict__ WpH,
                                         const uint32_t* __restrict__ WpM, int tile,
                                         WT* Wh, WT* Wm, int tid) {
    int n = tid >> 2, qp = (tid & 3) * 8;
    const uint32_t* sh = WpH + tile*2048 + n*32 + qp;
    const uint32_t* sm = WpM + tile*2048 + n*32 + qp;
    *(uint4*)&Wh[n][qp]   = *(const uint4*)sh;
    *(uint4*)&Wh[n][qp+4] = *(const uint4*)(sh+4);
    *(uint4*)&Wm[n][qp]   = *(const uint4*)sm;
    *(uint4*)&Wm[n][qp+4] = *(const uint4*)(sm+4);
}

__device__ __forceinline__ void mma64_compute(const XT* Xh, const XT* Xm,
                                              const WT* Wh, const WT* Wm,
                                              float acc[4][4], int mb, int nb, int gid, int t4) {
#pragma unroll
    for (int kc = 0; kc < 4; kc++) {
        int kp = kc*8;
        uint32_t ah[4], am[4];
        ah[0] = Xh[mb+gid  ][kp+t4];   ah[1] = Xh[mb+gid+8][kp+t4];
        ah[2] = Xh[mb+gid  ][kp+t4+4]; ah[3] = Xh[mb+gid+8][kp+t4+4];
        am[0] = Xm[mb+gid  ][kp+t4];   am[1] = Xm[mb+gid+8][kp+t4];
        am[2] = Xm[mb+gid  ][kp+t4+4]; am[3] = Xm[mb+gid+8][kp+t4+4];
#pragma unroll
        for (int nf = 0; nf < 4; nf++) {
            int n = nb + nf*8 + gid;
            uint32_t bh[2] = { Wh[n][kp+t4], Wh[n][kp+t4+4] };
            uint32_t bm[2] = { Wm[n][kp+t4], Wm[n][kp+t4+4] };
            mma_bf16(acc[nf], ah, bh);
            mma_bf16(acc[nf], ah, bm);
            mma_bf16(acc[nf], am, bh);
        }
    }
}

// ---------------- fused LN + QKV (mma) -> head layout -------------------------
__global__ __launch_bounds__(256) void lnqkv_kernel(
        const float* __restrict__ X, const float* __restrict__ lns, const float* __restrict__ lnb,
        const uint32_t* __restrict__ WpH, const uint32_t* __restrict__ WpM, int tile0,
        float* __restrict__ q, float* __restrict__ k, float* __restrict__ v) {
    __shared__ uint32_t Xh[64][36], Xm[64][36];
    __shared__ uint32_t Wh[64][36], Wm[64][36];
    int tid = threadIdx.x;
    long row0 = (long)blockIdx.x * 64;
    int w = tid >> 5, lane = tid & 31;
    int gid = lane >> 2, t4 = lane & 3;
    int mb = (w & 3) * 16, nb = (w >> 2) * 32;

    pack_x64(X, row0, ND, 0, lns, lnb, true, Xh, Xm, tid);
    float* Om[3] = {q, k, v};
#pragma unroll
    for (int m = 0; m < 3; m++) {
        if (m) __syncthreads();
        copy_w64(WpH, WpM, tile0 + m, Wh, Wm, tid);
        __syncthreads();
        float acc[4][4] = {};
        mma64_compute(Xh, Xm, Wh, Wm, acc, mb, nb, gid, t4);
        float* out = Om[m];
        int dh = t4*2;
#pragma unroll
        for (int nf = 0; nf < 4; nf++) {
            int h = (nb >> 3) + nf;
            long gt0 = row0 + mb + gid;
            long gt1 = gt0 + 8;
            long b0 = gt0 >> 10, t0 = gt0 & 1023;
            long b1 = gt1 >> 10, t1 = gt1 & 1023;
            float2 o0; o0.x = acc[nf][0]; o0.y = acc[nf][1];
            float2 o1; o1.x = acc[nf][2]; o1.y = acc[nf][3];
            *(float2*)(out + (((b0*8 + h)*1024) + t0)*8 + dh) = o0;
            *(float2*)(out + (((b1*8 + h)*1024) + t1)*8 + dh) = o1;
        }
    }
}

// ---------------- FUSED: wo + resid + ln2 + ffn1 + gelu + ffn2 + resid --------
// dynamic smem: Hs[64][68] f32 | Xh,Xm | Wh,Wm | Yh,Ym  (all 64x36 u32)
#define TSZ (64*36*4)
#define FUSED_SMEM (17408 + 6*TSZ)
__global__ __launch_bounds__(256) void attn_ffn_kernel(
        const float* __restrict__ attnIn,
        const uint32_t* __restrict__ WpH, const uint32_t* __restrict__ WpM,
        int woTile, int f1Tile0, int f2Tile0,
        const float* __restrict__ wo_b,
        const float* __restrict__ ln2s, const float* __restrict__ ln2b,
        const float* __restrict__ b1, const float* __restrict__ b2,
        float* __restrict__ h) {
    extern __shared__ char smem[];
    float (*Hs)[68] = (float(*)[68])smem;
    XT* Xh = (XT*)(smem + 17408);
    XT* Xm = (XT*)(smem + 17408 + TSZ);
    WT* Wh = (WT*)(smem + 17408 + 2*TSZ);
    WT* Wm = (WT*)(smem + 17408 + 3*TSZ);
    XT* Yh = (XT*)(smem + 17408 + 4*TSZ);
    XT* Ym = (XT*)(smem + 17408 + 5*TSZ);

    int tid = threadIdx.x;
    long row0 = (long)blockIdx.x * 64;
    int w = tid >> 5, lane = tid & 31;
    int gid = lane >> 2, t4 = lane & 3;
    int mb = (w & 3) * 16, nb = (w >> 2) * 32;

    // ---- 1. wo GEMM ----
    pack_x64(attnIn, row0, ND, 0, nullptr, nullptr, false, Xh, Xm, tid);
    copy_w64(WpH, WpM, woTile, Wh, Wm, tid);
    __syncthreads();
    float acc[4][4] = {};
    mma64_compute(Xh, Xm, Wh, Wm, acc, mb, nb, gid, t4);
#pragma unroll
    for (int nf = 0; nf < 4; nf++) {
        int col = nb + nf*8 + t4*2;
        float2 bb = *(const float2*)(wo_b + col);
        long r0 = row0 + mb + gid, r1 = r0 + 8;
        float2 rr0 = *(const float2*)(h + r0*ND + col);
        float2 rr1 = *(const float2*)(h + r1*ND + col);
        Hs[mb+gid  ][col]   = acc[nf][0] + bb.x + rr0.x;
        Hs[mb+gid  ][col+1] = acc[nf][1] + bb.y + rr0.y;
        Hs[mb+gid+8][col]   = acc[nf][2] + bb.x + rr1.x;
        Hs[mb+gid+8][col+1] = acc[nf][3] + bb.y + rr1.y;
    }
    __syncthreads();

    // ---- 2. LN2 on Hs -> pack into Xh/Xm ----
    {
        int r = tid >> 2, q = (tid & 3) * 16;
        float xv[16];
#pragma unroll
        for (int j = 0; j < 16; j++) xv[j] = Hs[r][q+j];
        float sum = 0.f;
#pragma unroll
        for (int j = 0; j < 16; j++) sum += xv[j];
        sum += __shfl_xor_sync(~0u, sum, 1);
        sum += __shfl_xor_sync(~0u, sum, 2);
        float mu = sum * (1.f/64.f);
        float vs = 0.f;
#pragma unroll
        for (int j = 0; j < 16; j++) { float d = xv[j] - mu; vs += d*d; }
        vs += __shfl_xor_sync(~0u, vs, 1);
        vs += __shfl_xor_sync(~0u, vs, 2);
        float inv = rsqrtf(vs * (1.f/64.f) + 1e-5f);
        int p0 = q >> 1;
#pragma unroll
        for (int u = 0; u < 8; u++) {
            float y0 = (xv[2*u]   - mu) * inv * ln2s[q+2*u]   + ln2b[q+2*u];
            float y1 = (xv[2*u+1] - mu) * inv * ln2s[q+2*u+1] + ln2b[q+2*u+1];
            uint32_t hh, m_;
            pack2(y0, y1, hh, m_);
            Xh[r][p0+u] = hh; Xm[r][p0+u] = m_;
        }
    }

    // ---- 3. chunk-interleaved ffn1 -> gelu -> Y smem -> ffn2 accumulate ----
    float acc2[4][4] = {};
    for (int c = 0; c < 4; c++) {
        __syncthreads();
        copy_w64(WpH, WpM, f1Tile0 + c, Wh, Wm, tid);
        __syncthreads();
        float ya[4][4] = {};
        mma64_compute(Xh, Xm, Wh, Wm, ya, mb, nb, gid, t4);
#pragma unroll
        for (int nf = 0; nf < 4; nf++) {
            int col = c*64 + nb + nf*8 + t4*2;
            float2 bb = *(const float2*)(b1 + col);
            float z0 = ya[nf][0] + bb.x, z1 = ya[nf][1] + bb.y;
            float z2 = ya[nf][2] + bb.x, z3 = ya[nf][3] + bb.y;
            float y0 = 0.5f*z0*(1.f + erff(z0*0.70710678118654752f));
            float y1 = 0.5f*z1*(1.f + erff(z1*0.70710678118654752f));
            float y2 = 0.5f*z2*(1.f + erff(z2*0.70710678118654752f));
            float y3 = 0.5f*z3*(1.f + erff(z3*0.70710678118654752f));
            int pi = (nb >> 1) + nf*4 + t4;
            uint32_t hh, m_;
            pack2(y0, y1, hh, m_); Yh[mb+gid  ][pi] = hh; Ym[mb+gid  ][pi] = m_;
            pack2(y2, y3, hh, m_); Yh[mb+gid+8][pi] = hh; Ym[mb+gid+8][pi] = m_;
        }
        __syncthreads();
        copy_w64(WpH, WpM, f2Tile0 + c, Wh, Wm, tid);
        __syncthreads();
        mma64_compute(Yh, Ym, Wh, Wm, acc2, mb, nb, gid, t4);
    }

    // ---- 4. epilogue: h = acc2 + b2 + Hs ----
#pragma unroll
    for (int nf = 0; nf < 4; nf++) {
        int col = nb + nf*8 + t4*2;
        float2 bb = *(const float2*)(b2 + col);
        long r0 = row0 + mb + gid, r1 = r0 + 8;
        float2 o0, o1;
        o0.x = acc2[nf][0] + bb.x + Hs[mb+gid  ][col];
        o0.y = acc2[nf][1] + bb.y + Hs[mb+gid  ][col+1];
        o1.x = acc2[nf][2] + bb.x + Hs[mb+gid+8][col];
        o1.y = acc2[nf][3] + bb.y + Hs[mb+gid+8][col+1];
        *(float2*)(h + r0*ND + col) = o0;
        *(float2*)(h + r1*ND + col) = o1;
    }
}

// ---------------- local windowed attention (heads 0..3), bound-max softmax ----
__global__ __launch_bounds__(128) void local_attn_kernel(
        const float* __restrict__ q, const float* __restrict__ k,
        const float* __restrict__ v, float* __restrict__ attn) {
    int bid = blockIdx.x;                  // b*32 + h*8 + w
    int w = bid & 7, h = (bid >> 3) & 3, b = bid >> 5;
    __shared__ float Ks[384][8];
    __shared__ float Vs[384][8];
    __shared__ float wmax[4];
    int tid = threadIdx.x;                 // 128
    int base = ((b*8 + h)*1024) * 8;
    int jlo = (w == 0) ? 128 : 0;
    int jhi = (w == 7) ? 256 : 384;
    for (int idx = tid; idx < 768; idx += 128) {
        int j = idx >> 1, half = (idx & 1) * 4;
        int tt = (w - 1)*128 + j;
        float4 kv = {0,0,0,0}, vv = {0,0,0,0};
        if (tt >= 0 && tt < 1024) {
            kv = *(const float4*)(k + base + tt*8 + half);
            vv = *(const float4*)(v + base + tt*8 + half);
        }
        *(float4*)&Ks[j][half] = kv;
        *(float4*)&Vs[j][half] = vv;
    }
    __syncthreads();
    float nm = 0.f;
    for (int r = tid; r < 384; r += 128) {
        float4 k0 = *(const float4*)&Ks[r][0];
        float4 k1 = *(const float4*)&Ks[r][4];
        float s2 = k0.x*k0.x + k0.y*k0.y + k0.z*k0.z + k0.w*k0.w
                 + k1.x*k1.x + k1.y*k1.y + k1.z*k1.z + k1.w*k1.w;
        nm = fmaxf(nm, s2);
    }
#pragma unroll
    for (int o = 16; o; o >>= 1) nm = fmaxf(nm, __shfl_xor_sync(~0u, nm, o));
    if ((tid & 31) == 0) wmax[tid >> 5] = nm;
    __syncthreads();
    float kmax2 = fmaxf(fmaxf(wmax[0], wmax[1]), fmaxf(wmax[2], wmax[3]));

    int t = w*128 + tid;
    float4 q0 = *(const float4*)(q + base + t*8);
    float4 q1 = *(const float4*)(q + base + t*8 + 4);
    float qr[8] = {q0.x,q0.y,q0.z,q0.w,q1.x,q1.y,q1.z,q1.w};
    const float scale = 0.35355339059327373f;   // 1/sqrt(8)
    float qn2 = 0.f;
#pragma unroll
    for (int e = 0; e < 8; e++) qn2 += qr[e]*qr[e];
    float m = scale * sqrtf(qn2 * kmax2);
    float l = 0.f, acc[8] = {};
    for (int j = jlo; j < jhi; j++) {
        float4 k0 = *(const float4*)&Ks[j][0];
        float4 k1 = *(const float4*)&Ks[j][4];
        float s = qr[0]*k0.x + qr[1]*k0.y + qr[2]*k0.z + qr[3]*k0.w
                + qr[4]*k1.x + qr[5]*k1.y + qr[6]*k1.z + qr[7]*k1.w;
        float p = __expf(s*scale - m);
        l += p;
        float4 v0 = *(const float4*)&Vs[j][0];
        float4 v1 = *(const float4*)&Vs[j][4];
        acc[0] += p*v0.x; acc[1] += p*v0.y; acc[2] += p*v0.z; acc[3] += p*v0.w;
        acc[4] += p*v1.x; acc[5] += p*v1.y; acc[6] += p*v1.z; acc[7] += p*v1.w;
    }
    float inv = 1.f / l;
    float4 o0, o1;
    o0.x = acc[0]*inv; o0.y = acc[1]*inv; o0.z = acc[2]*inv; o0.w = acc[3]*inv;
    o1.x = acc[4]*inv; o1.y = acc[5]*inv; o1.z = acc[6]*inv; o1.w = acc[7]*inv;
    long ob = ((long)(b*1024 + t)*64) + h*8;
    *(float4*)(attn + ob) = o0;
    *(float4*)(attn + ob + 4) = o1;
}

// ---------------- global linear attention (heads 4..7) -----------------------
__global__ void global_attn_kernel(const float* __restrict__ q, const float* __restrict__ k,
                                   const float* __restrict__ v, float* __restrict__ attn) {
    int b = blockIdx.x >> 2, h = blockIdx.x & 3;
    int tid = threadIdx.x;                 // 256
    int base = ((b*8 + 4 + h)*1024) * 8;
    __shared__ float red[8][72];
    __shared__ float M[8];
    __shared__ float C[64];
    int warp = tid >> 5, lane = tid & 31;

    float mx[8];
#pragma unroll
    for (int d = 0; d < 8; d++) mx[d] = -1e30f;
    for (int t = tid; t < 1024; t += 256) {
        float4 k0 = *(const float4*)(k + base + t*8);
        float4 k1 = *(const float4*)(k + base + t*8 + 4);
        mx[0]=fmaxf(mx[0],k0.x); mx[1]=fmaxf(mx[1],k0.y); mx[2]=fmaxf(mx[2],k0.z); mx[3]=fmaxf(mx[3],k0.w);
        mx[4]=fmaxf(mx[4],k1.x); mx[5]=fmaxf(mx[5],k1.y); mx[6]=fmaxf(mx[6],k1.z); mx[7]=fmaxf(mx[7],k1.w);
    }
#pragma unroll
    for (int d = 0; d < 8; d++)
        for (int o = 16; o; o >>= 1) mx[d] = fmaxf(mx[d], __shfl_xor_sync(~0u, mx[d], o));
    if (lane == 0)
        for (int d = 0; d < 8; d++) red[warp][d] = mx[d];
    __syncthreads();
    if (tid < 8) {
        float m_ = red[0][tid];
        for (int wv = 1; wv < 8; wv++) m_ = fmaxf(m_, red[wv][tid]);
        M[tid] = m_;
    }
    __syncthreads();

    float Z[8] = {}, ctx[64] = {};
    for (int t = tid; t < 1024; t += 256) {
        float4 k0 = *(const float4*)(k + base + t*8);
        float4 k1 = *(const float4*)(k + base + t*8 + 4);
        float4 v0 = *(const float4*)(v + base + t*8);
        float4 v1 = *(const float4*)(v + base + t*8 + 4);
        float kr[8] = {k0.x,k0.y,k0.z,k0.w,k1.x,k1.y,k1.z,k1.w};
        float vr[8] = {v0.x,v0.y,v0.z,v0.w,v1.x,v1.y,v1.z,v1.w};
#pragma unroll
        for (int d = 0; d < 8; d++) {
            float e_ = __expf(kr[d] - M[d]);
            Z[d] += e_;
#pragma unroll
            for (int e = 0; e < 8; e++) ctx[d*8 + e] += e_ * vr[e];
        }
    }
#pragma unroll
    for (int i = 0; i < 8; i++)
        for (int o = 16; o; o >>= 1) Z[i] += __shfl_xor_sync(~0u, Z[i], o);
#pragma unroll
    for (int i = 0; i < 64; i++)
        for (int o = 16; o; o >>= 1) ctx[i] += __shfl_xor_sync(~0u, ctx[i], o);
    if (lane == 0) {
        for (int i = 0; i < 8; i++)  red[warp][i] = Z[i];
        for (int i = 0; i < 64; i++) red[warp][8 + i] = ctx[i];
    }
    __syncthreads();
    if (tid < 64) {
        float s = 0.f, z = 0.f;
        int d = tid >> 3;
        for (int wv = 0; wv < 8; wv++) { s += red[wv][8 + tid]; z += red[wv][d]; }
        C[tid] = s / z;
    }
    __syncthreads();

    const float scale = 0.35355339059327373f;
    for (int t = tid; t < 1024; t += 256) {
        float4 q0 = *(const float4*)(q + base + t*8);
        float4 q1 = *(const float4*)(q + base + t*8 + 4);
        float qr[8] = {q0.x,q0.y,q0.z,q0.w,q1.x,q1.y,q1.z,q1.w};
        float qm = -1e30f;
#pragma unroll
        for (int d = 0; d < 8; d++) qm = fmaxf(qm, qr[d]);
        float qs = 0.f;
#pragma unroll
        for (int d = 0; d < 8; d++) { qr[d] = __expf(qr[d] - qm); qs += qr[d]; }
        float inv = scale / qs;
        float o_[8] = {};
#pragma unroll
        for (int d = 0; d < 8; d++) {
            float p = qr[d] * inv;
#pragma unroll
            for (int e = 0; e < 8; e++) o_[e] += p * C[d*8 + e];
        }
        long ob = (long)(b*1024 + t)*64 + (4 + h)*8;
        float4 oo0, oo1;
        oo0.x=o_[0]; oo0.y=o_[1]; oo0.z=o_[2]; oo0.w=o_[3];
        oo1.x=o_[4]; oo1.y=o_[5]; oo1.z=o_[6]; oo1.w=o_[7];
        *(float4*)(attn + ob) = oo0;
        *(float4*)(attn + ob + 4) = oo1;
    }
}

// ---------------- collapse: h(.,64) @ cw(64,5) + cb -> out --------------------
__global__ void collapse_kernel(const float* __restrict__ h, const float* __restrict__ cw,
                                const float* __restrict__ cb, float* __restrict__ out) {
    __shared__ float Xs[64][68];
    __shared__ float Ws[64][NDIN];
    __shared__ float Bs[NDIN];
    int tid = threadIdx.x;                 // 64
    int row0 = blockIdx.x * 64;
    for (int idx = tid; idx < 1024; idx += 64) {
        int i = idx >> 4, j = (idx & 15) * 4;
        *(float4*)&Xs[i][j] = *(const float4*)(h + (long)(row0 + i)*ND + j);
    }
    for (int idx = tid; idx < 64*NDIN; idx += 64) Ws[idx/NDIN][idx%NDIN] = cw[idx];
    if (tid < NDIN) Bs[tid] = cb[tid];
    __syncthreads();
    int r = tid;
    float acc[NDIN];
#pragma unroll
    for (int j = 0; j < NDIN; j++) acc[j] = Bs[j];
    for (int kk = 0; kk < 64; kk++) {
        float xv = Xs[r][kk];
#pragma unroll
        for (int j = 0; j < NDIN; j++) acc[j] += xv * Ws[kk][j];
    }
#pragma unroll
    for (int j = 0; j < NDIN; j++) out[(row0 + r)*NDIN + j] = acc[j];
}

// ---------------- launch ------------------------------------------------------
extern "C" void kernel_launch(void* const* d_in, const int* in_sizes, int n_in,
                              void* d_out, int out_size) {
    const float* x          = (const float*)d_in[0];
    const float* pos_emb    = (const float*)d_in[1];
    const float* expand_w   = (const float*)d_in[2];
    const float* expand_b   = (const float*)d_in[3];
    const float* emb_w      = (const float*)d_in[4];
    const float* emb_b      = (const float*)d_in[5];
    const float* conv_w     = (const float*)d_in[6];
    const float* conv_b     = (const float*)d_in[7];
    const float* ln1_s      = (const float*)d_in[8];
    const float* ln1_b      = (const float*)d_in[9];
    const float* wq         = (const float*)d_in[10];
    const float* wk         = (const float*)d_in[11];
    const float* wv         = (const float*)d_in[12];
    const float* wo         = (const float*)d_in[13];
    const float* wo_b       = (const float*)d_in[14];
    const float* ln2_s      = (const float*)d_in[15];
    const float* ln2_b      = (const float*)d_in[16];
    const float* ff_w1      = (const float*)d_in[17];
    const float* ff_b1      = (const float*)d_in[18];
    const float* ff_w2      = (const float*)d_in[19];
    const float* ff_b2      = (const float*)d_in[20];
    const float* collapse_w = (const float*)d_in[21];
    const float* collapse_b = (const float*)d_in[22];
    float* out = (float*)d_out;

    float *ph, *pq, *pk, *pv, *pattn, *pWc, *pbc;
    uint32_t *pWpH, *pWpM, *pAH, *pAM, *pBH, *pBM;
    cudaGetSymbolAddress((void**)&ph,   g_h);
    cudaGetSymbolAddress((void**)&pq,   g_q);
    cudaGetSymbolAddress((void**)&pk,   g_k);
    cudaGetSymbolAddress((void**)&pv,   g_v);
    cudaGetSymbolAddress((void**)&pattn,g_attn);
    cudaGetSymbolAddress((void**)&pWc,  g_Wc);
    cudaGetSymbolAddress((void**)&pbc,  g_bc);
    cudaGetSymbolAddress((void**)&pWpH, g_WpH);
    cudaGetSymbolAddress((void**)&pWpM, g_WpM);
    cudaGetSymbolAddress((void**)&pAH,  g_AH);
    cudaGetSymbolAddress((void**)&pAM,  g_AM);
    cudaGetSymbolAddress((void**)&pBH,  g_BH);
    cudaGetSymbolAddress((void**)&pBM,  g_BM);

    static bool attrSet = false;
    if (!attrSet) {
        cudaFuncSetAttribute(attn_ffn_kernel, cudaFuncAttributeMaxDynamicSharedMemorySize, FUSED_SMEM);
        cudaFuncSetAttribute(conv_kernel, cudaFuncAttributeMaxDynamicSharedMemorySize, CONV_SMEM);
        attrSet = true;
    }

    precompute_kernel<<<1, 64>>>(expand_w, expand_b, emb_w, emb_b, pWc, pbc);
    packw_kernel<<<24, 256>>>(wq, wk, wv, wo, ff_w1, ff_w2, pWpH, pWpM);
    packa_kernel<<<(1024*1536)/256, 256>>>(conv_w, pAH, pAM);
    packbx_kernel<<<(1536*4096)/256, 256>>>(x, pWc, pbc, pBH, pBM);
    conv_kernel<<<dim3(4096/CBN, 1024/CBM), 256, CONV_SMEM>>>(pAH, pAM, pBH, pBM, conv_b, pos_emb, ph);

    for (int l = 0; l < 2; l++) {
        int tb = l*12;
        lnqkv_kernel<<<NTOK/64, 256>>>(ph, ln1_s + l*64, ln1_b + l*64,
                                       pWpH, pWpM, tb + 0, pq, pk, pv);
        local_attn_kernel<<<NB*4*8, 128>>>(pq, pk, pv, pattn);
        global_attn_kernel<<<NB*4, 256>>>(pq, pk, pv, pattn);
        attn_ffn_kernel<<<NTOK/64, 256, FUSED_SMEM>>>(
            pattn, pWpH, pWpM, tb + 3, tb + 4, tb + 8,
            wo_b + l*64, ln2_s + l*64, ln2_b + l*64,
            ff_b1 + l*256, ff_b2 + l*64, ph);
    }
    collapse_kernel<<<NTOK/64, 64>>>(ph, collapse_w, collapse_b, out);
}

// round 13
// speedup vs baseline: 4.1512x; 1.0262x over previous
#include <cuda_runtime.h>
#include <cuda_bf16.h>
#include <cstdint>
#include <math.h>

// Problem constants: B=64, T=1024, DIN=5, D=64, H=8, DH=8, NLOCAL=4, WS=128, DEPTH=2
#define NB 64
#define NT 1024
#define NDIN 5
#define ND 64
#define NTOK (NB*NT)           // 65536

// ---------------- scratch (static device buffers) -----------------------------
__device__ float g_h[NTOK*ND];          // running hidden state
__device__ float g_q[NTOK*ND];          // [b][h][t][dh]
__device__ float g_k[NTOK*ND];
__device__ float g_v[NTOK*ND];
__device__ float g_attn[NTOK*ND];       // [b][t][h*8+dh]
__device__ float g_Wc[NDIN*ND];
__device__ float g_bc[ND];
// packed-weight tiles: 24 tiles x 64 n x 32 kpairs
__device__ uint32_t g_WpH[24*2048], g_WpM[24*2048];
// packed conv A: [1024 m][1536 kpair]
__device__ uint32_t g_AH[1024*1536], g_AM[1024*1536];
// packed conv B: [1536 kpair][4096 n]
__device__ uint32_t g_BH[1536*4096], g_BM[1536*4096];

typedef unsigned long long ull;

// ---------------- f32x2 packed helpers ----------------------------------------
__device__ __forceinline__ ull pk2(float lo, float hi) {
    ull r; asm("mov.b64 %0, {%1,%2};" : "=l"(r) : "f"(lo), "f"(hi)); return r;
}
__device__ __forceinline__ void upk2(ull v, float& lo, float& hi) {
    asm("mov.b64 {%0,%1}, %2;" : "=f"(lo), "=f"(hi) : "l"(v));
}
__device__ __forceinline__ ull fma2(ull a, ull b, ull c) {
    ull d; asm("fma.rn.f32x2 %0, %1, %2, %3;" : "=l"(d) : "l"(a), "l"(b), "l"(c)); return d;
}
__device__ __forceinline__ float ex2(float x) {
    float r; asm("ex2.approx.ftz.f32 %0, %1;" : "=f"(r) : "f"(x)); return r;
}

// ---------------- bf16 split helpers ------------------------------------------
__device__ __forceinline__ void pack2(float x0, float x1, uint32_t& hi, uint32_t& mid) {
    uint32_t h;
    asm("cvt.rn.bf16x2.f32 %0, %1, %2;" : "=r"(h) : "f"(x1), "f"(x0));
    float f0 = __uint_as_float(h << 16);
    float f1 = __uint_as_float(h & 0xFFFF0000u);
    float r0 = x0 - f0, r1 = x1 - f1;
    asm("cvt.rn.bf16x2.f32 %0, %1, %2;" : "=r"(mid) : "f"(r1), "f"(r0));
    hi = h;
}
__device__ __forceinline__ void mma_bf16(float* c, const uint32_t* a, const uint32_t* b) {
    asm volatile("mma.sync.aligned.m16n8k16.row.col.f32.bf16.bf16.f32 "
        "{%0,%1,%2,%3}, {%4,%5,%6,%7}, {%8,%9}, {%0,%1,%2,%3};"
        : "+f"(c[0]), "+f"(c[1]), "+f"(c[2]), "+f"(c[3])
        : "r"(a[0]), "r"(a[1]), "r"(a[2]), "r"(a[3]), "r"(b[0]), "r"(b[1]));
}

// ---------------- precompute combined expand@emb ------------------------------
__global__ void precompute_kernel(const float* __restrict__ ew, const float* __restrict__ eb,
                                  const float* __restrict__ mw, const float* __restrict__ mb,
                                  float* __restrict__ Wc, float* __restrict__ bc) {
    int j = threadIdx.x;             // 64 threads
    for (int i = 0; i < NDIN; i++) {
        float s = 0.f;
        for (int d = 0; d < ND; d++) s += ew[i*ND + d] * mw[d*ND + j];
        Wc[i*ND + j] = s;
    }
    float s = mb[j];
    for (int d = 0; d < ND; d++) s += eb[d] * mw[d*ND + j];
    bc[j] = s;
}

// ---------------- weight pre-pack: 24 tiles of 64x64 --------------------------
__global__ void packw_kernel(const float* __restrict__ wq, const float* __restrict__ wk,
                             const float* __restrict__ wv, const float* __restrict__ wo,
                             const float* __restrict__ w1, const float* __restrict__ w2,
                             uint32_t* __restrict__ WpH, uint32_t* __restrict__ WpM) {
    int tile = blockIdx.x;        // 0..23
    int l = tile / 12, t = tile - l*12;
    const float* src; int ldw, coloff;
    if (t == 0)      { src = wq + l*4096; ldw = 64; coloff = 0; }
    else if (t == 1) { src = wk + l*4096; ldw = 64; coloff = 0; }
    else if (t == 2) { src = wv + l*4096; ldw = 64; coloff = 0; }
    else if (t == 3) { src = wo + l*4096; ldw = 64; coloff = 0; }
    else if (t < 8)  { src = w1 + l*64*256; ldw = 256; coloff = (t-4)*64; }
    else             { src = w2 + l*256*64 + (t-8)*64*64; ldw = 64; coloff = 0; }
    int tid = threadIdx.x;        // 256
    int n = tid & 63, p0 = (tid >> 6) * 8;
    uint32_t* dh = WpH + tile*2048 + n*32;
    uint32_t* dm = WpM + tile*2048 + n*32;
#pragma unroll
    for (int u = 0; u < 8; u++) {
        int k = 2*(p0+u);
        float w0 = src[(long)k*ldw + coloff + n];
        float w1v = src[(long)(k+1)*ldw + coloff + n];
        uint32_t h, m_;
        pack2(w0, w1v, h, m_);
        dh[p0+u] = h; dm[p0+u] = m_;
    }
}

// ---------------- conv A pre-pack: conv_w -> [m][kpair] ------------------------
__global__ void packa_kernel(const float* __restrict__ A,
                             uint32_t* __restrict__ AH, uint32_t* __restrict__ AM) {
    int idx = blockIdx.x*256 + threadIdx.x;       // pair index [1024*1536)
    float2 v = *(const float2*)(A + (long)idx*2);
    uint32_t h, m_;
    pack2(v.x, v.y, h, m_);
    AH[idx] = h; AM[idx] = m_;
}

// ---------------- conv B pre-pack WITH fused expand ----------------------------
__global__ void packbx_kernel(const float* __restrict__ x,
                              const float* __restrict__ Wc, const float* __restrict__ bc,
                              uint32_t* __restrict__ BH, uint32_t* __restrict__ BM) {
    int idx = blockIdx.x*256 + threadIdx.x;       // [1536*4096)
    int kp2 = idx >> 12;
    int n = idx & 4095;
    int b = n >> 6, d = n & 63;
    int K0 = kp2*2, K1 = K0 + 1;
    int kt0 = K0/3, kq0 = K0 - kt0*3;
    int kt1 = K1/3, kq1 = K1 - kt1*3;
    int d0 = d + kq0 - 1, d1 = d + kq1 - 1;
    float v0 = 0.f, v1 = 0.f;
    if (d0 >= 0 && d0 < 64) {
        const float* xr = x + ((long)(b << 10) + kt0) * NDIN;
        v0 = bc[d0];
#pragma unroll
        for (int i = 0; i < NDIN; i++) v0 += xr[i] * Wc[i*ND + d0];
    }
    if (d1 >= 0 && d1 < 64) {
        const float* xr = x + ((long)(b << 10) + kt1) * NDIN;
        v1 = bc[d1];
#pragma unroll
        for (int i = 0; i < NDIN; i++) v1 += xr[i] * Wc[i*ND + d1];
    }
    uint32_t h, m_;
    pack2(v0, v1, h, m_);
    BH[idx] = h; BM[idx] = m_;
}

// ---------------- conv as GEMM, bf16x3 m16n8k16, stride-12 tiles ---------------
#define CBM 128
#define CBN 128
#define CBK 16
#define CONV_SMEM (4*2*128*12*4)   // 49152 B
__global__ __launch_bounds__(256) void conv_kernel(
        const uint32_t* __restrict__ AH, const uint32_t* __restrict__ AM,
        const uint32_t* __restrict__ BH, const uint32_t* __restrict__ BM,
        const float* __restrict__ conv_b, const float* __restrict__ pos_emb,
        float* __restrict__ Hout) {
    extern __shared__ uint32_t cs[];
    uint32_t (*Ah)[128][12] = (uint32_t(*)[128][12])cs;
    uint32_t (*Am)[128][12] = (uint32_t(*)[128][12])(cs + 2*128*12);
    uint32_t (*Bh)[128][12] = (uint32_t(*)[128][12])(cs + 4*128*12);
    uint32_t (*Bm)[128][12] = (uint32_t(*)[128][12])(cs + 6*128*12);
    int tid = threadIdx.x;
    int m0 = blockIdx.y * CBM;
    int n0 = blockIdx.x * CBN;

    int arow = tid >> 1;
    int ap = (tid & 1) * 4;
    int bj = tid & 127;
    int bp = (tid >> 7) * 4;

    int w = tid >> 5, lane = tid & 31;
    int gid = lane >> 2, t4 = lane & 3;
    int warpM = w >> 1, warpN = w & 1;
    int mbase = warpM * 32, nbase = warpN * 64;

    float acc[2][8][4];
#pragma unroll
    for (int mt = 0; mt < 2; mt++)
#pragma unroll
        for (int nt = 0; nt < 8; nt++)
#pragma unroll
            for (int r = 0; r < 4; r++) acc[mt][nt][r] = 0.f;

    auto loadA = [&](int k0, int buf) {
        const uint32_t* ph = AH + (long)(m0 + arow)*1536 + (k0 >> 1) + ap;
        const uint32_t* pm = AM + (long)(m0 + arow)*1536 + (k0 >> 1) + ap;
        uint4 vh = *(const uint4*)ph;
        uint4 vm = *(const uint4*)pm;
        Ah[buf][arow][ap+0] = vh.x; Ah[buf][arow][ap+1] = vh.y;
        Ah[buf][arow][ap+2] = vh.z; Ah[buf][arow][ap+3] = vh.w;
        Am[buf][arow][ap+0] = vm.x; Am[buf][arow][ap+1] = vm.y;
        Am[buf][arow][ap+2] = vm.z; Am[buf][arow][ap+3] = vm.w;
    };
    auto loadB = [&](int k0, int buf) {
        long base = (long)((k0 >> 1) + bp) * 4096 + n0 + bj;
#pragma unroll
        for (int u = 0; u < 4; u++) {
            Bh[buf][bj][bp+u] = BH[base + (long)u*4096];
            Bm[buf][bj][bp+u] = BM[base + (long)u*4096];
        }
    };

    loadA(0, 0); loadB(0, 0);
    __syncthreads();

    int cur = 0;
    for (int k0 = CBK; k0 <= 3072; k0 += CBK) {
        if (k0 < 3072) { loadA(k0, cur ^ 1); loadB(k0, cur ^ 1); }
        uint32_t ah[2][4], am[2][4];
#pragma unroll
        for (int mt = 0; mt < 2; mt++) {
            int r0 = mbase + mt*16 + gid;
            ah[mt][0] = Ah[cur][r0  ][t4];   ah[mt][1] = Ah[cur][r0+8][t4];
            ah[mt][2] = Ah[cur][r0  ][t4+4]; ah[mt][3] = Ah[cur][r0+8][t4+4];
            am[mt][0] = Am[cur][r0  ][t4];   am[mt][1] = Am[cur][r0+8][t4];
            am[mt][2] = Am[cur][r0  ][t4+4]; am[mt][3] = Am[cur][r0+8][t4+4];
        }
#pragma unroll
        for (int nt = 0; nt < 8; nt++) {
            int n = nbase + nt*8 + gid;
            uint32_t bhf[2] = { Bh[cur][n][t4], Bh[cur][n][t4+4] };
            uint32_t bmf[2] = { Bm[cur][n][t4], Bm[cur][n][t4+4] };
#pragma unroll
            for (int mt = 0; mt < 2; mt++) {
                mma_bf16(acc[mt][nt], ah[mt], bhf);
                mma_bf16(acc[mt][nt], ah[mt], bmf);
                mma_bf16(acc[mt][nt], am[mt], bhf);
            }
        }
        __syncthreads();
        cur ^= 1;
    }

#pragma unroll
    for (int mt = 0; mt < 2; mt++) {
        int row0r = m0 + mbase + mt*16 + gid;
        float cb0 = conv_b[row0r];
        float cb1 = conv_b[row0r + 8];
#pragma unroll
        for (int nt = 0; nt < 8; nt++) {
            int coln = n0 + nbase + nt*8 + t4*2;
            int b_ = coln >> 6, d_ = coln & 63;
            float2 pe0 = *(const float2*)(pos_emb + row0r*64 + d_);
            float2 pe1 = *(const float2*)(pos_emb + (row0r+8)*64 + d_);
            float2 o0, o1;
            o0.x = acc[mt][nt][0] + cb0 + pe0.x;
            o0.y = acc[mt][nt][1] + cb0 + pe0.y;
            o1.x = acc[mt][nt][2] + cb1 + pe1.x;
            o1.y = acc[mt][nt][3] + cb1 + pe1.y;
            *(float2*)(Hout + ((long)(b_ << 10) + row0r)*64 + d_) = o0;
            *(float2*)(Hout + ((long)(b_ << 10) + row0r + 8)*64 + d_) = o1;
        }
    }
}

// ================= mma-based 64-token GEMM helpers =============================
// stride 36 (=4 mod 32) -> fragment loads hit 32 distinct banks
typedef uint32_t XT[36];
typedef uint32_t WT[36];

__device__ __forceinline__ void pack_x64(const float* __restrict__ X, long row0, int ldx, int coloff,
                                         const float* __restrict__ lns, const float* __restrict__ lnb,
                                         bool doLN, XT* Xh, XT* Xm, int tid) {
    int r = tid >> 2, q = (tid & 3) * 16;
    const float* row = X + (row0 + r) * (long)ldx + coloff + q;
    float xv[16];
    *(float4*)&xv[0]  = *(const float4*)(row);
    *(float4*)&xv[4]  = *(const float4*)(row + 4);
    *(float4*)&xv[8]  = *(const float4*)(row + 8);
    *(float4*)&xv[12] = *(const float4*)(row + 12);
    if (doLN) {
        float sum = 0.f;
#pragma unroll
        for (int j = 0; j < 16; j++) sum += xv[j];
        sum += __shfl_xor_sync(~0u, sum, 1);
        sum += __shfl_xor_sync(~0u, sum, 2);
        float mu = sum * (1.f/64.f);
        float vs = 0.f;
#pragma unroll
        for (int j = 0; j < 16; j++) { float d = xv[j] - mu; vs += d*d; }
        vs += __shfl_xor_sync(~0u, vs, 1);
        vs += __shfl_xor_sync(~0u, vs, 2);
        float inv = rsqrtf(vs * (1.f/64.f) + 1e-5f);
#pragma unroll
        for (int j = 0; j < 16; j++) xv[j] = (xv[j] - mu) * inv * lns[q+j] + lnb[q+j];
    }
    int p0 = q >> 1;
#pragma unroll
    for (int u = 0; u < 8; u++) {
        uint32_t h, m_;
        pack2(xv[2*u], xv[2*u+1], h, m_);
        Xh[r][p0+u] = h; Xm[r][p0+u] = m_;
    }
}

__device__ __forceinline__ void copy_w64(const uint32_t* __restrict__ WpH,
                                         const uint32_t* __restrict__ WpM, int tile,
                                         WT* Wh, WT* Wm, int tid) {
    int n = tid >> 2, qp = (tid & 3) * 8;
    const uint32_t* sh = WpH + tile*2048 + n*32 + qp;
    const uint32_t* sm = WpM + tile*2048 + n*32 + qp;
    *(uint4*)&Wh[n][qp]   = *(const uint4*)sh;
    *(uint4*)&Wh[n][qp+4] = *(const uint4*)(sh+4);
    *(uint4*)&Wm[n][qp]   = *(const uint4*)sm;
    *(uint4*)&Wm[n][qp+4] = *(const uint4*)(sm+4);
}

__device__ __forceinline__ void mma64_compute(const XT* Xh, const XT* Xm,
                                              const WT* Wh, const WT* Wm,
                                              float acc[4][4], int mb, int nb, int gid, int t4) {
#pragma unroll
    for (int kc = 0; kc < 4; kc++) {
        int kp = kc*8;
        uint32_t ah[4], am[4];
        ah[0] = Xh[mb+gid  ][kp+t4];   ah[1] = Xh[mb+gid+8][kp+t4];
        ah[2] = Xh[mb+gid  ][kp+t4+4]; ah[3] = Xh[mb+gid+8][kp+t4+4];
        am[0] = Xm[mb+gid  ][kp+t4];   am[1] = Xm[mb+gid+8][kp+t4];
        am[2] = Xm[mb+gid  ][kp+t4+4]; am[3] = Xm[mb+gid+8][kp+t4+4];
#pragma unroll
        for (int nf = 0; nf < 4; nf++) {
            int n = nb + nf*8 + gid;
            uint32_t bh[2] = { Wh[n][kp+t4], Wh[n][kp+t4+4] };
            uint32_t bm[2] = { Wm[n][kp+t4], Wm[n][kp+t4+4] };
            mma_bf16(acc[nf], ah, bh);
            mma_bf16(acc[nf], ah, bm);
            mma_bf16(acc[nf], am, bh);
        }
    }
}

// ---------------- fused LN + QKV (mma) -> head layout -------------------------
__global__ __launch_bounds__(256) void lnqkv_kernel(
        const float* __restrict__ X, const float* __restrict__ lns, const float* __restrict__ lnb,
        const uint32_t* __restrict__ WpH, const uint32_t* __restrict__ WpM, int tile0,
        float* __restrict__ q, float* __restrict__ k, float* __restrict__ v) {
    __shared__ uint32_t Xh[64][36], Xm[64][36];
    __shared__ uint32_t Wh[64][36], Wm[64][36];
    int tid = threadIdx.x;
    long row0 = (long)blockIdx.x * 64;
    int w = tid >> 5, lane = tid & 31;
    int gid = lane >> 2, t4 = lane & 3;
    int mb = (w & 3) * 16, nb = (w >> 2) * 32;

    pack_x64(X, row0, ND, 0, lns, lnb, true, Xh, Xm, tid);
    float* Om[3] = {q, k, v};
#pragma unroll
    for (int m = 0; m < 3; m++) {
        if (m) __syncthreads();
        copy_w64(WpH, WpM, tile0 + m, Wh, Wm, tid);
        __syncthreads();
        float acc[4][4] = {};
        mma64_compute(Xh, Xm, Wh, Wm, acc, mb, nb, gid, t4);
        float* out = Om[m];
        int dh = t4*2;
#pragma unroll
        for (int nf = 0; nf < 4; nf++) {
            int h = (nb >> 3) + nf;
            long gt0 = row0 + mb + gid;
            long gt1 = gt0 + 8;
            long b0 = gt0 >> 10, t0 = gt0 & 1023;
            long b1 = gt1 >> 10, t1 = gt1 & 1023;
            float2 o0; o0.x = acc[nf][0]; o0.y = acc[nf][1];
            float2 o1; o1.x = acc[nf][2]; o1.y = acc[nf][3];
            *(float2*)(out + (((b0*8 + h)*1024) + t0)*8 + dh) = o0;
            *(float2*)(out + (((b1*8 + h)*1024) + t1)*8 + dh) = o1;
        }
    }
}

// ---------------- FUSED: wo + resid + ln2 + ffn1 + gelu + ffn2 + resid --------
#define TSZ (64*36*4)
#define FUSED_SMEM (17408 + 6*TSZ)
__global__ __launch_bounds__(256) void attn_ffn_kernel(
        const float* __restrict__ attnIn,
        const uint32_t* __restrict__ WpH, const uint32_t* __restrict__ WpM,
        int woTile, int f1Tile0, int f2Tile0,
        const float* __restrict__ wo_b,
        const float* __restrict__ ln2s, const float* __restrict__ ln2b,
        const float* __restrict__ b1, const float* __restrict__ b2,
        float* __restrict__ h) {
    extern __shared__ char smem[];
    float (*Hs)[68] = (float(*)[68])smem;
    XT* Xh = (XT*)(smem + 17408);
    XT* Xm = (XT*)(smem + 17408 + TSZ);
    WT* Wh = (WT*)(smem + 17408 + 2*TSZ);
    WT* Wm = (WT*)(smem + 17408 + 3*TSZ);
    XT* Yh = (XT*)(smem + 17408 + 4*TSZ);
    XT* Ym = (XT*)(smem + 17408 + 5*TSZ);

    int tid = threadIdx.x;
    long row0 = (long)blockIdx.x * 64;
    int w = tid >> 5, lane = tid & 31;
    int gid = lane >> 2, t4 = lane & 3;
    int mb = (w & 3) * 16, nb = (w >> 2) * 32;

    // ---- 1. wo GEMM ----
    pack_x64(attnIn, row0, ND, 0, nullptr, nullptr, false, Xh, Xm, tid);
    copy_w64(WpH, WpM, woTile, Wh, Wm, tid);
    __syncthreads();
    float acc[4][4] = {};
    mma64_compute(Xh, Xm, Wh, Wm, acc, mb, nb, gid, t4);
#pragma unroll
    for (int nf = 0; nf < 4; nf++) {
        int col = nb + nf*8 + t4*2;
        float2 bb = *(const float2*)(wo_b + col);
        long r0 = row0 + mb + gid, r1 = r0 + 8;
        float2 rr0 = *(const float2*)(h + r0*ND + col);
        float2 rr1 = *(const float2*)(h + r1*ND + col);
        Hs[mb+gid  ][col]   = acc[nf][0] + bb.x + rr0.x;
        Hs[mb+gid  ][col+1] = acc[nf][1] + bb.y + rr0.y;
        Hs[mb+gid+8][col]   = acc[nf][2] + bb.x + rr1.x;
        Hs[mb+gid+8][col+1] = acc[nf][3] + bb.y + rr1.y;
    }
    __syncthreads();

    // ---- 2. LN2 on Hs -> pack into Xh/Xm ----
    {
        int r = tid >> 2, q = (tid & 3) * 16;
        float xv[16];
#pragma unroll
        for (int j = 0; j < 16; j++) xv[j] = Hs[r][q+j];
        float sum = 0.f;
#pragma unroll
        for (int j = 0; j < 16; j++) sum += xv[j];
        sum += __shfl_xor_sync(~0u, sum, 1);
        sum += __shfl_xor_sync(~0u, sum, 2);
        float mu = sum * (1.f/64.f);
        float vs = 0.f;
#pragma unroll
        for (int j = 0; j < 16; j++) { float d = xv[j] - mu; vs += d*d; }
        vs += __shfl_xor_sync(~0u, vs, 1);
        vs += __shfl_xor_sync(~0u, vs, 2);
        float inv = rsqrtf(vs * (1.f/64.f) + 1e-5f);
        int p0 = q >> 1;
#pragma unroll
        for (int u = 0; u < 8; u++) {
            float y0 = (xv[2*u]   - mu) * inv * ln2s[q+2*u]   + ln2b[q+2*u];
            float y1 = (xv[2*u+1] - mu) * inv * ln2s[q+2*u+1] + ln2b[q+2*u+1];
            uint32_t hh, m_;
            pack2(y0, y1, hh, m_);
            Xh[r][p0+u] = hh; Xm[r][p0+u] = m_;
        }
    }

    // ---- 3. chunk-interleaved ffn1 -> gelu -> Y smem -> ffn2 accumulate ----
    float acc2[4][4] = {};
    for (int c = 0; c < 4; c++) {
        __syncthreads();
        copy_w64(WpH, WpM, f1Tile0 + c, Wh, Wm, tid);
        __syncthreads();
        float ya[4][4] = {};
        mma64_compute(Xh, Xm, Wh, Wm, ya, mb, nb, gid, t4);
#pragma unroll
        for (int nf = 0; nf < 4; nf++) {
            int col = c*64 + nb + nf*8 + t4*2;
            float2 bb = *(const float2*)(b1 + col);
            float z0 = ya[nf][0] + bb.x, z1 = ya[nf][1] + bb.y;
            float z2 = ya[nf][2] + bb.x, z3 = ya[nf][3] + bb.y;
            float y0 = 0.5f*z0*(1.f + erff(z0*0.70710678118654752f));
            float y1 = 0.5f*z1*(1.f + erff(z1*0.70710678118654752f));
            float y2 = 0.5f*z2*(1.f + erff(z2*0.70710678118654752f));
            float y3 = 0.5f*z3*(1.f + erff(z3*0.70710678118654752f));
            int pi = (nb >> 1) + nf*4 + t4;
            uint32_t hh, m_;
            pack2(y0, y1, hh, m_); Yh[mb+gid  ][pi] = hh; Ym[mb+gid  ][pi] = m_;
            pack2(y2, y3, hh, m_); Yh[mb+gid+8][pi] = hh; Ym[mb+gid+8][pi] = m_;
        }
        __syncthreads();
        copy_w64(WpH, WpM, f2Tile0 + c, Wh, Wm, tid);
        __syncthreads();
        mma64_compute(Yh, Ym, Wh, Wm, acc2, mb, nb, gid, t4);
    }

    // ---- 4. epilogue: h = acc2 + b2 + Hs ----
#pragma unroll
    for (int nf = 0; nf < 4; nf++) {
        int col = nb + nf*8 + t4*2;
        float2 bb = *(const float2*)(b2 + col);
        long r0 = row0 + mb + gid, r1 = r0 + 8;
        float2 o0, o1;
        o0.x = acc2[nf][0] + bb.x + Hs[mb+gid  ][col];
        o0.y = acc2[nf][1] + bb.y + Hs[mb+gid  ][col+1];
        o1.x = acc2[nf][2] + bb.x + Hs[mb+gid+8][col];
        o1.y = acc2[nf][3] + bb.y + Hs[mb+gid+8][col+1];
        *(float2*)(h + r0*ND + col) = o0;
        *(float2*)(h + r1*ND + col) = o1;
    }
}

// ---------------- local windowed attention, f32x2 + ex2 -----------------------
__global__ __launch_bounds__(128) void local_attn_kernel(
        const float* __restrict__ q, const float* __restrict__ k,
        const float* __restrict__ v, float* __restrict__ attn) {
    int bid = blockIdx.x;                  // b*32 + h*8 + w
    int w = bid & 7, h = (bid >> 3) & 3, b = bid >> 5;
    __shared__ __align__(16) float Ks[384][8];
    __shared__ __align__(16) float Vs[384][8];
    __shared__ float wmax[4];
    int tid = threadIdx.x;                 // 128
    int base = ((b*8 + h)*1024) * 8;
    int jlo = (w == 0) ? 128 : 0;
    int jhi = (w == 7) ? 256 : 384;
    for (int idx = tid; idx < 768; idx += 128) {
        int j = idx >> 1, half = (idx & 1) * 4;
        int tt = (w - 1)*128 + j;
        float4 kv = {0,0,0,0}, vv = {0,0,0,0};
        if (tt >= 0 && tt < 1024) {
            kv = *(const float4*)(k + base + tt*8 + half);
            vv = *(const float4*)(v + base + tt*8 + half);
        }
        *(float4*)&Ks[j][half] = kv;
        *(float4*)&Vs[j][half] = vv;
    }
    __syncthreads();
    float nm = 0.f;
    for (int r = tid; r < 384; r += 128) {
        float4 k0 = *(const float4*)&Ks[r][0];
        float4 k1 = *(const float4*)&Ks[r][4];
        float s2 = k0.x*k0.x + k0.y*k0.y + k0.z*k0.z + k0.w*k0.w
                 + k1.x*k1.x + k1.y*k1.y + k1.z*k1.z + k1.w*k1.w;
        nm = fmaxf(nm, s2);
    }
#pragma unroll
    for (int o = 16; o; o >>= 1) nm = fmaxf(nm, __shfl_xor_sync(~0u, nm, o));
    if ((tid & 31) == 0) wmax[tid >> 5] = nm;
    __syncthreads();
    float kmax2 = fmaxf(fmaxf(wmax[0], wmax[1]), fmaxf(wmax[2], wmax[3]));

    int t = w*128 + tid;
    float4 q0 = *(const float4*)(q + base + t*8);
    float4 q1 = *(const float4*)(q + base + t*8 + 4);
    const float scale = 0.35355339059327373f;   // 1/sqrt(8)
    const float L2E = 1.4426950408889634f;
    float qn2 = q0.x*q0.x + q0.y*q0.y + q0.z*q0.z + q0.w*q0.w
              + q1.x*q1.x + q1.y*q1.y + q1.z*q1.z + q1.w*q1.w;
    float sc = scale * L2E;
    // pre-scaled query packed as f32x2
    ull q01 = pk2(q0.x*sc, q0.y*sc), q23 = pk2(q0.z*sc, q0.w*sc);
    ull q45 = pk2(q1.x*sc, q1.y*sc), q67 = pk2(q1.z*sc, q1.w*sc);
    float m2 = sc * sqrtf(qn2 * kmax2);          // upper bound of score*log2e
    float l = 0.f;
    ull a0 = 0, a1 = 0, a2 = 0, a3 = 0;
    for (int j = jlo; j < jhi; j++) {
        ulonglong2 ka = *(const ulonglong2*)&Ks[j][0];
        ulonglong2 kb = *(const ulonglong2*)&Ks[j][4];
        ull d2 = fma2(q01, ka.x, fma2(q23, ka.y, fma2(q45, kb.x, fma2(q67, kb.y, 0ULL))));
        float slo, shi; upk2(d2, slo, shi);
        float p = ex2(slo + shi - m2);
        l += p;
        ull pp = pk2(p, p);
        ulonglong2 va = *(const ulonglong2*)&Vs[j][0];
        ulonglong2 vb = *(const ulonglong2*)&Vs[j][4];
        a0 = fma2(pp, va.x, a0); a1 = fma2(pp, va.y, a1);
        a2 = fma2(pp, vb.x, a2); a3 = fma2(pp, vb.y, a3);
    }
    float inv = 1.f / l;
    float e0,e1,e2,e3,e4,e5,e6,e7;
    upk2(a0, e0, e1); upk2(a1, e2, e3); upk2(a2, e4, e5); upk2(a3, e6, e7);
    float4 o0, o1;
    o0.x = e0*inv; o0.y = e1*inv; o0.z = e2*inv; o0.w = e3*inv;
    o1.x = e4*inv; o1.y = e5*inv; o1.z = e6*inv; o1.w = e7*inv;
    long ob = ((long)(b*1024 + t)*64) + h*8;
    *(float4*)(attn + ob) = o0;
    *(float4*)(attn + ob + 4) = o1;
}

// ---------------- global linear attention (heads 4..7), f32x2 ctx -------------
__global__ void global_attn_kernel(const float* __restrict__ q, const float* __restrict__ k,
                                   const float* __restrict__ v, float* __restrict__ attn) {
    int b = blockIdx.x >> 2, h = blockIdx.x & 3;
    int tid = threadIdx.x;                 // 256
    int base = ((b*8 + 4 + h)*1024) * 8;
    __shared__ float red[8][72];
    __shared__ float M[8];
    __shared__ __align__(16) float C[64];
    int warp = tid >> 5, lane = tid & 31;

    float mx[8];
#pragma unroll
    for (int d = 0; d < 8; d++) mx[d] = -1e30f;
    for (int t = tid; t < 1024; t += 256) {
        float4 k0 = *(const float4*)(k + base + t*8);
        float4 k1 = *(const float4*)(k + base + t*8 + 4);
        mx[0]=fmaxf(mx[0],k0.x); mx[1]=fmaxf(mx[1],k0.y); mx[2]=fmaxf(mx[2],k0.z); mx[3]=fmaxf(mx[3],k0.w);
        mx[4]=fmaxf(mx[4],k1.x); mx[5]=fmaxf(mx[5],k1.y); mx[6]=fmaxf(mx[6],k1.z); mx[7]=fmaxf(mx[7],k1.w);
    }
#pragma unroll
    for (int d = 0; d < 8; d++)
        for (int o = 16; o; o >>= 1) mx[d] = fmaxf(mx[d], __shfl_xor_sync(~0u, mx[d], o));
    if (lane == 0)
        for (int d = 0; d < 8; d++) red[warp][d] = mx[d];
    __syncthreads();
    if (tid < 8) {
        float m_ = red[0][tid];
        for (int wv = 1; wv < 8; wv++) m_ = fmaxf(m_, red[wv][tid]);
        M[tid] = m_;
    }
    __syncthreads();

    float Z[8] = {};
    ull ctx2[32];
#pragma unroll
    for (int i = 0; i < 32; i++) ctx2[i] = 0ULL;
    for (int t = tid; t < 1024; t += 256) {
        float4 k0 = *(const float4*)(k + base + t*8);
        float4 k1 = *(const float4*)(k + base + t*8 + 4);
        ulonglong2 va = *(const ulonglong2*)(v + base + t*8);
        ulonglong2 vb = *(const ulonglong2*)(v + base + t*8 + 4);
        ull vv[4] = {va.x, va.y, vb.x, vb.y};
        float kr[8] = {k0.x,k0.y,k0.z,k0.w,k1.x,k1.y,k1.z,k1.w};
#pragma unroll
        for (int d = 0; d < 8; d++) {
            float e_ = __expf(kr[d] - M[d]);
            Z[d] += e_;
            ull pd = pk2(e_, e_);
#pragma unroll
            for (int e2 = 0; e2 < 4; e2++) ctx2[d*4 + e2] = fma2(pd, vv[e2], ctx2[d*4 + e2]);
        }
    }
    float ctx[64];
#pragma unroll
    for (int i = 0; i < 32; i++) upk2(ctx2[i], ctx[2*i], ctx[2*i+1]);
#pragma unroll
    for (int i = 0; i < 8; i++)
        for (int o = 16; o; o >>= 1) Z[i] += __shfl_xor_sync(~0u, Z[i], o);
#pragma unroll
    for (int i = 0; i < 64; i++)
        for (int o = 16; o; o >>= 1) ctx[i] += __shfl_xor_sync(~0u, ctx[i], o);
    if (lane == 0) {
        for (int i = 0; i < 8; i++)  red[warp][i] = Z[i];
        for (int i = 0; i < 64; i++) red[warp][8 + i] = ctx[i];
    }
    __syncthreads();
    if (tid < 64) {
        float s = 0.f, z = 0.f;
        int d = tid >> 3;
        for (int wv = 0; wv < 8; wv++) { s += red[wv][8 + tid]; z += red[wv][d]; }
        C[tid] = s / z;
    }
    __syncthreads();

    const float scale = 0.35355339059327373f;
    for (int t = tid; t < 1024; t += 256) {
        float4 q0 = *(const float4*)(q + base + t*8);
        float4 q1 = *(const float4*)(q + base + t*8 + 4);
        float qr[8] = {q0.x,q0.y,q0.z,q0.w,q1.x,q1.y,q1.z,q1.w};
        float qm = -1e30f;
#pragma unroll
        for (int d = 0; d < 8; d++) qm = fmaxf(qm, qr[d]);
        float qs = 0.f;
#pragma unroll
        for (int d = 0; d < 8; d++) { qr[d] = __expf(qr[d] - qm); qs += qr[d]; }
        float inv = scale / qs;
        ull o2[4] = {0ULL, 0ULL, 0ULL, 0ULL};
#pragma unroll
        for (int d = 0; d < 8; d++) {
            float p = qr[d] * inv;
            ull pd = pk2(p, p);
            const ulonglong2* Cd = (const ulonglong2*)&C[d*8];
            ulonglong2 c0 = Cd[0], c1 = Cd[1];
            o2[0] = fma2(pd, c0.x, o2[0]); o2[1] = fma2(pd, c0.y, o2[1]);
            o2[2] = fma2(pd, c1.x, o2[2]); o2[3] = fma2(pd, c1.y, o2[3]);
        }
        float e0,e1,e2,e3,e4,e5,e6,e7;
        upk2(o2[0], e0, e1); upk2(o2[1], e2, e3); upk2(o2[2], e4, e5); upk2(o2[3], e6, e7);
        long ob = (long)(b*1024 + t)*64 + (4 + h)*8;
        float4 oo0, oo1;
        oo0.x=e0; oo0.y=e1; oo0.z=e2; oo0.w=e3;
        oo1.x=e4; oo1.y=e5; oo1.z=e6; oo1.w=e7;
        *(float4*)(attn + ob) = oo0;
        *(float4*)(attn + ob + 4) = oo1;
    }
}

// ---------------- collapse: h(.,64) @ cw(64,5) + cb -> out --------------------
__global__ void collapse_kernel(const float* __restrict__ h, const float* __restrict__ cw,
                                const float* __restrict__ cb, float* __restrict__ out) {
    __shared__ float Xs[64][68];
    __shared__ float Ws[64][NDIN];
    __shared__ float Bs[NDIN];
    int tid = threadIdx.x;                 // 64
    int row0 = blockIdx.x * 64;
    for (int idx = tid; idx < 1024; idx += 64) {
        int i = idx >> 4, j = (idx & 15) * 4;
        *(float4*)&Xs[i][j] = *(const float4*)(h + (long)(row0 + i)*ND + j);
    }
    for (int idx = tid; idx < 64*NDIN; idx += 64) Ws[idx/NDIN][idx%NDIN] = cw[idx];
    if (tid < NDIN) Bs[tid] = cb[tid];
    __syncthreads();
    int r = tid;
    float acc[NDIN];
#pragma unroll
    for (int j = 0; j < NDIN; j++) acc[j] = Bs[j];
    for (int kk = 0; kk < 64; kk++) {
        float xv = Xs[r][kk];
#pragma unroll
        for (int j = 0; j < NDIN; j++) acc[j] += xv * Ws[kk][j];
    }
#pragma unroll
    for (int j = 0; j < NDIN; j++) out[(row0 + r)*NDIN + j] = acc[j];
}

// ---------------- launch ------------------------------------------------------
extern "C" void kernel_launch(void* const* d_in, const int* in_sizes, int n_in,
                              void* d_out, int out_size) {
    const float* x          = (const float*)d_in[0];
    const float* pos_emb    = (const float*)d_in[1];
    const float* expand_w   = (const float*)d_in[2];
    const float* expand_b   = (const float*)d_in[3];
    const float* emb_w      = (const float*)d_in[4];
    const float* emb_b      = (const float*)d_in[5];
    const float* conv_w     = (const float*)d_in[6];
    const float* conv_b     = (const float*)d_in[7];
    const float* ln1_s      = (const float*)d_in[8];
    const float* ln1_b      = (const float*)d_in[9];
    const float* wq         = (const float*)d_in[10];
    const float* wk         = (const float*)d_in[11];
    const float* wv         = (const float*)d_in[12];
    const float* wo         = (const float*)d_in[13];
    const float* wo_b       = (const float*)d_in[14];
    const float* ln2_s      = (const float*)d_in[15];
    const float* ln2_b      = (const float*)d_in[16];
    const float* ff_w1      = (const float*)d_in[17];
    const float* ff_b1      = (const float*)d_in[18];
    const float* ff_w2      = (const float*)d_in[19];
    const float* ff_b2      = (const float*)d_in[20];
    const float* collapse_w = (const float*)d_in[21];
    const float* collapse_b = (const float*)d_in[22];
    float* out = (float*)d_out;

    float *ph, *pq, *pk, *pv, *pattn, *pWc, *pbc;
    uint32_t *pWpH, *pWpM, *pAH, *pAM, *pBH, *pBM;
    cudaGetSymbolAddress((void**)&ph,   g_h);
    cudaGetSymbolAddress((void**)&pq,   g_q);
    cudaGetSymbolAddress((void**)&pk,   g_k);
    cudaGetSymbolAddress((void**)&pv,   g_v);
    cudaGetSymbolAddress((void**)&pattn,g_attn);
    cudaGetSymbolAddress((void**)&pWc,  g_Wc);
    cudaGetSymbolAddress((void**)&pbc,  g_bc);
    cudaGetSymbolAddress((void**)&pWpH, g_WpH);
    cudaGetSymbolAddress((void**)&pWpM, g_WpM);
    cudaGetSymbolAddress((void**)&pAH,  g_AH);
    cudaGetSymbolAddress((void**)&pAM,  g_AM);
    cudaGetSymbolAddress((void**)&pBH,  g_BH);
    cudaGetSymbolAddress((void**)&pBM,  g_BM);

    static bool attrSet = false;
    if (!attrSet) {
        cudaFuncSetAttribute(attn_ffn_kernel, cudaFuncAttributeMaxDynamicSharedMemorySize, FUSED_SMEM);
        cudaFuncSetAttribute(conv_kernel, cudaFuncAttributeMaxDynamicSharedMemorySize, CONV_SMEM);
        attrSet = true;
    }

    precompute_kernel<<<1, 64>>>(expand_w, expand_b, emb_w, emb_b, pWc, pbc);
    packw_kernel<<<24, 256>>>(wq, wk, wv, wo, ff_w1, ff_w2, pWpH, pWpM);
    packa_kernel<<<(1024*1536)/256, 256>>>(conv_w, pAH, pAM);
    packbx_kernel<<<(1536*4096)/256, 256>>>(x, pWc, pbc, pBH, pBM);
    conv_kernel<<<dim3(4096/CBN, 1024/CBM), 256, CONV_SMEM>>>(pAH, pAM, pBH, pBM, conv_b, pos_emb, ph);

    for (int l = 0; l < 2; l++) {
        int tb = l*12;
        lnqkv_kernel<<<NTOK/64, 256>>>(ph, ln1_s + l*64, ln1_b + l*64,
                                       pWpH, pWpM, tb + 0, pq, pk, pv);
        local_attn_kernel<<<NB*4*8, 128>>>(pq, pk, pv, pattn);
        global_attn_kernel<<<NB*4, 256>>>(pq, pk, pv, pattn);
        attn_ffn_kernel<<<NTOK/64, 256, FUSED_SMEM>>>(
            pattn, pWpH, pWpM, tb + 3, tb + 4, tb + 8,
            wo_b + l*64, ln2_s + l*64, ln2_b + l*64,
            ff_b1 + l*256, ff_b2 + l*64, ph);
    }
    collapse_kernel<<<NTOK/64, 64>>>(ph, collapse_w, collapse_b, out);
}

// round 14
// speedup vs baseline: 4.2613x; 1.0265x over previous
#include <cuda_runtime.h>
#include <cuda_bf16.h>
#include <cstdint>
#include <math.h>

#define NB 64
#define NT 1024
#define NDIN 5
#define ND 64
#define NTOK (NB*NT)           // 65536

// ---------------- scratch ------------------------------------------------------
__device__ float g_h[NTOK*ND];
__device__ float g_q[NTOK*ND];
__device__ float g_k[NTOK*ND];
__device__ float g_v[NTOK*ND];
__device__ float g_attn[NTOK*ND];
__device__ float g_Wc[NDIN*ND];
__device__ float g_bc[ND];
__device__ uint32_t g_WpH[24*2048], g_WpM[24*2048];
__device__ uint32_t g_AH[1024*1536], g_AM[1024*1536];
__device__ uint32_t g_BH[1536*4096], g_BM[1536*4096];

typedef unsigned long long ull;

__device__ __forceinline__ ull pk2(float lo, float hi) {
    ull r; asm("mov.b64 %0, {%1,%2};" : "=l"(r) : "f"(lo), "f"(hi)); return r;
}
__device__ __forceinline__ void upk2(ull v, float& lo, float& hi) {
    asm("mov.b64 {%0,%1}, %2;" : "=f"(lo), "=f"(hi) : "l"(v));
}
__device__ __forceinline__ ull fma2(ull a, ull b, ull c) {
    ull d; asm("fma.rn.f32x2 %0, %1, %2, %3;" : "=l"(d) : "l"(a), "l"(b), "l"(c)); return d;
}
__device__ __forceinline__ float ex2(float x) {
    float r; asm("ex2.approx.ftz.f32 %0, %1;" : "=f"(r) : "f"(x)); return r;
}

__device__ __forceinline__ void pack2(float x0, float x1, uint32_t& hi, uint32_t& mid) {
    uint32_t h;
    asm("cvt.rn.bf16x2.f32 %0, %1, %2;" : "=r"(h) : "f"(x1), "f"(x0));
    float f0 = __uint_as_float(h << 16);
    float f1 = __uint_as_float(h & 0xFFFF0000u);
    float r0 = x0 - f0, r1 = x1 - f1;
    asm("cvt.rn.bf16x2.f32 %0, %1, %2;" : "=r"(mid) : "f"(r1), "f"(r0));
    hi = h;
}
__device__ __forceinline__ void mma_bf16(float* c, const uint32_t* a, const uint32_t* b) {
    asm volatile("mma.sync.aligned.m16n8k16.row.col.f32.bf16.bf16.f32 "
        "{%0,%1,%2,%3}, {%4,%5,%6,%7}, {%8,%9}, {%0,%1,%2,%3};"
        : "+f"(c[0]), "+f"(c[1]), "+f"(c[2]), "+f"(c[3])
        : "r"(a[0]), "r"(a[1]), "r"(a[2]), "r"(a[3]), "r"(b[0]), "r"(b[1]));
}

// ---------------- precompute combined expand@emb ------------------------------
__global__ void precompute_kernel(const float* __restrict__ ew, const float* __restrict__ eb,
                                  const float* __restrict__ mw, const float* __restrict__ mb,
                                  float* __restrict__ Wc, float* __restrict__ bc) {
    int j = threadIdx.x;
    for (int i = 0; i < NDIN; i++) {
        float s = 0.f;
        for (int d = 0; d < ND; d++) s += ew[i*ND + d] * mw[d*ND + j];
        Wc[i*ND + j] = s;
    }
    float s = mb[j];
    for (int d = 0; d < ND; d++) s += eb[d] * mw[d*ND + j];
    bc[j] = s;
}

// ---------------- weight pre-pack ---------------------------------------------
__global__ void packw_kernel(const float* __restrict__ wq, const float* __restrict__ wk,
                             const float* __restrict__ wv, const float* __restrict__ wo,
                             const float* __restrict__ w1, const float* __restrict__ w2,
                             uint32_t* __restrict__ WpH, uint32_t* __restrict__ WpM) {
    int tile = blockIdx.x;
    int l = tile / 12, t = tile - l*12;
    const float* src; int ldw, coloff;
    if (t == 0)      { src = wq + l*4096; ldw = 64; coloff = 0; }
    else if (t == 1) { src = wk + l*4096; ldw = 64; coloff = 0; }
    else if (t == 2) { src = wv + l*4096; ldw = 64; coloff = 0; }
    else if (t == 3) { src = wo + l*4096; ldw = 64; coloff = 0; }
    else if (t < 8)  { src = w1 + l*64*256; ldw = 256; coloff = (t-4)*64; }
    else             { src = w2 + l*256*64 + (t-8)*64*64; ldw = 64; coloff = 0; }
    int tid = threadIdx.x;
    int n = tid & 63, p0 = (tid >> 6) * 8;
    uint32_t* dh = WpH + tile*2048 + n*32;
    uint32_t* dm = WpM + tile*2048 + n*32;
#pragma unroll
    for (int u = 0; u < 8; u++) {
        int k = 2*(p0+u);
        float w0 = src[(long)k*ldw + coloff + n];
        float w1v = src[(long)(k+1)*ldw + coloff + n];
        uint32_t h, m_;
        pack2(w0, w1v, h, m_);
        dh[p0+u] = h; dm[p0+u] = m_;
    }
}

__global__ void packa_kernel(const float* __restrict__ A,
                             uint32_t* __restrict__ AH, uint32_t* __restrict__ AM) {
    int idx = blockIdx.x*256 + threadIdx.x;
    float2 v = *(const float2*)(A + (long)idx*2);
    uint32_t h, m_;
    pack2(v.x, v.y, h, m_);
    AH[idx] = h; AM[idx] = m_;
}

__global__ void packbx_kernel(const float* __restrict__ x,
                              const float* __restrict__ Wc, const float* __restrict__ bc,
                              uint32_t* __restrict__ BH, uint32_t* __restrict__ BM) {
    int idx = blockIdx.x*256 + threadIdx.x;
    int kp2 = idx >> 12;
    int n = idx & 4095;
    int b = n >> 6, d = n & 63;
    int K0 = kp2*2, K1 = K0 + 1;
    int kt0 = K0/3, kq0 = K0 - kt0*3;
    int kt1 = K1/3, kq1 = K1 - kt1*3;
    int d0 = d + kq0 - 1, d1 = d + kq1 - 1;
    float v0 = 0.f, v1 = 0.f;
    if (d0 >= 0 && d0 < 64) {
        const float* xr = x + ((long)(b << 10) + kt0) * NDIN;
        v0 = bc[d0];
#pragma unroll
        for (int i = 0; i < NDIN; i++) v0 += xr[i] * Wc[i*ND + d0];
    }
    if (d1 >= 0 && d1 < 64) {
        const float* xr = x + ((long)(b << 10) + kt1) * NDIN;
        v1 = bc[d1];
#pragma unroll
        for (int i = 0; i < NDIN; i++) v1 += xr[i] * Wc[i*ND + d1];
    }
    uint32_t h, m_;
    pack2(v0, v1, h, m_);
    BH[idx] = h; BM[idx] = m_;
}

// ---------------- conv as GEMM (unchanged, verified) --------------------------
#define CBM 128
#define CBN 128
#define CBK 16
#define CONV_SMEM (4*2*128*12*4)   // 49152 B
__global__ __launch_bounds__(256) void conv_kernel(
        const uint32_t* __restrict__ AH, const uint32_t* __restrict__ AM,
        const uint32_t* __restrict__ BH, const uint32_t* __restrict__ BM,
        const float* __restrict__ conv_b, const float* __restrict__ pos_emb,
        float* __restrict__ Hout) {
    extern __shared__ uint32_t cs[];
    uint32_t (*Ah)[128][12] = (uint32_t(*)[128][12])cs;
    uint32_t (*Am)[128][12] = (uint32_t(*)[128][12])(cs + 2*128*12);
    uint32_t (*Bh)[128][12] = (uint32_t(*)[128][12])(cs + 4*128*12);
    uint32_t (*Bm)[128][12] = (uint32_t(*)[128][12])(cs + 6*128*12);
    int tid = threadIdx.x;
    int m0 = blockIdx.y * CBM;
    int n0 = blockIdx.x * CBN;

    int arow = tid >> 1;
    int ap = (tid & 1) * 4;
    int bj = tid & 127;
    int bp = (tid >> 7) * 4;

    int w = tid >> 5, lane = tid & 31;
    int gid = lane >> 2, t4 = lane & 3;
    int warpM = w >> 1, warpN = w & 1;
    int mbase = warpM * 32, nbase = warpN * 64;

    float acc[2][8][4];
#pragma unroll
    for (int mt = 0; mt < 2; mt++)
#pragma unroll
        for (int nt = 0; nt < 8; nt++)
#pragma unroll
            for (int r = 0; r < 4; r++) acc[mt][nt][r] = 0.f;

    auto loadA = [&](int k0, int buf) {
        const uint32_t* ph = AH + (long)(m0 + arow)*1536 + (k0 >> 1) + ap;
        const uint32_t* pm = AM + (long)(m0 + arow)*1536 + (k0 >> 1) + ap;
        uint4 vh = *(const uint4*)ph;
        uint4 vm = *(const uint4*)pm;
        Ah[buf][arow][ap+0] = vh.x; Ah[buf][arow][ap+1] = vh.y;
        Ah[buf][arow][ap+2] = vh.z; Ah[buf][arow][ap+3] = vh.w;
        Am[buf][arow][ap+0] = vm.x; Am[buf][arow][ap+1] = vm.y;
        Am[buf][arow][ap+2] = vm.z; Am[buf][arow][ap+3] = vm.w;
    };
    auto loadB = [&](int k0, int buf) {
        long base = (long)((k0 >> 1) + bp) * 4096 + n0 + bj;
#pragma unroll
        for (int u = 0; u < 4; u++) {
            Bh[buf][bj][bp+u] = BH[base + (long)u*4096];
            Bm[buf][bj][bp+u] = BM[base + (long)u*4096];
        }
    };

    loadA(0, 0); loadB(0, 0);
    __syncthreads();

    int cur = 0;
    for (int k0 = CBK; k0 <= 3072; k0 += CBK) {
        if (k0 < 3072) { loadA(k0, cur ^ 1); loadB(k0, cur ^ 1); }
        uint32_t ah[2][4], am[2][4];
#pragma unroll
        for (int mt = 0; mt < 2; mt++) {
            int r0 = mbase + mt*16 + gid;
            ah[mt][0] = Ah[cur][r0  ][t4];   ah[mt][1] = Ah[cur][r0+8][t4];
            ah[mt][2] = Ah[cur][r0  ][t4+4]; ah[mt][3] = Ah[cur][r0+8][t4+4];
            am[mt][0] = Am[cur][r0  ][t4];   am[mt][1] = Am[cur][r0+8][t4];
            am[mt][2] = Am[cur][r0  ][t4+4]; am[mt][3] = Am[cur][r0+8][t4+4];
        }
#pragma unroll
        for (int nt = 0; nt < 8; nt++) {
            int n = nbase + nt*8 + gid;
            uint32_t bhf[2] = { Bh[cur][n][t4], Bh[cur][n][t4+4] };
            uint32_t bmf[2] = { Bm[cur][n][t4], Bm[cur][n][t4+4] };
#pragma unroll
            for (int mt = 0; mt < 2; mt++) {
                mma_bf16(acc[mt][nt], ah[mt], bhf);
                mma_bf16(acc[mt][nt], ah[mt], bmf);
                mma_bf16(acc[mt][nt], am[mt], bhf);
            }
        }
        __syncthreads();
        cur ^= 1;
    }

#pragma unroll
    for (int mt = 0; mt < 2; mt++) {
        int row0r = m0 + mbase + mt*16 + gid;
        float cb0 = conv_b[row0r];
        float cb1 = conv_b[row0r + 8];
#pragma unroll
        for (int nt = 0; nt < 8; nt++) {
            int coln = n0 + nbase + nt*8 + t4*2;
            int b_ = coln >> 6, d_ = coln & 63;
            float2 pe0 = *(const float2*)(pos_emb + row0r*64 + d_);
            float2 pe1 = *(const float2*)(pos_emb + (row0r+8)*64 + d_);
            float2 o0, o1;
            o0.x = acc[mt][nt][0] + cb0 + pe0.x;
            o0.y = acc[mt][nt][1] + cb0 + pe0.y;
            o1.x = acc[mt][nt][2] + cb1 + pe1.x;
            o1.y = acc[mt][nt][3] + cb1 + pe1.y;
            *(float2*)(Hout + ((long)(b_ << 10) + row0r)*64 + d_) = o0;
            *(float2*)(Hout + ((long)(b_ << 10) + row0r + 8)*64 + d_) = o1;
        }
    }
}

// ================= mma GEMM helpers =============================
typedef uint32_t XT[36];
typedef uint32_t WT[36];

__device__ __forceinline__ void pack_x64(const float* __restrict__ X, long row0, int ldx, int coloff,
                                         const float* __restrict__ lns, const float* __restrict__ lnb,
                                         bool doLN, XT* Xh, XT* Xm, int tid) {
    int r = tid >> 2, q = (tid & 3) * 16;
    const float* row = X + (row0 + r) * (long)ldx + coloff + q;
    float xv[16];
    *(float4*)&xv[0]  = *(const float4*)(row);
    *(float4*)&xv[4]  = *(const float4*)(row + 4);
    *(float4*)&xv[8]  = *(const float4*)(row + 8);
    *(float4*)&xv[12] = *(const float4*)(row + 12);
    if (doLN) {
        float sum = 0.f;
#pragma unroll
        for (int j = 0; j < 16; j++) sum += xv[j];
        sum += __shfl_xor_sync(~0u, sum, 1);
        sum += __shfl_xor_sync(~0u, sum, 2);
        float mu = sum * (1.f/64.f);
        float vs = 0.f;
#pragma unroll
        for (int j = 0; j < 16; j++) { float d = xv[j] - mu; vs += d*d; }
        vs += __shfl_xor_sync(~0u, vs, 1);
        vs += __shfl_xor_sync(~0u, vs, 2);
        float inv = rsqrtf(vs * (1.f/64.f) + 1e-5f);
#pragma unroll
        for (int j = 0; j < 16; j++) xv[j] = (xv[j] - mu) * inv * lns[q+j] + lnb[q+j];
    }
    int p0 = q >> 1;
#pragma unroll
    for (int u = 0; u < 8; u++) {
        uint32_t h, m_;
        pack2(xv[2*u], xv[2*u+1], h, m_);
        Xh[r][p0+u] = h; Xm[r][p0+u] = m_;
    }
}

__device__ __forceinline__ void copy_w64(const uint32_t* __restrict__ WpH,
                                         const uint32_t* __restrict__ WpM, int tile,
                                         WT* Wh, WT* Wm, int tid) {
    int n = tid >> 2, qp = (tid & 3) * 8;
    const uint32_t* sh = WpH + tile*2048 + n*32 + qp;
    const uint32_t* sm = WpM + tile*2048 + n*32 + qp;
    *(uint4*)&Wh[n][qp]   = *(const uint4*)sh;
    *(uint4*)&Wh[n][qp+4] = *(const uint4*)(sh+4);
    *(uint4*)&Wm[n][qp]   = *(const uint4*)sm;
    *(uint4*)&Wm[n][qp+4] = *(const uint4*)(sm+4);
}

__device__ __forceinline__ void mma64_compute(const XT* Xh, const XT* Xm,
                                              const WT* Wh, const WT* Wm,
                                              float acc[4][4], int mb, int nb, int gid, int t4) {
#pragma unroll
    for (int kc = 0; kc < 4; kc++) {
        int kp = kc*8;
        uint32_t ah[4], am[4];
        ah[0] = Xh[mb+gid  ][kp+t4];   ah[1] = Xh[mb+gid+8][kp+t4];
        ah[2] = Xh[mb+gid  ][kp+t4+4]; ah[3] = Xh[mb+gid+8][kp+t4+4];
        am[0] = Xm[mb+gid  ][kp+t4];   am[1] = Xm[mb+gid+8][kp+t4];
        am[2] = Xm[mb+gid  ][kp+t4+4]; am[3] = Xm[mb+gid+8][kp+t4+4];
#pragma unroll
        for (int nf = 0; nf < 4; nf++) {
            int n = nb + nf*8 + gid;
            uint32_t bh[2] = { Wh[n][kp+t4], Wh[n][kp+t4+4] };
            uint32_t bm[2] = { Wm[n][kp+t4], Wm[n][kp+t4+4] };
            mma_bf16(acc[nf], ah, bh);
            mma_bf16(acc[nf], ah, bm);
            mma_bf16(acc[nf], am, bh);
        }
    }
}

// ---------------- fused LN + QKV: all 3 W tiles resident ----------------------
#define TSZ (64*36*4)
#define QKV_SMEM (8*TSZ)    // Xh,Xm + 3x(Wh,Wm) = 73728 B
__global__ __launch_bounds__(256) void lnqkv_kernel(
        const float* __restrict__ X, const float* __restrict__ lns, const float* __restrict__ lnb,
        const uint32_t* __restrict__ WpH, const uint32_t* __restrict__ WpM, int tile0,
        float* __restrict__ q, float* __restrict__ k, float* __restrict__ v) {
    extern __shared__ char qsm[];
    XT* Xh = (XT*)qsm;
    XT* Xm = (XT*)(qsm + TSZ);
    int tid = threadIdx.x;
    long row0 = (long)blockIdx.x * 64;
    int w = tid >> 5, lane = tid & 31;
    int gid = lane >> 2, t4 = lane & 3;
    int mb = (w & 3) * 16, nb = (w >> 2) * 32;

    pack_x64(X, row0, ND, 0, lns, lnb, true, Xh, Xm, tid);
#pragma unroll
    for (int m = 0; m < 3; m++) {
        WT* Wh = (WT*)(qsm + (2 + 2*m)*TSZ);
        WT* Wm = (WT*)(qsm + (3 + 2*m)*TSZ);
        copy_w64(WpH, WpM, tile0 + m, Wh, Wm, tid);
    }
    __syncthreads();
    float* Om[3] = {q, k, v};
#pragma unroll
    for (int m = 0; m < 3; m++) {
        WT* Wh = (WT*)(qsm + (2 + 2*m)*TSZ);
        WT* Wm = (WT*)(qsm + (3 + 2*m)*TSZ);
        float acc[4][4] = {};
        mma64_compute(Xh, Xm, Wh, Wm, acc, mb, nb, gid, t4);
        float* out = Om[m];
        int dh = t4*2;
#pragma unroll
        for (int nf = 0; nf < 4; nf++) {
            int h = (nb >> 3) + nf;
            long gt0 = row0 + mb + gid;
            long gt1 = gt0 + 8;
            long b0 = gt0 >> 10, t0 = gt0 & 1023;
            long b1 = gt1 >> 10, t1 = gt1 & 1023;
            float2 o0; o0.x = acc[nf][0]; o0.y = acc[nf][1];
            float2 o1; o1.x = acc[nf][2]; o1.y = acc[nf][3];
            *(float2*)(out + (((b0*8 + h)*1024) + t0)*8 + dh) = o0;
            *(float2*)(out + (((b1*8 + h)*1024) + t1)*8 + dh) = o1;
        }
    }
}

// ---------------- FUSED: wo + resid + ln2 + ffn1 + gelu + ffn2 + resid --------
#define FUSED_SMEM (17408 + 6*TSZ)
__global__ __launch_bounds__(256) void attn_ffn_kernel(
        const float* __restrict__ attnIn,
        const uint32_t* __restrict__ WpH, const uint32_t* __restrict__ WpM,
        int woTile, int f1Tile0, int f2Tile0,
        const float* __restrict__ wo_b,
        const float* __restrict__ ln2s, const float* __restrict__ ln2b,
        const float* __restrict__ b1, const float* __restrict__ b2,
        float* __restrict__ h) {
    extern __shared__ char smem[];
    float (*Hs)[68] = (float(*)[68])smem;
    XT* Xh = (XT*)(smem + 17408);
    XT* Xm = (XT*)(smem + 17408 + TSZ);
    WT* Wh = (WT*)(smem + 17408 + 2*TSZ);
    WT* Wm = (WT*)(smem + 17408 + 3*TSZ);
    XT* Yh = (XT*)(smem + 17408 + 4*TSZ);
    XT* Ym = (XT*)(smem + 17408 + 5*TSZ);

    int tid = threadIdx.x;
    long row0 = (long)blockIdx.x * 64;
    int w = tid >> 5, lane = tid & 31;
    int gid = lane >> 2, t4 = lane & 3;
    int mb = (w & 3) * 16, nb = (w >> 2) * 32;

    pack_x64(attnIn, row0, ND, 0, nullptr, nullptr, false, Xh, Xm, tid);
    copy_w64(WpH, WpM, woTile, Wh, Wm, tid);
    __syncthreads();
    float acc[4][4] = {};
    mma64_compute(Xh, Xm, Wh, Wm, acc, mb, nb, gid, t4);
#pragma unroll
    for (int nf = 0; nf < 4; nf++) {
        int col = nb + nf*8 + t4*2;
        float2 bb = *(const float2*)(wo_b + col);
        long r0 = row0 + mb + gid, r1 = r0 + 8;
        float2 rr0 = *(const float2*)(h + r0*ND + col);
        float2 rr1 = *(const float2*)(h + r1*ND + col);
        Hs[mb+gid  ][col]   = acc[nf][0] + bb.x + rr0.x;
        Hs[mb+gid  ][col+1] = acc[nf][1] + bb.y + rr0.y;
        Hs[mb+gid+8][col]   = acc[nf][2] + bb.x + rr1.x;
        Hs[mb+gid+8][col+1] = acc[nf][3] + bb.y + rr1.y;
    }
    __syncthreads();

    {
        int r = tid >> 2, q = (tid & 3) * 16;
        float xv[16];
#pragma unroll
        for (int j = 0; j < 16; j++) xv[j] = Hs[r][q+j];
        float sum = 0.f;
#pragma unroll
        for (int j = 0; j < 16; j++) sum += xv[j];
        sum += __shfl_xor_sync(~0u, sum, 1);
        sum += __shfl_xor_sync(~0u, sum, 2);
        float mu = sum * (1.f/64.f);
        float vs = 0.f;
#pragma unroll
        for (int j = 0; j < 16; j++) { float d = xv[j] - mu; vs += d*d; }
        vs += __shfl_xor_sync(~0u, vs, 1);
        vs += __shfl_xor_sync(~0u, vs, 2);
        float inv = rsqrtf(vs * (1.f/64.f) + 1e-5f);
        int p0 = q >> 1;
#pragma unroll
        for (int u = 0; u < 8; u++) {
            float y0 = (xv[2*u]   - mu) * inv * ln2s[q+2*u]   + ln2b[q+2*u];
            float y1 = (xv[2*u+1] - mu) * inv * ln2s[q+2*u+1] + ln2b[q+2*u+1];
            uint32_t hh, m_;
            pack2(y0, y1, hh, m_);
            Xh[r][p0+u] = hh; Xm[r][p0+u] = m_;
        }
    }

    float acc2[4][4] = {};
    for (int c = 0; c < 4; c++) {
        __syncthreads();
        copy_w64(WpH, WpM, f1Tile0 + c, Wh, Wm, tid);
        __syncthreads();
        float ya[4][4] = {};
        mma64_compute(Xh, Xm, Wh, Wm, ya, mb, nb, gid, t4);
#pragma unroll
        for (int nf = 0; nf < 4; nf++) {
            int col = c*64 + nb + nf*8 + t4*2;
            float2 bb = *(const float2*)(b1 + col);
            float z0 = ya[nf][0] + bb.x, z1 = ya[nf][1] + bb.y;
            float z2 = ya[nf][2] + bb.x, z3 = ya[nf][3] + bb.y;
            float y0 = 0.5f*z0*(1.f + erff(z0*0.70710678118654752f));
            float y1 = 0.5f*z1*(1.f + erff(z1*0.70710678118654752f));
            float y2 = 0.5f*z2*(1.f + erff(z2*0.70710678118654752f));
            float y3 = 0.5f*z3*(1.f + erff(z3*0.70710678118654752f));
            int pi = (nb >> 1) + nf*4 + t4;
            uint32_t hh, m_;
            pack2(y0, y1, hh, m_); Yh[mb+gid  ][pi] = hh; Ym[mb+gid  ][pi] = m_;
            pack2(y2, y3, hh, m_); Yh[mb+gid+8][pi] = hh; Ym[mb+gid+8][pi] = m_;
        }
        __syncthreads();
        copy_w64(WpH, WpM, f2Tile0 + c, Wh, Wm, tid);
        __syncthreads();
        mma64_compute(Yh, Ym, Wh, Wm, acc2, mb, nb, gid, t4);
    }

#pragma unroll
    for (int nf = 0; nf < 4; nf++) {
        int col = nb + nf*8 + t4*2;
        float2 bb = *(const float2*)(b2 + col);
        long r0 = row0 + mb + gid, r1 = r0 + 8;
        float2 o0, o1;
        o0.x = acc2[nf][0] + bb.x + Hs[mb+gid  ][col];
        o0.y = acc2[nf][1] + bb.y + Hs[mb+gid  ][col+1];
        o1.x = acc2[nf][2] + bb.x + Hs[mb+gid+8][col];
        o1.y = acc2[nf][3] + bb.y + Hs[mb+gid+8][col+1];
        *(float2*)(h + r0*ND + col) = o0;
        *(float2*)(h + r1*ND + col) = o1;
    }
}

// ---------------- MERGED attention: local (blocks<1024) + global --------------
// local: 256 threads handle a pair of adjacent windows sharing a 512-row span.
__global__ __launch_bounds__(256) void merged_attn_kernel(
        const float* __restrict__ q, const float* __restrict__ k,
        const float* __restrict__ v, float* __restrict__ attn) {
    __shared__ __align__(16) float Ks[512][8];
    __shared__ __align__(16) float Vs[512][8];
    __shared__ float wmax[2][4];
    __shared__ float red[8][72];
    __shared__ float M[8];
    __shared__ __align__(16) float C[64];

    int tid = threadIdx.x;
    if (blockIdx.x < 1024) {
        // ---------- local path ----------
        int bid = blockIdx.x;                  // b*16 + h*4 + wpair
        int wpair = bid & 3, h = (bid >> 2) & 3, b = bid >> 4;
        int wb = wpair * 2;
        int half = tid >> 7;                   // 0/1 -> window wb / wb+1
        int t128 = tid & 127;
        int w = wb + half;
        int base = ((b*8 + h)*1024) * 8;
        int ts = (wb - 1) * 128;               // span start token
        // load 512-row span (zero padded)
        for (int idx = tid; idx < 1024; idx += 256) {
            int j = idx >> 1, hf = (idx & 1) * 4;
            int tt = ts + j;
            float4 kv = {0,0,0,0}, vv = {0,0,0,0};
            if (tt >= 0 && tt < 1024) {
                kv = *(const float4*)(k + base + tt*8 + hf);
                vv = *(const float4*)(v + base + tt*8 + hf);
            }
            *(float4*)&Ks[j][hf] = kv;
            *(float4*)&Vs[j][hf] = vv;
        }
        __syncthreads();
        int off = half * 128;                  // window offset within span
        float nm = 0.f;
        for (int r = t128; r < 384; r += 128) {
            float4 k0 = *(const float4*)&Ks[off + r][0];
            float4 k1 = *(const float4*)&Ks[off + r][4];
            float s2 = k0.x*k0.x + k0.y*k0.y + k0.z*k0.z + k0.w*k0.w
                     + k1.x*k1.x + k1.y*k1.y + k1.z*k1.z + k1.w*k1.w;
            nm = fmaxf(nm, s2);
        }
#pragma unroll
        for (int o = 16; o; o >>= 1) nm = fmaxf(nm, __shfl_xor_sync(~0u, nm, o));
        if ((t128 & 31) == 0) wmax[half][t128 >> 5] = nm;
        __syncthreads();
        float kmax2 = fmaxf(fmaxf(wmax[half][0], wmax[half][1]),
                            fmaxf(wmax[half][2], wmax[half][3]));

        int jlo = (w == 0) ? 128 : 0;
        int jhi = (w == 7) ? 256 : 384;
        int t = w*128 + t128;
        float4 q0 = *(const float4*)(q + base + t*8);
        float4 q1 = *(const float4*)(q + base + t*8 + 4);
        const float scale = 0.35355339059327373f;
        const float L2E = 1.4426950408889634f;
        float qn2 = q0.x*q0.x + q0.y*q0.y + q0.z*q0.z + q0.w*q0.w
                  + q1.x*q1.x + q1.y*q1.y + q1.z*q1.z + q1.w*q1.w;
        float sc = scale * L2E;
        ull q01 = pk2(q0.x*sc, q0.y*sc), q23 = pk2(q0.z*sc, q0.w*sc);
        ull q45 = pk2(q1.x*sc, q1.y*sc), q67 = pk2(q1.z*sc, q1.w*sc);
        float m2 = sc * sqrtf(qn2 * kmax2);
        float l = 0.f;
        ull a0 = 0, a1 = 0, a2 = 0, a3 = 0;
        for (int j = jlo; j < jhi; j++) {
            int sj = off + j;
            ulonglong2 ka = *(const ulonglong2*)&Ks[sj][0];
            ulonglong2 kb = *(const ulonglong2*)&Ks[sj][4];
            ull d2 = fma2(q01, ka.x, fma2(q23, ka.y, fma2(q45, kb.x, fma2(q67, kb.y, 0ULL))));
            float slo, shi; upk2(d2, slo, shi);
            float p = ex2(slo + shi - m2);
            l += p;
            ull pp = pk2(p, p);
            ulonglong2 va = *(const ulonglong2*)&Vs[sj][0];
            ulonglong2 vb = *(const ulonglong2*)&Vs[sj][4];
            a0 = fma2(pp, va.x, a0); a1 = fma2(pp, va.y, a1);
            a2 = fma2(pp, vb.x, a2); a3 = fma2(pp, vb.y, a3);
        }
        float inv = 1.f / l;
        float e0,e1,e2,e3,e4,e5,e6,e7;
        upk2(a0, e0, e1); upk2(a1, e2, e3); upk2(a2, e4, e5); upk2(a3, e6, e7);
        float4 o0, o1;
        o0.x = e0*inv; o0.y = e1*inv; o0.z = e2*inv; o0.w = e3*inv;
        o1.x = e4*inv; o1.y = e5*inv; o1.z = e6*inv; o1.w = e7*inv;
        long ob = ((long)(b*1024 + t)*64) + h*8;
        *(float4*)(attn + ob) = o0;
        *(float4*)(attn + ob + 4) = o1;
        return;
    }

    // ---------- global path ----------
    int gb = blockIdx.x - 1024;
    int b = gb >> 2, h = gb & 3;
    int base = ((b*8 + 4 + h)*1024) * 8;
    int warp = tid >> 5, lane = tid & 31;

    float mx[8];
#pragma unroll
    for (int d = 0; d < 8; d++) mx[d] = -1e30f;
    for (int t = tid; t < 1024; t += 256) {
        float4 k0 = *(const float4*)(k + base + t*8);
        float4 k1 = *(const float4*)(k + base + t*8 + 4);
        mx[0]=fmaxf(mx[0],k0.x); mx[1]=fmaxf(mx[1],k0.y); mx[2]=fmaxf(mx[2],k0.z); mx[3]=fmaxf(mx[3],k0.w);
        mx[4]=fmaxf(mx[4],k1.x); mx[5]=fmaxf(mx[5],k1.y); mx[6]=fmaxf(mx[6],k1.z); mx[7]=fmaxf(mx[7],k1.w);
    }
#pragma unroll
    for (int d = 0; d < 8; d++)
        for (int o = 16; o; o >>= 1) mx[d] = fmaxf(mx[d], __shfl_xor_sync(~0u, mx[d], o));
    if (lane == 0)
        for (int d = 0; d < 8; d++) red[warp][d] = mx[d];
    __syncthreads();
    if (tid < 8) {
        float m_ = red[0][tid];
        for (int wv = 1; wv < 8; wv++) m_ = fmaxf(m_, red[wv][tid]);
        M[tid] = m_;
    }
    __syncthreads();

    float Z[8] = {};
    ull ctx2[32];
#pragma unroll
    for (int i = 0; i < 32; i++) ctx2[i] = 0ULL;
    for (int t = tid; t < 1024; t += 256) {
        float4 k0 = *(const float4*)(k + base + t*8);
        float4 k1 = *(const float4*)(k + base + t*8 + 4);
        ulonglong2 va = *(const ulonglong2*)(v + base + t*8);
        ulonglong2 vb = *(const ulonglong2*)(v + base + t*8 + 4);
        ull vv[4] = {va.x, va.y, vb.x, vb.y};
        float kr[8] = {k0.x,k0.y,k0.z,k0.w,k1.x,k1.y,k1.z,k1.w};
#pragma unroll
        for (int d = 0; d < 8; d++) {
            float e_ = __expf(kr[d] - M[d]);
            Z[d] += e_;
            ull pd = pk2(e_, e_);
#pragma unroll
            for (int e2i = 0; e2i < 4; e2i++) ctx2[d*4 + e2i] = fma2(pd, vv[e2i], ctx2[d*4 + e2i]);
        }
    }
    float ctx[64];
#pragma unroll
    for (int i = 0; i < 32; i++) upk2(ctx2[i], ctx[2*i], ctx[2*i+1]);
#pragma unroll
    for (int i = 0; i < 8; i++)
        for (int o = 16; o; o >>= 1) Z[i] += __shfl_xor_sync(~0u, Z[i], o);
#pragma unroll
    for (int i = 0; i < 64; i++)
        for (int o = 16; o; o >>= 1) ctx[i] += __shfl_xor_sync(~0u, ctx[i], o);
    if (lane == 0) {
        for (int i = 0; i < 8; i++)  red[warp][i] = Z[i];
        for (int i = 0; i < 64; i++) red[warp][8 + i] = ctx[i];
    }
    __syncthreads();
    if (tid < 64) {
        float s = 0.f, z = 0.f;
        int d = tid >> 3;
        for (int wv = 0; wv < 8; wv++) { s += red[wv][8 + tid]; z += red[wv][d]; }
        C[tid] = s / z;
    }
    __syncthreads();

    const float scale = 0.35355339059327373f;
    for (int t = tid; t < 1024; t += 256) {
        float4 q0 = *(const float4*)(q + base + t*8);
        float4 q1 = *(const float4*)(q + base + t*8 + 4);
        float qr[8] = {q0.x,q0.y,q0.z,q0.w,q1.x,q1.y,q1.z,q1.w};
        float qm = -1e30f;
#pragma unroll
        for (int d = 0; d < 8; d++) qm = fmaxf(qm, qr[d]);
        float qs = 0.f;
#pragma unroll
        for (int d = 0; d < 8; d++) { qr[d] = __expf(qr[d] - qm); qs += qr[d]; }
        float inv = scale / qs;
        ull o2[4] = {0ULL, 0ULL, 0ULL, 0ULL};
#pragma unroll
        for (int d = 0; d < 8; d++) {
            float p = qr[d] * inv;
            ull pd = pk2(p, p);
            const ulonglong2* Cd = (const ulonglong2*)&C[d*8];
            ulonglong2 c0 = Cd[0], c1 = Cd[1];
            o2[0] = fma2(pd, c0.x, o2[0]); o2[1] = fma2(pd, c0.y, o2[1]);
            o2[2] = fma2(pd, c1.x, o2[2]); o2[3] = fma2(pd, c1.y, o2[3]);
        }
        float e0,e1,e2,e3,e4,e5,e6,e7;
        upk2(o2[0], e0, e1); upk2(o2[1], e2, e3); upk2(o2[2], e4, e5); upk2(o2[3], e6, e7);
        long ob = (long)(b*1024 + t)*64 + (4 + h)*8;
        float4 oo0, oo1;
        oo0.x=e0; oo0.y=e1; oo0.z=e2; oo0.w=e3;
        oo1.x=e4; oo1.y=e5; oo1.z=e6; oo1.w=e7;
        *(float4*)(attn + ob) = oo0;
        *(float4*)(attn + ob + 4) = oo1;
    }
}

// ---------------- collapse: 256 threads, split-K + shfl ----------------------
__global__ __launch_bounds__(256) void collapse_kernel(
        const float* __restrict__ h, const float* __restrict__ cw,
        const float* __restrict__ cb, float* __restrict__ out) {
    __shared__ float Xs[64][68];
    __shared__ float Ws[64][NDIN];
    __shared__ float Bs[NDIN];
    int tid = threadIdx.x;                 // 256
    int row0 = blockIdx.x * 64;
    for (int idx = tid; idx < 1024; idx += 256) {
        int i = idx >> 4, j = (idx & 15) * 4;
        *(float4*)&Xs[i][j] = *(const float4*)(h + (long)(row0 + i)*ND + j);
    }
    for (int idx = tid; idx < 64*NDIN; idx += 256) Ws[idx/NDIN][idx%NDIN] = cw[idx];
    if (tid < NDIN) Bs[tid] = cb[tid];
    __syncthreads();
    int r = tid >> 2, qk = (tid & 3) * 16;
    float acc[NDIN] = {};
    for (int kk = qk; kk < qk + 16; kk++) {
        float xv = Xs[r][kk];
#pragma unroll
        for (int j = 0; j < NDIN; j++) acc[j] += xv * Ws[kk][j];
    }
#pragma unroll
    for (int j = 0; j < NDIN; j++) {
        acc[j] += __shfl_xor_sync(~0u, acc[j], 1);
        acc[j] += __shfl_xor_sync(~0u, acc[j], 2);
    }
    if ((tid & 3) == 0) {
#pragma unroll
        for (int j = 0; j < NDIN; j++) out[(row0 + r)*NDIN + j] = acc[j] + Bs[j];
    }
}

// ---------------- launch ------------------------------------------------------
extern "C" void kernel_launch(void* const* d_in, const int* in_sizes, int n_in,
                              void* d_out, int out_size) {
    const float* x          = (const float*)d_in[0];
    const float* pos_emb    = (const float*)d_in[1];
    const float* expand_w   = (const float*)d_in[2];
    const float* expand_b   = (const float*)d_in[3];
    const float* emb_w      = (const float*)d_in[4];
    const float* emb_b      = (const float*)d_in[5];
    const float* conv_w     = (const float*)d_in[6];
    const float* conv_b     = (const float*)d_in[7];
    const float* ln1_s      = (const float*)d_in[8];
    const float* ln1_b      = (const float*)d_in[9];
    const float* wq         = (const float*)d_in[10];
    const float* wk         = (const float*)d_in[11];
    const float* wv         = (const float*)d_in[12];
    const float* wo         = (const float*)d_in[13];
    const float* wo_b       = (const float*)d_in[14];
    const float* ln2_s      = (const float*)d_in[15];
    const float* ln2_b      = (const float*)d_in[16];
    const float* ff_w1      = (const float*)d_in[17];
    const float* ff_b1      = (const float*)d_in[18];
    const float* ff_w2      = (const float*)d_in[19];
    const float* ff_b2      = (const float*)d_in[20];
    const float* collapse_w = (const float*)d_in[21];
    const float* collapse_b = (const float*)d_in[22];
    float* out = (float*)d_out;

    float *ph, *pq, *pk, *pv, *pattn, *pWc, *pbc;
    uint32_t *pWpH, *pWpM, *pAH, *pAM, *pBH, *pBM;
    cudaGetSymbolAddress((void**)&ph,   g_h);
    cudaGetSymbolAddress((void**)&pq,   g_q);
    cudaGetSymbolAddress((void**)&pk,   g_k);
    cudaGetSymbolAddress((void**)&pv,   g_v);
    cudaGetSymbolAddress((void**)&pattn,g_attn);
    cudaGetSymbolAddress((void**)&pWc,  g_Wc);
    cudaGetSymbolAddress((void**)&pbc,  g_bc);
    cudaGetSymbolAddress((void**)&pWpH, g_WpH);
    cudaGetSymbolAddress((void**)&pWpM, g_WpM);
    cudaGetSymbolAddress((void**)&pAH,  g_AH);
    cudaGetSymbolAddress((void**)&pAM,  g_AM);
    cudaGetSymbolAddress((void**)&pBH,  g_BH);
    cudaGetSymbolAddress((void**)&pBM,  g_BM);

    static bool attrSet = false;
    if (!attrSet) {
        cudaFuncSetAttribute(attn_ffn_kernel, cudaFuncAttributeMaxDynamicSharedMemorySize, FUSED_SMEM);
        cudaFuncSetAttribute(conv_kernel, cudaFuncAttributeMaxDynamicSharedMemorySize, CONV_SMEM);
        cudaFuncSetAttribute(lnqkv_kernel, cudaFuncAttributeMaxDynamicSharedMemorySize, QKV_SMEM);
        attrSet = true;
    }

    precompute_kernel<<<1, 64>>>(expand_w, expand_b, emb_w, emb_b, pWc, pbc);
    packw_kernel<<<24, 256>>>(wq, wk, wv, wo, ff_w1, ff_w2, pWpH, pWpM);
    packa_kernel<<<(1024*1536)/256, 256>>>(conv_w, pAH, pAM);
    packbx_kernel<<<(1536*4096)/256, 256>>>(x, pWc, pbc, pBH, pBM);
    conv_kernel<<<dim3(4096/CBN, 1024/CBM), 256, CONV_SMEM>>>(pAH, pAM, pBH, pBM, conv_b, pos_emb, ph);

    for (int l = 0; l < 2; l++) {
        int tb = l*12;
        lnqkv_kernel<<<NTOK/64, 256, QKV_SMEM>>>(ph, ln1_s + l*64, ln1_b + l*64,
                                                 pWpH, pWpM, tb + 0, pq, pk, pv);
        merged_attn_kernel<<<1024 + 256, 256>>>(pq, pk, pv, pattn);
        attn_ffn_kernel<<<NTOK/64, 256, FUSED_SMEM>>>(
            pattn, pWpH, pWpM, tb + 3, tb + 4, tb + 8,
            wo_b + l*64, ln2_s + l*64, ln2_b + l*64,
            ff_b1 + l*256, ff_b2 + l*64, ph);
    }
    collapse_kernel<<<NTOK/64, 256>>>(ph, collapse_w, collapse_b, out);
}

// round 17
// speedup vs baseline: 4.7810x; 1.1220x over previous
#include <cuda_runtime.h>
#include <cuda_bf16.h>
#include <cuda_fp16.h>
#include <cstdint>
#include <math.h>

#define NB 64
#define NT 1024
#define NDIN 5
#define ND 64
#define NTOK (NB*NT)           // 65536

// ---------------- scratch ------------------------------------------------------
__device__ float g_h[NTOK*ND];
__device__ float g_q[NTOK*ND];
__device__ float g_k[NTOK*ND];
__device__ float g_v[NTOK*ND];
__device__ float g_attn[NTOK*ND];
__device__ float g_Wc[NDIN*ND];
__device__ float g_bc[ND];
__device__ uint32_t g_WpH[24*2048], g_WpM[24*2048];
// conv A packed fp16: [1024 m][1536 kpair] (hi / mid)
__device__ uint32_t g_AH[1024*1536], g_AM[1024*1536];
// conv B packed fp16 single (x64 scaled): [1536 kpair][4096 n]
__device__ uint32_t g_BH[1536*4096];

typedef unsigned long long ull;

__device__ __forceinline__ ull pk2(float lo, float hi) {
    ull r; asm("mov.b64 %0, {%1,%2};" : "=l"(r) : "f"(lo), "f"(hi)); return r;
}
__device__ __forceinline__ void upk2(ull v, float& lo, float& hi) {
    asm("mov.b64 {%0,%1}, %2;" : "=f"(lo), "=f"(hi) : "l"(v));
}
__device__ __forceinline__ ull fma2(ull a, ull b, ull c) {
    ull d; asm("fma.rn.f32x2 %0, %1, %2, %3;" : "=l"(d) : "l"(a), "l"(b), "l"(c)); return d;
}
__device__ __forceinline__ float ex2(float x) {
    float r; asm("ex2.approx.ftz.f32 %0, %1;" : "=f"(r) : "f"(x)); return r;
}

// bf16 split (GEMM family, unchanged)
__device__ __forceinline__ void pack2(float x0, float x1, uint32_t& hi, uint32_t& mid) {
    uint32_t h;
    asm("cvt.rn.bf16x2.f32 %0, %1, %2;" : "=r"(h) : "f"(x1), "f"(x0));
    float f0 = __uint_as_float(h << 16);
    float f1 = __uint_as_float(h & 0xFFFF0000u);
    float r0 = x0 - f0, r1 = x1 - f1;
    asm("cvt.rn.bf16x2.f32 %0, %1, %2;" : "=r"(mid) : "f"(r1), "f"(r0));
    hi = h;
}
__device__ __forceinline__ void mma_bf16(float* c, const uint32_t* a, const uint32_t* b) {
    asm volatile("mma.sync.aligned.m16n8k16.row.col.f32.bf16.bf16.f32 "
        "{%0,%1,%2,%3}, {%4,%5,%6,%7}, {%8,%9}, {%0,%1,%2,%3};"
        : "+f"(c[0]), "+f"(c[1]), "+f"(c[2]), "+f"(c[3])
        : "r"(a[0]), "r"(a[1]), "r"(a[2]), "r"(a[3]), "r"(b[0]), "r"(b[1]));
}

// fp16 split helpers (conv)
__device__ __forceinline__ void pack2h(float x0, float x1, uint32_t& hi, uint32_t& mid) {
    __half2 h = __floats2half2_rn(x0, x1);
    float2 f = __half22float2(h);
    __half2 m = __floats2half2_rn(x0 - f.x, x1 - f.y);
    hi = *(uint32_t*)&h; mid = *(uint32_t*)&m;
}
__device__ __forceinline__ uint32_t pack1h(float x0, float x1) {
    __half2 h = __floats2half2_rn(x0, x1);
    return *(uint32_t*)&h;
}
__device__ __forceinline__ void mma_f16(float* c, const uint32_t* a, const uint32_t* b) {
    asm volatile("mma.sync.aligned.m16n8k16.row.col.f32.f16.f16.f32 "
        "{%0,%1,%2,%3}, {%4,%5,%6,%7}, {%8,%9}, {%0,%1,%2,%3};"
        : "+f"(c[0]), "+f"(c[1]), "+f"(c[2]), "+f"(c[3])
        : "r"(a[0]), "r"(a[1]), "r"(a[2]), "r"(a[3]), "r"(b[0]), "r"(b[1]));
}

// ---------------- precompute combined expand@emb ------------------------------
__global__ void precompute_kernel(const float* __restrict__ ew, const float* __restrict__ eb,
                                  const float* __restrict__ mw, const float* __restrict__ mb,
                                  float* __restrict__ Wc, float* __restrict__ bc) {
    int j = threadIdx.x;
    for (int i = 0; i < NDIN; i++) {
        float s = 0.f;
        for (int d = 0; d < ND; d++) s += ew[i*ND + d] * mw[d*ND + j];
        Wc[i*ND + j] = s;
    }
    float s = mb[j];
    for (int d = 0; d < ND; d++) s += eb[d] * mw[d*ND + j];
    bc[j] = s;
}

// ---------------- weight pre-pack (bf16, GEMM family) --------------------------
__global__ void packw_kernel(const float* __restrict__ wq, const float* __restrict__ wk,
                             const float* __restrict__ wv, const float* __restrict__ wo,
                             const float* __restrict__ w1, const float* __restrict__ w2,
                             uint32_t* __restrict__ WpH, uint32_t* __restrict__ WpM) {
    int tile = blockIdx.x;
    int l = tile / 12, t = tile - l*12;
    const float* src; int ldw, coloff;
    if (t == 0)      { src = wq + l*4096; ldw = 64; coloff = 0; }
    else if (t == 1) { src = wk + l*4096; ldw = 64; coloff = 0; }
    else if (t == 2) { src = wv + l*4096; ldw = 64; coloff = 0; }
    else if (t == 3) { src = wo + l*4096; ldw = 64; coloff = 0; }
    else if (t < 8)  { src = w1 + l*64*256; ldw = 256; coloff = (t-4)*64; }
    else             { src = w2 + l*256*64 + (t-8)*64*64; ldw = 64; coloff = 0; }
    int tid = threadIdx.x;
    int n = tid & 63, p0 = (tid >> 6) * 8;
    uint32_t* dh = WpH + tile*2048 + n*32;
    uint32_t* dm = WpM + tile*2048 + n*32;
#pragma unroll
    for (int u = 0; u < 8; u++) {
        int k = 2*(p0+u);
        float w0 = src[(long)k*ldw + coloff + n];
        float w1v = src[(long)(k+1)*ldw + coloff + n];
        uint32_t h, m_;
        pack2(w0, w1v, h, m_);
        dh[p0+u] = h; dm[p0+u] = m_;
    }
}

// ---------------- conv A pre-pack (fp16 split) ---------------------------------
__global__ void packa_kernel(const float* __restrict__ A,
                             uint32_t* __restrict__ AH, uint32_t* __restrict__ AM) {
    int idx = blockIdx.x*256 + threadIdx.x;
    float2 v = *(const float2*)(A + (long)idx*2);
    uint32_t h, m_;
    pack2h(v.x, v.y, h, m_);
    AH[idx] = h; AM[idx] = m_;
}

// ---------------- conv B pre-pack WITH fused expand (fp16 single, x64) ---------
__global__ void packbx_kernel(const float* __restrict__ x,
                              const float* __restrict__ Wc, const float* __restrict__ bc,
                              uint32_t* __restrict__ BH) {
    int idx = blockIdx.x*256 + threadIdx.x;       // [1536*4096)
    int kp2 = idx >> 12;
    int n = idx & 4095;
    int b = n >> 6, d = n & 63;
    int K0 = kp2*2, K1 = K0 + 1;
    int kt0 = K0/3, kq0 = K0 - kt0*3;
    int kt1 = K1/3, kq1 = K1 - kt1*3;
    int d0 = d + kq0 - 1, d1 = d + kq1 - 1;
    float v0 = 0.f, v1 = 0.f;
    if (d0 >= 0 && d0 < 64) {
        const float* xr = x + ((long)(b << 10) + kt0) * NDIN;
        v0 = bc[d0];
#pragma unroll
        for (int i = 0; i < NDIN; i++) v0 += xr[i] * Wc[i*ND + d0];
    }
    if (d1 >= 0 && d1 < 64) {
        const float* xr = x + ((long)(b << 10) + kt1) * NDIN;
        v1 = bc[d1];
#pragma unroll
        for (int i = 0; i < NDIN; i++) v1 += xr[i] * Wc[i*ND + d1];
    }
    BH[idx] = pack1h(v0 * 64.f, v1 * 64.f);
}

// ---------------- conv as GEMM: fp16, A 2-term x B 1-term ----------------------
#define CBM 128
#define CBN 128
#define CBK 16
#define CONV_SMEM (3*2*128*12*4)   // 36864 B
__global__ __launch_bounds__(256) void conv_kernel(
        const uint32_t* __restrict__ AH, const uint32_t* __restrict__ AM,
        const uint32_t* __restrict__ BH,
        const float* __restrict__ conv_b, const float* __restrict__ pos_emb,
        float* __restrict__ Hout) {
    extern __shared__ uint32_t cs[];
    uint32_t (*Ah)[128][12] = (uint32_t(*)[128][12])cs;
    uint32_t (*Am)[128][12] = (uint32_t(*)[128][12])(cs + 2*128*12);
    uint32_t (*Bh)[128][12] = (uint32_t(*)[128][12])(cs + 4*128*12);
    int tid = threadIdx.x;
    int m0 = blockIdx.y * CBM;
    int n0 = blockIdx.x * CBN;

    int arow = tid >> 1;
    int ap = (tid & 1) * 4;
    int bj = tid & 127;
    int bp = (tid >> 7) * 4;

    int w = tid >> 5, lane = tid & 31;
    int gid = lane >> 2, t4 = lane & 3;
    int warpM = w >> 1, warpN = w & 1;
    int mbase = warpM * 32, nbase = warpN * 64;

    float acc[2][8][4];
#pragma unroll
    for (int mt = 0; mt < 2; mt++)
#pragma unroll
        for (int nt = 0; nt < 8; nt++)
#pragma unroll
            for (int r = 0; r < 4; r++) acc[mt][nt][r] = 0.f;

    auto loadA = [&](int k0, int buf) {
        const uint32_t* ph = AH + (long)(m0 + arow)*1536 + (k0 >> 1) + ap;
        const uint32_t* pm = AM + (long)(m0 + arow)*1536 + (k0 >> 1) + ap;
        uint4 vh = *(const uint4*)ph;
        uint4 vm = *(const uint4*)pm;
        Ah[buf][arow][ap+0] = vh.x; Ah[buf][arow][ap+1] = vh.y;
        Ah[buf][arow][ap+2] = vh.z; Ah[buf][arow][ap+3] = vh.w;
        Am[buf][arow][ap+0] = vm.x; Am[buf][arow][ap+1] = vm.y;
        Am[buf][arow][ap+2] = vm.z; Am[buf][arow][ap+3] = vm.w;
    };
    auto loadB = [&](int k0, int buf) {
        long base = (long)((k0 >> 1) + bp) * 4096 + n0 + bj;
#pragma unroll
        for (int u = 0; u < 4; u++)
            Bh[buf][bj][bp+u] = BH[base + (long)u*4096];
    };

    loadA(0, 0); loadB(0, 0);
    __syncthreads();

    int cur = 0;
    for (int k0 = CBK; k0 <= 3072; k0 += CBK) {
        if (k0 < 3072) { loadA(k0, cur ^ 1); loadB(k0, cur ^ 1); }
        uint32_t ah[2][4], am[2][4];
#pragma unroll
        for (int mt = 0; mt < 2; mt++) {
            int r0 = mbase + mt*16 + gid;
            ah[mt][0] = Ah[cur][r0  ][t4];   ah[mt][1] = Ah[cur][r0+8][t4];
            ah[mt][2] = Ah[cur][r0  ][t4+4]; ah[mt][3] = Ah[cur][r0+8][t4+4];
            am[mt][0] = Am[cur][r0  ][t4];   am[mt][1] = Am[cur][r0+8][t4];
            am[mt][2] = Am[cur][r0  ][t4+4]; am[mt][3] = Am[cur][r0+8][t4+4];
        }
#pragma unroll
        for (int nt = 0; nt < 8; nt++) {
            int n = nbase + nt*8 + gid;
            uint32_t bhf[2] = { Bh[cur][n][t4], Bh[cur][n][t4+4] };
#pragma unroll
            for (int mt = 0; mt < 2; mt++) {
                mma_f16(acc[mt][nt], ah[mt], bhf);
                mma_f16(acc[mt][nt], am[mt], bhf);
            }
        }
        __syncthreads();
        cur ^= 1;
    }

    const float INV64 = 1.f/64.f;
#pragma unroll
    for (int mt = 0; mt < 2; mt++) {
        int row0r = m0 + mbase + mt*16 + gid;
        float cb0 = conv_b[row0r];
        float cb1 = conv_b[row0r + 8];
#pragma unroll
        for (int nt = 0; nt < 8; nt++) {
            int coln = n0 + nbase + nt*8 + t4*2;
            int b_ = coln >> 6, d_ = coln & 63;
            float2 pe0 = *(const float2*)(pos_emb + row0r*64 + d_);
            float2 pe1 = *(const float2*)(pos_emb + (row0r+8)*64 + d_);
            float2 o0, o1;
            o0.x = acc[mt][nt][0]*INV64 + cb0 + pe0.x;
            o0.y = acc[mt][nt][1]*INV64 + cb0 + pe0.y;
            o1.x = acc[mt][nt][2]*INV64 + cb1 + pe1.x;
            o1.y = acc[mt][nt][3]*INV64 + cb1 + pe1.y;
            *(float2*)(Hout + ((long)(b_ << 10) + row0r)*64 + d_) = o0;
            *(float2*)(Hout + ((long)(b_ << 10) + row0r + 8)*64 + d_) = o1;
        }
    }
}

// ================= mma GEMM helpers (bf16x3, unchanged) ========================
typedef uint32_t XT[36];
typedef uint32_t WT[36];

__device__ __forceinline__ void pack_x64(const float* __restrict__ X, long row0, int ldx, int coloff,
                                         const float* __restrict__ lns, const float* __restrict__ lnb,
                                         bool doLN, XT* Xh, XT* Xm, int tid) {
    int r = tid >> 2, q = (tid & 3) * 16;
    const float* row = X + (row0 + r) * (long)ldx + coloff + q;
    float xv[16];
    *(float4*)&xv[0]  = *(const float4*)(row);
    *(float4*)&xv[4]  = *(const float4*)(row + 4);
    *(float4*)&xv[8]  = *(const float4*)(row + 8);
    *(float4*)&xv[12] = *(const float4*)(row + 12);
    if (doLN) {
        float sum = 0.f;
#pragma unroll
        for (int j = 0; j < 16; j++) sum += xv[j];
        sum += __shfl_xor_sync(~0u, sum, 1);
        sum += __shfl_xor_sync(~0u, sum, 2);
        float mu = sum * (1.f/64.f);
        float vs = 0.f;
#pragma unroll
        for (int j = 0; j < 16; j++) { float d = xv[j] - mu; vs += d*d; }
        vs += __shfl_xor_sync(~0u, vs, 1);
        vs += __shfl_xor_sync(~0u, vs, 2);
        float inv = rsqrtf(vs * (1.f/64.f) + 1e-5f);
#pragma unroll
        for (int j = 0; j < 16; j++) xv[j] = (xv[j] - mu) * inv * lns[q+j] + lnb[q+j];
    }
    int p0 = q >> 1;
#pragma unroll
    for (int u = 0; u < 8; u++) {
        uint32_t h, m_;
        pack2(xv[2*u], xv[2*u+1], h, m_);
        Xh[r][p0+u] = h; Xm[r][p0+u] = m_;
    }
}

__device__ __forceinline__ void copy_w64(const uint32_t* __restrict__ WpH,
                                         const uint32_t* __restrict__ WpM, int tile,
                                         WT* Wh, WT* Wm, int tid) {
    int n = tid >> 2, qp = (tid & 3) * 8;
    const uint32_t* sh = WpH + tile*2048 + n*32 + qp;
    const uint32_t* sm = WpM + tile*2048 + n*32 + qp;
    *(uint4*)&Wh[n][qp]   = *(const uint4*)sh;
    *(uint4*)&Wh[n][qp+4] = *(const uint4*)(sh+4);
    *(uint4*)&Wm[n][qp]   = *(const uint4*)sm;
    *(uint4*)&Wm[n][qp+4] = *(const uint4*)(sm+4);
}

__device__ __forceinline__ void mma64_compute(const XT* Xh, const XT* Xm,
                                              const WT* Wh, const WT* Wm,
                                              float acc[4][4], int mb, int nb, int gid, int t4) {
#pragma unroll
    for (int kc = 0; kc < 4; kc++) {
        int kp = kc*8;
        uint32_t ah[4], am[4];
        ah[0] = Xh[mb+gid  ][kp+t4];   ah[1] = Xh[mb+gid+8][kp+t4];
        ah[2] = Xh[mb+gid  ][kp+t4+4]; ah[3] = Xh[mb+gid+8][kp+t4+4];
        am[0] = Xm[mb+gid  ][kp+t4];   am[1] = Xm[mb+gid+8][kp+t4];
        am[2] = Xm[mb+gid  ][kp+t4+4]; am[3] = Xm[mb+gid+8][kp+t4+4];
#pragma unroll
        for (int nf = 0; nf < 4; nf++) {
            int n = nb + nf*8 + gid;
            uint32_t bh[2] = { Wh[n][kp+t4], Wh[n][kp+t4+4] };
            uint32_t bm[2] = { Wm[n][kp+t4], Wm[n][kp+t4+4] };
            mma_bf16(acc[nf], ah, bh);
            mma_bf16(acc[nf], ah, bm);
            mma_bf16(acc[nf], am, bh);
        }
    }
}

// ---------------- fused LN + QKV: all 3 W tiles resident ----------------------
#define TSZ (64*36*4)
#define QKV_SMEM (8*TSZ)
__global__ __launch_bounds__(256) void lnqkv_kernel(
        const float* __restrict__ X, const float* __restrict__ lns, const float* __restrict__ lnb,
        const uint32_t* __restrict__ WpH, const uint32_t* __restrict__ WpM, int tile0,
        float* __restrict__ q, float* __restrict__ k, float* __restrict__ v) {
    extern __shared__ char qsm[];
    XT* Xh = (XT*)qsm;
    XT* Xm = (XT*)(qsm + TSZ);
    int tid = threadIdx.x;
    long row0 = (long)blockIdx.x * 64;
    int w = tid >> 5, lane = tid & 31;
    int gid = lane >> 2, t4 = lane & 3;
    int mb = (w & 3) * 16, nb = (w >> 2) * 32;

    pack_x64(X, row0, ND, 0, lns, lnb, true, Xh, Xm, tid);
#pragma unroll
    for (int m = 0; m < 3; m++) {
        WT* Wh = (WT*)(qsm + (2 + 2*m)*TSZ);
        WT* Wm = (WT*)(qsm + (3 + 2*m)*TSZ);
        copy_w64(WpH, WpM, tile0 + m, Wh, Wm, tid);
    }
    __syncthreads();
    float* Om[3] = {q, k, v};
#pragma unroll
    for (int m = 0; m < 3; m++) {
        WT* Wh = (WT*)(qsm + (2 + 2*m)*TSZ);
        WT* Wm = (WT*)(qsm + (3 + 2*m)*TSZ);
        float acc[4][4] = {};
        mma64_compute(Xh, Xm, Wh, Wm, acc, mb, nb, gid, t4);
        float* out = Om[m];
        int dh = t4*2;
#pragma unroll
        for (int nf = 0; nf < 4; nf++) {
            int h = (nb >> 3) + nf;
            long gt0 = row0 + mb + gid;
            long gt1 = gt0 + 8;
            long b0 = gt0 >> 10, t0 = gt0 & 1023;
            long b1 = gt1 >> 10, t1 = gt1 & 1023;
            float2 o0; o0.x = acc[nf][0]; o0.y = acc[nf][1];
            float2 o1; o1.x = acc[nf][2]; o1.y = acc[nf][3];
            *(float2*)(out + (((b0*8 + h)*1024) + t0)*8 + dh) = o0;
            *(float2*)(out + (((b1*8 + h)*1024) + t1)*8 + dh) = o1;
        }
    }
}

// ---------------- FUSED: wo + resid + ln2 + ffn1 + gelu + ffn2 + resid --------
#define FUSED_SMEM (17408 + 6*TSZ)
__global__ __launch_bounds__(256) void attn_ffn_kernel(
        const float* __restrict__ attnIn,
        const uint32_t* __restrict__ WpH, const uint32_t* __restrict__ WpM,
        int woTile, int f1Tile0, int f2Tile0,
        const float* __restrict__ wo_b,
        const float* __restrict__ ln2s, const float* __restrict__ ln2b,
        const float* __restrict__ b1, const float* __restrict__ b2,
        float* __restrict__ h) {
    extern __shared__ char smem[];
    float (*Hs)[68] = (float(*)[68])smem;
    XT* Xh = (XT*)(smem + 17408);
    XT* Xm = (XT*)(smem + 17408 + TSZ);
    WT* Wh = (WT*)(smem + 17408 + 2*TSZ);
    WT* Wm = (WT*)(smem + 17408 + 3*TSZ);
    XT* Yh = (XT*)(smem + 17408 + 4*TSZ);
    XT* Ym = (XT*)(smem + 17408 + 5*TSZ);

    int tid = threadIdx.x;
    long row0 = (long)blockIdx.x * 64;
    int w = tid >> 5, lane = tid & 31;
    int gid = lane >> 2, t4 = lane & 3;
    int mb = (w & 3) * 16, nb = (w >> 2) * 32;

    pack_x64(attnIn, row0, ND, 0, nullptr, nullptr, false, Xh, Xm, tid);
    copy_w64(WpH, WpM, woTile, Wh, Wm, tid);
    __syncthreads();
    float acc[4][4] = {};
    mma64_compute(Xh, Xm, Wh, Wm, acc, mb, nb, gid, t4);
#pragma unroll
    for (int nf = 0; nf < 4; nf++) {
        int col = nb + nf*8 + t4*2;
        float2 bb = *(const float2*)(wo_b + col);
        long r0 = row0 + mb + gid, r1 = r0 + 8;
        float2 rr0 = *(const float2*)(h + r0*ND + col);
        float2 rr1 = *(const float2*)(h + r1*ND + col);
        Hs[mb+gid  ][col]   = acc[nf][0] + bb.x + rr0.x;
        Hs[mb+gid  ][col+1] = acc[nf][1] + bb.y + rr0.y;
        Hs[mb+gid+8][col]   = acc[nf][2] + bb.x + rr1.x;
        Hs[mb+gid+8][col+1] = acc[nf][3] + bb.y + rr1.y;
    }
    __syncthreads();

    {
        int r = tid >> 2, q = (tid & 3) * 16;
        float xv[16];
#pragma unroll
        for (int j = 0; j < 16; j++) xv[j] = Hs[r][q+j];
        float sum = 0.f;
#pragma unroll
        for (int j = 0; j < 16; j++) sum += xv[j];
        sum += __shfl_xor_sync(~0u, sum, 1);
        sum += __shfl_xor_sync(~0u, sum, 2);
        float mu = sum * (1.f/64.f);
        float vs = 0.f;
#pragma unroll
        for (int j = 0; j < 16; j++) { float d = xv[j] - mu; vs += d*d; }
        vs += __shfl_xor_sync(~0u, vs, 1);
        vs += __shfl_xor_sync(~0u, vs, 2);
        float inv = rsqrtf(vs * (1.f/64.f) + 1e-5f);
        int p0 = q >> 1;
#pragma unroll
        for (int u = 0; u < 8; u++) {
            float y0 = (xv[2*u]   - mu) * inv * ln2s[q+2*u]   + ln2b[q+2*u];
            float y1 = (xv[2*u+1] - mu) * inv * ln2s[q+2*u+1] + ln2b[q+2*u+1];
            uint32_t hh, m_;
            pack2(y0, y1, hh, m_);
            Xh[r][p0+u] = hh; Xm[r][p0+u] = m_;
        }
    }

    float acc2[4][4] = {};
    for (int c = 0; c < 4; c++) {
        __syncthreads();
        copy_w64(WpH, WpM, f1Tile0 + c, Wh, Wm, tid);
        __syncthreads();
        float ya[4][4] = {};
        mma64_compute(Xh, Xm, Wh, Wm, ya, mb, nb, gid, t4);
#pragma unroll
        for (int nf = 0; nf < 4; nf++) {
            int col = c*64 + nb + nf*8 + t4*2;
            float2 bb = *(const float2*)(b1 + col);
            float z0 = ya[nf][0] + bb.x, z1 = ya[nf][1] + bb.y;
            float z2 = ya[nf][2] + bb.x, z3 = ya[nf][3] + bb.y;
            float y0 = 0.5f*z0*(1.f + erff(z0*0.70710678118654752f));
            float y1 = 0.5f*z1*(1.f + erff(z1*0.70710678118654752f));
            float y2 = 0.5f*z2*(1.f + erff(z2*0.70710678118654752f));
            float y3 = 0.5f*z3*(1.f + erff(z3*0.70710678118654752f));
            int pi = (nb >> 1) + nf*4 + t4;
            uint32_t hh, m_;
            pack2(y0, y1, hh, m_); Yh[mb+gid  ][pi] = hh; Ym[mb+gid  ][pi] = m_;
            pack2(y2, y3, hh, m_); Yh[mb+gid+8][pi] = hh; Ym[mb+gid+8][pi] = m_;
        }
        __syncthreads();
        copy_w64(WpH, WpM, f2Tile0 + c, Wh, Wm, tid);
        __syncthreads();
        mma64_compute(Yh, Ym, Wh, Wm, acc2, mb, nb, gid, t4);
    }

#pragma unroll
    for (int nf = 0; nf < 4; nf++) {
        int col = nb + nf*8 + t4*2;
        float2 bb = *(const float2*)(b2 + col);
        long r0 = row0 + mb + gid, r1 = r0 + 8;
        float2 o0, o1;
        o0.x = acc2[nf][0] + bb.x + Hs[mb+gid  ][col];
        o0.y = acc2[nf][1] + bb.y + Hs[mb+gid  ][col+1];
        o1.x = acc2[nf][2] + bb.x + Hs[mb+gid+8][col];
        o1.y = acc2[nf][3] + bb.y + Hs[mb+gid+8][col+1];
        *(float2*)(h + r0*ND + col) = o0;
        *(float2*)(h + r1*ND + col) = o1;
    }
}

// ---------------- MERGED attention --------------------------------------------
__global__ __launch_bounds__(256) void merged_attn_kernel(
        const float* __restrict__ q, const float* __restrict__ k,
        const float* __restrict__ v, float* __restrict__ attn) {
    __shared__ __align__(16) float Ks[512][8];
    __shared__ __align__(16) float Vs[512][8];
    __shared__ float wmax[2][4];
    __shared__ float red[8][72];
    __shared__ float M[8];
    __shared__ __align__(16) float C[64];

    int tid = threadIdx.x;
    if (blockIdx.x < 1024) {
        int bid = blockIdx.x;
        int wpair = bid & 3, h = (bid >> 2) & 3, b = bid >> 4;
        int wb = wpair * 2;
        int half = tid >> 7;
        int t128 = tid & 127;
        int w = wb + half;
        int base = ((b*8 + h)*1024) * 8;
        int ts = (wb - 1) * 128;
        for (int idx = tid; idx < 1024; idx += 256) {
            int j = idx >> 1, hf = (idx & 1) * 4;
            int tt = ts + j;
            float4 kv = {0,0,0,0}, vv = {0,0,0,0};
            if (tt >= 0 && tt < 1024) {
                kv = *(const float4*)(k + base + tt*8 + hf);
                vv = *(const float4*)(v + base + tt*8 + hf);
            }
            *(float4*)&Ks[j][hf] = kv;
            *(float4*)&Vs[j][hf] = vv;
        }
        __syncthreads();
        int off = half * 128;
        float nm = 0.f;
        for (int r = t128; r < 384; r += 128) {
            float4 k0 = *(const float4*)&Ks[off + r][0];
            float4 k1 = *(const float4*)&Ks[off + r][4];
            float s2 = k0.x*k0.x + k0.y*k0.y + k0.z*k0.z + k0.w*k0.w
                     + k1.x*k1.x + k1.y*k1.y + k1.z*k1.z + k1.w*k1.w;
            nm = fmaxf(nm, s2);
        }
#pragma unroll
        for (int o = 16; o; o >>= 1) nm = fmaxf(nm, __shfl_xor_sync(~0u, nm, o));
        if ((t128 & 31) == 0) wmax[half][t128 >> 5] = nm;
        __syncthreads();
        float kmax2 = fmaxf(fmaxf(wmax[half][0], wmax[half][1]),
                            fmaxf(wmax[half][2], wmax[half][3]));

        int jlo = (w == 0) ? 128 : 0;
        int jhi = (w == 7) ? 256 : 384;
        int t = w*128 + t128;
        float4 q0 = *(const float4*)(q + base + t*8);
        float4 q1 = *(const float4*)(q + base + t*8 + 4);
        const float scale = 0.35355339059327373f;
        const float L2E = 1.4426950408889634f;
        float qn2 = q0.x*q0.x + q0.y*q0.y + q0.z*q0.z + q0.w*q0.w
                  + q1.x*q1.x + q1.y*q1.y + q1.z*q1.z + q1.w*q1.w;
        float sc = scale * L2E;
        ull q01 = pk2(q0.x*sc, q0.y*sc), q23 = pk2(q0.z*sc, q0.w*sc);
        ull q45 = pk2(q1.x*sc, q1.y*sc), q67 = pk2(q1.z*sc, q1.w*sc);
        float m2 = sc * sqrtf(qn2 * kmax2);
        float l = 0.f;
        ull a0 = 0, a1 = 0, a2 = 0, a3 = 0;
        for (int j = jlo; j < jhi; j++) {
            int sj = off + j;
            ulonglong2 ka = *(const ulonglong2*)&Ks[sj][0];
            ulonglong2 kb = *(const ulonglong2*)&Ks[sj][4];
            ull d2 = fma2(q01, ka.x, fma2(q23, ka.y, fma2(q45, kb.x, fma2(q67, kb.y, 0ULL))));
            float slo, shi; upk2(d2, slo, shi);
            float p = ex2(slo + shi - m2);
            l += p;
            ull pp = pk2(p, p);
            ulonglong2 va = *(const ulonglong2*)&Vs[sj][0];
            ulonglong2 vb = *(const ulonglong2*)&Vs[sj][4];
            a0 = fma2(pp, va.x, a0); a1 = fma2(pp, va.y, a1);
            a2 = fma2(pp, vb.x, a2); a3 = fma2(pp, vb.y, a3);
        }
        float inv = 1.f / l;
        float e0,e1,e2,e3,e4,e5,e6,e7;
        upk2(a0, e0, e1); upk2(a1, e2, e3); upk2(a2, e4, e5); upk2(a3, e6, e7);
        float4 o0, o1;
        o0.x = e0*inv; o0.y = e1*inv; o0.z = e2*inv; o0.w = e3*inv;
        o1.x = e4*inv; o1.y = e5*inv; o1.z = e6*inv; o1.w = e7*inv;
        long ob = ((long)(b*1024 + t)*64) + h*8;
        *(float4*)(attn + ob) = o0;
        *(float4*)(attn + ob + 4) = o1;
        return;
    }

    int gb = blockIdx.x - 1024;
    int b = gb >> 2, h = gb & 3;
    int base = ((b*8 + 4 + h)*1024) * 8;
    int warp = tid >> 5, lane = tid & 31;

    float mx[8];
#pragma unroll
    for (int d = 0; d < 8; d++) mx[d] = -1e30f;
    for (int t = tid; t < 1024; t += 256) {
        float4 k0 = *(const float4*)(k + base + t*8);
        float4 k1 = *(const float4*)(k + base + t*8 + 4);
        mx[0]=fmaxf(mx[0],k0.x); mx[1]=fmaxf(mx[1],k0.y); mx[2]=fmaxf(mx[2],k0.z); mx[3]=fmaxf(mx[3],k0.w);
        mx[4]=fmaxf(mx[4],k1.x); mx[5]=fmaxf(mx[5],k1.y); mx[6]=fmaxf(mx[6],k1.z); mx[7]=fmaxf(mx[7],k1.w);
    }
#pragma unroll
    for (int d = 0; d < 8; d++)
        for (int o = 16; o; o >>= 1) mx[d] = fmaxf(mx[d], __shfl_xor_sync(~0u, mx[d], o));
    if (lane == 0)
        for (int d = 0; d < 8; d++) red[warp][d] = mx[d];
    __syncthreads();
    if (tid < 8) {
        float m_ = red[0][tid];
        for (int wv = 1; wv < 8; wv++) m_ = fmaxf(m_, red[wv][tid]);
        M[tid] = m_;
    }
    __syncthreads();

    float Z[8] = {};
    ull ctx2[32];
#pragma unroll
    for (int i = 0; i < 32; i++) ctx2[i] = 0ULL;
    for (int t = tid; t < 1024; t += 256) {
        float4 k0 = *(const float4*)(k + base + t*8);
        float4 k1 = *(const float4*)(k + base + t*8 + 4);
        ulonglong2 va = *(const ulonglong2*)(v + base + t*8);
        ulonglong2 vb = *(const ulonglong2*)(v + base + t*8 + 4);
        ull vv[4] = {va.x, va.y, vb.x, vb.y};
        float kr[8] = {k0.x,k0.y,k0.z,k0.w,k1.x,k1.y,k1.z,k1.w};
#pragma unroll
        for (int d = 0; d < 8; d++) {
            float e_ = __expf(kr[d] - M[d]);
            Z[d] += e_;
            ull pd = pk2(e_, e_);
#pragma unroll
            for (int e2i = 0; e2i < 4; e2i++) ctx2[d*4 + e2i] = fma2(pd, vv[e2i], ctx2[d*4 + e2i]);
        }
    }
    float ctx[64];
#pragma unroll
    for (int i = 0; i < 32; i++) upk2(ctx2[i], ctx[2*i], ctx[2*i+1]);
#pragma unroll
    for (int i = 0; i < 8; i++)
        for (int o = 16; o; o >>= 1) Z[i] += __shfl_xor_sync(~0u, Z[i], o);
#pragma unroll
    for (int i = 0; i < 64; i++)
        for (int o = 16; o; o >>= 1) ctx[i] += __shfl_xor_sync(~0u, ctx[i], o);
    if (lane == 0) {
        for (int i = 0; i < 8; i++)  red[warp][i] = Z[i];
        for (int i = 0; i < 64; i++) red[warp][8 + i] = ctx[i];
    }
    __syncthreads();
    if (tid < 64) {
        float s = 0.f, z = 0.f;
        int d = tid >> 3;
        for (int wv = 0; wv < 8; wv++) { s += red[wv][8 + tid]; z += red[wv][d]; }
        C[tid] = s / z;
    }
    __syncthreads();

    const float scale = 0.35355339059327373f;
    for (int t = tid; t < 1024; t += 256) {
        float4 q0 = *(const float4*)(q + base + t*8);
        float4 q1 = *(const float4*)(q + base + t*8 + 4);
        float qr[8] = {q0.x,q0.y,q0.z,q0.w,q1.x,q1.y,q1.z,q1.w};
        float qm = -1e30f;
#pragma unroll
        for (int d = 0; d < 8; d++) qm = fmaxf(qm, qr[d]);
        float qs = 0.f;
#pragma unroll
        for (int d = 0; d < 8; d++) { qr[d] = __expf(qr[d] - qm); qs += qr[d]; }
        float inv = scale / qs;
        ull o2[4] = {0ULL, 0ULL, 0ULL, 0ULL};
#pragma unroll
        for (int d = 0; d < 8; d++) {
            float p = qr[d] * inv;
            ull pd = pk2(p, p);
            const ulonglong2* Cd = (const ulonglong2*)&C[d*8];
            ulonglong2 c0 = Cd[0], c1 = Cd[1];
            o2[0] = fma2(pd, c0.x, o2[0]); o2[1] = fma2(pd, c0.y, o2[1]);
            o2[2] = fma2(pd, c1.x, o2[2]); o2[3] = fma2(pd, c1.y, o2[3]);
        }
        float e0,e1,e2,e3,e4,e5,e6,e7;
        upk2(o2[0], e0, e1); upk2(o2[1], e2, e3); upk2(o2[2], e4, e5); upk2(o2[3], e6, e7);
        long ob = (long)(b*1024 + t)*64 + (4 + h)*8;
        float4 oo0, oo1;
        oo0.x=e0; oo0.y=e1; oo0.z=e2; oo0.w=e3;
        oo1.x=e4; oo1.y=e5; oo1.z=e6; oo1.w=e7;
        *(float4*)(attn + ob) = oo0;
        *(float4*)(attn + ob + 4) = oo1;
    }
}

// ---------------- collapse -----------------------------------------------------
__global__ __launch_bounds__(256) void collapse_kernel(
        const float* __restrict__ h, const float* __restrict__ cw,
        const float* __restrict__ cb, float* __restrict__ out) {
    __shared__ float Xs[64][68];
    __shared__ float Ws[64][NDIN];
    __shared__ float Bs[NDIN];
    int tid = threadIdx.x;
    int row0 = blockIdx.x * 64;
    for (int idx = tid; idx < 1024; idx += 256) {
        int i = idx >> 4, j = (idx & 15) * 4;
        *(float4*)&Xs[i][j] = *(const float4*)(h + (long)(row0 + i)*ND + j);
    }
    for (int idx = tid; idx < 64*NDIN; idx += 256) Ws[idx/NDIN][idx%NDIN] = cw[idx];
    if (tid < NDIN) Bs[tid] = cb[tid];
    __syncthreads();
    int r = tid >> 2, qk = (tid & 3) * 16;
    float acc[NDIN] = {};
    for (int kk = qk; kk < qk + 16; kk++) {
        float xv = Xs[r][kk];
#pragma unroll
        for (int j = 0; j < NDIN; j++) acc[j] += xv * Ws[kk][j];
    }
#pragma unroll
    for (int j = 0; j < NDIN; j++) {
        acc[j] += __shfl_xor_sync(~0u, acc[j], 1);
        acc[j] += __shfl_xor_sync(~0u, acc[j], 2);
    }
    if ((tid & 3) == 0) {
#pragma unroll
        for (int j = 0; j < NDIN; j++) out[(row0 + r)*NDIN + j] = acc[j] + Bs[j];
    }
}

// ---------------- launch ------------------------------------------------------
extern "C" void kernel_launch(void* const* d_in, const int* in_sizes, int n_in,
                              void* d_out, int out_size) {
    const float* x          = (const float*)d_in[0];
    const float* pos_emb    = (const float*)d_in[1];
    const float* expand_w   = (const float*)d_in[2];
    const float* expand_b   = (const float*)d_in[3];
    const float* emb_w      = (const float*)d_in[4];
    const float* emb_b      = (const float*)d_in[5];
    const float* conv_w     = (const float*)d_in[6];
    const float* conv_b     = (const float*)d_in[7];
    const float* ln1_s      = (const float*)d_in[8];
    const float* ln1_b      = (const float*)d_in[9];
    const float* wq         = (const float*)d_in[10];
    const float* wk         = (const float*)d_in[11];
    const float* wv         = (const float*)d_in[12];
    const float* wo         = (const float*)d_in[13];
    const float* wo_b       = (const float*)d_in[14];
    const float* ln2_s      = (const float*)d_in[15];
    const float* ln2_b      = (const float*)d_in[16];
    const float* ff_w1      = (const float*)d_in[17];
    const float* ff_b1      = (const float*)d_in[18];
    const float* ff_w2      = (const float*)d_in[19];
    const float* ff_b2      = (const float*)d_in[20];
    const float* collapse_w = (const float*)d_in[21];
    const float* collapse_b = (const float*)d_in[22];
    float* out = (float*)d_out;

    float *ph, *pq, *pk, *pv, *pattn, *pWc, *pbc;
    uint32_t *pWpH, *pWpM, *pAH, *pAM, *pBH;
    cudaGetSymbolAddress((void**)&ph,   g_h);
    cudaGetSymbolAddress((void**)&pq,   g_q);
    cudaGetSymbolAddress((void**)&pk,   g_k);
    cudaGetSymbolAddress((void**)&pv,   g_v);
    cudaGetSymbolAddress((void**)&pattn,g_attn);
    cudaGetSymbolAddress((void**)&pWc,  g_Wc);
    cudaGetSymbolAddress((void**)&pbc,  g_bc);
    cudaGetSymbolAddress((void**)&pWpH, g_WpH);
    cudaGetSymbolAddress((void**)&pWpM, g_WpM);
    cudaGetSymbolAddress((void**)&pAH,  g_AH);
    cudaGetSymbolAddress((void**)&pAM,  g_AM);
    cudaGetSymbolAddress((void**)&pBH,  g_BH);

    static bool attrSet = false;
    if (!attrSet) {
        cudaFuncSetAttribute(attn_ffn_kernel, cudaFuncAttributeMaxDynamicSharedMemorySize, FUSED_SMEM);
        cudaFuncSetAttribute(conv_kernel, cudaFuncAttributeMaxDynamicSharedMemorySize, CONV_SMEM);
        cudaFuncSetAttribute(lnqkv_kernel, cudaFuncAttributeMaxDynamicSharedMemorySize, QKV_SMEM);
        attrSet = true;
    }

    precompute_kernel<<<1, 64>>>(expand_w, expand_b, emb_w, emb_b, pWc, pbc);
    packw_kernel<<<24, 256>>>(wq, wk, wv, wo, ff_w1, ff_w2, pWpH, pWpM);
    packa_kernel<<<(1024*1536)/256, 256>>>(conv_w, pAH, pAM);
    packbx_kernel<<<(1536*4096)/256, 256>>>(x, pWc, pbc, pBH);
    conv_kernel<<<dim3(4096/CBN, 1024/CBM), 256, CONV_SMEM>>>(pAH, pAM, pBH, conv_b, pos_emb, ph);

    for (int l = 0; l < 2; l++) {
        int tb = l*12;
        lnqkv_kernel<<<NTOK/64, 256, QKV_SMEM>>>(ph, ln1_s + l*64, ln1_b + l*64,
                                                 pWpH, pWpM, tb + 0, pq, pk, pv);
        merged_attn_kernel<<<1024 + 256, 256>>>(pq, pk, pv, pattn);
        attn_ffn_kernel<<<NTOK/64, 256, FUSED_SMEM>>>(
            pattn, pWpH, pWpM, tb + 3, tb + 4, tb + 8,
            wo_b + l*64, ln2_s + l*64, ln2_b + l*64,
            ff_b1 + l*256, ff_b2 + l*64, ph);
    }
    collapse_kernel<<<NTOK/64, 256>>>(ph, collapse_w, collapse_b, out);
}